// round 1
// baseline (speedup 1.0000x reference)
#include <cuda_runtime.h>

#define NB   2
#define NF   8192
#define DIMM 512
#define NH   8
#define DH   64
#define LM   256
#define QD   1536
#define TOT  (NB*NF)    // 16384
#define NBH  (NB*NH)    // 16
#define KER  33

// ------------------------- scratch (device globals, no allocs) -------------
__device__ float g_X  [TOT*DIMM];
__device__ float g_XN [TOT*DIMM];
__device__ float g_QKV[TOT*QD];
__device__ float g_QL [NBH*LM*DH];
__device__ float g_KL [NBH*LM*DH];
__device__ float g_S1 [NBH*NF*LM];
__device__ float g_S3 [NBH*LM*NF];
__device__ float g_S2 [NBH*LM*LM];
__device__ float g_Zb [NBH*LM*LM];
__device__ float g_Z2b[NBH*LM*LM];
__device__ float g_Pb [NBH*LM*LM];
__device__ float g_Tb [NBH*LM*LM];
__device__ float g_T2b[NBH*LM*LM];
__device__ float g_AV [NBH*LM*DH];
__device__ float g_ZAV[NBH*LM*DH];
__device__ float g_OH [NBH*NF*DH];
__device__ float g_OT [TOT*DIMM];
__device__ unsigned int g_scale[2];

// ------------------------- reductions --------------------------------------
__device__ __forceinline__ float blockReduce(float v, bool domax) {
    __shared__ float sh[32];
    __syncthreads();
    #pragma unroll
    for (int o = 16; o > 0; o >>= 1) {
        float w = __shfl_down_sync(0xffffffffu, v, o);
        v = domax ? fmaxf(v, w) : v + w;
    }
    int lane = threadIdx.x & 31, wid = threadIdx.x >> 5;
    if (lane == 0) sh[wid] = v;
    __syncthreads();
    int nw = (blockDim.x + 31) >> 5;
    if (wid == 0) {
        v = (lane < nw) ? sh[lane] : (domax ? -1e30f : 0.f);
        #pragma unroll
        for (int o = 16; o > 0; o >>= 1) {
            float w = __shfl_down_sync(0xffffffffu, v, o);
            v = domax ? fmaxf(v, w) : v + w;
        }
        if (lane == 0) sh[0] = v;
    }
    __syncthreads();
    return sh[0];
}

// ------------------------- generic batched GEMM ----------------------------
// C[r,c] = alpha * sum_k A[r,k] * (TRANSB ? B[c,k] : B[k,c]),  batch z:
// offset = (z>>3)*s1 + (z&7)*s2 for each of A,B,C.
// Epilogues: 0 plain; 1 relu(acc+bias) with input-proj row remap into g_X;
//            2 scale cols<512 by 0.125 (q scaling); 3 C += acc + bias.
template<int TRANSB>
__global__ void __launch_bounds__(256) gemm_k(
    int M, int N, int K,
    const float* __restrict__ A, int lda, long long sA1, long long sA2,
    const float* __restrict__ Bp, int ldb, long long sB1, long long sB2,
    float* __restrict__ C, int ldc, long long sC1, long long sC2,
    float alpha, int ep, const float* __restrict__ bias)
{
    __shared__ float As[16][68];
    __shared__ float Bs[16][68];
    int z = blockIdx.z;
    A  += (long long)(z >> 3) * sA1 + (long long)(z & 7) * sA2;
    Bp += (long long)(z >> 3) * sB1 + (long long)(z & 7) * sB2;
    C  += (long long)(z >> 3) * sC1 + (long long)(z & 7) * sC2;
    int row0 = blockIdx.y << 6;
    int col0 = blockIdx.x << 6;
    int tid = threadIdx.x;
    int tx = tid & 15, ty = tid >> 4;

    float acc[4][4];
    #pragma unroll
    for (int i = 0; i < 4; i++)
        #pragma unroll
        for (int j = 0; j < 4; j++) acc[i][j] = 0.f;

    int lin = tid << 2;
    for (int k0 = 0; k0 < K; k0 += 16) {
        // A tile: 64 rows x 16 k, 4 consecutive k per thread
        {
            int r  = lin >> 4;
            int kk = lin & 15;
            int gr = row0 + r;
            float4 v = make_float4(0.f, 0.f, 0.f, 0.f);
            if (gr < M) v = *(const float4*)(A + (long long)gr * lda + k0 + kk);
            As[kk + 0][r] = v.x;
            As[kk + 1][r] = v.y;
            As[kk + 2][r] = v.z;
            As[kk + 3][r] = v.w;
        }
        // B tile
        if (!TRANSB) {
            int kk = lin >> 6;
            int n  = lin & 63;
            float4 v = *(const float4*)(Bp + (long long)(k0 + kk) * ldb + col0 + n);
            *(float4*)&Bs[kk][n] = v;
        } else {
            int n  = lin >> 4;
            int kk = lin & 15;
            float4 v = *(const float4*)(Bp + (long long)(col0 + n) * ldb + k0 + kk);
            Bs[kk + 0][n] = v.x;
            Bs[kk + 1][n] = v.y;
            Bs[kk + 2][n] = v.z;
            Bs[kk + 3][n] = v.w;
        }
        __syncthreads();
        #pragma unroll
        for (int kk = 0; kk < 16; kk++) {
            float4 a = *(const float4*)&As[kk][ty << 2];
            float4 b = *(const float4*)&Bs[kk][tx << 2];
            acc[0][0] += a.x * b.x; acc[0][1] += a.x * b.y; acc[0][2] += a.x * b.z; acc[0][3] += a.x * b.w;
            acc[1][0] += a.y * b.x; acc[1][1] += a.y * b.y; acc[1][2] += a.y * b.z; acc[1][3] += a.y * b.w;
            acc[2][0] += a.z * b.x; acc[2][1] += a.z * b.y; acc[2][2] += a.z * b.z; acc[2][3] += a.z * b.w;
            acc[3][0] += a.w * b.x; acc[3][1] += a.w * b.y; acc[3][2] += a.w * b.z; acc[3][3] += a.w * b.w;
        }
        __syncthreads();
    }

    #pragma unroll
    for (int i = 0; i < 4; i++) {
        int r = row0 + (ty << 2) + i;
        if (r >= M) continue;
        #pragma unroll
        for (int j = 0; j < 4; j++) {
            int c = col0 + (tx << 2) + j;
            if (c >= N) continue;
            float a = acc[i][j];
            if (ep == 1) {
                int bb = r / 8191;
                long long o = (long long)(r + bb + 1) * ldc + c;
                float v = a + bias[c];
                C[o] = v > 0.f ? v : 0.f;
            } else if (ep == 2) {
                C[(long long)r * ldc + c] = a * (c < 512 ? 0.125f : 1.0f);
            } else if (ep == 3) {
                long long o = (long long)r * ldc + c;
                C[o] = C[o] + a + bias[c];
            } else {
                C[(long long)r * ldc + c] = alpha * a;
            }
        }
    }
}

// ------------------------- layernorm (rows of 512) --------------------------
__global__ void __launch_bounds__(256) ln_k(const float* __restrict__ X, float* __restrict__ Y,
                                            const float* __restrict__ g, const float* __restrict__ b)
{
    long long row = blockIdx.x;
    const float* x = X + row * DIMM;
    float* y = Y + row * DIMM;
    int t = threadIdx.x;
    float v0 = x[t], v1 = x[t + 256];
    float mu  = blockReduce(v0 + v1, false) * (1.f / 512.f);
    float d0 = v0 - mu, d1 = v1 - mu;
    float var = blockReduce(d0 * d0 + d1 * d1, false) * (1.f / 512.f);
    float inv = rsqrtf(var + 1e-5f);
    y[t]       = d0 * inv * g[t]       + b[t];
    y[t + 256] = d1 * inv * g[t + 256] + b[t + 256];
}

// ------------------------- row softmax (smem-resident row) ------------------
__global__ void __launch_bounds__(256) softmax_k(float* __restrict__ S, int cols)
{
    extern __shared__ float buf[];
    long long row = blockIdx.x;
    float* s = S + row * cols;
    int t = threadIdx.x;
    float mx = -1e30f;
    for (int i = t; i < cols; i += 256) { float v = s[i]; buf[i] = v; mx = fmaxf(mx, v); }
    float bmax = blockReduce(mx, true);
    float sum = 0.f;
    for (int i = t; i < cols; i += 256) { float e = __expf(buf[i] - bmax); buf[i] = e; sum += e; }
    float bsum = blockReduce(sum, false);
    float inv = 1.f / bsum;
    for (int i = t; i < cols; i += 256) s[i] = buf[i] * inv;
}

// ------------------------- landmarks (mean of 32 consecutive rows) ----------
__global__ void __launch_bounds__(64) landmark_k()
{
    int zz = blockIdx.x;          // bh*256 + mi
    int mi = zz & 255, bh = zz >> 8;
    int b = bh >> 3, h = bh & 7;
    int d = threadIdx.x;
    const float* base = g_QKV + (long long)(b * NF + mi * 32) * QD + h * 64 + d;
    float sq = 0.f, sk = 0.f;
    #pragma unroll 8
    for (int il = 0; il < 32; il++) {
        sq += base[(long long)il * QD];
        sk += base[(long long)il * QD + 512];
    }
    long long o = ((long long)bh * LM + mi) * DH + d;
    g_QL[o] = sq * (1.f / 32.f);
    g_KL[o] = sk * (1.f / 32.f);
}

// ------------------------- pinv helpers -------------------------------------
__global__ void reset_k() { g_scale[0] = 0u; g_scale[1] = 0u; }

__global__ void __launch_bounds__(256) scalemax_k()
{
    int z = blockIdx.x;
    int i = threadIdx.x;
    const float* S = g_S2 + ((long long)z << 16);
    float rs = 0.f, cs = 0.f;
    for (int j = 0; j < 256; j++) { rs += S[(i << 8) + j]; cs += S[(j << 8) + i]; }
    float rm = blockReduce(rs, true);   // "col" in ref: max row-sum
    float cm = blockReduce(cs, true);   // "row" in ref: max col-sum
    if (i == 0) {
        atomicMax(&g_scale[0], __float_as_uint(rm));
        atomicMax(&g_scale[1], __float_as_uint(cm));
    }
}

__global__ void __launch_bounds__(256) zinit_k()
{
    int idx = blockIdx.x * 256 + threadIdx.x;       // 16*65536 total
    float inv = 1.0f / (__uint_as_float(g_scale[0]) * __uint_as_float(g_scale[1]));
    int z = idx >> 16, r = idx & 65535;
    int i = r >> 8, j = r & 255;
    g_Zb[((long long)z << 16) + (i << 8) + j] = g_S2[((long long)z << 16) + (j << 8) + i] * inv;
}

__global__ void __launch_bounds__(256) negI_k(const float* __restrict__ src, float* __restrict__ dst, float c)
{
    int idx = blockIdx.x * 256 + threadIdx.x;
    int i = (idx >> 8) & 255, j = idx & 255;
    dst[idx] = (i == j ? c : 0.f) - src[idx];
}

// ------------------------- depthwise conv residual (adds into g_OH) ---------
__global__ void __launch_bounds__(256) conv_k(const float* __restrict__ cw)
{
    __shared__ float sv[160 * 64];
    __shared__ float sw[KER];
    int tile = blockIdx.x;   // 64 tiles of 128 rows
    int bh = blockIdx.y;     // 16
    int b = bh >> 3, h = bh & 7;
    int n0 = tile * 128;
    int t = threadIdx.x;
    if (t < KER) sw[t] = cw[h * KER + t];
    for (int idx = t; idx < 160 * 64; idx += 256) {
        int r = idx >> 6, d = idx & 63;
        int nn = n0 - 16 + r;
        float v = 0.f;
        if (nn >= 0 && nn < NF) v = g_QKV[(long long)(b * NF + nn) * QD + 1024 + h * 64 + d];
        sv[idx] = v;
    }
    __syncthreads();
    int d = t & 63, r0 = t >> 6;
    for (int rr = r0; rr < 128; rr += 4) {
        float a = 0.f;
        #pragma unroll
        for (int k = 0; k < KER; k++) a += sv[(rr + k) * 64 + d] * sw[k];
        long long o = ((long long)bh * NF + n0 + rr) * DH + d;
        g_OH[o] += a;
    }
}

// ------------------------- (b,h,n,d) -> (b,n, h*64+d) -----------------------
__global__ void __launch_bounds__(256) trans_k()
{
    long long o = (long long)blockIdx.x * 256 + threadIdx.x;
    int c = (int)(o & 511);
    long long bn = o >> 9;
    int n = (int)(bn & (NF - 1));
    int b = (int)(bn >> 13);
    int h = c >> 6, d = c & 63;
    g_OT[o] = g_OH[(((long long)(b * NH + h) * NF + n) << 6) + d];
}

// ------------------------- cls token fill -----------------------------------
__global__ void __launch_bounds__(256) cls_k(const float* __restrict__ ct)
{
    int idx = blockIdx.x * 256 + threadIdx.x;   // 1024
    int b = idx >> 9, c = idx & 511;
    g_X[(long long)b * NF * DIMM + c] = ct[c];
}

// ------------------------- final LN + head ----------------------------------
__global__ void __launch_bounds__(256) final_k(const float* __restrict__ fg, const float* __restrict__ fb,
                                               const float* __restrict__ w2, const float* __restrict__ b2,
                                               float* __restrict__ out)
{
    int b = blockIdx.x;
    const float* x = g_X + (long long)b * NF * DIMM;
    int t = threadIdx.x;
    float v0 = x[t], v1 = x[t + 256];
    float mu  = blockReduce(v0 + v1, false) * (1.f / 512.f);
    float d0 = v0 - mu, d1 = v1 - mu;
    float var = blockReduce(d0 * d0 + d1 * d1, false) * (1.f / 512.f);
    float inv = rsqrtf(var + 1e-5f);
    float n0 = d0 * inv * fg[t]       + fb[t];
    float n1 = d1 * inv * fg[t + 256] + fb[t + 256];
    float p0 = n0 * w2[2 * t]     + n1 * w2[2 * (t + 256)];
    float p1 = n0 * w2[2 * t + 1] + n1 * w2[2 * (t + 256) + 1];
    p0 = blockReduce(p0, false);
    p1 = blockReduce(p1, false);
    if (t == 0) {
        out[b * 2 + 0] = p0 + b2[0];
        out[b * 2 + 1] = p1 + b2[1];
    }
}

// ------------------------- host orchestration -------------------------------
enum { EP_NONE = 0, EP_RELU_REMAP = 1, EP_SCALEQ = 2, EP_ADDBIAS = 3 };

static inline void gemm(int transB, int M, int N, int K,
                        const float* A, int lda, long long sA1, long long sA2,
                        const float* Bp, int ldb, long long sB1, long long sB2,
                        float* C, int ldc, long long sC1, long long sC2,
                        int batch, float alpha, int ep, const float* bias)
{
    dim3 g(N >> 6, (M + 63) >> 6, batch);
    if (transB)
        gemm_k<1><<<g, 256>>>(M, N, K, A, lda, sA1, sA2, Bp, ldb, sB1, sB2, C, ldc, sC1, sC2, alpha, ep, bias);
    else
        gemm_k<0><<<g, 256>>>(M, N, K, A, lda, sA1, sA2, Bp, ldb, sB1, sB2, C, ldc, sC1, sC2, alpha, ep, bias);
}

extern "C" void kernel_launch(void* const* d_in, const int* in_sizes, int n_in,
                              void* d_out, int out_size)
{
    const float* h_in  = (const float*)d_in[0];
    const float* w1    = (const float*)d_in[1];
    const float* b1    = (const float*)d_in[2];
    const float* clst  = (const float*)d_in[3];
    const float* ln_g  = (const float*)d_in[4];
    const float* ln_b  = (const float*)d_in[5];
    const float* wqkv  = (const float*)d_in[6];
    const float* wout  = (const float*)d_in[7];
    const float* bout  = (const float*)d_in[8];
    const float* cw    = (const float*)d_in[9];
    const float* fg    = (const float*)d_in[10];
    const float* fb    = (const float*)d_in[11];
    const float* w2    = (const float*)d_in[12];
    const float* b2    = (const float*)d_in[13];
    float* out = (float*)d_out;

    float *X, *XN, *QKV, *QL, *KL, *S1, *S2, *S3, *Z, *Z2, *P, *T, *T2, *AV, *ZAV, *OH, *OT;
    cudaGetSymbolAddress((void**)&X,   g_X);
    cudaGetSymbolAddress((void**)&XN,  g_XN);
    cudaGetSymbolAddress((void**)&QKV, g_QKV);
    cudaGetSymbolAddress((void**)&QL,  g_QL);
    cudaGetSymbolAddress((void**)&KL,  g_KL);
    cudaGetSymbolAddress((void**)&S1,  g_S1);
    cudaGetSymbolAddress((void**)&S2,  g_S2);
    cudaGetSymbolAddress((void**)&S3,  g_S3);
    cudaGetSymbolAddress((void**)&Z,   g_Zb);
    cudaGetSymbolAddress((void**)&Z2,  g_Z2b);
    cudaGetSymbolAddress((void**)&P,   g_Pb);
    cudaGetSymbolAddress((void**)&T,   g_Tb);
    cudaGetSymbolAddress((void**)&T2,  g_T2b);
    cudaGetSymbolAddress((void**)&AV,  g_AV);
    cudaGetSymbolAddress((void**)&ZAV, g_ZAV);
    cudaGetSymbolAddress((void**)&OH,  g_OH);
    cudaGetSymbolAddress((void**)&OT,  g_OT);

    const long long SQb = (long long)NF * QD;           // 12582912 (b-stride in QKV)
    const long long S2s = (long long)LM * LM;           // 65536
    const long long S1s = (long long)NF * LM;           // 2097152
    const long long AVs = (long long)LM * DH;           // 16384
    const long long OHs = (long long)NF * DH;           // 524288

    // input projection: X[b, n+1, :] = relu(h @ w1 + b1); X[b,0,:] = cls
    gemm(0, NB * 8191, DIMM, 1024, h_in, 1024, 0, 0, w1, DIMM, 0, 0,
         X, DIMM, 0, 0, 1, 1.f, EP_RELU_REMAP, b1);
    cls_k<<<4, 256>>>(clst);

    for (int L = 0; L < 2; L++) {
        ln_k<<<TOT, 256>>>(X, XN, ln_g + L * DIMM, ln_b + L * DIMM);

        // qkv = ln(x) @ Wqkv  (q cols scaled by 1/8)
        gemm(0, TOT, QD, DIMM, XN, DIMM, 0, 0, wqkv + (long long)L * DIMM * QD, QD, 0, 0,
             QKV, QD, 0, 0, 1, 1.f, EP_SCALEQ, nullptr);

        landmark_k<<<NBH * LM, 64>>>();

        // sim2 = QL @ KL^T, softmax
        gemm(1, LM, LM, DH, QL, DH, 8 * AVs, AVs, KL, DH, 8 * AVs, AVs,
             S2, LM, 8 * S2s, S2s, NBH, 1.f, EP_NONE, nullptr);
        softmax_k<<<NBH * LM, 256, LM * 4>>>(S2, LM);

        // Moore-Penrose pinv of S2 -> Z (6 Newton iters, result lands in Z)
        reset_k<<<1, 1>>>();
        scalemax_k<<<NBH, 256>>>();
        zinit_k<<<4096, 256>>>();
        for (int it = 0; it < 6; it++) {
            float* Zin  = (it & 1) ? Z2 : Z;
            float* Zout = (it & 1) ? Z  : Z2;
            gemm(0, LM, LM, LM, S2, LM, 8 * S2s, S2s, Zin, LM, 8 * S2s, S2s,
                 P, LM, 8 * S2s, S2s, NBH, 1.f, EP_NONE, nullptr);
            negI_k<<<4096, 256>>>(P, T, 7.f);
            gemm(0, LM, LM, LM, P, LM, 8 * S2s, S2s, T, LM, 8 * S2s, S2s,
                 T2, LM, 8 * S2s, S2s, NBH, 1.f, EP_NONE, nullptr);
            negI_k<<<4096, 256>>>(T2, T, 15.f);
            gemm(0, LM, LM, LM, P, LM, 8 * S2s, S2s, T, LM, 8 * S2s, S2s,
                 T2, LM, 8 * S2s, S2s, NBH, 1.f, EP_NONE, nullptr);
            negI_k<<<4096, 256>>>(T2, T, 13.f);
            gemm(0, LM, LM, LM, Zin, LM, 8 * S2s, S2s, T, LM, 8 * S2s, S2s,
                 Zout, LM, 8 * S2s, S2s, NBH, 0.25f, EP_NONE, nullptr);
        }

        // sim1 = Q @ KL^T  (Q strided in QKV), softmax
        gemm(1, NF, LM, DH, QKV, QD, SQb, 64, KL, DH, 8 * AVs, AVs,
             S1, LM, 8 * S1s, S1s, NBH, 1.f, EP_NONE, nullptr);
        softmax_k<<<NBH * NF, 256, LM * 4>>>(S1, LM);

        // sim3 = QL @ K^T, softmax over 8192
        gemm(1, LM, NF, DH, QL, DH, 8 * AVs, AVs, QKV + 512, QD, SQb, 64,
             S3, NF, 8 * S1s, S1s, NBH, 1.f, EP_NONE, nullptr);
        softmax_k<<<NBH * LM, 256, NF * 4>>>(S3, NF);

        // AV = attn3 @ V
        gemm(0, LM, DH, NF, S3, NF, 8 * S1s, S1s, QKV + 1024, QD, SQb, 64,
             AV, DH, 8 * AVs, AVs, NBH, 1.f, EP_NONE, nullptr);
        // ZAV = Z @ AV
        gemm(0, LM, DH, LM, Z, LM, 8 * S2s, S2s, AV, DH, 8 * AVs, AVs,
             ZAV, DH, 8 * AVs, AVs, NBH, 1.f, EP_NONE, nullptr);
        // OH = attn1 @ ZAV
        gemm(0, NF, DH, LM, S1, LM, 8 * S1s, S1s, ZAV, DH, 8 * AVs, AVs,
             OH, DH, 8 * OHs, OHs, NBH, 1.f, EP_NONE, nullptr);

        // OH += depthwise conv residual of V
        { dim3 g(NF / 128, NBH); conv_k<<<g, 256>>>(cw + L * NH * KER); }

        // transpose heads back, then X += OHt @ Wout + bout
        trans_k<<<(TOT * DIMM) / 256, 256>>>();
        gemm(0, TOT, DIMM, DIMM, OT, DIMM, 0, 0, wout + (long long)L * DIMM * DIMM, DIMM, 0, 0,
             X, DIMM, 0, 0, 1, 1.f, EP_ADDBIAS, bout + L * DIMM);
    }

    final_k<<<NB, 256>>>(fg, fb, w2, b2, out);
}

// round 2
// speedup vs baseline: 1.1712x; 1.1712x over previous
#include <cuda_runtime.h>

#define NB   2
#define NF   8192
#define DIMM 512
#define NH   8
#define DH   64
#define LM   256
#define QD   1536
#define TOT  (NB*NF)    // 16384
#define NBH  (NB*NH)    // 16
#define KER  33
#define KSPL 8

// ------------------------- scratch (device globals, no allocs) -------------
__device__ float g_X  [TOT*DIMM];
__device__ float g_XN [TOT*DIMM];
__device__ float g_QKV[TOT*QD];
__device__ float g_QL [NBH*LM*DH];
__device__ float g_KL [NBH*LM*DH];
__device__ float g_S1 [NBH*NF*LM];
__device__ float g_S3 [NBH*LM*NF];
__device__ float g_S2 [NBH*LM*LM];
__device__ float g_Zb [NBH*LM*LM];
__device__ float g_Z2b[NBH*LM*LM];
__device__ float g_Pb [NBH*LM*LM];
__device__ float g_Tb [NBH*LM*LM];
__device__ float g_T2b[NBH*LM*LM];
__device__ float g_AV [NBH*LM*DH];
__device__ float g_AVp[NBH*KSPL*LM*DH];
__device__ float g_ZAV[NBH*LM*DH];
__device__ float g_OH [NBH*NF*DH];
__device__ float g_OT [TOT*DIMM];
__device__ unsigned int g_scale[2];

enum { EP_NONE = 0, EP_RELU_REMAP = 1, EP_SCALEQ = 2, EP_ADDBIAS = 3 };

// ------------------------- reductions --------------------------------------
__device__ __forceinline__ float blockReduce(float v, bool domax) {
    __shared__ float sh[32];
    __syncthreads();
    #pragma unroll
    for (int o = 16; o > 0; o >>= 1) {
        float w = __shfl_down_sync(0xffffffffu, v, o);
        v = domax ? fmaxf(v, w) : v + w;
    }
    int lane = threadIdx.x & 31, wid = threadIdx.x >> 5;
    if (lane == 0) sh[wid] = v;
    __syncthreads();
    int nw = (blockDim.x + 31) >> 5;
    if (wid == 0) {
        v = (lane < nw) ? sh[lane] : (domax ? -1e30f : 0.f);
        #pragma unroll
        for (int o = 16; o > 0; o >>= 1) {
            float w = __shfl_down_sync(0xffffffffu, v, o);
            v = domax ? fmaxf(v, w) : v + w;
        }
        if (lane == 0) sh[0] = v;
    }
    __syncthreads();
    return sh[0];
}

// ===================== 128x128x16 GEMM, 8x8 microtile =======================
// C[r,c] = alpha * sum_k A[r,k] * (TRANSB ? B[c,k] : B[k,c])
// batch z: offset = (z>>3)*s1 + (z&7)*s2
template<int TRANSB>
__global__ void __launch_bounds__(256, 2) gemm128_k(
    int M, int N, int K,
    const float* __restrict__ A, int lda, long long sA1, long long sA2,
    const float* __restrict__ Bp, int ldb, long long sB1, long long sB2,
    float* __restrict__ C, int ldc, long long sC1, long long sC2,
    float alpha, int ep, const float* __restrict__ bias)
{
    __shared__ float As[16][136];
    __shared__ float Bs[16][136];
    int z = blockIdx.z;
    A  += (long long)(z >> 3) * sA1 + (long long)(z & 7) * sA2;
    Bp += (long long)(z >> 3) * sB1 + (long long)(z & 7) * sB2;
    C  += (long long)(z >> 3) * sC1 + (long long)(z & 7) * sC2;
    int row0 = blockIdx.y << 7;
    int col0 = blockIdx.x << 7;
    int tid = threadIdx.x;
    int tx = tid & 15, ty = tid >> 4;   // 8 cols per tx, 8 rows per ty

    float acc[8][8];
    #pragma unroll
    for (int i = 0; i < 8; i++)
        #pragma unroll
        for (int j = 0; j < 8; j++) acc[i][j] = 0.f;

    for (int k0 = 0; k0 < K; k0 += 16) {
        // A tile: 128 rows x 16 k
        #pragma unroll
        for (int l = 0; l < 2; l++) {
            int idx = tid + l * 256;
            int r  = idx >> 2;
            int kk = (idx & 3) << 2;
            float4 v = make_float4(0.f, 0.f, 0.f, 0.f);
            int gr = row0 + r;
            if (gr < M) v = *(const float4*)(A + (long long)gr * lda + k0 + kk);
            As[kk + 0][r] = v.x;
            As[kk + 1][r] = v.y;
            As[kk + 2][r] = v.z;
            As[kk + 3][r] = v.w;
        }
        // B tile: 16 k x 128 cols
        #pragma unroll
        for (int l = 0; l < 2; l++) {
            int idx = tid + l * 256;
            if (!TRANSB) {
                int kk = idx >> 5;
                int n  = (idx & 31) << 2;
                float4 v = *(const float4*)(Bp + (long long)(k0 + kk) * ldb + col0 + n);
                *(float4*)&Bs[kk][n] = v;
            } else {
                int n  = idx >> 2;
                int kk = (idx & 3) << 2;
                float4 v = *(const float4*)(Bp + (long long)(col0 + n) * ldb + k0 + kk);
                Bs[kk + 0][n] = v.x;
                Bs[kk + 1][n] = v.y;
                Bs[kk + 2][n] = v.z;
                Bs[kk + 3][n] = v.w;
            }
        }
        __syncthreads();
        #pragma unroll
        for (int kk = 0; kk < 16; kk++) {
            float4 a0 = *(const float4*)&As[kk][(ty << 3)];
            float4 a1 = *(const float4*)&As[kk][(ty << 3) + 4];
            float4 b0 = *(const float4*)&Bs[kk][(tx << 3)];
            float4 b1 = *(const float4*)&Bs[kk][(tx << 3) + 4];
            float av[8] = {a0.x, a0.y, a0.z, a0.w, a1.x, a1.y, a1.z, a1.w};
            float bv[8] = {b0.x, b0.y, b0.z, b0.w, b1.x, b1.y, b1.z, b1.w};
            #pragma unroll
            for (int i = 0; i < 8; i++)
                #pragma unroll
                for (int j = 0; j < 8; j++)
                    acc[i][j] += av[i] * bv[j];
        }
        __syncthreads();
    }

    #pragma unroll
    for (int i = 0; i < 8; i++) {
        int r = row0 + (ty << 3) + i;
        if (r >= M) continue;
        #pragma unroll
        for (int j = 0; j < 8; j++) {
            int c = col0 + (tx << 3) + j;
            float a = acc[i][j];
            if (ep == EP_RELU_REMAP) {
                int bb = r / 8191;
                long long o = (long long)(r + bb + 1) * ldc + c;
                float v = a + bias[c];
                C[o] = v > 0.f ? v : 0.f;
            } else if (ep == EP_SCALEQ) {
                C[(long long)r * ldc + c] = a * (c < 512 ? 0.125f : 1.0f);
            } else if (ep == EP_ADDBIAS) {
                long long o = (long long)r * ldc + c;
                C[o] = C[o] + a + bias[c];
            } else {
                C[(long long)r * ldc + c] = alpha * a;
            }
        }
    }
}

// ===================== 64x64x16 GEMM, 4x4 microtile =========================
// batch z = ((b*8 + h)*SPLIT + s); offsets use sX1(b), sX2(h), sX3(s).
// bmode=1: B_eff[k][n] = bdiag*(k==n) - B[k][n]  (notrans path only)
template<int TRANSB>
__global__ void __launch_bounds__(256) gemm64_k(
    int M, int N, int K,
    const float* __restrict__ A, int lda, long long sA1, long long sA2, long long sA3,
    const float* __restrict__ Bp, int ldb, long long sB1, long long sB2, long long sB3,
    float* __restrict__ C, int ldc, long long sC1, long long sC2, long long sC3,
    int SPLIT, float alpha, int ep, const float* __restrict__ bias,
    int bmode, float bdiag)
{
    __shared__ float As[16][68];
    __shared__ float Bs[16][68];
    int z = blockIdx.z;
    int s  = z % SPLIT;
    int bh = z / SPLIT;
    int hh = bh & 7, bb = bh >> 3;
    A  += (long long)bb * sA1 + (long long)hh * sA2 + (long long)s * sA3;
    Bp += (long long)bb * sB1 + (long long)hh * sB2 + (long long)s * sB3;
    C  += (long long)bb * sC1 + (long long)hh * sC2 + (long long)s * sC3;
    int row0 = blockIdx.y << 6;
    int col0 = blockIdx.x << 6;
    int tid = threadIdx.x;
    int tx = tid & 15, ty = tid >> 4;

    float acc[4][4];
    #pragma unroll
    for (int i = 0; i < 4; i++)
        #pragma unroll
        for (int j = 0; j < 4; j++) acc[i][j] = 0.f;

    int lin = tid << 2;
    for (int k0 = 0; k0 < K; k0 += 16) {
        {
            int r  = lin >> 4;
            int kk = lin & 15;
            int gr = row0 + r;
            float4 v = make_float4(0.f, 0.f, 0.f, 0.f);
            if (gr < M) v = *(const float4*)(A + (long long)gr * lda + k0 + kk);
            As[kk + 0][r] = v.x;
            As[kk + 1][r] = v.y;
            As[kk + 2][r] = v.z;
            As[kk + 3][r] = v.w;
        }
        if (!TRANSB) {
            int kk = lin >> 6;
            int n  = lin & 63;
            float4 v = *(const float4*)(Bp + (long long)(k0 + kk) * ldb + col0 + n);
            if (bmode) {
                int gk = k0 + kk, gn = col0 + n;
                v.x = (gk == gn + 0 ? bdiag : 0.f) - v.x;
                v.y = (gk == gn + 1 ? bdiag : 0.f) - v.y;
                v.z = (gk == gn + 2 ? bdiag : 0.f) - v.z;
                v.w = (gk == gn + 3 ? bdiag : 0.f) - v.w;
            }
            *(float4*)&Bs[kk][n] = v;
        } else {
            int n  = lin >> 4;
            int kk = lin & 15;
            float4 v = *(const float4*)(Bp + (long long)(col0 + n) * ldb + k0 + kk);
            Bs[kk + 0][n] = v.x;
            Bs[kk + 1][n] = v.y;
            Bs[kk + 2][n] = v.z;
            Bs[kk + 3][n] = v.w;
        }
        __syncthreads();
        #pragma unroll
        for (int kk = 0; kk < 16; kk++) {
            float4 a = *(const float4*)&As[kk][ty << 2];
            float4 b = *(const float4*)&Bs[kk][tx << 2];
            acc[0][0] += a.x * b.x; acc[0][1] += a.x * b.y; acc[0][2] += a.x * b.z; acc[0][3] += a.x * b.w;
            acc[1][0] += a.y * b.x; acc[1][1] += a.y * b.y; acc[1][2] += a.y * b.z; acc[1][3] += a.y * b.w;
            acc[2][0] += a.z * b.x; acc[2][1] += a.z * b.y; acc[2][2] += a.z * b.z; acc[2][3] += a.z * b.w;
            acc[3][0] += a.w * b.x; acc[3][1] += a.w * b.y; acc[3][2] += a.w * b.z; acc[3][3] += a.w * b.w;
        }
        __syncthreads();
    }

    #pragma unroll
    for (int i = 0; i < 4; i++) {
        int r = row0 + (ty << 2) + i;
        if (r >= M) continue;
        #pragma unroll
        for (int j = 0; j < 4; j++) {
            int c = col0 + (tx << 2) + j;
            float a = acc[i][j];
            if (ep == EP_ADDBIAS) {
                long long o = (long long)r * ldc + c;
                C[o] = C[o] + a + bias[c];
            } else {
                C[(long long)r * ldc + c] = alpha * a;
            }
        }
    }
}

// ------------------------- layernorm (rows of 512) --------------------------
__global__ void __launch_bounds__(256) ln_k(const float* __restrict__ X, float* __restrict__ Y,
                                            const float* __restrict__ g, const float* __restrict__ b)
{
    long long row = blockIdx.x;
    const float* x = X + row * DIMM;
    float* y = Y + row * DIMM;
    int t = threadIdx.x;
    float v0 = x[t], v1 = x[t + 256];
    float mu  = blockReduce(v0 + v1, false) * (1.f / 512.f);
    float d0 = v0 - mu, d1 = v1 - mu;
    float var = blockReduce(d0 * d0 + d1 * d1, false) * (1.f / 512.f);
    float inv = rsqrtf(var + 1e-5f);
    y[t]       = d0 * inv * g[t]       + b[t];
    y[t + 256] = d1 * inv * g[t + 256] + b[t + 256];
}

// ------------------------- row softmax (smem-resident row) ------------------
__global__ void __launch_bounds__(256) softmax_k(float* __restrict__ S, int cols)
{
    extern __shared__ float buf[];
    long long row = blockIdx.x;
    float* s = S + row * cols;
    int t = threadIdx.x;
    float mx = -1e30f;
    for (int i = t; i < cols; i += 256) { float v = s[i]; buf[i] = v; mx = fmaxf(mx, v); }
    float bmax = blockReduce(mx, true);
    float sum = 0.f;
    for (int i = t; i < cols; i += 256) { float e = __expf(buf[i] - bmax); buf[i] = e; sum += e; }
    float bsum = blockReduce(sum, false);
    float inv = 1.f / bsum;
    for (int i = t; i < cols; i += 256) s[i] = buf[i] * inv;
}

// ------------------------- landmarks (mean of 32 consecutive rows) ----------
__global__ void __launch_bounds__(64) landmark_k()
{
    int zz = blockIdx.x;          // bh*256 + mi
    int mi = zz & 255, bh = zz >> 8;
    int b = bh >> 3, h = bh & 7;
    int d = threadIdx.x;
    const float* base = g_QKV + (long long)(b * NF + mi * 32) * QD + h * 64 + d;
    float sq = 0.f, sk = 0.f;
    #pragma unroll 8
    for (int il = 0; il < 32; il++) {
        sq += base[(long long)il * QD];
        sk += base[(long long)il * QD + 512];
    }
    long long o = ((long long)bh * LM + mi) * DH + d;
    g_QL[o] = sq * (1.f / 32.f);
    g_KL[o] = sk * (1.f / 32.f);
}

// ------------------------- pinv helpers -------------------------------------
__global__ void reset_k() { g_scale[0] = 0u; g_scale[1] = 0u; }

__global__ void __launch_bounds__(256) scalemax_k()
{
    int z = blockIdx.x;
    int i = threadIdx.x;
    const float* S = g_S2 + ((long long)z << 16);
    float rs = 0.f, cs = 0.f;
    for (int j = 0; j < 256; j++) { rs += S[(i << 8) + j]; cs += S[(j << 8) + i]; }
    float rm = blockReduce(rs, true);
    float cm = blockReduce(cs, true);
    if (i == 0) {
        atomicMax(&g_scale[0], __float_as_uint(rm));
        atomicMax(&g_scale[1], __float_as_uint(cm));
    }
}

__global__ void __launch_bounds__(256) zinit_k()
{
    int idx = blockIdx.x * 256 + threadIdx.x;       // 16*65536 total
    float inv = 1.0f / (__uint_as_float(g_scale[0]) * __uint_as_float(g_scale[1]));
    int z = idx >> 16, r = idx & 65535;
    int i = r >> 8, j = r & 255;
    g_Zb[((long long)z << 16) + (i << 8) + j] = g_S2[((long long)z << 16) + (j << 8) + i] * inv;
}

// ------------------------- split-K reduce for AV ----------------------------
__global__ void __launch_bounds__(256) avreduce_k()
{
    int idx = blockIdx.x * 256 + threadIdx.x;       // NBH*LM*DH = 262144
    int bh = idx >> 14;
    int r  = idx & 16383;
    const float* p = g_AVp + ((long long)bh << 17);
    float s = 0.f;
    #pragma unroll
    for (int k = 0; k < KSPL; k++) s += p[(k << 14) + r];
    g_AV[idx] = s;
}

// ------------------------- depthwise conv residual (adds into g_OH) ---------
__global__ void __launch_bounds__(256) conv_k(const float* __restrict__ cw)
{
    __shared__ float sv[160 * 64];
    __shared__ float sw[KER];
    int tile = blockIdx.x;
    int bh = blockIdx.y;
    int b = bh >> 3, h = bh & 7;
    int n0 = tile * 128;
    int t = threadIdx.x;
    if (t < KER) sw[t] = cw[h * KER + t];
    for (int idx = t; idx < 160 * 64; idx += 256) {
        int r = idx >> 6, d = idx & 63;
        int nn = n0 - 16 + r;
        float v = 0.f;
        if (nn >= 0 && nn < NF) v = g_QKV[(long long)(b * NF + nn) * QD + 1024 + h * 64 + d];
        sv[idx] = v;
    }
    __syncthreads();
    int d = t & 63, r0 = t >> 6;
    for (int rr = r0; rr < 128; rr += 4) {
        float a = 0.f;
        #pragma unroll
        for (int k = 0; k < KER; k++) a += sv[(rr + k) * 64 + d] * sw[k];
        long long o = ((long long)bh * NF + n0 + rr) * DH + d;
        g_OH[o] += a;
    }
}

// ------------------------- (b,h,n,d) -> (b,n, h*64+d) -----------------------
__global__ void __launch_bounds__(256) trans_k()
{
    long long o = (long long)blockIdx.x * 256 + threadIdx.x;
    int c = (int)(o & 511);
    long long bn = o >> 9;
    int n = (int)(bn & (NF - 1));
    int b = (int)(bn >> 13);
    int h = c >> 6, d = c & 63;
    g_OT[o] = g_OH[(((long long)(b * NH + h) * NF + n) << 6) + d];
}

// ------------------------- cls token fill -----------------------------------
__global__ void __launch_bounds__(256) cls_k(const float* __restrict__ ct)
{
    int idx = blockIdx.x * 256 + threadIdx.x;   // 1024
    int b = idx >> 9, c = idx & 511;
    g_X[(long long)b * NF * DIMM + c] = ct[c];
}

// ------------------------- final LN + head ----------------------------------
__global__ void __launch_bounds__(256) final_k(const float* __restrict__ fg, const float* __restrict__ fb,
                                               const float* __restrict__ w2, const float* __restrict__ b2,
                                               float* __restrict__ out)
{
    int b = blockIdx.x;
    const float* x = g_X + (long long)b * NF * DIMM;
    int t = threadIdx.x;
    float v0 = x[t], v1 = x[t + 256];
    float mu  = blockReduce(v0 + v1, false) * (1.f / 512.f);
    float d0 = v0 - mu, d1 = v1 - mu;
    float var = blockReduce(d0 * d0 + d1 * d1, false) * (1.f / 512.f);
    float inv = rsqrtf(var + 1e-5f);
    float n0 = d0 * inv * fg[t]       + fb[t];
    float n1 = d1 * inv * fg[t + 256] + fb[t + 256];
    float p0 = n0 * w2[2 * t]     + n1 * w2[2 * (t + 256)];
    float p1 = n0 * w2[2 * t + 1] + n1 * w2[2 * (t + 256) + 1];
    p0 = blockReduce(p0, false);
    p1 = blockReduce(p1, false);
    if (t == 0) {
        out[b * 2 + 0] = p0 + b2[0];
        out[b * 2 + 1] = p1 + b2[1];
    }
}

// ------------------------- host orchestration -------------------------------
static inline void gemm128(int transB, int M, int N, int K,
                           const float* A, int lda, long long sA1, long long sA2,
                           const float* Bp, int ldb, long long sB1, long long sB2,
                           float* C, int ldc, long long sC1, long long sC2,
                           int batch, float alpha, int ep, const float* bias)
{
    dim3 g(N >> 7, (M + 127) >> 7, batch);
    if (transB)
        gemm128_k<1><<<g, 256>>>(M, N, K, A, lda, sA1, sA2, Bp, ldb, sB1, sB2, C, ldc, sC1, sC2, alpha, ep, bias);
    else
        gemm128_k<0><<<g, 256>>>(M, N, K, A, lda, sA1, sA2, Bp, ldb, sB1, sB2, C, ldc, sC1, sC2, alpha, ep, bias);
}

static inline void gemm64(int transB, int M, int N, int K,
                          const float* A, int lda, long long sA1, long long sA2, long long sA3,
                          const float* Bp, int ldb, long long sB1, long long sB2, long long sB3,
                          float* C, int ldc, long long sC1, long long sC2, long long sC3,
                          int SPLIT, int batchZ, float alpha, int ep, const float* bias,
                          int bmode, float bdiag)
{
    dim3 g(N >> 6, (M + 63) >> 6, batchZ);
    if (transB)
        gemm64_k<1><<<g, 256>>>(M, N, K, A, lda, sA1, sA2, sA3, Bp, ldb, sB1, sB2, sB3,
                                C, ldc, sC1, sC2, sC3, SPLIT, alpha, ep, bias, bmode, bdiag);
    else
        gemm64_k<0><<<g, 256>>>(M, N, K, A, lda, sA1, sA2, sA3, Bp, ldb, sB1, sB2, sB3,
                                C, ldc, sC1, sC2, sC3, SPLIT, alpha, ep, bias, bmode, bdiag);
}

extern "C" void kernel_launch(void* const* d_in, const int* in_sizes, int n_in,
                              void* d_out, int out_size)
{
    const float* h_in  = (const float*)d_in[0];
    const float* w1    = (const float*)d_in[1];
    const float* b1    = (const float*)d_in[2];
    const float* clst  = (const float*)d_in[3];
    const float* ln_g  = (const float*)d_in[4];
    const float* ln_b  = (const float*)d_in[5];
    const float* wqkv  = (const float*)d_in[6];
    const float* wout  = (const float*)d_in[7];
    const float* bout  = (const float*)d_in[8];
    const float* cw    = (const float*)d_in[9];
    const float* fg    = (const float*)d_in[10];
    const float* fb    = (const float*)d_in[11];
    const float* w2    = (const float*)d_in[12];
    const float* b2    = (const float*)d_in[13];
    float* out = (float*)d_out;

    float *X, *XN, *QKV, *QL, *KL, *S1, *S2, *S3, *Z, *Z2, *P, *T, *T2, *AV, *AVp, *ZAV, *OH, *OT;
    cudaGetSymbolAddress((void**)&X,   g_X);
    cudaGetSymbolAddress((void**)&XN,  g_XN);
    cudaGetSymbolAddress((void**)&QKV, g_QKV);
    cudaGetSymbolAddress((void**)&QL,  g_QL);
    cudaGetSymbolAddress((void**)&KL,  g_KL);
    cudaGetSymbolAddress((void**)&S1,  g_S1);
    cudaGetSymbolAddress((void**)&S2,  g_S2);
    cudaGetSymbolAddress((void**)&S3,  g_S3);
    cudaGetSymbolAddress((void**)&Z,   g_Zb);
    cudaGetSymbolAddress((void**)&Z2,  g_Z2b);
    cudaGetSymbolAddress((void**)&P,   g_Pb);
    cudaGetSymbolAddress((void**)&T,   g_Tb);
    cudaGetSymbolAddress((void**)&T2,  g_T2b);
    cudaGetSymbolAddress((void**)&AV,  g_AV);
    cudaGetSymbolAddress((void**)&AVp, g_AVp);
    cudaGetSymbolAddress((void**)&ZAV, g_ZAV);
    cudaGetSymbolAddress((void**)&OH,  g_OH);
    cudaGetSymbolAddress((void**)&OT,  g_OT);

    const long long SQb = (long long)NF * QD;
    const long long S2s = (long long)LM * LM;
    const long long S1s = (long long)NF * LM;
    const long long AVs = (long long)LM * DH;
    const long long OHs = (long long)NF * DH;

    // input projection: X[b, n+1, :] = relu(h @ w1 + b1); X[b,0,:] = cls
    gemm128(0, NB * 8191, DIMM, 1024, h_in, 1024, 0, 0, w1, DIMM, 0, 0,
            X, DIMM, 0, 0, 1, 1.f, EP_RELU_REMAP, b1);
    cls_k<<<4, 256>>>(clst);

    for (int L = 0; L < 2; L++) {
        ln_k<<<TOT, 256>>>(X, XN, ln_g + L * DIMM, ln_b + L * DIMM);

        // qkv = ln(x) @ Wqkv  (q cols scaled by 1/8)
        gemm128(0, TOT, QD, DIMM, XN, DIMM, 0, 0, wqkv + (long long)L * DIMM * QD, QD, 0, 0,
                QKV, QD, 0, 0, 1, 1.f, EP_SCALEQ, nullptr);

        landmark_k<<<NBH * LM, 64>>>();

        // sim2 = QL @ KL^T, softmax
        gemm64(1, LM, LM, DH, QL, DH, 8 * AVs, AVs, 0, KL, DH, 8 * AVs, AVs, 0,
               S2, LM, 8 * S2s, S2s, 0, 1, NBH, 1.f, EP_NONE, nullptr, 0, 0.f);
        softmax_k<<<NBH * LM, 256, LM * 4>>>(S2, LM);

        // Moore-Penrose pinv of S2 -> Z (6 Newton iters, (cI - X) fused in B-load)
        reset_k<<<1, 1>>>();
        scalemax_k<<<NBH, 256>>>();
        zinit_k<<<4096, 256>>>();
        for (int it = 0; it < 6; it++) {
            float* Zin  = (it & 1) ? Z2 : Z;
            float* Zout = (it & 1) ? Z  : Z2;
            // P = S2 @ Zin
            gemm64(0, LM, LM, LM, S2, LM, 8 * S2s, S2s, 0, Zin, LM, 8 * S2s, S2s, 0,
                   P, LM, 8 * S2s, S2s, 0, 1, NBH, 1.f, EP_NONE, nullptr, 0, 0.f);
            // T2 = P @ (7I - P)
            gemm64(0, LM, LM, LM, P, LM, 8 * S2s, S2s, 0, P, LM, 8 * S2s, S2s, 0,
                   T2, LM, 8 * S2s, S2s, 0, 1, NBH, 1.f, EP_NONE, nullptr, 1, 7.f);
            // T = P @ (15I - T2)
            gemm64(0, LM, LM, LM, P, LM, 8 * S2s, S2s, 0, T2, LM, 8 * S2s, S2s, 0,
                   T, LM, 8 * S2s, S2s, 0, 1, NBH, 1.f, EP_NONE, nullptr, 1, 15.f);
            // Zout = 0.25 * Zin @ (13I - T)
            gemm64(0, LM, LM, LM, Zin, LM, 8 * S2s, S2s, 0, T, LM, 8 * S2s, S2s, 0,
                   Zout, LM, 8 * S2s, S2s, 0, 1, NBH, 0.25f, EP_NONE, nullptr, 1, 13.f);
        }

        // sim1 = Q @ KL^T, softmax
        gemm128(1, NF, LM, DH, QKV, QD, SQb, 64, KL, DH, 8 * AVs, AVs,
                S1, LM, 8 * S1s, S1s, NBH, 1.f, EP_NONE, nullptr);
        softmax_k<<<NBH * NF, 256, LM * 4>>>(S1, LM);

        // sim3 = QL @ K^T, softmax over 8192
        gemm128(1, LM, NF, DH, QL, DH, 8 * AVs, AVs, QKV + 512, QD, SQb, 64,
                S3, NF, 8 * S1s, S1s, NBH, 1.f, EP_NONE, nullptr);
        softmax_k<<<NBH * LM, 256, NF * 4>>>(S3, NF);

        // AV = attn3 @ V  (split-K by 8 into partials, then reduce)
        gemm64(0, LM, DH, NF / KSPL,
               S3, NF, 8 * S1s, S1s, 1024,
               QKV + 1024, QD, SQb, 64, 1024LL * QD,
               AVp, DH, 64 * AVs, 8 * AVs, AVs,
               KSPL, NBH * KSPL, 1.f, EP_NONE, nullptr, 0, 0.f);
        avreduce_k<<<1024, 256>>>();

        // ZAV = Z @ AV
        gemm64(0, LM, DH, LM, Z, LM, 8 * S2s, S2s, 0, AV, DH, 8 * AVs, AVs, 0,
               ZAV, DH, 8 * AVs, AVs, 0, 1, NBH, 1.f, EP_NONE, nullptr, 0, 0.f);
        // OH = attn1 @ ZAV
        gemm64(0, NF, DH, LM, S1, LM, 8 * S1s, S1s, 0, ZAV, DH, 8 * AVs, AVs, 0,
               OH, DH, 8 * OHs, OHs, 0, 1, NBH, 1.f, EP_NONE, nullptr, 0, 0.f);

        // OH += depthwise conv residual of V
        { dim3 g(NF / 128, NBH); conv_k<<<g, 256>>>(cw + L * NH * KER); }

        // transpose heads back, then X += OHt @ Wout + bout
        trans_k<<<(TOT * DIMM) / 256, 256>>>();
        gemm128(0, TOT, DIMM, DIMM, OT, DIMM, 0, 0, wout + (long long)L * DIMM * DIMM, DIMM, 0, 0,
                X, DIMM, 0, 0, 1, 1.f, EP_ADDBIAS, bout + L * DIMM);
    }

    final_k<<<NB, 256>>>(fg, fb, w2, b2, out);
}

// round 3
// speedup vs baseline: 1.2518x; 1.0688x over previous
#include <cuda_runtime.h>

#define NB   2
#define NF   8192
#define DIMM 512
#define NH   8
#define DH   64
#define LM   256
#define QD   1536
#define TOT  (NB*NF)    // 16384
#define NBH  (NB*NH)    // 16
#define KER  33
#define KSPL 8

// ------------------------- scratch (device globals, no allocs) -------------
__device__ float g_X  [TOT*DIMM];
__device__ float g_XN [TOT*DIMM];
__device__ float g_QKV[TOT*QD];
__device__ float g_QL [NBH*LM*DH];
__device__ float g_KL [NBH*LM*DH];
__device__ float g_S1 [NBH*NF*LM];
__device__ float g_S3 [NBH*LM*NF];
__device__ float g_S2 [NBH*LM*LM];
__device__ float g_Zb [NBH*LM*LM];
__device__ float g_Z2b[NBH*LM*LM];
__device__ float g_Pb [NBH*LM*LM];
__device__ float g_Tb [NBH*LM*LM];
__device__ float g_T2b[NBH*LM*LM];
__device__ float g_AV [NBH*LM*DH];
__device__ float g_AVp[NBH*KSPL*LM*DH];
__device__ float g_ZAV[NBH*LM*DH];
__device__ float g_OH [NBH*NF*DH];
__device__ unsigned int g_scale[2];

enum { EP_NONE = 0, EP_RELU_REMAP = 1, EP_SCALEQ = 2, EP_ADDBIAS = 3 };

// ------------------------- reductions --------------------------------------
__device__ __forceinline__ float blockReduce(float v, bool domax) {
    __shared__ float sh[32];
    __syncthreads();
    #pragma unroll
    for (int o = 16; o > 0; o >>= 1) {
        float w = __shfl_down_sync(0xffffffffu, v, o);
        v = domax ? fmaxf(v, w) : v + w;
    }
    int lane = threadIdx.x & 31, wid = threadIdx.x >> 5;
    if (lane == 0) sh[wid] = v;
    __syncthreads();
    int nw = (blockDim.x + 31) >> 5;
    if (wid == 0) {
        v = (lane < nw) ? sh[lane] : (domax ? -1e30f : 0.f);
        #pragma unroll
        for (int o = 16; o > 0; o >>= 1) {
            float w = __shfl_down_sync(0xffffffffu, v, o);
            v = domax ? fmaxf(v, w) : v + w;
        }
        if (lane == 0) sh[0] = v;
    }
    __syncthreads();
    return sh[0];
}

// ===================== 128x128x16 GEMM, 8x8 microtile, double-buffered ======
// C[r,c] = alpha * sum_k A[r,k] * (TRANSB ? B[c,k] : B[k,c])
// amode=1: A element (r,k) read from OH layout: ((b*8+h)*8192+n)*64+d
template<int TRANSB>
__global__ void __launch_bounds__(256, 2) gemm128_k(
    int M, int N, int K,
    const float* __restrict__ A, int lda, long long sA1, long long sA2,
    const float* __restrict__ Bp, int ldb, long long sB1, long long sB2,
    float* __restrict__ C, int ldc, long long sC1, long long sC2,
    float alpha, int ep, const float* __restrict__ bias, int amode)
{
    __shared__ float As[2][16 * 136];
    __shared__ float Bs[2][16 * 136];
    int z = blockIdx.z;
    A  += (long long)(z >> 3) * sA1 + (long long)(z & 7) * sA2;
    Bp += (long long)(z >> 3) * sB1 + (long long)(z & 7) * sB2;
    C  += (long long)(z >> 3) * sC1 + (long long)(z & 7) * sC2;
    int row0 = blockIdx.y << 7;
    int col0 = blockIdx.x << 7;
    int tid = threadIdx.x;
    int tx = tid & 15, ty = tid >> 4;

    // loader coords
    int a_r  = tid >> 2;            // 0..63 ; second half a_r+64
    int a_kk = (tid & 3) << 2;
    int bn_kk = tid >> 5;           // notrans: 0..7 ; second half +8
    int bn_n  = (tid & 31) << 2;
    int bt_n  = tid >> 2;           // trans: 0..63 ; second half +64
    int bt_kk = (tid & 3) << 2;

    float acc[8][8];
    #pragma unroll
    for (int i = 0; i < 8; i++)
        #pragma unroll
        for (int j = 0; j < 8; j++) acc[i][j] = 0.f;

    float4 pa0, pa1, pb0, pb1;

    auto fetch = [&](int k0) {
        int gr0 = row0 + a_r, gr1 = gr0 + 64;
        if (amode == 0) {
            pa0 = make_float4(0.f, 0.f, 0.f, 0.f);
            pa1 = pa0;
            if (gr0 < M) pa0 = *(const float4*)(A + (long long)gr0 * lda + k0 + a_kk);
            if (gr1 < M) pa1 = *(const float4*)(A + (long long)gr1 * lda + k0 + a_kk);
        } else {
            int k = k0 + a_kk;
            int h = k >> 6, d = k & 63;
            long long o0 = ((((long long)(gr0 >> 13) * 8 + h) << 13) + (gr0 & 8191)) * 64 + d;
            long long o1 = ((((long long)(gr1 >> 13) * 8 + h) << 13) + (gr1 & 8191)) * 64 + d;
            pa0 = *(const float4*)(A + o0);
            pa1 = *(const float4*)(A + o1);
        }
        if (!TRANSB) {
            pb0 = *(const float4*)(Bp + (long long)(k0 + bn_kk) * ldb + col0 + bn_n);
            pb1 = *(const float4*)(Bp + (long long)(k0 + bn_kk + 8) * ldb + col0 + bn_n);
        } else {
            pb0 = *(const float4*)(Bp + (long long)(col0 + bt_n) * ldb + k0 + bt_kk);
            pb1 = *(const float4*)(Bp + (long long)(col0 + bt_n + 64) * ldb + k0 + bt_kk);
        }
    };

    auto stash = [&](int b) {
        float* Ab = As[b];
        Ab[(a_kk + 0) * 136 + a_r] = pa0.x;
        Ab[(a_kk + 1) * 136 + a_r] = pa0.y;
        Ab[(a_kk + 2) * 136 + a_r] = pa0.z;
        Ab[(a_kk + 3) * 136 + a_r] = pa0.w;
        Ab[(a_kk + 0) * 136 + a_r + 64] = pa1.x;
        Ab[(a_kk + 1) * 136 + a_r + 64] = pa1.y;
        Ab[(a_kk + 2) * 136 + a_r + 64] = pa1.z;
        Ab[(a_kk + 3) * 136 + a_r + 64] = pa1.w;
        float* Bb = Bs[b];
        if (!TRANSB) {
            *(float4*)&Bb[bn_kk * 136 + bn_n] = pb0;
            *(float4*)&Bb[(bn_kk + 8) * 136 + bn_n] = pb1;
        } else {
            Bb[(bt_kk + 0) * 136 + bt_n] = pb0.x;
            Bb[(bt_kk + 1) * 136 + bt_n] = pb0.y;
            Bb[(bt_kk + 2) * 136 + bt_n] = pb0.z;
            Bb[(bt_kk + 3) * 136 + bt_n] = pb0.w;
            Bb[(bt_kk + 0) * 136 + bt_n + 64] = pb1.x;
            Bb[(bt_kk + 1) * 136 + bt_n + 64] = pb1.y;
            Bb[(bt_kk + 2) * 136 + bt_n + 64] = pb1.z;
            Bb[(bt_kk + 3) * 136 + bt_n + 64] = pb1.w;
        }
    };

    fetch(0);
    stash(0);
    __syncthreads();

    int nt = K >> 4;
    for (int t = 0; t < nt; t++) {
        int buf = t & 1;
        if (t + 1 < nt) fetch((t + 1) << 4);
        const float* Ab = As[buf];
        const float* Bb = Bs[buf];
        #pragma unroll
        for (int kk = 0; kk < 16; kk++) {
            float4 a0 = *(const float4*)&Ab[kk * 136 + (ty << 3)];
            float4 a1 = *(const float4*)&Ab[kk * 136 + (ty << 3) + 4];
            float4 b0 = *(const float4*)&Bb[kk * 136 + (tx << 3)];
            float4 b1 = *(const float4*)&Bb[kk * 136 + (tx << 3) + 4];
            float av[8] = {a0.x, a0.y, a0.z, a0.w, a1.x, a1.y, a1.z, a1.w};
            float bv[8] = {b0.x, b0.y, b0.z, b0.w, b1.x, b1.y, b1.z, b1.w};
            #pragma unroll
            for (int i = 0; i < 8; i++)
                #pragma unroll
                for (int j = 0; j < 8; j++)
                    acc[i][j] += av[i] * bv[j];
        }
        if (t + 1 < nt) stash(buf ^ 1);
        __syncthreads();
    }

    #pragma unroll
    for (int i = 0; i < 8; i++) {
        int r = row0 + (ty << 3) + i;
        if (r >= M) continue;
        #pragma unroll
        for (int j = 0; j < 8; j++) {
            int c = col0 + (tx << 3) + j;
            float a = acc[i][j];
            if (ep == EP_RELU_REMAP) {
                int bb = r / 8191;
                long long o = (long long)(r + bb + 1) * ldc + c;
                float v = a + bias[c];
                C[o] = v > 0.f ? v : 0.f;
            } else if (ep == EP_SCALEQ) {
                C[(long long)r * ldc + c] = a * (c < 512 ? 0.125f : 1.0f);
            } else if (ep == EP_ADDBIAS) {
                long long o = (long long)r * ldc + c;
                C[o] = C[o] + a + bias[c];
            } else {
                C[(long long)r * ldc + c] = alpha * a;
            }
        }
    }
}

// ===================== 64x64x16 GEMM, 4x4 microtile, double-buffered ========
// batch z = bh*SPLIT + s;  bmode=1: B_eff = bdiag*I - B (notrans only)
template<int TRANSB>
__global__ void __launch_bounds__(256) gemm64_k(
    int M, int N, int K,
    const float* __restrict__ A, int lda, long long sA1, long long sA2, long long sA3,
    const float* __restrict__ Bp, int ldb, long long sB1, long long sB2, long long sB3,
    float* __restrict__ C, int ldc, long long sC1, long long sC2, long long sC3,
    int SPLIT, float alpha, int ep, const float* __restrict__ bias,
    int bmode, float bdiag)
{
    __shared__ float As[2][16 * 68];
    __shared__ float Bs[2][16 * 68];
    int z = blockIdx.z;
    int s  = z % SPLIT;
    int bh = z / SPLIT;
    int hh = bh & 7, bb = bh >> 3;
    A  += (long long)bb * sA1 + (long long)hh * sA2 + (long long)s * sA3;
    Bp += (long long)bb * sB1 + (long long)hh * sB2 + (long long)s * sB3;
    C  += (long long)bb * sC1 + (long long)hh * sC2 + (long long)s * sC3;
    int row0 = blockIdx.y << 6;
    int col0 = blockIdx.x << 6;
    int tid = threadIdx.x;
    int tx = tid & 15, ty = tid >> 4;

    int a_r  = tid >> 2;          // 0..63
    int a_kk = (tid & 3) << 2;
    int bn_kk = tid >> 4;         // notrans: 0..15
    int bn_n  = (tid & 15) << 2;
    int bt_n  = tid >> 2;
    int bt_kk = (tid & 3) << 2;

    float acc[4][4];
    #pragma unroll
    for (int i = 0; i < 4; i++)
        #pragma unroll
        for (int j = 0; j < 4; j++) acc[i][j] = 0.f;

    float4 pa, pb;

    auto fetch = [&](int k0) {
        int gr = row0 + a_r;
        pa = make_float4(0.f, 0.f, 0.f, 0.f);
        if (gr < M) pa = *(const float4*)(A + (long long)gr * lda + k0 + a_kk);
        if (!TRANSB) {
            pb = *(const float4*)(Bp + (long long)(k0 + bn_kk) * ldb + col0 + bn_n);
        } else {
            pb = *(const float4*)(Bp + (long long)(col0 + bt_n) * ldb + k0 + bt_kk);
        }
    };

    auto stash = [&](int b, int k0) {
        float* Ab = As[b];
        Ab[(a_kk + 0) * 68 + a_r] = pa.x;
        Ab[(a_kk + 1) * 68 + a_r] = pa.y;
        Ab[(a_kk + 2) * 68 + a_r] = pa.z;
        Ab[(a_kk + 3) * 68 + a_r] = pa.w;
        float* Bb = Bs[b];
        if (!TRANSB) {
            float4 v = pb;
            if (bmode) {
                int gk = k0 + bn_kk, gn = col0 + bn_n;
                v.x = (gk == gn + 0 ? bdiag : 0.f) - v.x;
                v.y = (gk == gn + 1 ? bdiag : 0.f) - v.y;
                v.z = (gk == gn + 2 ? bdiag : 0.f) - v.z;
                v.w = (gk == gn + 3 ? bdiag : 0.f) - v.w;
            }
            *(float4*)&Bb[bn_kk * 68 + bn_n] = v;
        } else {
            Bb[(bt_kk + 0) * 68 + bt_n] = pb.x;
            Bb[(bt_kk + 1) * 68 + bt_n] = pb.y;
            Bb[(bt_kk + 2) * 68 + bt_n] = pb.z;
            Bb[(bt_kk + 3) * 68 + bt_n] = pb.w;
        }
    };

    fetch(0);
    stash(0, 0);
    __syncthreads();

    int nt = K >> 4;
    for (int t = 0; t < nt; t++) {
        int buf = t & 1;
        if (t + 1 < nt) fetch((t + 1) << 4);
        const float* Ab = As[buf];
        const float* Bb = Bs[buf];
        #pragma unroll
        for (int kk = 0; kk < 16; kk++) {
            float4 a = *(const float4*)&Ab[kk * 68 + (ty << 2)];
            float4 b = *(const float4*)&Bb[kk * 68 + (tx << 2)];
            acc[0][0] += a.x * b.x; acc[0][1] += a.x * b.y; acc[0][2] += a.x * b.z; acc[0][3] += a.x * b.w;
            acc[1][0] += a.y * b.x; acc[1][1] += a.y * b.y; acc[1][2] += a.y * b.z; acc[1][3] += a.y * b.w;
            acc[2][0] += a.z * b.x; acc[2][1] += a.z * b.y; acc[2][2] += a.z * b.z; acc[2][3] += a.z * b.w;
            acc[3][0] += a.w * b.x; acc[3][1] += a.w * b.y; acc[3][2] += a.w * b.z; acc[3][3] += a.w * b.w;
        }
        if (t + 1 < nt) stash(buf ^ 1, (t + 1) << 4);
        __syncthreads();
    }

    #pragma unroll
    for (int i = 0; i < 4; i++) {
        int r = row0 + (ty << 2) + i;
        if (r >= M) continue;
        #pragma unroll
        for (int j = 0; j < 4; j++) {
            int c = col0 + (tx << 2) + j;
            float a = acc[i][j];
            if (ep == EP_ADDBIAS) {
                long long o = (long long)r * ldc + c;
                C[o] = C[o] + a + bias[c];
            } else {
                C[(long long)r * ldc + c] = alpha * a;
            }
        }
    }
}

// ------------------------- layernorm (rows of 512) --------------------------
__global__ void __launch_bounds__(256) ln_k(const float* __restrict__ X, float* __restrict__ Y,
                                            const float* __restrict__ g, const float* __restrict__ b)
{
    long long row = blockIdx.x;
    const float* x = X + row * DIMM;
    float* y = Y + row * DIMM;
    int t = threadIdx.x;
    float v0 = x[t], v1 = x[t + 256];
    float mu  = blockReduce(v0 + v1, false) * (1.f / 512.f);
    float d0 = v0 - mu, d1 = v1 - mu;
    float var = blockReduce(d0 * d0 + d1 * d1, false) * (1.f / 512.f);
    float inv = rsqrtf(var + 1e-5f);
    y[t]       = d0 * inv * g[t]       + b[t];
    y[t + 256] = d1 * inv * g[t + 256] + b[t + 256];
}

// ------------------------- warp-per-row softmax, 256 cols -------------------
__global__ void __launch_bounds__(256) softmax256_k(float* __restrict__ S)
{
    long long row = ((long long)blockIdx.x << 3) + (threadIdx.x >> 5);
    int lane = threadIdx.x & 31;
    float* s = S + (row << 8);
    float4 va = *(float4*)(s + (lane << 3));
    float4 vb = *(float4*)(s + (lane << 3) + 4);
    float m = fmaxf(fmaxf(fmaxf(va.x, va.y), fmaxf(va.z, va.w)),
                    fmaxf(fmaxf(vb.x, vb.y), fmaxf(vb.z, vb.w)));
    #pragma unroll
    for (int o = 16; o > 0; o >>= 1) m = fmaxf(m, __shfl_xor_sync(0xffffffffu, m, o));
    va.x = __expf(va.x - m); va.y = __expf(va.y - m); va.z = __expf(va.z - m); va.w = __expf(va.w - m);
    vb.x = __expf(vb.x - m); vb.y = __expf(vb.y - m); vb.z = __expf(vb.z - m); vb.w = __expf(vb.w - m);
    float sum = va.x + va.y + va.z + va.w + vb.x + vb.y + vb.z + vb.w;
    #pragma unroll
    for (int o = 16; o > 0; o >>= 1) sum += __shfl_xor_sync(0xffffffffu, sum, o);
    float inv = 1.f / sum;
    va.x *= inv; va.y *= inv; va.z *= inv; va.w *= inv;
    vb.x *= inv; vb.y *= inv; vb.z *= inv; vb.w *= inv;
    *(float4*)(s + (lane << 3)) = va;
    *(float4*)(s + (lane << 3) + 4) = vb;
}

// ------------------------- block softmax (long rows) ------------------------
__global__ void __launch_bounds__(256) softmax_k(float* __restrict__ S, int cols)
{
    extern __shared__ float buf[];
    long long row = blockIdx.x;
    float* s = S + row * cols;
    int t = threadIdx.x;
    float mx = -1e30f;
    for (int i = t; i < cols; i += 256) { float v = s[i]; buf[i] = v; mx = fmaxf(mx, v); }
    float bmax = blockReduce(mx, true);
    float sum = 0.f;
    for (int i = t; i < cols; i += 256) { float e = __expf(buf[i] - bmax); buf[i] = e; sum += e; }
    float bsum = blockReduce(sum, false);
    float inv = 1.f / bsum;
    for (int i = t; i < cols; i += 256) s[i] = buf[i] * inv;
}

// ------------------------- landmarks (mean of 32 consecutive rows) ----------
__global__ void __launch_bounds__(64) landmark_k()
{
    int zz = blockIdx.x;          // bh*256 + mi
    int mi = zz & 255, bh = zz >> 8;
    int b = bh >> 3, h = bh & 7;
    int d = threadIdx.x;
    const float* base = g_QKV + (long long)(b * NF + mi * 32) * QD + h * 64 + d;
    float sq = 0.f, sk = 0.f;
    #pragma unroll 8
    for (int il = 0; il < 32; il++) {
        sq += base[(long long)il * QD];
        sk += base[(long long)il * QD + 512];
    }
    long long o = ((long long)bh * LM + mi) * DH + d;
    g_QL[o] = sq * (1.f / 32.f);
    g_KL[o] = sk * (1.f / 32.f);
}

// ------------------------- pinv helpers -------------------------------------
__global__ void reset_k() { g_scale[0] = 0u; g_scale[1] = 0u; }

__global__ void __launch_bounds__(256) scalemax_k()
{
    int z = blockIdx.x;
    int i = threadIdx.x;
    const float* S = g_S2 + ((long long)z << 16);
    float rs = 0.f, cs = 0.f;
    for (int j = 0; j < 256; j++) { rs += S[(i << 8) + j]; cs += S[(j << 8) + i]; }
    float rm = blockReduce(rs, true);
    float cm = blockReduce(cs, true);
    if (i == 0) {
        atomicMax(&g_scale[0], __float_as_uint(rm));
        atomicMax(&g_scale[1], __float_as_uint(cm));
    }
}

__global__ void __launch_bounds__(256) zinit_k()
{
    int idx = blockIdx.x * 256 + threadIdx.x;
    float inv = 1.0f / (__uint_as_float(g_scale[0]) * __uint_as_float(g_scale[1]));
    int z = idx >> 16, r = idx & 65535;
    int i = r >> 8, j = r & 255;
    g_Zb[((long long)z << 16) + (i << 8) + j] = g_S2[((long long)z << 16) + (j << 8) + i] * inv;
}

// ------------------------- split-K reduce for AV ----------------------------
__global__ void __launch_bounds__(256) avreduce_k()
{
    int idx = blockIdx.x * 256 + threadIdx.x;       // NBH*LM*DH = 262144
    int bh = idx >> 14;
    int r  = idx & 16383;
    const float* p = g_AVp + ((long long)bh << 17);
    float s = 0.f;
    #pragma unroll
    for (int k = 0; k < KSPL; k++) s += p[(k << 14) + r];
    g_AV[idx] = s;
}

// ------------------------- depthwise conv residual (adds into g_OH) ---------
__global__ void __launch_bounds__(256) conv_k(const float* __restrict__ cw)
{
    __shared__ float sv[160 * 64];
    __shared__ float sw[KER];
    int tile = blockIdx.x;
    int bh = blockIdx.y;
    int b = bh >> 3, h = bh & 7;
    int n0 = tile * 128;
    int t = threadIdx.x;
    if (t < KER) sw[t] = cw[h * KER + t];
    for (int idx = t; idx < 160 * 64; idx += 256) {
        int r = idx >> 6, d = idx & 63;
        int nn = n0 - 16 + r;
        float v = 0.f;
        if (nn >= 0 && nn < NF) v = g_QKV[(long long)(b * NF + nn) * QD + 1024 + h * 64 + d];
        sv[idx] = v;
    }
    __syncthreads();
    int d = t & 63, r0 = t >> 6;
    for (int rr = r0; rr < 128; rr += 4) {
        float a = 0.f;
        #pragma unroll
        for (int k = 0; k < KER; k++) a += sv[(rr + k) * 64 + d] * sw[k];
        long long o = ((long long)bh * NF + n0 + rr) * DH + d;
        g_OH[o] += a;
    }
}

// ------------------------- cls token fill -----------------------------------
__global__ void __launch_bounds__(256) cls_k(const float* __restrict__ ct)
{
    int idx = blockIdx.x * 256 + threadIdx.x;   // 1024
    int b = idx >> 9, c = idx & 511;
    g_X[(long long)b * NF * DIMM + c] = ct[c];
}

// ------------------------- final LN + head ----------------------------------
__global__ void __launch_bounds__(256) final_k(const float* __restrict__ fg, const float* __restrict__ fb,
                                               const float* __restrict__ w2, const float* __restrict__ b2,
                                               float* __restrict__ out)
{
    int b = blockIdx.x;
    const float* x = g_X + (long long)b * NF * DIMM;
    int t = threadIdx.x;
    float v0 = x[t], v1 = x[t + 256];
    float mu  = blockReduce(v0 + v1, false) * (1.f / 512.f);
    float d0 = v0 - mu, d1 = v1 - mu;
    float var = blockReduce(d0 * d0 + d1 * d1, false) * (1.f / 512.f);
    float inv = rsqrtf(var + 1e-5f);
    float n0 = d0 * inv * fg[t]       + fb[t];
    float n1 = d1 * inv * fg[t + 256] + fb[t + 256];
    float p0 = n0 * w2[2 * t]     + n1 * w2[2 * (t + 256)];
    float p1 = n0 * w2[2 * t + 1] + n1 * w2[2 * (t + 256) + 1];
    p0 = blockReduce(p0, false);
    p1 = blockReduce(p1, false);
    if (t == 0) {
        out[b * 2 + 0] = p0 + b2[0];
        out[b * 2 + 1] = p1 + b2[1];
    }
}

// ------------------------- host orchestration -------------------------------
static inline void gemm128(int transB, int M, int N, int K,
                           const float* A, int lda, long long sA1, long long sA2,
                           const float* Bp, int ldb, long long sB1, long long sB2,
                           float* C, int ldc, long long sC1, long long sC2,
                           int batch, float alpha, int ep, const float* bias, int amode = 0)
{
    dim3 g(N >> 7, (M + 127) >> 7, batch);
    if (transB)
        gemm128_k<1><<<g, 256>>>(M, N, K, A, lda, sA1, sA2, Bp, ldb, sB1, sB2, C, ldc, sC1, sC2, alpha, ep, bias, amode);
    else
        gemm128_k<0><<<g, 256>>>(M, N, K, A, lda, sA1, sA2, Bp, ldb, sB1, sB2, C, ldc, sC1, sC2, alpha, ep, bias, amode);
}

static inline void gemm64(int transB, int M, int N, int K,
                          const float* A, int lda, long long sA1, long long sA2, long long sA3,
                          const float* Bp, int ldb, long long sB1, long long sB2, long long sB3,
                          float* C, int ldc, long long sC1, long long sC2, long long sC3,
                          int SPLIT, int batchZ, float alpha, int ep, const float* bias,
                          int bmode, float bdiag)
{
    dim3 g(N >> 6, (M + 63) >> 6, batchZ);
    if (transB)
        gemm64_k<1><<<g, 256>>>(M, N, K, A, lda, sA1, sA2, sA3, Bp, ldb, sB1, sB2, sB3,
                                C, ldc, sC1, sC2, sC3, SPLIT, alpha, ep, bias, bmode, bdiag);
    else
        gemm64_k<0><<<g, 256>>>(M, N, K, A, lda, sA1, sA2, sA3, Bp, ldb, sB1, sB2, sB3,
                                C, ldc, sC1, sC2, sC3, SPLIT, alpha, ep, bias, bmode, bdiag);
}

extern "C" void kernel_launch(void* const* d_in, const int* in_sizes, int n_in,
                              void* d_out, int out_size)
{
    const float* h_in  = (const float*)d_in[0];
    const float* w1    = (const float*)d_in[1];
    const float* b1    = (const float*)d_in[2];
    const float* clst  = (const float*)d_in[3];
    const float* ln_g  = (const float*)d_in[4];
    const float* ln_b  = (const float*)d_in[5];
    const float* wqkv  = (const float*)d_in[6];
    const float* wout  = (const float*)d_in[7];
    const float* bout  = (const float*)d_in[8];
    const float* cw    = (const float*)d_in[9];
    const float* fg    = (const float*)d_in[10];
    const float* fb    = (const float*)d_in[11];
    const float* w2    = (const float*)d_in[12];
    const float* b2    = (const float*)d_in[13];
    float* out = (float*)d_out;

    float *X, *XN, *QKV, *QL, *KL, *S1, *S2, *S3, *Z, *Z2, *P, *T, *T2, *AV, *AVp, *ZAV, *OH;
    cudaGetSymbolAddress((void**)&X,   g_X);
    cudaGetSymbolAddress((void**)&XN,  g_XN);
    cudaGetSymbolAddress((void**)&QKV, g_QKV);
    cudaGetSymbolAddress((void**)&QL,  g_QL);
    cudaGetSymbolAddress((void**)&KL,  g_KL);
    cudaGetSymbolAddress((void**)&S1,  g_S1);
    cudaGetSymbolAddress((void**)&S2,  g_S2);
    cudaGetSymbolAddress((void**)&S3,  g_S3);
    cudaGetSymbolAddress((void**)&Z,   g_Zb);
    cudaGetSymbolAddress((void**)&Z2,  g_Z2b);
    cudaGetSymbolAddress((void**)&P,   g_Pb);
    cudaGetSymbolAddress((void**)&T,   g_Tb);
    cudaGetSymbolAddress((void**)&T2,  g_T2b);
    cudaGetSymbolAddress((void**)&AV,  g_AV);
    cudaGetSymbolAddress((void**)&AVp, g_AVp);
    cudaGetSymbolAddress((void**)&ZAV, g_ZAV);
    cudaGetSymbolAddress((void**)&OH,  g_OH);

    const long long SQb = (long long)NF * QD;
    const long long S2s = (long long)LM * LM;
    const long long S1s = (long long)NF * LM;
    const long long AVs = (long long)LM * DH;
    const long long OHs = (long long)NF * DH;

    // input projection: X[b, n+1, :] = relu(h @ w1 + b1); X[b,0,:] = cls
    gemm128(0, NB * 8191, DIMM, 1024, h_in, 1024, 0, 0, w1, DIMM, 0, 0,
            X, DIMM, 0, 0, 1, 1.f, EP_RELU_REMAP, b1);
    cls_k<<<4, 256>>>(clst);

    for (int L = 0; L < 2; L++) {
        ln_k<<<TOT, 256>>>(X, XN, ln_g + L * DIMM, ln_b + L * DIMM);

        // qkv = ln(x) @ Wqkv  (q cols scaled by 1/8)
        gemm128(0, TOT, QD, DIMM, XN, DIMM, 0, 0, wqkv + (long long)L * DIMM * QD, QD, 0, 0,
                QKV, QD, 0, 0, 1, 1.f, EP_SCALEQ, nullptr);

        landmark_k<<<NBH * LM, 64>>>();

        // sim2 = QL @ KL^T, softmax
        gemm64(1, LM, LM, DH, QL, DH, 8 * AVs, AVs, 0, KL, DH, 8 * AVs, AVs, 0,
               S2, LM, 8 * S2s, S2s, 0, 1, NBH, 1.f, EP_NONE, nullptr, 0, 0.f);
        softmax256_k<<<NBH * LM / 8, 256>>>(S2);

        // Moore-Penrose pinv of S2 -> Z (6 Newton iters, (cI - X) fused in B-load)
        reset_k<<<1, 1>>>();
        scalemax_k<<<NBH, 256>>>();
        zinit_k<<<4096, 256>>>();
        for (int it = 0; it < 6; it++) {
            float* Zin  = (it & 1) ? Z2 : Z;
            float* Zout = (it & 1) ? Z  : Z2;
            gemm64(0, LM, LM, LM, S2, LM, 8 * S2s, S2s, 0, Zin, LM, 8 * S2s, S2s, 0,
                   P, LM, 8 * S2s, S2s, 0, 1, NBH, 1.f, EP_NONE, nullptr, 0, 0.f);
            gemm64(0, LM, LM, LM, P, LM, 8 * S2s, S2s, 0, P, LM, 8 * S2s, S2s, 0,
                   T2, LM, 8 * S2s, S2s, 0, 1, NBH, 1.f, EP_NONE, nullptr, 1, 7.f);
            gemm64(0, LM, LM, LM, P, LM, 8 * S2s, S2s, 0, T2, LM, 8 * S2s, S2s, 0,
                   T, LM, 8 * S2s, S2s, 0, 1, NBH, 1.f, EP_NONE, nullptr, 1, 15.f);
            gemm64(0, LM, LM, LM, Zin, LM, 8 * S2s, S2s, 0, T, LM, 8 * S2s, S2s, 0,
                   Zout, LM, 8 * S2s, S2s, 0, 1, NBH, 0.25f, EP_NONE, nullptr, 1, 13.f);
        }

        // sim1 = Q @ KL^T, softmax
        gemm128(1, NF, LM, DH, QKV, QD, SQb, 64, KL, DH, 8 * AVs, AVs,
                S1, LM, 8 * S1s, S1s, NBH, 1.f, EP_NONE, nullptr);
        softmax256_k<<<NBH * NF / 8, 256>>>(S1);

        // sim3 = QL @ K^T, softmax over 8192
        gemm128(1, LM, NF, DH, QL, DH, 8 * AVs, AVs, QKV + 512, QD, SQb, 64,
                S3, NF, 8 * S1s, S1s, NBH, 1.f, EP_NONE, nullptr);
        softmax_k<<<NBH * LM, 256, NF * 4>>>(S3, NF);

        // AV = attn3 @ V  (split-K by 8 into partials, then reduce)
        gemm64(0, LM, DH, NF / KSPL,
               S3, NF, 8 * S1s, S1s, 1024,
               QKV + 1024, QD, SQb, 64, 1024LL * QD,
               AVp, DH, 64 * AVs, 8 * AVs, AVs,
               KSPL, NBH * KSPL, 1.f, EP_NONE, nullptr, 0, 0.f);
        avreduce_k<<<1024, 256>>>();

        // ZAV = Z @ AV
        gemm64(0, LM, DH, LM, Z, LM, 8 * S2s, S2s, 0, AV, DH, 8 * AVs, AVs, 0,
               ZAV, DH, 8 * AVs, AVs, 0, 1, NBH, 1.f, EP_NONE, nullptr, 0, 0.f);
        // OH = attn1 @ ZAV
        gemm64(0, NF, DH, LM, S1, LM, 8 * S1s, S1s, 0, ZAV, DH, 8 * AVs, AVs, 0,
               OH, DH, 8 * OHs, OHs, 0, 1, NBH, 1.f, EP_NONE, nullptr, 0, 0.f);

        // OH += depthwise conv residual of V
        { dim3 g(NF / 128, NBH); conv_k<<<g, 256>>>(cw + L * NH * KER); }

        // X += OH(head-layout) @ Wout + bout   (transpose fused into A-load)
        gemm128(0, TOT, DIMM, DIMM, OH, 0, 0, 0, wout + (long long)L * DIMM * DIMM, DIMM, 0, 0,
                X, DIMM, 0, 0, 1, 1.f, EP_ADDBIAS, bout + L * DIMM, 1);
    }

    final_k<<<NB, 256>>>(fg, fb, w2, b2, out);
}

// round 5
// speedup vs baseline: 1.2728x; 1.0168x over previous
#include <cuda_runtime.h>

#define NB   2
#define NF   8192
#define DIMM 512
#define NH   8
#define DH   64
#define LM   256
#define QD   1536
#define TOT  (NB*NF)    // 16384
#define NBH  (NB*NH)    // 16
#define KER  33
#define KSPL 8

// ------------------------- scratch (device globals, no allocs) -------------
__device__ float g_X  [TOT*DIMM];
__device__ float g_XN [TOT*DIMM];
__device__ float g_QKV[TOT*QD];
__device__ float g_QL [NBH*LM*DH];
__device__ float g_KL [NBH*LM*DH];
__device__ float g_S1 [NBH*NF*LM];
__device__ float g_S3 [NBH*LM*NF];
__device__ float g_S2 [NBH*LM*LM];
__device__ float g_Zb [NBH*LM*LM];
__device__ float g_Z2b[NBH*LM*LM];
__device__ float g_Pb [NBH*LM*LM];
__device__ float g_Tb [NBH*LM*LM];
__device__ float g_T2b[NBH*LM*LM];
__device__ float g_AV [NBH*LM*DH];
__device__ float g_AVp[NBH*KSPL*LM*DH];
__device__ float g_ZAV[NBH*LM*DH];
__device__ float g_OH [NBH*NF*DH];
__device__ unsigned int g_scale[2];

enum { EP_NONE = 0, EP_RELU_REMAP = 1, EP_SCALEQ = 2, EP_ADDBIAS = 3 };

__device__ __forceinline__ unsigned f2tf32(float f) {
    unsigned r;
    asm("cvt.rna.tf32.f32 %0, %1;" : "=r"(r) : "f"(f));
    return r;
}

// ===================== mma.sync tf32 GEMM, 128x128 tile =====================
// C[r,c] = sum_k A[r,k] * B[k,c]   (A row-major [M,K], B row-major [K,N])
// amode=1: A element (r,k) from OH layout ((b*8+h)*8192+n)*64+d
// 8 warps, warp tile 32x64 (2 m16-tiles x 8 n8-tiles), K chunk 16.
__global__ void __launch_bounds__(256) mgemm_k(
    int M, int K,
    const float* __restrict__ A, int lda, int amode,
    const float* __restrict__ B, int ldb,
    float* __restrict__ C, int ldc,
    int ep, const float* __restrict__ bias)
{
    // fragment-order smem: Af[kt][mt(8)][lane][4], Bf[kt][nt(16)][lane][2]
    __shared__ unsigned Af[2048];
    __shared__ unsigned Bf[2048];

    int tid = threadIdx.x;
    int lane = tid & 31, wid = tid >> 5;
    int wm = wid & 3, wn = wid >> 2;        // m-group (4), n-group (2)
    int row0 = blockIdx.y << 7, col0 = blockIdx.x << 7;

    float acc[2][8][4];
    #pragma unroll
    for (int mi = 0; mi < 2; mi++)
        #pragma unroll
        for (int ni = 0; ni < 8; ni++)
            #pragma unroll
            for (int q = 0; q < 4; q++) acc[mi][ni][q] = 0.f;

    float4 pa[2], pb[2];

    auto fetch = [&](int k0) {
        #pragma unroll
        for (int i = 0; i < 2; i++) {
            int f = tid + (i << 8);
            int r = f >> 2, k4 = (f & 3) << 2;
            int gr = row0 + r;
            if (amode == 0) {
                pa[i] = make_float4(0.f, 0.f, 0.f, 0.f);
                if (gr < M) pa[i] = *(const float4*)(A + (long long)gr * lda + k0 + k4);
            } else {
                int k = k0 + k4;
                int h = k >> 6, d = k & 63;
                long long o = ((((long long)(gr >> 13) << 3) + h) * 8192 + (gr & 8191)) * 64 + d;
                pa[i] = *(const float4*)(A + o);
            }
        }
        #pragma unroll
        for (int i = 0; i < 2; i++) {
            int f = tid + (i << 8);
            int k = f >> 5, n4 = (f & 31) << 2;
            pb[i] = *(const float4*)(B + (long long)(k0 + k) * ldb + col0 + n4);
        }
    };

    fetch(0);
    int nch = K >> 4;
    for (int it = 0; it < nch; it++) {
        // ---- stash A into fragment layout ----
        #pragma unroll
        for (int i = 0; i < 2; i++) {
            int f = tid + (i << 8);
            int r = f >> 2, k4 = (f & 3) << 2;
            int mt = r >> 4, rho = r & 15;
            float v[4] = {pa[i].x, pa[i].y, pa[i].z, pa[i].w};
            #pragma unroll
            for (int kk = 0; kk < 4; kk++) {
                int cf = k4 + kk;
                int kt = cf >> 3, c = cf & 7;
                int j = ((c >> 2) << 1) | (rho >> 3);
                int l = ((rho & 7) << 2) | (c & 3);
                Af[(((kt << 3) + mt) << 7) + (l << 2) + j] = f2tf32(v[kk]);
            }
        }
        // ---- stash B ----
        #pragma unroll
        for (int i = 0; i < 2; i++) {
            int f = tid + (i << 8);
            int k = f >> 5, n4 = (f & 31) << 2;
            int kt = k >> 3, c = k & 7, j = c >> 2;
            float v[4] = {pb[i].x, pb[i].y, pb[i].z, pb[i].w};
            #pragma unroll
            for (int nu = 0; nu < 4; nu++) {
                int n = n4 + nu;
                int nt = n >> 3;
                int l = ((n & 7) << 2) | (c & 3);
                Bf[(((kt << 4) + nt) << 6) + (l << 1) + j] = f2tf32(v[nu]);
            }
        }
        __syncthreads();
        if (it + 1 < nch) fetch((it + 1) << 4);
        // ---- compute: 2 k8 steps x 2 m-tiles x 8 n-tiles ----
        #pragma unroll
        for (int kt = 0; kt < 2; kt++) {
            unsigned a[2][4];
            #pragma unroll
            for (int mi = 0; mi < 2; mi++) {
                int mt = (wm << 1) + mi;
                *(uint4*)a[mi] = *(const uint4*)&Af[(((kt << 3) + mt) << 7) + (lane << 2)];
            }
            unsigned b[8][2];
            #pragma unroll
            for (int ni = 0; ni < 8; ni++) {
                int nt = (wn << 3) + ni;
                *(uint2*)b[ni] = *(const uint2*)&Bf[(((kt << 4) + nt) << 6) + (lane << 1)];
            }
            #pragma unroll
            for (int mi = 0; mi < 2; mi++)
                #pragma unroll
                for (int ni = 0; ni < 8; ni++)
                    asm volatile(
                        "mma.sync.aligned.m16n8k8.row.col.f32.tf32.tf32.f32 "
                        "{%0,%1,%2,%3}, {%4,%5,%6,%7}, {%8,%9}, {%0,%1,%2,%3};"
                        : "+f"(acc[mi][ni][0]), "+f"(acc[mi][ni][1]),
                          "+f"(acc[mi][ni][2]), "+f"(acc[mi][ni][3])
                        : "r"(a[mi][0]), "r"(a[mi][1]), "r"(a[mi][2]), "r"(a[mi][3]),
                          "r"(b[ni][0]), "r"(b[ni][1]));
        }
        __syncthreads();
    }

    // ---- epilogue: direct gmem, float2 per (tile, half) ----
    int rbase = row0 + (wm << 5) + (lane >> 2);
    int cbase = col0 + (wn << 6) + ((lane & 3) << 1);
    #pragma unroll
    for (int mi = 0; mi < 2; mi++) {
        #pragma unroll
        for (int half = 0; half < 2; half++) {
            int r = rbase + (mi << 4) + (half << 3);
            if (r >= M) continue;
            #pragma unroll
            for (int ni = 0; ni < 8; ni++) {
                int c = cbase + (ni << 3);
                float v0 = acc[mi][ni][half * 2];
                float v1 = acc[mi][ni][half * 2 + 1];
                if (ep == EP_RELU_REMAP) {
                    long long o = (long long)(r + r / 8191 + 1) * ldc + c;
                    v0 = fmaxf(v0 + bias[c], 0.f);
                    v1 = fmaxf(v1 + bias[c + 1], 0.f);
                    *(float2*)(C + o) = make_float2(v0, v1);
                } else if (ep == EP_SCALEQ) {
                    float sc = (c < 512) ? 0.125f : 1.0f;
                    *(float2*)(C + (long long)r * ldc + c) = make_float2(v0 * sc, v1 * sc);
                } else if (ep == EP_ADDBIAS) {
                    long long o = (long long)r * ldc + c;
                    float2 old = *(float2*)(C + o);
                    *(float2*)(C + o) = make_float2(old.x + v0 + bias[c],
                                                    old.y + v1 + bias[c + 1]);
                } else {
                    *(float2*)(C + (long long)r * ldc + c) = make_float2(v0, v1);
                }
            }
        }
    }
}

// ------------------------- reductions --------------------------------------
__device__ __forceinline__ float blockReduce(float v, bool domax) {
    __shared__ float sh[32];
    __syncthreads();
    #pragma unroll
    for (int o = 16; o > 0; o >>= 1) {
        float w = __shfl_down_sync(0xffffffffu, v, o);
        v = domax ? fmaxf(v, w) : v + w;
    }
    int lane = threadIdx.x & 31, wid = threadIdx.x >> 5;
    if (lane == 0) sh[wid] = v;
    __syncthreads();
    int nw = (blockDim.x + 31) >> 5;
    if (wid == 0) {
        v = (lane < nw) ? sh[lane] : (domax ? -1e30f : 0.f);
        #pragma unroll
        for (int o = 16; o > 0; o >>= 1) {
            float w = __shfl_down_sync(0xffffffffu, v, o);
            v = domax ? fmaxf(v, w) : v + w;
        }
        if (lane == 0) sh[0] = v;
    }
    __syncthreads();
    return sh[0];
}

// ===================== 128x128x16 SIMT GEMM (TRANSB users) ==================
template<int TRANSB>
__global__ void __launch_bounds__(256, 2) gemm128_k(
    int M, int N, int K,
    const float* __restrict__ A, int lda, long long sA1, long long sA2,
    const float* __restrict__ Bp, int ldb, long long sB1, long long sB2,
    float* __restrict__ C, int ldc, long long sC1, long long sC2,
    float alpha, int ep, const float* __restrict__ bias, int amode)
{
    __shared__ float As[2][16 * 136];
    __shared__ float Bs[2][16 * 136];
    int z = blockIdx.z;
    A  += (long long)(z >> 3) * sA1 + (long long)(z & 7) * sA2;
    Bp += (long long)(z >> 3) * sB1 + (long long)(z & 7) * sB2;
    C  += (long long)(z >> 3) * sC1 + (long long)(z & 7) * sC2;
    int row0 = blockIdx.y << 7;
    int col0 = blockIdx.x << 7;
    int tid = threadIdx.x;
    int tx = tid & 15, ty = tid >> 4;

    int a_r  = tid >> 2;
    int a_kk = (tid & 3) << 2;
    int bn_kk = tid >> 5;
    int bn_n  = (tid & 31) << 2;
    int bt_n  = tid >> 2;
    int bt_kk = (tid & 3) << 2;

    float acc[8][8];
    #pragma unroll
    for (int i = 0; i < 8; i++)
        #pragma unroll
        for (int j = 0; j < 8; j++) acc[i][j] = 0.f;

    float4 pa0, pa1, pb0, pb1;

    auto fetch = [&](int k0) {
        int gr0 = row0 + a_r, gr1 = gr0 + 64;
        pa0 = make_float4(0.f, 0.f, 0.f, 0.f);
        pa1 = pa0;
        if (gr0 < M) pa0 = *(const float4*)(A + (long long)gr0 * lda + k0 + a_kk);
        if (gr1 < M) pa1 = *(const float4*)(A + (long long)gr1 * lda + k0 + a_kk);
        if (!TRANSB) {
            pb0 = *(const float4*)(Bp + (long long)(k0 + bn_kk) * ldb + col0 + bn_n);
            pb1 = *(const float4*)(Bp + (long long)(k0 + bn_kk + 8) * ldb + col0 + bn_n);
        } else {
            pb0 = *(const float4*)(Bp + (long long)(col0 + bt_n) * ldb + k0 + bt_kk);
            pb1 = *(const float4*)(Bp + (long long)(col0 + bt_n + 64) * ldb + k0 + bt_kk);
        }
    };

    auto stash = [&](int b) {
        float* Ab = As[b];
        Ab[(a_kk + 0) * 136 + a_r] = pa0.x;
        Ab[(a_kk + 1) * 136 + a_r] = pa0.y;
        Ab[(a_kk + 2) * 136 + a_r] = pa0.z;
        Ab[(a_kk + 3) * 136 + a_r] = pa0.w;
        Ab[(a_kk + 0) * 136 + a_r + 64] = pa1.x;
        Ab[(a_kk + 1) * 136 + a_r + 64] = pa1.y;
        Ab[(a_kk + 2) * 136 + a_r + 64] = pa1.z;
        Ab[(a_kk + 3) * 136 + a_r + 64] = pa1.w;
        float* Bb = Bs[b];
        if (!TRANSB) {
            *(float4*)&Bb[bn_kk * 136 + bn_n] = pb0;
            *(float4*)&Bb[(bn_kk + 8) * 136 + bn_n] = pb1;
        } else {
            Bb[(bt_kk + 0) * 136 + bt_n] = pb0.x;
            Bb[(bt_kk + 1) * 136 + bt_n] = pb0.y;
            Bb[(bt_kk + 2) * 136 + bt_n] = pb0.z;
            Bb[(bt_kk + 3) * 136 + bt_n] = pb0.w;
            Bb[(bt_kk + 0) * 136 + bt_n + 64] = pb1.x;
            Bb[(bt_kk + 1) * 136 + bt_n + 64] = pb1.y;
            Bb[(bt_kk + 2) * 136 + bt_n + 64] = pb1.z;
            Bb[(bt_kk + 3) * 136 + bt_n + 64] = pb1.w;
        }
    };

    fetch(0);
    stash(0);
    __syncthreads();

    int nt = K >> 4;
    for (int t = 0; t < nt; t++) {
        int buf = t & 1;
        if (t + 1 < nt) fetch((t + 1) << 4);
        const float* Ab = As[buf];
        const float* Bb = Bs[buf];
        #pragma unroll
        for (int kk = 0; kk < 16; kk++) {
            float4 a0 = *(const float4*)&Ab[kk * 136 + (ty << 3)];
            float4 a1 = *(const float4*)&Ab[kk * 136 + (ty << 3) + 4];
            float4 b0 = *(const float4*)&Bb[kk * 136 + (tx << 3)];
            float4 b1 = *(const float4*)&Bb[kk * 136 + (tx << 3) + 4];
            float av[8] = {a0.x, a0.y, a0.z, a0.w, a1.x, a1.y, a1.z, a1.w};
            float bv[8] = {b0.x, b0.y, b0.z, b0.w, b1.x, b1.y, b1.z, b1.w};
            #pragma unroll
            for (int i = 0; i < 8; i++)
                #pragma unroll
                for (int j = 0; j < 8; j++)
                    acc[i][j] += av[i] * bv[j];
        }
        if (t + 1 < nt) stash(buf ^ 1);
        __syncthreads();
    }

    #pragma unroll
    for (int i = 0; i < 8; i++) {
        int r = row0 + (ty << 3) + i;
        if (r >= M) continue;
        #pragma unroll
        for (int j = 0; j < 8; j++) {
            int c = col0 + (tx << 3) + j;
            C[(long long)r * ldc + c] = alpha * acc[i][j];
        }
    }
}

// ===================== 64x64x16 GEMM, 4x4 microtile, double-buffered ========
template<int TRANSB>
__global__ void __launch_bounds__(256) gemm64_k(
    int M, int N, int K,
    const float* __restrict__ A, int lda, long long sA1, long long sA2, long long sA3,
    const float* __restrict__ Bp, int ldb, long long sB1, long long sB2, long long sB3,
    float* __restrict__ C, int ldc, long long sC1, long long sC2, long long sC3,
    int SPLIT, float alpha, int ep, const float* __restrict__ bias,
    int bmode, float bdiag)
{
    __shared__ float As[2][16 * 68];
    __shared__ float Bs[2][16 * 68];
    int z = blockIdx.z;
    int s  = z % SPLIT;
    int bh = z / SPLIT;
    int hh = bh & 7, bb = bh >> 3;
    A  += (long long)bb * sA1 + (long long)hh * sA2 + (long long)s * sA3;
    Bp += (long long)bb * sB1 + (long long)hh * sB2 + (long long)s * sB3;
    C  += (long long)bb * sC1 + (long long)hh * sC2 + (long long)s * sC3;
    int row0 = blockIdx.y << 6;
    int col0 = blockIdx.x << 6;
    int tid = threadIdx.x;
    int tx = tid & 15, ty = tid >> 4;

    int a_r  = tid >> 2;
    int a_kk = (tid & 3) << 2;
    int bn_kk = tid >> 4;
    int bn_n  = (tid & 15) << 2;
    int bt_n  = tid >> 2;
    int bt_kk = (tid & 3) << 2;

    float acc[4][4];
    #pragma unroll
    for (int i = 0; i < 4; i++)
        #pragma unroll
        for (int j = 0; j < 4; j++) acc[i][j] = 0.f;

    float4 pa, pb;

    auto fetch = [&](int k0) {
        int gr = row0 + a_r;
        pa = make_float4(0.f, 0.f, 0.f, 0.f);
        if (gr < M) pa = *(const float4*)(A + (long long)gr * lda + k0 + a_kk);
        if (!TRANSB) {
            pb = *(const float4*)(Bp + (long long)(k0 + bn_kk) * ldb + col0 + bn_n);
        } else {
            pb = *(const float4*)(Bp + (long long)(col0 + bt_n) * ldb + k0 + bt_kk);
        }
    };

    auto stash = [&](int b, int k0) {
        float* Ab = As[b];
        Ab[(a_kk + 0) * 68 + a_r] = pa.x;
        Ab[(a_kk + 1) * 68 + a_r] = pa.y;
        Ab[(a_kk + 2) * 68 + a_r] = pa.z;
        Ab[(a_kk + 3) * 68 + a_r] = pa.w;
        float* Bb = Bs[b];
        if (!TRANSB) {
            float4 v = pb;
            if (bmode) {
                int gk = k0 + bn_kk, gn = col0 + bn_n;
                v.x = (gk == gn + 0 ? bdiag : 0.f) - v.x;
                v.y = (gk == gn + 1 ? bdiag : 0.f) - v.y;
                v.z = (gk == gn + 2 ? bdiag : 0.f) - v.z;
                v.w = (gk == gn + 3 ? bdiag : 0.f) - v.w;
            }
            *(float4*)&Bb[bn_kk * 68 + bn_n] = v;
        } else {
            Bb[(bt_kk + 0) * 68 + bt_n] = pb.x;
            Bb[(bt_kk + 1) * 68 + bt_n] = pb.y;
            Bb[(bt_kk + 2) * 68 + bt_n] = pb.z;
            Bb[(bt_kk + 3) * 68 + bt_n] = pb.w;
        }
    };

    fetch(0);
    stash(0, 0);
    __syncthreads();

    int nt = K >> 4;
    for (int t = 0; t < nt; t++) {
        int buf = t & 1;
        if (t + 1 < nt) fetch((t + 1) << 4);
        const float* Ab = As[buf];
        const float* Bb = Bs[buf];
        #pragma unroll
        for (int kk = 0; kk < 16; kk++) {
            float4 a = *(const float4*)&Ab[kk * 68 + (ty << 2)];
            float4 b = *(const float4*)&Bb[kk * 68 + (tx << 2)];
            acc[0][0] += a.x * b.x; acc[0][1] += a.x * b.y; acc[0][2] += a.x * b.z; acc[0][3] += a.x * b.w;
            acc[1][0] += a.y * b.x; acc[1][1] += a.y * b.y; acc[1][2] += a.y * b.z; acc[1][3] += a.y * b.w;
            acc[2][0] += a.z * b.x; acc[2][1] += a.z * b.y; acc[2][2] += a.z * b.z; acc[2][3] += a.z * b.w;
            acc[3][0] += a.w * b.x; acc[3][1] += a.w * b.y; acc[3][2] += a.w * b.z; acc[3][3] += a.w * b.w;
        }
        if (t + 1 < nt) stash(buf ^ 1, (t + 1) << 4);
        __syncthreads();
    }

    #pragma unroll
    for (int i = 0; i < 4; i++) {
        int r = row0 + (ty << 2) + i;
        if (r >= M) continue;
        #pragma unroll
        for (int j = 0; j < 4; j++) {
            int c = col0 + (tx << 2) + j;
            C[(long long)r * ldc + c] = alpha * acc[i][j];
        }
    }
}

// ------------------------- layernorm (rows of 512) --------------------------
__global__ void __launch_bounds__(256) ln_k(const float* __restrict__ X, float* __restrict__ Y,
                                            const float* __restrict__ g, const float* __restrict__ b)
{
    long long row = blockIdx.x;
    const float* x = X + row * DIMM;
    float* y = Y + row * DIMM;
    int t = threadIdx.x;
    float v0 = x[t], v1 = x[t + 256];
    float mu  = blockReduce(v0 + v1, false) * (1.f / 512.f);
    float d0 = v0 - mu, d1 = v1 - mu;
    float var = blockReduce(d0 * d0 + d1 * d1, false) * (1.f / 512.f);
    float inv = rsqrtf(var + 1e-5f);
    y[t]       = d0 * inv * g[t]       + b[t];
    y[t + 256] = d1 * inv * g[t + 256] + b[t + 256];
}

// ------------------------- warp-per-row softmax, 256 cols -------------------
__global__ void __launch_bounds__(256) softmax256_k(float* __restrict__ S)
{
    long long row = ((long long)blockIdx.x << 3) + (threadIdx.x >> 5);
    int lane = threadIdx.x & 31;
    float* s = S + (row << 8);
    float4 va = *(float4*)(s + (lane << 3));
    float4 vb = *(float4*)(s + (lane << 3) + 4);
    float m = fmaxf(fmaxf(fmaxf(va.x, va.y), fmaxf(va.z, va.w)),
                    fmaxf(fmaxf(vb.x, vb.y), fmaxf(vb.z, vb.w)));
    #pragma unroll
    for (int o = 16; o > 0; o >>= 1) m = fmaxf(m, __shfl_xor_sync(0xffffffffu, m, o));
    va.x = __expf(va.x - m); va.y = __expf(va.y - m); va.z = __expf(va.z - m); va.w = __expf(va.w - m);
    vb.x = __expf(vb.x - m); vb.y = __expf(vb.y - m); vb.z = __expf(vb.z - m); vb.w = __expf(vb.w - m);
    float sum = va.x + va.y + va.z + va.w + vb.x + vb.y + vb.z + vb.w;
    #pragma unroll
    for (int o = 16; o > 0; o >>= 1) sum += __shfl_xor_sync(0xffffffffu, sum, o);
    float inv = 1.f / sum;
    va.x *= inv; va.y *= inv; va.z *= inv; va.w *= inv;
    vb.x *= inv; vb.y *= inv; vb.z *= inv; vb.w *= inv;
    *(float4*)(s + (lane << 3)) = va;
    *(float4*)(s + (lane << 3) + 4) = vb;
}

// ------------------------- block softmax (long rows) ------------------------
__global__ void __launch_bounds__(256) softmax_k(float* __restrict__ S, int cols)
{
    extern __shared__ float buf[];
    long long row = blockIdx.x;
    float* s = S + row * cols;
    int t = threadIdx.x;
    float mx = -1e30f;
    for (int i = t; i < cols; i += 256) { float v = s[i]; buf[i] = v; mx = fmaxf(mx, v); }
    float bmax = blockReduce(mx, true);
    float sum = 0.f;
    for (int i = t; i < cols; i += 256) { float e = __expf(buf[i] - bmax); buf[i] = e; sum += e; }
    float bsum = blockReduce(sum, false);
    float inv = 1.f / bsum;
    for (int i = t; i < cols; i += 256) s[i] = buf[i] * inv;
}

// ------------------------- landmarks (mean of 32 consecutive rows) ----------
__global__ void __launch_bounds__(64) landmark_k()
{
    int zz = blockIdx.x;
    int mi = zz & 255, bh = zz >> 8;
    int b = bh >> 3, h = bh & 7;
    int d = threadIdx.x;
    const float* base = g_QKV + (long long)(b * NF + mi * 32) * QD + h * 64 + d;
    float sq = 0.f, sk = 0.f;
    #pragma unroll 8
    for (int il = 0; il < 32; il++) {
        sq += base[(long long)il * QD];
        sk += base[(long long)il * QD + 512];
    }
    long long o = ((long long)bh * LM + mi) * DH + d;
    g_QL[o] = sq * (1.f / 32.f);
    g_KL[o] = sk * (1.f / 32.f);
}

// ------------------------- pinv helpers -------------------------------------
__global__ void reset_k() { g_scale[0] = 0u; g_scale[1] = 0u; }

__global__ void __launch_bounds__(256) scalemax_k()
{
    int z = blockIdx.x;
    int i = threadIdx.x;
    const float* S = g_S2 + ((long long)z << 16);
    float rs = 0.f, cs = 0.f;
    for (int j = 0; j < 256; j++) { rs += S[(i << 8) + j]; cs += S[(j << 8) + i]; }
    float rm = blockReduce(rs, true);
    float cm = blockReduce(cs, true);
    if (i == 0) {
        atomicMax(&g_scale[0], __float_as_uint(rm));
        atomicMax(&g_scale[1], __float_as_uint(cm));
    }
}

__global__ void __launch_bounds__(256) zinit_k()
{
    int idx = blockIdx.x * 256 + threadIdx.x;
    float inv = 1.0f / (__uint_as_float(g_scale[0]) * __uint_as_float(g_scale[1]));
    int z = idx >> 16, r = idx & 65535;
    int i = r >> 8, j = r & 255;
    g_Zb[((long long)z << 16) + (i << 8) + j] = g_S2[((long long)z << 16) + (j << 8) + i] * inv;
}

// ------------------------- split-K reduce for AV ----------------------------
__global__ void __launch_bounds__(256) avreduce_k()
{
    int idx = blockIdx.x * 256 + threadIdx.x;
    int bh = idx >> 14;
    int r  = idx & 16383;
    const float* p = g_AVp + ((long long)bh << 17);
    float s = 0.f;
    #pragma unroll
    for (int k = 0; k < KSPL; k++) s += p[(k << 14) + r];
    g_AV[idx] = s;
}

// ------------------------- depthwise conv residual (adds into g_OH) ---------
__global__ void __launch_bounds__(256) conv_k(const float* __restrict__ cw)
{
    __shared__ float sv[160 * 64];
    __shared__ float sw[KER];
    int tile = blockIdx.x;
    int bh = blockIdx.y;
    int b = bh >> 3, h = bh & 7;
    int n0 = tile * 128;
    int t = threadIdx.x;
    if (t < KER) sw[t] = cw[h * KER + t];
    for (int idx = t; idx < 160 * 64; idx += 256) {
        int r = idx >> 6, d = idx & 63;
        int nn = n0 - 16 + r;
        float v = 0.f;
        if (nn >= 0 && nn < NF) v = g_QKV[(long long)(b * NF + nn) * QD + 1024 + h * 64 + d];
        sv[idx] = v;
    }
    __syncthreads();
    int d = t & 63, r0 = t >> 6;
    for (int rr = r0; rr < 128; rr += 4) {
        float a = 0.f;
        #pragma unroll
        for (int k = 0; k < KER; k++) a += sv[(rr + k) * 64 + d] * sw[k];
        long long o = ((long long)bh * NF + n0 + rr) * DH + d;
        g_OH[o] += a;
    }
}

// ------------------------- cls token fill -----------------------------------
__global__ void __launch_bounds__(256) cls_k(const float* __restrict__ ct)
{
    int idx = blockIdx.x * 256 + threadIdx.x;
    int b = idx >> 9, c = idx & 511;
    g_X[(long long)b * NF * DIMM + c] = ct[c];
}

// ------------------------- final LN + head ----------------------------------
__global__ void __launch_bounds__(256) final_k(const float* __restrict__ fg, const float* __restrict__ fb,
                                               const float* __restrict__ w2, const float* __restrict__ b2,
                                               float* __restrict__ out)
{
    int b = blockIdx.x;
    const float* x = g_X + (long long)b * NF * DIMM;
    int t = threadIdx.x;
    float v0 = x[t], v1 = x[t + 256];
    float mu  = blockReduce(v0 + v1, false) * (1.f / 512.f);
    float d0 = v0 - mu, d1 = v1 - mu;
    float var = blockReduce(d0 * d0 + d1 * d1, false) * (1.f / 512.f);
    float inv = rsqrtf(var + 1e-5f);
    float n0 = d0 * inv * fg[t]       + fb[t];
    float n1 = d1 * inv * fg[t + 256] + fb[t + 256];
    float p0 = n0 * w2[2 * t]     + n1 * w2[2 * (t + 256)];
    float p1 = n0 * w2[2 * t + 1] + n1 * w2[2 * (t + 256) + 1];
    p0 = blockReduce(p0, false);
    p1 = blockReduce(p1, false);
    if (t == 0) {
        out[b * 2 + 0] = p0 + b2[0];
        out[b * 2 + 1] = p1 + b2[1];
    }
}

// ------------------------- host orchestration -------------------------------
static inline void gemm128(int transB, int M, int N, int K,
                           const float* A, int lda, long long sA1, long long sA2,
                           const float* Bp, int ldb, long long sB1, long long sB2,
                           float* C, int ldc, long long sC1, long long sC2,
                           int batch, float alpha, int ep, const float* bias, int amode = 0)
{
    dim3 g(N >> 7, (M + 127) >> 7, batch);
    if (transB)
        gemm128_k<1><<<g, 256>>>(M, N, K, A, lda, sA1, sA2, Bp, ldb, sB1, sB2, C, ldc, sC1, sC2, alpha, ep, bias, amode);
    else
        gemm128_k<0><<<g, 256>>>(M, N, K, A, lda, sA1, sA2, Bp, ldb, sB1, sB2, C, ldc, sC1, sC2, alpha, ep, bias, amode);
}

static inline void gemm64(int transB, int M, int N, int K,
                          const float* A, int lda, long long sA1, long long sA2, long long sA3,
                          const float* Bp, int ldb, long long sB1, long long sB2, long long sB3,
                          float* C, int ldc, long long sC1, long long sC2, long long sC3,
                          int SPLIT, int batchZ, float alpha, int ep, const float* bias,
                          int bmode, float bdiag)
{
    dim3 g(N >> 6, (M + 63) >> 6, batchZ);
    if (transB)
        gemm64_k<1><<<g, 256>>>(M, N, K, A, lda, sA1, sA2, sA3, Bp, ldb, sB1, sB2, sB3,
                                C, ldc, sC1, sC2, sC3, SPLIT, alpha, ep, bias, bmode, bdiag);
    else
        gemm64_k<0><<<g, 256>>>(M, N, K, A, lda, sA1, sA2, sA3, Bp, ldb, sB1, sB2, sB3,
                                C, ldc, sC1, sC2, sC3, SPLIT, alpha, ep, bias, bmode, bdiag);
}

static inline void mgemm(int M, int N, int K,
                         const float* A, int lda, int amode,
                         const float* B, int ldb,
                         float* C, int ldc, int ep, const float* bias)
{
    dim3 g(N >> 7, (M + 127) >> 7);
    mgemm_k<<<g, 256>>>(M, K, A, lda, amode, B, ldb, C, ldc, ep, bias);
}

extern "C" void kernel_launch(void* const* d_in, const int* in_sizes, int n_in,
                              void* d_out, int out_size)
{
    const float* h_in  = (const float*)d_in[0];
    const float* w1    = (const float*)d_in[1];
    const float* b1    = (const float*)d_in[2];
    const float* clst  = (const float*)d_in[3];
    const float* ln_g  = (const float*)d_in[4];
    const float* ln_b  = (const float*)d_in[5];
    const float* wqkv  = (const float*)d_in[6];
    const float* wout  = (const float*)d_in[7];
    const float* bout  = (const float*)d_in[8];
    const float* cw    = (const float*)d_in[9];
    const float* fg    = (const float*)d_in[10];
    const float* fb    = (const float*)d_in[11];
    const float* w2    = (const float*)d_in[12];
    const float* b2    = (const float*)d_in[13];
    float* out = (float*)d_out;

    float *X, *XN, *QKV, *QL, *KL, *S1, *S2, *S3, *Z, *Z2, *P, *T, *T2, *AV, *AVp, *ZAV, *OH;
    cudaGetSymbolAddress((void**)&X,   g_X);
    cudaGetSymbolAddress((void**)&XN,  g_XN);
    cudaGetSymbolAddress((void**)&QKV, g_QKV);
    cudaGetSymbolAddress((void**)&QL,  g_QL);
    cudaGetSymbolAddress((void**)&KL,  g_KL);
    cudaGetSymbolAddress((void**)&S1,  g_S1);
    cudaGetSymbolAddress((void**)&S2,  g_S2);
    cudaGetSymbolAddress((void**)&S3,  g_S3);
    cudaGetSymbolAddress((void**)&Z,   g_Zb);
    cudaGetSymbolAddress((void**)&Z2,  g_Z2b);
    cudaGetSymbolAddress((void**)&P,   g_Pb);
    cudaGetSymbolAddress((void**)&T,   g_Tb);
    cudaGetSymbolAddress((void**)&T2,  g_T2b);
    cudaGetSymbolAddress((void**)&AV,  g_AV);
    cudaGetSymbolAddress((void**)&AVp, g_AVp);
    cudaGetSymbolAddress((void**)&ZAV, g_ZAV);
    cudaGetSymbolAddress((void**)&OH,  g_OH);

    const long long SQb = (long long)NF * QD;
    const long long S2s = (long long)LM * LM;
    const long long S1s = (long long)NF * LM;
    const long long AVs = (long long)LM * DH;
    const long long OHs = (long long)NF * DH;

    // input projection (mma.sync tf32): X[b, n+1, :] = relu(h @ w1 + b1)
    mgemm(NB * 8191, DIMM, 1024, h_in, 1024, 0, w1, DIMM, X, DIMM, EP_RELU_REMAP, b1);
    cls_k<<<4, 256>>>(clst);

    for (int L = 0; L < 2; L++) {
        ln_k<<<TOT, 256>>>(X, XN, ln_g + L * DIMM, ln_b + L * DIMM);

        // qkv = ln(x) @ Wqkv (mma.sync tf32; q cols scaled by 1/8)
        mgemm(TOT, QD, DIMM, XN, DIMM, 0, wqkv + (long long)L * DIMM * QD, QD,
              QKV, QD, EP_SCALEQ, nullptr);

        landmark_k<<<NBH * LM, 64>>>();

        // sim2 = QL @ KL^T, softmax
        gemm64(1, LM, LM, DH, QL, DH, 8 * AVs, AVs, 0, KL, DH, 8 * AVs, AVs, 0,
               S2, LM, 8 * S2s, S2s, 0, 1, NBH, 1.f, EP_NONE, nullptr, 0, 0.f);
        softmax256_k<<<NBH * LM / 8, 256>>>(S2);

        // Moore-Penrose pinv of S2 -> Z
        reset_k<<<1, 1>>>();
        scalemax_k<<<NBH, 256>>>();
        zinit_k<<<4096, 256>>>();
        for (int it = 0; it < 6; it++) {
            float* Zin  = (it & 1) ? Z2 : Z;
            float* Zout = (it & 1) ? Z  : Z2;
            gemm64(0, LM, LM, LM, S2, LM, 8 * S2s, S2s, 0, Zin, LM, 8 * S2s, S2s, 0,
                   P, LM, 8 * S2s, S2s, 0, 1, NBH, 1.f, EP_NONE, nullptr, 0, 0.f);
            gemm64(0, LM, LM, LM, P, LM, 8 * S2s, S2s, 0, P, LM, 8 * S2s, S2s, 0,
                   T2, LM, 8 * S2s, S2s, 0, 1, NBH, 1.f, EP_NONE, nullptr, 1, 7.f);
            gemm64(0, LM, LM, LM, P, LM, 8 * S2s, S2s, 0, T2, LM, 8 * S2s, S2s, 0,
                   T, LM, 8 * S2s, S2s, 0, 1, NBH, 1.f, EP_NONE, nullptr, 1, 15.f);
            gemm64(0, LM, LM, LM, Zin, LM, 8 * S2s, S2s, 0, T, LM, 8 * S2s, S2s, 0,
                   Zout, LM, 8 * S2s, S2s, 0, 1, NBH, 0.25f, EP_NONE, nullptr, 1, 13.f);
        }

        // sim1 = Q @ KL^T, softmax
        gemm128(1, NF, LM, DH, QKV, QD, SQb, 64, KL, DH, 8 * AVs, AVs,
                S1, LM, 8 * S1s, S1s, NBH, 1.f, EP_NONE, nullptr);
        softmax256_k<<<NBH * NF / 8, 256>>>(S1);

        // sim3 = QL @ K^T, softmax over 8192
        gemm128(1, LM, NF, DH, QL, DH, 8 * AVs, AVs, QKV + 512, QD, SQb, 64,
                S3, NF, 8 * S1s, S1s, NBH, 1.f, EP_NONE, nullptr);
        softmax_k<<<NBH * LM, 256, NF * 4>>>(S3, NF);

        // AV = attn3 @ V  (split-K by 8 into partials, then reduce)
        gemm64(0, LM, DH, NF / KSPL,
               S3, NF, 8 * S1s, S1s, 1024,
               QKV + 1024, QD, SQb, 64, 1024LL * QD,
               AVp, DH, 64 * AVs, 8 * AVs, AVs,
               KSPL, NBH * KSPL, 1.f, EP_NONE, nullptr, 0, 0.f);
        avreduce_k<<<1024, 256>>>();

        // ZAV = Z @ AV
        gemm64(0, LM, DH, LM, Z, LM, 8 * S2s, S2s, 0, AV, DH, 8 * AVs, AVs, 0,
               ZAV, DH, 8 * AVs, AVs, 0, 1, NBH, 1.f, EP_NONE, nullptr, 0, 0.f);
        // OH = attn1 @ ZAV
        gemm64(0, NF, DH, LM, S1, LM, 8 * S1s, S1s, 0, ZAV, DH, 8 * AVs, AVs, 0,
               OH, DH, 8 * OHs, OHs, 0, 1, NBH, 1.f, EP_NONE, nullptr, 0, 0.f);

        // OH += depthwise conv residual of V
        { dim3 g(NF / 128, NBH); conv_k<<<g, 256>>>(cw + L * NH * KER); }

        // X += OH(head-layout) @ Wout + bout  (mma.sync tf32, transpose in A-load)
        mgemm(TOT, DIMM, DIMM, OH, 0, 1, wout + (long long)L * DIMM * DIMM, DIMM,
              X, DIMM, EP_ADDBIAS, bout + L * DIMM);
    }

    final_k<<<NB, 256>>>(fg, fb, w2, b2, out);
}

// round 6
// speedup vs baseline: 1.8236x; 1.4327x over previous
#include <cuda_runtime.h>

#define NB   2
#define NF   8192
#define DIMM 512
#define NH   8
#define DH   64
#define LM   256
#define QD   1536
#define TOT  (NB*NF)    // 16384
#define NBH  (NB*NH)    // 16
#define KER  33
#define KSPL 8

// ------------------------- scratch (device globals, no allocs) -------------
__device__ float g_X  [TOT*DIMM];
__device__ float g_XN [TOT*DIMM];
__device__ float g_QKV[TOT*QD];
__device__ float g_QL [NBH*LM*DH];
__device__ float g_KL [NBH*LM*DH];
__device__ float g_S1 [NBH*NF*LM];
__device__ float g_S3 [NBH*LM*NF];
__device__ float g_S2 [NBH*LM*LM];
__device__ float g_Zb [NBH*LM*LM];
__device__ float g_Z2b[NBH*LM*LM];
__device__ float g_Pb [NBH*LM*LM];
__device__ float g_Tb [NBH*LM*LM];
__device__ float g_T2b[NBH*LM*LM];
__device__ float g_AV [NBH*LM*DH];
__device__ float g_AVp[NBH*KSPL*LM*DH];
__device__ float g_ZAV[NBH*LM*DH];
__device__ float g_OH [NBH*NF*DH];
__device__ float g_WT [2621440];     // transposed weights: w1T | qkvT(2) | outT(2)
__device__ unsigned int g_scale[2];

enum { EP_NONE = 0, EP_RELU_REMAP = 1, EP_SCALEQ = 2, EP_ADDBIAS = 3 };

// WT offsets
#define OW1   0
#define OQKV(L) (524288 + (L) * 786432)
#define OOUT(L) (2097152 + (L) * 262144)

// ------------------------- weight transpose (K x N -> N x K) ----------------
__global__ void __launch_bounds__(256) transT_k(const float* __restrict__ src,
                                                float* __restrict__ dst, int K, int N)
{
    __shared__ float t[32][33];
    int kb = blockIdx.x << 5, nb = blockIdx.y << 5;
    int x = threadIdx.x & 31, y = threadIdx.x >> 5;   // 32 x 8
    #pragma unroll
    for (int i = 0; i < 32; i += 8)
        t[y + i][x] = src[(long long)(kb + y + i) * N + nb + x];
    __syncthreads();
    #pragma unroll
    for (int i = 0; i < 32; i += 8)
        dst[(long long)(nb + y + i) * K + kb + x] = t[x][y + i];
}

// ===================== mgemm2: cp.async + ldmatrix tf32 =====================
// C[r,c] = sum_k A[r,k] * BT[c][k]   (A row-major [M,K], BT n-major [N][K])
// amode=1: A element (r,k) from OH layout ((b*8+h)*8192+n)*64+d
// CTA tile 128x256, 8 warps of 64x64, K chunk 32, double-buffered smem.
__device__ __forceinline__ void cp16(unsigned dst, const void* src, int nbytes) {
    asm volatile("cp.async.cg.shared.global [%0], [%1], 16, %2;"
                 :: "r"(dst), "l"(src), "r"(nbytes) : "memory");
}

__global__ void __launch_bounds__(256) mgemm2_k(
    int M, int K,
    const float* __restrict__ A, int lda, int amode,
    const float* __restrict__ BT,
    float* __restrict__ C, int ldc,
    int ep, const float* __restrict__ bias)
{
    extern __shared__ float smem[];   // 2 stages x (A 4096 + B 8192 floats) = 96KB
    int tid = threadIdx.x;
    int lane = tid & 31, wid = tid >> 5;
    int wm = wid & 1, wn = wid >> 1;
    int row0 = blockIdx.y << 7, col0 = blockIdx.x << 8;

    unsigned sbase;
    asm("{ .reg .u64 t; cvta.to.shared.u64 t, %1; cvt.u32.u64 %0, t; }"
        : "=r"(sbase) : "l"(smem));

    float acc[4][8][4];
    #pragma unroll
    for (int mi = 0; mi < 4; mi++)
        #pragma unroll
        for (int ni = 0; ni < 8; ni++)
            #pragma unroll
            for (int q = 0; q < 4; q++) acc[mi][ni][q] = 0.f;

    auto fill = [&](int s, int k0) {
        unsigned Ab = sbase + s * 49152u;
        unsigned Bb = Ab + 16384u;
        // A tile: 128 rows x 32 k, 16B per cp.async, SW128 swizzle
        #pragma unroll
        for (int it = 0; it < 4; it++) {
            int idx = (it << 8) + tid;
            int q = idx & 7, r = idx >> 3;
            int gr = row0 + r;
            const float* src;
            int nb = 16;
            if (amode == 0) {
                int gra = gr < M ? gr : (M - 1);
                if (gr >= M) nb = 0;
                src = A + (long long)gra * lda + k0 + (q << 2);
            } else {
                int k = k0 + (q << 2);
                int h = k >> 6, d = k & 63;
                src = A + ((((long long)(gr >> 13) << 3) + h) * 8192 + (gr & 8191)) * 64 + d;
            }
            unsigned dst = Ab + (((r << 5) + ((q ^ (r & 7)) << 2)) << 2);
            cp16(dst, src, nb);
        }
        // B tile: 256 n-rows x 32 k
        #pragma unroll
        for (int it = 0; it < 8; it++) {
            int idx = (it << 8) + tid;
            int q = idx & 7, n = idx >> 3;
            const float* src = BT + (long long)(col0 + n) * K + k0 + (q << 2);
            unsigned dst = Bb + (((n << 5) + ((q ^ (n & 7)) << 2)) << 2);
            cp16(dst, src, 16);
        }
        asm volatile("cp.async.commit_group;" ::: "memory");
    };

    auto compute = [&](int s) {
        unsigned Ab = sbase + s * 49152u;
        unsigned Bb = Ab + 16384u;
        int j = lane >> 3, rho = lane & 7;
        #pragma unroll
        for (int kt = 0; kt < 4; kt++) {
            unsigned a[4][4];
            #pragma unroll
            for (int mi = 0; mi < 4; mi++) {
                int row = (wm << 6) + (mi << 4) + ((j & 1) << 3) + rho;
                int quad = (kt << 1) + (j >> 1);
                unsigned ad = Ab + (((row << 5) + ((quad ^ (row & 7)) << 2)) << 2);
                asm volatile("ldmatrix.sync.aligned.m8n8.x4.shared.b16 {%0,%1,%2,%3}, [%4];"
                    : "=r"(a[mi][0]), "=r"(a[mi][1]), "=r"(a[mi][2]), "=r"(a[mi][3])
                    : "r"(ad));
            }
            unsigned b[8][2];
            #pragma unroll
            for (int np = 0; np < 4; np++) {
                int row = (((wn << 3) + (np << 1) + (j >> 1)) << 3) + rho;
                int quad = (kt << 1) + (j & 1);
                unsigned bd = Bb + (((row << 5) + ((quad ^ (row & 7)) << 2)) << 2);
                asm volatile("ldmatrix.sync.aligned.m8n8.x4.shared.b16 {%0,%1,%2,%3}, [%4];"
                    : "=r"(b[np * 2][0]), "=r"(b[np * 2][1]),
                      "=r"(b[np * 2 + 1][0]), "=r"(b[np * 2 + 1][1])
                    : "r"(bd));
            }
            #pragma unroll
            for (int mi = 0; mi < 4; mi++)
                #pragma unroll
                for (int ni = 0; ni < 8; ni++)
                    asm volatile(
                        "mma.sync.aligned.m16n8k8.row.col.f32.tf32.tf32.f32 "
                        "{%0,%1,%2,%3}, {%4,%5,%6,%7}, {%8,%9}, {%0,%1,%2,%3};"
                        : "+f"(acc[mi][ni][0]), "+f"(acc[mi][ni][1]),
                          "+f"(acc[mi][ni][2]), "+f"(acc[mi][ni][3])
                        : "r"(a[mi][0]), "r"(a[mi][1]), "r"(a[mi][2]), "r"(a[mi][3]),
                          "r"(b[ni][0]), "r"(b[ni][1]));
        }
    };

    fill(0, 0);
    int nch = K >> 5;
    for (int ch = 0; ch < nch; ch++) {
        if (ch + 1 < nch) {
            fill((ch + 1) & 1, (ch + 1) << 5);
            asm volatile("cp.async.wait_group 1;" ::: "memory");
        } else {
            asm volatile("cp.async.wait_group 0;" ::: "memory");
        }
        __syncthreads();
        compute(ch & 1);
        __syncthreads();
    }

    // epilogue: float2 stores, fused ops
    int rb = row0 + (wm << 6) + (lane >> 2);
    int cb = col0 + (wn << 6) + ((lane & 3) << 1);
    #pragma unroll
    for (int mi = 0; mi < 4; mi++) {
        #pragma unroll
        for (int half = 0; half < 2; half++) {
            int r = rb + (mi << 4) + (half << 3);
            if (r >= M) continue;
            #pragma unroll
            for (int ni = 0; ni < 8; ni++) {
                int c = cb + (ni << 3);
                float v0 = acc[mi][ni][half * 2];
                float v1 = acc[mi][ni][half * 2 + 1];
                if (ep == EP_RELU_REMAP) {
                    long long o = (long long)(r + r / 8191 + 1) * ldc + c;
                    v0 = fmaxf(v0 + bias[c], 0.f);
                    v1 = fmaxf(v1 + bias[c + 1], 0.f);
                    *(float2*)(C + o) = make_float2(v0, v1);
                } else if (ep == EP_SCALEQ) {
                    float sc = (c < 512) ? 0.125f : 1.0f;
                    *(float2*)(C + (long long)r * ldc + c) = make_float2(v0 * sc, v1 * sc);
                } else if (ep == EP_ADDBIAS) {
                    long long o = (long long)r * ldc + c;
                    float2 old = *(float2*)(C + o);
                    *(float2*)(C + o) = make_float2(old.x + v0 + bias[c],
                                                    old.y + v1 + bias[c + 1]);
                } else {
                    *(float2*)(C + (long long)r * ldc + c) = make_float2(v0, v1);
                }
            }
        }
    }
}

// ------------------------- reductions --------------------------------------
__device__ __forceinline__ float blockReduce(float v, bool domax) {
    __shared__ float sh[32];
    __syncthreads();
    #pragma unroll
    for (int o = 16; o > 0; o >>= 1) {
        float w = __shfl_down_sync(0xffffffffu, v, o);
        v = domax ? fmaxf(v, w) : v + w;
    }
    int lane = threadIdx.x & 31, wid = threadIdx.x >> 5;
    if (lane == 0) sh[wid] = v;
    __syncthreads();
    int nw = (blockDim.x + 31) >> 5;
    if (wid == 0) {
        v = (lane < nw) ? sh[lane] : (domax ? -1e30f : 0.f);
        #pragma unroll
        for (int o = 16; o > 0; o >>= 1) {
            float w = __shfl_down_sync(0xffffffffu, v, o);
            v = domax ? fmaxf(v, w) : v + w;
        }
        if (lane == 0) sh[0] = v;
    }
    __syncthreads();
    return sh[0];
}

// ===================== 128x128x16 SIMT GEMM (TRANSB users) ==================
template<int TRANSB>
__global__ void __launch_bounds__(256, 2) gemm128_k(
    int M, int N, int K,
    const float* __restrict__ A, int lda, long long sA1, long long sA2,
    const float* __restrict__ Bp, int ldb, long long sB1, long long sB2,
    float* __restrict__ C, int ldc, long long sC1, long long sC2,
    float alpha, int ep, const float* __restrict__ bias, int amode)
{
    __shared__ float As[2][16 * 136];
    __shared__ float Bs[2][16 * 136];
    int z = blockIdx.z;
    A  += (long long)(z >> 3) * sA1 + (long long)(z & 7) * sA2;
    Bp += (long long)(z >> 3) * sB1 + (long long)(z & 7) * sB2;
    C  += (long long)(z >> 3) * sC1 + (long long)(z & 7) * sC2;
    int row0 = blockIdx.y << 7;
    int col0 = blockIdx.x << 7;
    int tid = threadIdx.x;
    int tx = tid & 15, ty = tid >> 4;

    int a_r  = tid >> 2;
    int a_kk = (tid & 3) << 2;
    int bn_kk = tid >> 5;
    int bn_n  = (tid & 31) << 2;
    int bt_n  = tid >> 2;
    int bt_kk = (tid & 3) << 2;

    float acc[8][8];
    #pragma unroll
    for (int i = 0; i < 8; i++)
        #pragma unroll
        for (int j = 0; j < 8; j++) acc[i][j] = 0.f;

    float4 pa0, pa1, pb0, pb1;

    auto fetch = [&](int k0) {
        int gr0 = row0 + a_r, gr1 = gr0 + 64;
        pa0 = make_float4(0.f, 0.f, 0.f, 0.f);
        pa1 = pa0;
        if (gr0 < M) pa0 = *(const float4*)(A + (long long)gr0 * lda + k0 + a_kk);
        if (gr1 < M) pa1 = *(const float4*)(A + (long long)gr1 * lda + k0 + a_kk);
        if (!TRANSB) {
            pb0 = *(const float4*)(Bp + (long long)(k0 + bn_kk) * ldb + col0 + bn_n);
            pb1 = *(const float4*)(Bp + (long long)(k0 + bn_kk + 8) * ldb + col0 + bn_n);
        } else {
            pb0 = *(const float4*)(Bp + (long long)(col0 + bt_n) * ldb + k0 + bt_kk);
            pb1 = *(const float4*)(Bp + (long long)(col0 + bt_n + 64) * ldb + k0 + bt_kk);
        }
    };

    auto stash = [&](int b) {
        float* Ab = As[b];
        Ab[(a_kk + 0) * 136 + a_r] = pa0.x;
        Ab[(a_kk + 1) * 136 + a_r] = pa0.y;
        Ab[(a_kk + 2) * 136 + a_r] = pa0.z;
        Ab[(a_kk + 3) * 136 + a_r] = pa0.w;
        Ab[(a_kk + 0) * 136 + a_r + 64] = pa1.x;
        Ab[(a_kk + 1) * 136 + a_r + 64] = pa1.y;
        Ab[(a_kk + 2) * 136 + a_r + 64] = pa1.z;
        Ab[(a_kk + 3) * 136 + a_r + 64] = pa1.w;
        float* Bb = Bs[b];
        if (!TRANSB) {
            *(float4*)&Bb[bn_kk * 136 + bn_n] = pb0;
            *(float4*)&Bb[(bn_kk + 8) * 136 + bn_n] = pb1;
        } else {
            Bb[(bt_kk + 0) * 136 + bt_n] = pb0.x;
            Bb[(bt_kk + 1) * 136 + bt_n] = pb0.y;
            Bb[(bt_kk + 2) * 136 + bt_n] = pb0.z;
            Bb[(bt_kk + 3) * 136 + bt_n] = pb0.w;
            Bb[(bt_kk + 0) * 136 + bt_n + 64] = pb1.x;
            Bb[(bt_kk + 1) * 136 + bt_n + 64] = pb1.y;
            Bb[(bt_kk + 2) * 136 + bt_n + 64] = pb1.z;
            Bb[(bt_kk + 3) * 136 + bt_n + 64] = pb1.w;
        }
    };

    fetch(0);
    stash(0);
    __syncthreads();

    int nt = K >> 4;
    for (int t = 0; t < nt; t++) {
        int buf = t & 1;
        if (t + 1 < nt) fetch((t + 1) << 4);
        const float* Ab = As[buf];
        const float* Bb = Bs[buf];
        #pragma unroll
        for (int kk = 0; kk < 16; kk++) {
            float4 a0 = *(const float4*)&Ab[kk * 136 + (ty << 3)];
            float4 a1 = *(const float4*)&Ab[kk * 136 + (ty << 3) + 4];
            float4 b0 = *(const float4*)&Bb[kk * 136 + (tx << 3)];
            float4 b1 = *(const float4*)&Bb[kk * 136 + (tx << 3) + 4];
            float av[8] = {a0.x, a0.y, a0.z, a0.w, a1.x, a1.y, a1.z, a1.w};
            float bv[8] = {b0.x, b0.y, b0.z, b0.w, b1.x, b1.y, b1.z, b1.w};
            #pragma unroll
            for (int i = 0; i < 8; i++)
                #pragma unroll
                for (int j = 0; j < 8; j++)
                    acc[i][j] += av[i] * bv[j];
        }
        if (t + 1 < nt) stash(buf ^ 1);
        __syncthreads();
    }

    #pragma unroll
    for (int i = 0; i < 8; i++) {
        int r = row0 + (ty << 3) + i;
        if (r >= M) continue;
        #pragma unroll
        for (int j = 0; j < 8; j++) {
            int c = col0 + (tx << 3) + j;
            C[(long long)r * ldc + c] = alpha * acc[i][j];
        }
    }
}

// ===================== 64x64x16 GEMM, 4x4 microtile, double-buffered ========
template<int TRANSB>
__global__ void __launch_bounds__(256) gemm64_k(
    int M, int N, int K,
    const float* __restrict__ A, int lda, long long sA1, long long sA2, long long sA3,
    const float* __restrict__ Bp, int ldb, long long sB1, long long sB2, long long sB3,
    float* __restrict__ C, int ldc, long long sC1, long long sC2, long long sC3,
    int SPLIT, float alpha, int ep, const float* __restrict__ bias,
    int bmode, float bdiag)
{
    __shared__ float As[2][16 * 68];
    __shared__ float Bs[2][16 * 68];
    int z = blockIdx.z;
    int s  = z % SPLIT;
    int bh = z / SPLIT;
    int hh = bh & 7, bb = bh >> 3;
    A  += (long long)bb * sA1 + (long long)hh * sA2 + (long long)s * sA3;
    Bp += (long long)bb * sB1 + (long long)hh * sB2 + (long long)s * sB3;
    C  += (long long)bb * sC1 + (long long)hh * sC2 + (long long)s * sC3;
    int row0 = blockIdx.y << 6;
    int col0 = blockIdx.x << 6;
    int tid = threadIdx.x;
    int tx = tid & 15, ty = tid >> 4;

    int a_r  = tid >> 2;
    int a_kk = (tid & 3) << 2;
    int bn_kk = tid >> 4;
    int bn_n  = (tid & 15) << 2;
    int bt_n  = tid >> 2;
    int bt_kk = (tid & 3) << 2;

    float acc[4][4];
    #pragma unroll
    for (int i = 0; i < 4; i++)
        #pragma unroll
        for (int j = 0; j < 4; j++) acc[i][j] = 0.f;

    float4 pa, pb;

    auto fetch = [&](int k0) {
        int gr = row0 + a_r;
        pa = make_float4(0.f, 0.f, 0.f, 0.f);
        if (gr < M) pa = *(const float4*)(A + (long long)gr * lda + k0 + a_kk);
        if (!TRANSB) {
            pb = *(const float4*)(Bp + (long long)(k0 + bn_kk) * ldb + col0 + bn_n);
        } else {
            pb = *(const float4*)(Bp + (long long)(col0 + bt_n) * ldb + k0 + bt_kk);
        }
    };

    auto stash = [&](int b, int k0) {
        float* Ab = As[b];
        Ab[(a_kk + 0) * 68 + a_r] = pa.x;
        Ab[(a_kk + 1) * 68 + a_r] = pa.y;
        Ab[(a_kk + 2) * 68 + a_r] = pa.z;
        Ab[(a_kk + 3) * 68 + a_r] = pa.w;
        float* Bb = Bs[b];
        if (!TRANSB) {
            float4 v = pb;
            if (bmode) {
                int gk = k0 + bn_kk, gn = col0 + bn_n;
                v.x = (gk == gn + 0 ? bdiag : 0.f) - v.x;
                v.y = (gk == gn + 1 ? bdiag : 0.f) - v.y;
                v.z = (gk == gn + 2 ? bdiag : 0.f) - v.z;
                v.w = (gk == gn + 3 ? bdiag : 0.f) - v.w;
            }
            *(float4*)&Bb[bn_kk * 68 + bn_n] = v;
        } else {
            Bb[(bt_kk + 0) * 68 + bt_n] = pb.x;
            Bb[(bt_kk + 1) * 68 + bt_n] = pb.y;
            Bb[(bt_kk + 2) * 68 + bt_n] = pb.z;
            Bb[(bt_kk + 3) * 68 + bt_n] = pb.w;
        }
    };

    fetch(0);
    stash(0, 0);
    __syncthreads();

    int nt = K >> 4;
    for (int t = 0; t < nt; t++) {
        int buf = t & 1;
        if (t + 1 < nt) fetch((t + 1) << 4);
        const float* Ab = As[buf];
        const float* Bb = Bs[buf];
        #pragma unroll
        for (int kk = 0; kk < 16; kk++) {
            float4 a = *(const float4*)&Ab[kk * 68 + (ty << 2)];
            float4 b = *(const float4*)&Bb[kk * 68 + (tx << 2)];
            acc[0][0] += a.x * b.x; acc[0][1] += a.x * b.y; acc[0][2] += a.x * b.z; acc[0][3] += a.x * b.w;
            acc[1][0] += a.y * b.x; acc[1][1] += a.y * b.y; acc[1][2] += a.y * b.z; acc[1][3] += a.y * b.w;
            acc[2][0] += a.z * b.x; acc[2][1] += a.z * b.y; acc[2][2] += a.z * b.z; acc[2][3] += a.z * b.w;
            acc[3][0] += a.w * b.x; acc[3][1] += a.w * b.y; acc[3][2] += a.w * b.z; acc[3][3] += a.w * b.w;
        }
        if (t + 1 < nt) stash(buf ^ 1, (t + 1) << 4);
        __syncthreads();
    }

    #pragma unroll
    for (int i = 0; i < 4; i++) {
        int r = row0 + (ty << 2) + i;
        if (r >= M) continue;
        #pragma unroll
        for (int j = 0; j < 4; j++) {
            int c = col0 + (tx << 2) + j;
            C[(long long)r * ldc + c] = alpha * acc[i][j];
        }
    }
}

// ------------------------- layernorm (rows of 512) --------------------------
__global__ void __launch_bounds__(256) ln_k(const float* __restrict__ X, float* __restrict__ Y,
                                            const float* __restrict__ g, const float* __restrict__ b)
{
    long long row = blockIdx.x;
    const float* x = X + row * DIMM;
    float* y = Y + row * DIMM;
    int t = threadIdx.x;
    float v0 = x[t], v1 = x[t + 256];
    float mu  = blockReduce(v0 + v1, false) * (1.f / 512.f);
    float d0 = v0 - mu, d1 = v1 - mu;
    float var = blockReduce(d0 * d0 + d1 * d1, false) * (1.f / 512.f);
    float inv = rsqrtf(var + 1e-5f);
    y[t]       = d0 * inv * g[t]       + b[t];
    y[t + 256] = d1 * inv * g[t + 256] + b[t + 256];
}

// ------------------------- warp-per-row softmax, 256 cols -------------------
__global__ void __launch_bounds__(256) softmax256_k(float* __restrict__ S)
{
    long long row = ((long long)blockIdx.x << 3) + (threadIdx.x >> 5);
    int lane = threadIdx.x & 31;
    float* s = S + (row << 8);
    float4 va = *(float4*)(s + (lane << 3));
    float4 vb = *(float4*)(s + (lane << 3) + 4);
    float m = fmaxf(fmaxf(fmaxf(va.x, va.y), fmaxf(va.z, va.w)),
                    fmaxf(fmaxf(vb.x, vb.y), fmaxf(vb.z, vb.w)));
    #pragma unroll
    for (int o = 16; o > 0; o >>= 1) m = fmaxf(m, __shfl_xor_sync(0xffffffffu, m, o));
    va.x = __expf(va.x - m); va.y = __expf(va.y - m); va.z = __expf(va.z - m); va.w = __expf(va.w - m);
    vb.x = __expf(vb.x - m); vb.y = __expf(vb.y - m); vb.z = __expf(vb.z - m); vb.w = __expf(vb.w - m);
    float sum = va.x + va.y + va.z + va.w + vb.x + vb.y + vb.z + vb.w;
    #pragma unroll
    for (int o = 16; o > 0; o >>= 1) sum += __shfl_xor_sync(0xffffffffu, sum, o);
    float inv = 1.f / sum;
    va.x *= inv; va.y *= inv; va.z *= inv; va.w *= inv;
    vb.x *= inv; vb.y *= inv; vb.z *= inv; vb.w *= inv;
    *(float4*)(s + (lane << 3)) = va;
    *(float4*)(s + (lane << 3) + 4) = vb;
}

// ------------------------- block softmax (long rows) ------------------------
__global__ void __launch_bounds__(256) softmax_k(float* __restrict__ S, int cols)
{
    extern __shared__ float buf[];
    long long row = blockIdx.x;
    float* s = S + row * cols;
    int t = threadIdx.x;
    float mx = -1e30f;
    for (int i = t; i < cols; i += 256) { float v = s[i]; buf[i] = v; mx = fmaxf(mx, v); }
    float bmax = blockReduce(mx, true);
    float sum = 0.f;
    for (int i = t; i < cols; i += 256) { float e = __expf(buf[i] - bmax); buf[i] = e; sum += e; }
    float bsum = blockReduce(sum, false);
    float inv = 1.f / bsum;
    for (int i = t; i < cols; i += 256) s[i] = buf[i] * inv;
}

// ------------------------- landmarks (mean of 32 consecutive rows) ----------
__global__ void __launch_bounds__(64) landmark_k()
{
    int zz = blockIdx.x;
    int mi = zz & 255, bh = zz >> 8;
    int b = bh >> 3, h = bh & 7;
    int d = threadIdx.x;
    const float* base = g_QKV + (long long)(b * NF + mi * 32) * QD + h * 64 + d;
    float sq = 0.f, sk = 0.f;
    #pragma unroll 8
    for (int il = 0; il < 32; il++) {
        sq += base[(long long)il * QD];
        sk += base[(long long)il * QD + 512];
    }
    long long o = ((long long)bh * LM + mi) * DH + d;
    g_QL[o] = sq * (1.f / 32.f);
    g_KL[o] = sk * (1.f / 32.f);
}

// ------------------------- pinv helpers -------------------------------------
__global__ void reset_k() { g_scale[0] = 0u; g_scale[1] = 0u; }

__global__ void __launch_bounds__(256) scalemax_k()
{
    int z = blockIdx.x;
    int i = threadIdx.x;
    const float* S = g_S2 + ((long long)z << 16);
    float rs = 0.f, cs = 0.f;
    for (int j = 0; j < 256; j++) { rs += S[(i << 8) + j]; cs += S[(j << 8) + i]; }
    float rm = blockReduce(rs, true);
    float cm = blockReduce(cs, true);
    if (i == 0) {
        atomicMax(&g_scale[0], __float_as_uint(rm));
        atomicMax(&g_scale[1], __float_as_uint(cm));
    }
}

__global__ void __launch_bounds__(256) zinit_k()
{
    int idx = blockIdx.x * 256 + threadIdx.x;
    float inv = 1.0f / (__uint_as_float(g_scale[0]) * __uint_as_float(g_scale[1]));
    int z = idx >> 16, r = idx & 65535;
    int i = r >> 8, j = r & 255;
    g_Zb[((long long)z << 16) + (i << 8) + j] = g_S2[((long long)z << 16) + (j << 8) + i] * inv;
}

// ------------------------- split-K reduce for AV ----------------------------
__global__ void __launch_bounds__(256) avreduce_k()
{
    int idx = blockIdx.x * 256 + threadIdx.x;
    int bh = idx >> 14;
    int r  = idx & 16383;
    const float* p = g_AVp + ((long long)bh << 17);
    float s = 0.f;
    #pragma unroll
    for (int k = 0; k < KSPL; k++) s += p[(k << 14) + r];
    g_AV[idx] = s;
}

// ------------------------- depthwise conv residual (adds into g_OH) ---------
__global__ void __launch_bounds__(256) conv_k(const float* __restrict__ cw)
{
    __shared__ float sv[160 * 64];
    __shared__ float sw[KER];
    int tile = blockIdx.x;
    int bh = blockIdx.y;
    int b = bh >> 3, h = bh & 7;
    int n0 = tile * 128;
    int t = threadIdx.x;
    if (t < KER) sw[t] = cw[h * KER + t];
    for (int idx = t; idx < 160 * 64; idx += 256) {
        int r = idx >> 6, d = idx & 63;
        int nn = n0 - 16 + r;
        float v = 0.f;
        if (nn >= 0 && nn < NF) v = g_QKV[(long long)(b * NF + nn) * QD + 1024 + h * 64 + d];
        sv[idx] = v;
    }
    __syncthreads();
    int d = t & 63, r0 = t >> 6;
    for (int rr = r0; rr < 128; rr += 4) {
        float a = 0.f;
        #pragma unroll
        for (int k = 0; k < KER; k++) a += sv[(rr + k) * 64 + d] * sw[k];
        long long o = ((long long)bh * NF + n0 + rr) * DH + d;
        g_OH[o] += a;
    }
}

// ------------------------- cls token fill -----------------------------------
__global__ void __launch_bounds__(256) cls_k(const float* __restrict__ ct)
{
    int idx = blockIdx.x * 256 + threadIdx.x;
    int b = idx >> 9, c = idx & 511;
    g_X[(long long)b * NF * DIMM + c] = ct[c];
}

// ------------------------- final LN + head ----------------------------------
__global__ void __launch_bounds__(256) final_k(const float* __restrict__ fg, const float* __restrict__ fb,
                                               const float* __restrict__ w2, const float* __restrict__ b2,
                                               float* __restrict__ out)
{
    int b = blockIdx.x;
    const float* x = g_X + (long long)b * NF * DIMM;
    int t = threadIdx.x;
    float v0 = x[t], v1 = x[t + 256];
    float mu  = blockReduce(v0 + v1, false) * (1.f / 512.f);
    float d0 = v0 - mu, d1 = v1 - mu;
    float var = blockReduce(d0 * d0 + d1 * d1, false) * (1.f / 512.f);
    float inv = rsqrtf(var + 1e-5f);
    float n0 = d0 * inv * fg[t]       + fb[t];
    float n1 = d1 * inv * fg[t + 256] + fb[t + 256];
    float p0 = n0 * w2[2 * t]     + n1 * w2[2 * (t + 256)];
    float p1 = n0 * w2[2 * t + 1] + n1 * w2[2 * (t + 256) + 1];
    p0 = blockReduce(p0, false);
    p1 = blockReduce(p1, false);
    if (t == 0) {
        out[b * 2 + 0] = p0 + b2[0];
        out[b * 2 + 1] = p1 + b2[1];
    }
}

// ------------------------- host orchestration -------------------------------
static inline void gemm128(int transB, int M, int N, int K,
                           const float* A, int lda, long long sA1, long long sA2,
                           const float* Bp, int ldb, long long sB1, long long sB2,
                           float* C, int ldc, long long sC1, long long sC2,
                           int batch, float alpha, int ep, const float* bias, int amode = 0)
{
    dim3 g(N >> 7, (M + 127) >> 7, batch);
    if (transB)
        gemm128_k<1><<<g, 256>>>(M, N, K, A, lda, sA1, sA2, Bp, ldb, sB1, sB2, C, ldc, sC1, sC2, alpha, ep, bias, amode);
    else
        gemm128_k<0><<<g, 256>>>(M, N, K, A, lda, sA1, sA2, Bp, ldb, sB1, sB2, C, ldc, sC1, sC2, alpha, ep, bias, amode);
}

static inline void gemm64(int transB, int M, int N, int K,
                          const float* A, int lda, long long sA1, long long sA2, long long sA3,
                          const float* Bp, int ldb, long long sB1, long long sB2, long long sB3,
                          float* C, int ldc, long long sC1, long long sC2, long long sC3,
                          int SPLIT, int batchZ, float alpha, int ep, const float* bias,
                          int bmode, float bdiag)
{
    dim3 g(N >> 6, (M + 63) >> 6, batchZ);
    if (transB)
        gemm64_k<1><<<g, 256>>>(M, N, K, A, lda, sA1, sA2, sA3, Bp, ldb, sB1, sB2, sB3,
                                C, ldc, sC1, sC2, sC3, SPLIT, alpha, ep, bias, bmode, bdiag);
    else
        gemm64_k<0><<<g, 256>>>(M, N, K, A, lda, sA1, sA2, sA3, Bp, ldb, sB1, sB2, sB3,
                                C, ldc, sC1, sC2, sC3, SPLIT, alpha, ep, bias, bmode, bdiag);
}

static inline void mgemm2(int M, int N, int K,
                          const float* A, int lda, int amode,
                          const float* BT,
                          float* C, int ldc, int ep, const float* bias)
{
    cudaFuncSetAttribute(mgemm2_k, cudaFuncAttributeMaxDynamicSharedMemorySize, 98304);
    dim3 g(N >> 8, (M + 127) >> 7);
    mgemm2_k<<<g, 256, 98304>>>(M, K, A, lda, amode, BT, C, ldc, ep, bias);
}

static inline void transT(const float* src, float* dst, int K, int N)
{
    dim3 g(K >> 5, N >> 5);
    transT_k<<<g, 256>>>(src, dst, K, N);
}

extern "C" void kernel_launch(void* const* d_in, const int* in_sizes, int n_in,
                              void* d_out, int out_size)
{
    const float* h_in  = (const float*)d_in[0];
    const float* w1    = (const float*)d_in[1];
    const float* b1    = (const float*)d_in[2];
    const float* clst  = (const float*)d_in[3];
    const float* ln_g  = (const float*)d_in[4];
    const float* ln_b  = (const float*)d_in[5];
    const float* wqkv  = (const float*)d_in[6];
    const float* wout  = (const float*)d_in[7];
    const float* bout  = (const float*)d_in[8];
    const float* cw    = (const float*)d_in[9];
    const float* fg    = (const float*)d_in[10];
    const float* fb    = (const float*)d_in[11];
    const float* w2    = (const float*)d_in[12];
    const float* b2    = (const float*)d_in[13];
    float* out = (float*)d_out;

    float *X, *XN, *QKV, *QL, *KL, *S1, *S2, *S3, *Z, *Z2, *P, *T, *T2, *AV, *AVp, *ZAV, *OH, *WT;
    cudaGetSymbolAddress((void**)&X,   g_X);
    cudaGetSymbolAddress((void**)&XN,  g_XN);
    cudaGetSymbolAddress((void**)&QKV, g_QKV);
    cudaGetSymbolAddress((void**)&QL,  g_QL);
    cudaGetSymbolAddress((void**)&KL,  g_KL);
    cudaGetSymbolAddress((void**)&S1,  g_S1);
    cudaGetSymbolAddress((void**)&S2,  g_S2);
    cudaGetSymbolAddress((void**)&S3,  g_S3);
    cudaGetSymbolAddress((void**)&Z,   g_Zb);
    cudaGetSymbolAddress((void**)&Z2,  g_Z2b);
    cudaGetSymbolAddress((void**)&P,   g_Pb);
    cudaGetSymbolAddress((void**)&T,   g_Tb);
    cudaGetSymbolAddress((void**)&T2,  g_T2b);
    cudaGetSymbolAddress((void**)&AV,  g_AV);
    cudaGetSymbolAddress((void**)&AVp, g_AVp);
    cudaGetSymbolAddress((void**)&ZAV, g_ZAV);
    cudaGetSymbolAddress((void**)&OH,  g_OH);
    cudaGetSymbolAddress((void**)&WT,  g_WT);

    const long long SQb = (long long)NF * QD;
    const long long S2s = (long long)LM * LM;
    const long long S1s = (long long)NF * LM;
    const long long AVs = (long long)LM * DH;
    const long long OHs = (long long)NF * DH;

    // pre-transpose all weight matrices to n-major for cp.async B operand
    transT(w1, WT + OW1, 1024, DIMM);
    for (int L = 0; L < 2; L++) {
        transT(wqkv + (long long)L * DIMM * QD, WT + OQKV(L), DIMM, QD);
        transT(wout + (long long)L * DIMM * DIMM, WT + OOUT(L), DIMM, DIMM);
    }

    // input projection: X[b, n+1, :] = relu(h @ w1 + b1)
    mgemm2(NB * 8191, DIMM, 1024, h_in, 1024, 0, WT + OW1, X, DIMM, EP_RELU_REMAP, b1);
    cls_k<<<4, 256>>>(clst);

    for (int L = 0; L < 2; L++) {
        ln_k<<<TOT, 256>>>(X, XN, ln_g + L * DIMM, ln_b + L * DIMM);

        // qkv = ln(x) @ Wqkv (q cols scaled by 1/8)
        mgemm2(TOT, QD, DIMM, XN, DIMM, 0, WT + OQKV(L), QKV, QD, EP_SCALEQ, nullptr);

        landmark_k<<<NBH * LM, 64>>>();

        // sim2 = QL @ KL^T, softmax
        gemm64(1, LM, LM, DH, QL, DH, 8 * AVs, AVs, 0, KL, DH, 8 * AVs, AVs, 0,
               S2, LM, 8 * S2s, S2s, 0, 1, NBH, 1.f, EP_NONE, nullptr, 0, 0.f);
        softmax256_k<<<NBH * LM / 8, 256>>>(S2);

        // Moore-Penrose pinv of S2 -> Z
        reset_k<<<1, 1>>>();
        scalemax_k<<<NBH, 256>>>();
        zinit_k<<<4096, 256>>>();
        for (int it = 0; it < 6; it++) {
            float* Zin  = (it & 1) ? Z2 : Z;
            float* Zout = (it & 1) ? Z  : Z2;
            gemm64(0, LM, LM, LM, S2, LM, 8 * S2s, S2s, 0, Zin, LM, 8 * S2s, S2s, 0,
                   P, LM, 8 * S2s, S2s, 0, 1, NBH, 1.f, EP_NONE, nullptr, 0, 0.f);
            gemm64(0, LM, LM, LM, P, LM, 8 * S2s, S2s, 0, P, LM, 8 * S2s, S2s, 0,
                   T2, LM, 8 * S2s, S2s, 0, 1, NBH, 1.f, EP_NONE, nullptr, 1, 7.f);
            gemm64(0, LM, LM, LM, P, LM, 8 * S2s, S2s, 0, T2, LM, 8 * S2s, S2s, 0,
                   T, LM, 8 * S2s, S2s, 0, 1, NBH, 1.f, EP_NONE, nullptr, 1, 15.f);
            gemm64(0, LM, LM, LM, Zin, LM, 8 * S2s, S2s, 0, T, LM, 8 * S2s, S2s, 0,
                   Zout, LM, 8 * S2s, S2s, 0, 1, NBH, 0.25f, EP_NONE, nullptr, 1, 13.f);
        }

        // sim1 = Q @ KL^T, softmax
        gemm128(1, NF, LM, DH, QKV, QD, SQb, 64, KL, DH, 8 * AVs, AVs,
                S1, LM, 8 * S1s, S1s, NBH, 1.f, EP_NONE, nullptr);
        softmax256_k<<<NBH * NF / 8, 256>>>(S1);

        // sim3 = QL @ K^T, softmax over 8192
        gemm128(1, LM, NF, DH, QL, DH, 8 * AVs, AVs, QKV + 512, QD, SQb, 64,
                S3, NF, 8 * S1s, S1s, NBH, 1.f, EP_NONE, nullptr);
        softmax_k<<<NBH * LM, 256, NF * 4>>>(S3, NF);

        // AV = attn3 @ V  (split-K by 8 into partials, then reduce)
        gemm64(0, LM, DH, NF / KSPL,
               S3, NF, 8 * S1s, S1s, 1024,
               QKV + 1024, QD, SQb, 64, 1024LL * QD,
               AVp, DH, 64 * AVs, 8 * AVs, AVs,
               KSPL, NBH * KSPL, 1.f, EP_NONE, nullptr, 0, 0.f);
        avreduce_k<<<1024, 256>>>();

        // ZAV = Z @ AV
        gemm64(0, LM, DH, LM, Z, LM, 8 * S2s, S2s, 0, AV, DH, 8 * AVs, AVs, 0,
               ZAV, DH, 8 * AVs, AVs, 0, 1, NBH, 1.f, EP_NONE, nullptr, 0, 0.f);
        // OH = attn1 @ ZAV
        gemm64(0, NF, DH, LM, S1, LM, 8 * S1s, S1s, 0, ZAV, DH, 8 * AVs, AVs, 0,
               OH, DH, 8 * OHs, OHs, 0, 1, NBH, 1.f, EP_NONE, nullptr, 0, 0.f);

        // OH += depthwise conv residual of V
        { dim3 g(NF / 128, NBH); conv_k<<<g, 256>>>(cw + L * NH * KER); }

        // X += OH(head-layout) @ Wout + bout  (transpose fused in A-load)
        mgemm2(TOT, DIMM, DIMM, OH, 0, 1, WT + OOUT(L), X, DIMM, EP_ADDBIAS, bout + L * DIMM);
    }

    final_k<<<NB, 256>>>(fg, fb, w2, b2, out);
}

// round 7
// speedup vs baseline: 1.8328x; 1.0050x over previous
#include <cuda_runtime.h>

#define NB   2
#define NF   8192
#define DIMM 512
#define NH   8
#define DH   64
#define LM   256
#define QD   1536
#define TOT  (NB*NF)    // 16384
#define NBH  (NB*NH)    // 16
#define KER  33
#define KSPL 8

// ------------------------- scratch (device globals, no allocs) -------------
__device__ float g_X  [TOT*DIMM];
__device__ float g_XN [TOT*DIMM];
__device__ float g_QKV[TOT*QD];
__device__ float g_QL [NBH*LM*DH];
__device__ float g_KL [NBH*LM*DH];
__device__ float g_S1 [NBH*NF*LM];
__device__ float g_S3 [NBH*LM*NF];
__device__ float g_S2 [NBH*LM*LM];
__device__ float g_Zb [NBH*LM*LM];
__device__ float g_Z2b[NBH*LM*LM];
__device__ float g_Pb [NBH*LM*LM];
__device__ float g_Tb [NBH*LM*LM];
__device__ float g_T2b[NBH*LM*LM];
__device__ float g_AV [NBH*LM*DH];
__device__ float g_AVp[NBH*KSPL*LM*DH];
__device__ float g_ZAV[NBH*LM*DH];
__device__ float g_OH [NBH*NF*DH];
__device__ float g_WT [2621440];     // transposed weights
__device__ unsigned int g_scale[2];

enum { EP_NONE = 0, EP_RELU_REMAP = 1, EP_SCALEQ = 2, EP_ADDBIAS = 3 };

#define OW1   0
#define OQKV(L) (524288 + (L) * 786432)
#define OOUT(L) (2097152 + (L) * 262144)

__device__ __forceinline__ unsigned f2tf32(float f) {
    unsigned r;
    asm("cvt.rna.tf32.f32 %0, %1;" : "=r"(r) : "f"(f));
    return r;
}

#define MMA_TF32(d, a, b) \
    asm volatile("mma.sync.aligned.m16n8k8.row.col.f32.tf32.tf32.f32 " \
        "{%0,%1,%2,%3}, {%4,%5,%6,%7}, {%8,%9}, {%0,%1,%2,%3};" \
        : "+f"((d)[0]), "+f"((d)[1]), "+f"((d)[2]), "+f"((d)[3]) \
        : "r"((a)[0]), "r"((a)[1]), "r"((a)[2]), "r"((a)[3]), \
          "r"((b)[0]), "r"((b)[1]))

// ------------------------- weight transpose (K x N -> N x K) ----------------
__global__ void __launch_bounds__(256) transT_k(const float* __restrict__ src,
                                                float* __restrict__ dst, int K, int N)
{
    __shared__ float t[32][33];
    int kb = blockIdx.x << 5, nb = blockIdx.y << 5;
    int x = threadIdx.x & 31, y = threadIdx.x >> 5;
    #pragma unroll
    for (int i = 0; i < 32; i += 8)
        t[y + i][x] = src[(long long)(kb + y + i) * N + nb + x];
    __syncthreads();
    #pragma unroll
    for (int i = 0; i < 32; i += 8)
        dst[(long long)(nb + y + i) * K + kb + x] = t[x][y + i];
}

// ===================== mgemm2: cp.async + ldmatrix tf32, batched ============
// C = A @ BT^T.  A row-major [M,K] (amode=1: OH-layout gather),
// BT n-major [N][K] with row stride ldbt.  batch z: (z>>3)*s1 + (z&7)*s2.
__device__ __forceinline__ void cp16(unsigned dst, const void* src, int nbytes) {
    asm volatile("cp.async.cg.shared.global [%0], [%1], 16, %2;"
                 :: "r"(dst), "l"(src), "r"(nbytes) : "memory");
}

__global__ void __launch_bounds__(256) mgemm2_k(
    int M, int K,
    const float* __restrict__ A, int lda, long long sA1, long long sA2, int amode,
    const float* __restrict__ BT, int ldbt, long long sBT1, long long sBT2,
    float* __restrict__ C, int ldc, long long sC1, long long sC2,
    int ep, const float* __restrict__ bias)
{
    extern __shared__ float smem[];   // 2 stages x (A 4096 + B 8192 floats) = 96KB
    int tid = threadIdx.x;
    int lane = tid & 31, wid = tid >> 5;
    int wm = wid & 1, wn = wid >> 1;
    int row0 = blockIdx.y << 7, col0 = blockIdx.x << 8;
    int z = blockIdx.z;
    A  += (long long)(z >> 3) * sA1 + (long long)(z & 7) * sA2;
    BT += (long long)(z >> 3) * sBT1 + (long long)(z & 7) * sBT2;
    C  += (long long)(z >> 3) * sC1 + (long long)(z & 7) * sC2;

    unsigned sbase;
    asm("{ .reg .u64 t; cvta.to.shared.u64 t, %1; cvt.u32.u64 %0, t; }"
        : "=r"(sbase) : "l"(smem));

    float acc[4][8][4];
    #pragma unroll
    for (int mi = 0; mi < 4; mi++)
        #pragma unroll
        for (int ni = 0; ni < 8; ni++)
            #pragma unroll
            for (int q = 0; q < 4; q++) acc[mi][ni][q] = 0.f;

    auto fill = [&](int s, int k0) {
        unsigned Ab = sbase + s * 49152u;
        unsigned Bb = Ab + 16384u;
        #pragma unroll
        for (int it = 0; it < 4; it++) {
            int idx = (it << 8) + tid;
            int q = idx & 7, r = idx >> 3;
            int gr = row0 + r;
            const float* src;
            int nb = 16;
            if (amode == 0) {
                int gra = gr < M ? gr : (M - 1);
                if (gr >= M) nb = 0;
                src = A + (long long)gra * lda + k0 + (q << 2);
            } else {
                int k = k0 + (q << 2);
                int h = k >> 6, d = k & 63;
                src = A + ((((long long)(gr >> 13) << 3) + h) * 8192 + (gr & 8191)) * 64 + d;
            }
            unsigned dst = Ab + (((r << 5) + ((q ^ (r & 7)) << 2)) << 2);
            cp16(dst, src, nb);
        }
        #pragma unroll
        for (int it = 0; it < 8; it++) {
            int idx = (it << 8) + tid;
            int q = idx & 7, n = idx >> 3;
            const float* src = BT + (long long)(col0 + n) * ldbt + k0 + (q << 2);
            unsigned dst = Bb + (((n << 5) + ((q ^ (n & 7)) << 2)) << 2);
            cp16(dst, src, 16);
        }
        asm volatile("cp.async.commit_group;" ::: "memory");
    };

    auto compute = [&](int s) {
        unsigned Ab = sbase + s * 49152u;
        unsigned Bb = Ab + 16384u;
        int j = lane >> 3, rho = lane & 7;
        #pragma unroll
        for (int kt = 0; kt < 4; kt++) {
            unsigned a[4][4];
            #pragma unroll
            for (int mi = 0; mi < 4; mi++) {
                int row = (wm << 6) + (mi << 4) + ((j & 1) << 3) + rho;
                int quad = (kt << 1) + (j >> 1);
                unsigned ad = Ab + (((row << 5) + ((quad ^ (row & 7)) << 2)) << 2);
                asm volatile("ldmatrix.sync.aligned.m8n8.x4.shared.b16 {%0,%1,%2,%3}, [%4];"
                    : "=r"(a[mi][0]), "=r"(a[mi][1]), "=r"(a[mi][2]), "=r"(a[mi][3])
                    : "r"(ad));
            }
            unsigned b[8][2];
            #pragma unroll
            for (int np = 0; np < 4; np++) {
                int row = (((wn << 3) + (np << 1) + (j >> 1)) << 3) + rho;
                int quad = (kt << 1) + (j & 1);
                unsigned bd = Bb + (((row << 5) + ((quad ^ (row & 7)) << 2)) << 2);
                asm volatile("ldmatrix.sync.aligned.m8n8.x4.shared.b16 {%0,%1,%2,%3}, [%4];"
                    : "=r"(b[np * 2][0]), "=r"(b[np * 2][1]),
                      "=r"(b[np * 2 + 1][0]), "=r"(b[np * 2 + 1][1])
                    : "r"(bd));
            }
            #pragma unroll
            for (int mi = 0; mi < 4; mi++)
                #pragma unroll
                for (int ni = 0; ni < 8; ni++)
                    MMA_TF32(acc[mi][ni], a[mi], b[ni]);
        }
    };

    fill(0, 0);
    int nch = K >> 5;
    for (int ch = 0; ch < nch; ch++) {
        if (ch + 1 < nch) {
            fill((ch + 1) & 1, (ch + 1) << 5);
            asm volatile("cp.async.wait_group 1;" ::: "memory");
        } else {
            asm volatile("cp.async.wait_group 0;" ::: "memory");
        }
        __syncthreads();
        compute(ch & 1);
        __syncthreads();
    }

    int rb = row0 + (wm << 6) + (lane >> 2);
    int cb = col0 + (wn << 6) + ((lane & 3) << 1);
    #pragma unroll
    for (int mi = 0; mi < 4; mi++) {
        #pragma unroll
        for (int half = 0; half < 2; half++) {
            int r = rb + (mi << 4) + (half << 3);
            if (r >= M) continue;
            #pragma unroll
            for (int ni = 0; ni < 8; ni++) {
                int c = cb + (ni << 3);
                float v0 = acc[mi][ni][half * 2];
                float v1 = acc[mi][ni][half * 2 + 1];
                if (ep == EP_RELU_REMAP) {
                    long long o = (long long)(r + r / 8191 + 1) * ldc + c;
                    v0 = fmaxf(v0 + bias[c], 0.f);
                    v1 = fmaxf(v1 + bias[c + 1], 0.f);
                    *(float2*)(C + o) = make_float2(v0, v1);
                } else if (ep == EP_SCALEQ) {
                    float sc = (c < 512) ? 0.125f : 1.0f;
                    *(float2*)(C + (long long)r * ldc + c) = make_float2(v0 * sc, v1 * sc);
                } else if (ep == EP_ADDBIAS) {
                    long long o = (long long)r * ldc + c;
                    float2 old = *(float2*)(C + o);
                    *(float2*)(C + o) = make_float2(old.x + v0 + bias[c],
                                                    old.y + v1 + bias[c + 1]);
                } else {
                    *(float2*)(C + (long long)r * ldc + c) = make_float2(v0, v1);
                }
            }
        }
    }
}

// ===================== pgemm: 3xTF32 256x256x256 batched (pinv) =============
// C = alpha * A @ Beff, Beff = (bmode ? bd*I - B : B).  All 256x256, z-batch 16.
// CTA 128x128, 8 warps of 32x64, K chunk 16, reg-prefetch double buffer.
// smem rows padded to 20 floats (80B) -> conflict-free fragment LDS.
__global__ void __launch_bounds__(256) pgemm_k(
    const float* __restrict__ Ag, const float* __restrict__ Bg,
    float* __restrict__ Cg, float alpha, int bmode, float bd)
{
    extern __shared__ float ps[];   // 2 stages x 10240 floats = 80KB
    int tid = threadIdx.x;
    int lane = tid & 31, wid = tid >> 5;
    int wm = wid & 3, wn = wid >> 2;
    int row0 = blockIdx.y << 7, col0 = blockIdx.x << 7;
    long long zo = (long long)blockIdx.z << 16;
    Ag += zo; Bg += zo; Cg += zo;

    float acc[2][8][4];
    #pragma unroll
    for (int mi = 0; mi < 2; mi++)
        #pragma unroll
        for (int ni = 0; ni < 8; ni++)
            #pragma unroll
            for (int q = 0; q < 4; q++) acc[mi][ni][q] = 0.f;

    float4 pa[2];
    float pb[8];

    auto fetch = [&](int k0) {
        #pragma unroll
        for (int i = 0; i < 2; i++) {
            int f = (i << 8) + tid;
            int r = f >> 2, q = f & 3;
            pa[i] = *(const float4*)(Ag + ((long long)(row0 + r) << 8) + k0 + (q << 2));
        }
        #pragma unroll
        for (int i = 0; i < 8; i++) {
            int f = (i << 8) + tid;
            int n = f & 127, kk = f >> 7;
            int gk = k0 + kk, gn = col0 + n;
            float v = Bg[((long long)gk << 8) + gn];
            if (bmode) v = (gk == gn ? bd : 0.f) - v;
            pb[i] = v;
        }
    };

    auto stash = [&](int s) {
        float* Sb = ps + s * 10240;
        #pragma unroll
        for (int i = 0; i < 2; i++) {
            int f = (i << 8) + tid;
            int r = f >> 2, q = f & 3;
            float v[4] = {pa[i].x, pa[i].y, pa[i].z, pa[i].w};
            #pragma unroll
            for (int j = 0; j < 4; j++) {
                float h = __uint_as_float(f2tf32(v[j]));
                float l = __uint_as_float(f2tf32(v[j] - h));
                Sb[r * 20 + (q << 2) + j] = h;
                Sb[2560 + r * 20 + (q << 2) + j] = l;
            }
        }
        #pragma unroll
        for (int i = 0; i < 8; i++) {
            int f = (i << 8) + tid;
            int n = f & 127, kk = f >> 7;
            float v = pb[i];
            float h = __uint_as_float(f2tf32(v));
            float l = __uint_as_float(f2tf32(v - h));
            Sb[5120 + n * 20 + kk] = h;
            Sb[7680 + n * 20 + kk] = l;
        }
    };

    auto compute = [&](int s) {
        const float* Sb = ps + s * 10240;
        int g = lane >> 2, t = lane & 3;
        #pragma unroll
        for (int kt = 0; kt < 2; kt++) {
            int kb = kt << 3;
            unsigned ah[2][4], al[2][4];
            #pragma unroll
            for (int mi = 0; mi < 2; mi++) {
                int m = (wm << 5) + (mi << 4) + g;
                ah[mi][0] = __float_as_uint(Sb[m * 20 + kb + t]);
                ah[mi][1] = __float_as_uint(Sb[(m + 8) * 20 + kb + t]);
                ah[mi][2] = __float_as_uint(Sb[m * 20 + kb + t + 4]);
                ah[mi][3] = __float_as_uint(Sb[(m + 8) * 20 + kb + t + 4]);
                al[mi][0] = __float_as_uint(Sb[2560 + m * 20 + kb + t]);
                al[mi][1] = __float_as_uint(Sb[2560 + (m + 8) * 20 + kb + t]);
                al[mi][2] = __float_as_uint(Sb[2560 + m * 20 + kb + t + 4]);
                al[mi][3] = __float_as_uint(Sb[2560 + (m + 8) * 20 + kb + t + 4]);
            }
            unsigned bh[8][2], bl[8][2];
            #pragma unroll
            for (int ni = 0; ni < 8; ni++) {
                int n = (wn << 6) + (ni << 3) + g;
                bh[ni][0] = __float_as_uint(Sb[5120 + n * 20 + kb + t]);
                bh[ni][1] = __float_as_uint(Sb[5120 + n * 20 + kb + t + 4]);
                bl[ni][0] = __float_as_uint(Sb[7680 + n * 20 + kb + t]);
                bl[ni][1] = __float_as_uint(Sb[7680 + n * 20 + kb + t + 4]);
            }
            #pragma unroll
            for (int mi = 0; mi < 2; mi++)
                #pragma unroll
                for (int ni = 0; ni < 8; ni++) {
                    MMA_TF32(acc[mi][ni], ah[mi], bh[ni]);
                    MMA_TF32(acc[mi][ni], ah[mi], bl[ni]);
                    MMA_TF32(acc[mi][ni], al[mi], bh[ni]);
                }
        }
    };

    fetch(0);
    for (int ch = 0; ch < 16; ch++) {
        stash(ch & 1);
        __syncthreads();
        if (ch < 15) fetch((ch + 1) << 4);
        compute(ch & 1);
        __syncthreads();
    }

    int g = lane >> 2, t = lane & 3;
    #pragma unroll
    for (int mi = 0; mi < 2; mi++) {
        #pragma unroll
        for (int half = 0; half < 2; half++) {
            int r = row0 + (wm << 5) + (mi << 4) + (half << 3) + g;
            #pragma unroll
            for (int ni = 0; ni < 8; ni++) {
                int c = col0 + (wn << 6) + (ni << 3) + (t << 1);
                *(float2*)(Cg + ((long long)r << 8) + c) =
                    make_float2(acc[mi][ni][half * 2] * alpha,
                                acc[mi][ni][half * 2 + 1] * alpha);
            }
        }
    }
}

// ------------------------- reductions --------------------------------------
__device__ __forceinline__ float blockReduce(float v, bool domax) {
    __shared__ float sh[32];
    __syncthreads();
    #pragma unroll
    for (int o = 16; o > 0; o >>= 1) {
        float w = __shfl_down_sync(0xffffffffu, v, o);
        v = domax ? fmaxf(v, w) : v + w;
    }
    int lane = threadIdx.x & 31, wid = threadIdx.x >> 5;
    if (lane == 0) sh[wid] = v;
    __syncthreads();
    int nw = (blockDim.x + 31) >> 5;
    if (wid == 0) {
        v = (lane < nw) ? sh[lane] : (domax ? -1e30f : 0.f);
        #pragma unroll
        for (int o = 16; o > 0; o >>= 1) {
            float w = __shfl_down_sync(0xffffffffu, v, o);
            v = domax ? fmaxf(v, w) : v + w;
        }
        if (lane == 0) sh[0] = v;
    }
    __syncthreads();
    return sh[0];
}

// ===================== 64x64x16 SIMT GEMM (AV/ZAV/OH) =======================
template<int TRANSB>
__global__ void __launch_bounds__(256) gemm64_k(
    int M, int N, int K,
    const float* __restrict__ A, int lda, long long sA1, long long sA2, long long sA3,
    const float* __restrict__ Bp, int ldb, long long sB1, long long sB2, long long sB3,
    float* __restrict__ C, int ldc, long long sC1, long long sC2, long long sC3,
    int SPLIT, float alpha, int ep, const float* __restrict__ bias,
    int bmode, float bdiag)
{
    __shared__ float As[2][16 * 68];
    __shared__ float Bs[2][16 * 68];
    int z = blockIdx.z;
    int s  = z % SPLIT;
    int bh = z / SPLIT;
    int hh = bh & 7, bb = bh >> 3;
    A  += (long long)bb * sA1 + (long long)hh * sA2 + (long long)s * sA3;
    Bp += (long long)bb * sB1 + (long long)hh * sB2 + (long long)s * sB3;
    C  += (long long)bb * sC1 + (long long)hh * sC2 + (long long)s * sC3;
    int row0 = blockIdx.y << 6;
    int col0 = blockIdx.x << 6;
    int tid = threadIdx.x;
    int tx = tid & 15, ty = tid >> 4;

    int a_r  = tid >> 2;
    int a_kk = (tid & 3) << 2;
    int bn_kk = tid >> 4;
    int bn_n  = (tid & 15) << 2;
    int bt_n  = tid >> 2;
    int bt_kk = (tid & 3) << 2;

    float acc[4][4];
    #pragma unroll
    for (int i = 0; i < 4; i++)
        #pragma unroll
        for (int j = 0; j < 4; j++) acc[i][j] = 0.f;

    float4 pa, pb;

    auto fetch = [&](int k0) {
        int gr = row0 + a_r;
        pa = make_float4(0.f, 0.f, 0.f, 0.f);
        if (gr < M) pa = *(const float4*)(A + (long long)gr * lda + k0 + a_kk);
        if (!TRANSB) {
            pb = *(const float4*)(Bp + (long long)(k0 + bn_kk) * ldb + col0 + bn_n);
        } else {
            pb = *(const float4*)(Bp + (long long)(col0 + bt_n) * ldb + k0 + bt_kk);
        }
    };

    auto stash = [&](int b, int k0) {
        float* Ab = As[b];
        Ab[(a_kk + 0) * 68 + a_r] = pa.x;
        Ab[(a_kk + 1) * 68 + a_r] = pa.y;
        Ab[(a_kk + 2) * 68 + a_r] = pa.z;
        Ab[(a_kk + 3) * 68 + a_r] = pa.w;
        float* Bb = Bs[b];
        if (!TRANSB) {
            float4 v = pb;
            if (bmode) {
                int gk = k0 + bn_kk, gn = col0 + bn_n;
                v.x = (gk == gn + 0 ? bdiag : 0.f) - v.x;
                v.y = (gk == gn + 1 ? bdiag : 0.f) - v.y;
                v.z = (gk == gn + 2 ? bdiag : 0.f) - v.z;
                v.w = (gk == gn + 3 ? bdiag : 0.f) - v.w;
            }
            *(float4*)&Bb[bn_kk * 68 + bn_n] = v;
        } else {
            Bb[(bt_kk + 0) * 68 + bt_n] = pb.x;
            Bb[(bt_kk + 1) * 68 + bt_n] = pb.y;
            Bb[(bt_kk + 2) * 68 + bt_n] = pb.z;
            Bb[(bt_kk + 3) * 68 + bt_n] = pb.w;
        }
    };

    fetch(0);
    stash(0, 0);
    __syncthreads();

    int nt = K >> 4;
    for (int t = 0; t < nt; t++) {
        int buf = t & 1;
        if (t + 1 < nt) fetch((t + 1) << 4);
        const float* Ab = As[buf];
        const float* Bb = Bs[buf];
        #pragma unroll
        for (int kk = 0; kk < 16; kk++) {
            float4 a = *(const float4*)&Ab[kk * 68 + (ty << 2)];
            float4 b = *(const float4*)&Bb[kk * 68 + (tx << 2)];
            acc[0][0] += a.x * b.x; acc[0][1] += a.x * b.y; acc[0][2] += a.x * b.z; acc[0][3] += a.x * b.w;
            acc[1][0] += a.y * b.x; acc[1][1] += a.y * b.y; acc[1][2] += a.y * b.z; acc[1][3] += a.y * b.w;
            acc[2][0] += a.z * b.x; acc[2][1] += a.z * b.y; acc[2][2] += a.z * b.z; acc[2][3] += a.z * b.w;
            acc[3][0] += a.w * b.x; acc[3][1] += a.w * b.y; acc[3][2] += a.w * b.z; acc[3][3] += a.w * b.w;
        }
        if (t + 1 < nt) stash(buf ^ 1, (t + 1) << 4);
        __syncthreads();
    }

    #pragma unroll
    for (int i = 0; i < 4; i++) {
        int r = row0 + (ty << 2) + i;
        if (r >= M) continue;
        #pragma unroll
        for (int j = 0; j < 4; j++) {
            int c = col0 + (tx << 2) + j;
            C[(long long)r * ldc + c] = alpha * acc[i][j];
        }
    }
}

// ------------------------- layernorm (rows of 512) --------------------------
__global__ void __launch_bounds__(256) ln_k(const float* __restrict__ X, float* __restrict__ Y,
                                            const float* __restrict__ g, const float* __restrict__ b)
{
    long long row = blockIdx.x;
    const float* x = X + row * DIMM;
    float* y = Y + row * DIMM;
    int t = threadIdx.x;
    float v0 = x[t], v1 = x[t + 256];
    float mu  = blockReduce(v0 + v1, false) * (1.f / 512.f);
    float d0 = v0 - mu, d1 = v1 - mu;
    float var = blockReduce(d0 * d0 + d1 * d1, false) * (1.f / 512.f);
    float inv = rsqrtf(var + 1e-5f);
    y[t]       = d0 * inv * g[t]       + b[t];
    y[t + 256] = d1 * inv * g[t + 256] + b[t + 256];
}

// ------------------------- warp-per-row softmax, 256 cols -------------------
__global__ void __launch_bounds__(256) softmax256_k(float* __restrict__ S)
{
    long long row = ((long long)blockIdx.x << 3) + (threadIdx.x >> 5);
    int lane = threadIdx.x & 31;
    float* s = S + (row << 8);
    float4 va = *(float4*)(s + (lane << 3));
    float4 vb = *(float4*)(s + (lane << 3) + 4);
    float m = fmaxf(fmaxf(fmaxf(va.x, va.y), fmaxf(va.z, va.w)),
                    fmaxf(fmaxf(vb.x, vb.y), fmaxf(vb.z, vb.w)));
    #pragma unroll
    for (int o = 16; o > 0; o >>= 1) m = fmaxf(m, __shfl_xor_sync(0xffffffffu, m, o));
    va.x = __expf(va.x - m); va.y = __expf(va.y - m); va.z = __expf(va.z - m); va.w = __expf(va.w - m);
    vb.x = __expf(vb.x - m); vb.y = __expf(vb.y - m); vb.z = __expf(vb.z - m); vb.w = __expf(vb.w - m);
    float sum = va.x + va.y + va.z + va.w + vb.x + vb.y + vb.z + vb.w;
    #pragma unroll
    for (int o = 16; o > 0; o >>= 1) sum += __shfl_xor_sync(0xffffffffu, sum, o);
    float inv = 1.f / sum;
    va.x *= inv; va.y *= inv; va.z *= inv; va.w *= inv;
    vb.x *= inv; vb.y *= inv; vb.z *= inv; vb.w *= inv;
    *(float4*)(s + (lane << 3)) = va;
    *(float4*)(s + (lane << 3) + 4) = vb;
}

// ------------------------- block softmax (long rows) ------------------------
__global__ void __launch_bounds__(256) softmax_k(float* __restrict__ S, int cols)
{
    extern __shared__ float buf[];
    long long row = blockIdx.x;
    float* s = S + row * cols;
    int t = threadIdx.x;
    float mx = -1e30f;
    for (int i = t; i < cols; i += 256) { float v = s[i]; buf[i] = v; mx = fmaxf(mx, v); }
    float bmax = blockReduce(mx, true);
    float sum = 0.f;
    for (int i = t; i < cols; i += 256) { float e = __expf(buf[i] - bmax); buf[i] = e; sum += e; }
    float bsum = blockReduce(sum, false);
    float inv = 1.f / bsum;
    for (int i = t; i < cols; i += 256) s[i] = buf[i] * inv;
}

// ------------------------- landmarks (mean of 32 consecutive rows) ----------
__global__ void __launch_bounds__(64) landmark_k()
{
    int zz = blockIdx.x;
    int mi = zz & 255, bh = zz >> 8;
    int b = bh >> 3, h = bh & 7;
    int d = threadIdx.x;
    const float* base = g_QKV + (long long)(b * NF + mi * 32) * QD + h * 64 + d;
    float sq = 0.f, sk = 0.f;
    #pragma unroll 8
    for (int il = 0; il < 32; il++) {
        sq += base[(long long)il * QD];
        sk += base[(long long)il * QD + 512];
    }
    long long o = ((long long)bh * LM + mi) * DH + d;
    g_QL[o] = sq * (1.f / 32.f);
    g_KL[o] = sk * (1.f / 32.f);
}

// ------------------------- pinv helpers -------------------------------------
__global__ void reset_k() { g_scale[0] = 0u; g_scale[1] = 0u; }

__global__ void __launch_bounds__(256) scalemax_k()
{
    int z = blockIdx.x;
    int i = threadIdx.x;
    const float* S = g_S2 + ((long long)z << 16);
    float rs = 0.f, cs = 0.f;
    for (int j = 0; j < 256; j++) { rs += S[(i << 8) + j]; cs += S[(j << 8) + i]; }
    float rm = blockReduce(rs, true);
    float cm = blockReduce(cs, true);
    if (i == 0) {
        atomicMax(&g_scale[0], __float_as_uint(rm));
        atomicMax(&g_scale[1], __float_as_uint(cm));
    }
}

__global__ void __launch_bounds__(256) zinit_k()
{
    int idx = blockIdx.x * 256 + threadIdx.x;
    float inv = 1.0f / (__uint_as_float(g_scale[0]) * __uint_as_float(g_scale[1]));
    int z = idx >> 16, r = idx & 65535;
    int i = r >> 8, j = r & 255;
    g_Zb[((long long)z << 16) + (i << 8) + j] = g_S2[((long long)z << 16) + (j << 8) + i] * inv;
}

// ------------------------- split-K reduce for AV ----------------------------
__global__ void __launch_bounds__(256) avreduce_k()
{
    int idx = blockIdx.x * 256 + threadIdx.x;
    int bh = idx >> 14;
    int r  = idx & 16383;
    const float* p = g_AVp + ((long long)bh << 17);
    float s = 0.f;
    #pragma unroll
    for (int k = 0; k < KSPL; k++) s += p[(k << 14) + r];
    g_AV[idx] = s;
}

// ------------------------- depthwise conv residual (adds into g_OH) ---------
__global__ void __launch_bounds__(256) conv_k(const float* __restrict__ cw)
{
    __shared__ float sv[160 * 64];
    __shared__ float sw[KER];
    int tile = blockIdx.x;
    int bh = blockIdx.y;
    int b = bh >> 3, h = bh & 7;
    int n0 = tile * 128;
    int t = threadIdx.x;
    if (t < KER) sw[t] = cw[h * KER + t];
    for (int idx = t; idx < 160 * 64; idx += 256) {
        int r = idx >> 6, d = idx & 63;
        int nn = n0 - 16 + r;
        float v = 0.f;
        if (nn >= 0 && nn < NF) v = g_QKV[(long long)(b * NF + nn) * QD + 1024 + h * 64 + d];
        sv[idx] = v;
    }
    __syncthreads();
    int d = t & 63, r0 = t >> 6;
    for (int rr = r0; rr < 128; rr += 4) {
        float a = 0.f;
        #pragma unroll
        for (int k = 0; k < KER; k++) a += sv[(rr + k) * 64 + d] * sw[k];
        long long o = ((long long)bh * NF + n0 + rr) * DH + d;
        g_OH[o] += a;
    }
}

// ------------------------- cls token fill -----------------------------------
__global__ void __launch_bounds__(256) cls_k(const float* __restrict__ ct)
{
    int idx = blockIdx.x * 256 + threadIdx.x;
    int b = idx >> 9, c = idx & 511;
    g_X[(long long)b * NF * DIMM + c] = ct[c];
}

// ------------------------- final LN + head ----------------------------------
__global__ void __launch_bounds__(256) final_k(const float* __restrict__ fg, const float* __restrict__ fb,
                                               const float* __restrict__ w2, const float* __restrict__ b2,
                                               float* __restrict__ out)
{
    int b = blockIdx.x;
    const float* x = g_X + (long long)b * NF * DIMM;
    int t = threadIdx.x;
    float v0 = x[t], v1 = x[t + 256];
    float mu  = blockReduce(v0 + v1, false) * (1.f / 512.f);
    float d0 = v0 - mu, d1 = v1 - mu;
    float var = blockReduce(d0 * d0 + d1 * d1, false) * (1.f / 512.f);
    float inv = rsqrtf(var + 1e-5f);
    float n0 = d0 * inv * fg[t]       + fb[t];
    float n1 = d1 * inv * fg[t + 256] + fb[t + 256];
    float p0 = n0 * w2[2 * t]     + n1 * w2[2 * (t + 256)];
    float p1 = n0 * w2[2 * t + 1] + n1 * w2[2 * (t + 256) + 1];
    p0 = blockReduce(p0, false);
    p1 = blockReduce(p1, false);
    if (t == 0) {
        out[b * 2 + 0] = p0 + b2[0];
        out[b * 2 + 1] = p1 + b2[1];
    }
}

// ------------------------- host orchestration -------------------------------
static inline void gemm64(int transB, int M, int N, int K,
                          const float* A, int lda, long long sA1, long long sA2, long long sA3,
                          const float* Bp, int ldb, long long sB1, long long sB2, long long sB3,
                          float* C, int ldc, long long sC1, long long sC2, long long sC3,
                          int SPLIT, int batchZ, float alpha, int ep, const float* bias,
                          int bmode, float bdiag)
{
    dim3 g(N >> 6, (M + 63) >> 6, batchZ);
    if (transB)
        gemm64_k<1><<<g, 256>>>(M, N, K, A, lda, sA1, sA2, sA3, Bp, ldb, sB1, sB2, sB3,
                                C, ldc, sC1, sC2, sC3, SPLIT, alpha, ep, bias, bmode, bdiag);
    else
        gemm64_k<0><<<g, 256>>>(M, N, K, A, lda, sA1, sA2, sA3, Bp, ldb, sB1, sB2, sB3,
                                C, ldc, sC1, sC2, sC3, SPLIT, alpha, ep, bias, bmode, bdiag);
}

static inline void mgemm2(int M, int N, int K,
                          const float* A, int lda, long long sA1, long long sA2, int amode,
                          const float* BT, int ldbt, long long sBT1, long long sBT2,
                          float* C, int ldc, long long sC1, long long sC2,
                          int batch, int ep, const float* bias)
{
    cudaFuncSetAttribute(mgemm2_k, cudaFuncAttributeMaxDynamicSharedMemorySize, 98304);
    dim3 g(N >> 8, (M + 127) >> 7, batch);
    mgemm2_k<<<g, 256, 98304>>>(M, K, A, lda, sA1, sA2, amode, BT, ldbt, sBT1, sBT2,
                                C, ldc, sC1, sC2, ep, bias);
}

static inline void pgemm(const float* A, const float* B, float* C,
                         float alpha, int bmode, float bd)
{
    cudaFuncSetAttribute(pgemm_k, cudaFuncAttributeMaxDynamicSharedMemorySize, 81920);
    dim3 g(2, 2, NBH);
    pgemm_k<<<g, 256, 81920>>>(A, B, C, alpha, bmode, bd);
}

static inline void transT(const float* src, float* dst, int K, int N)
{
    dim3 g(K >> 5, N >> 5);
    transT_k<<<g, 256>>>(src, dst, K, N);
}

extern "C" void kernel_launch(void* const* d_in, const int* in_sizes, int n_in,
                              void* d_out, int out_size)
{
    const float* h_in  = (const float*)d_in[0];
    const float* w1    = (const float*)d_in[1];
    const float* b1    = (const float*)d_in[2];
    const float* clst  = (const float*)d_in[3];
    const float* ln_g  = (const float*)d_in[4];
    const float* ln_b  = (const float*)d_in[5];
    const float* wqkv  = (const float*)d_in[6];
    const float* wout  = (const float*)d_in[7];
    const float* bout  = (const float*)d_in[8];
    const float* cw    = (const float*)d_in[9];
    const float* fg    = (const float*)d_in[10];
    const float* fb    = (const float*)d_in[11];
    const float* w2    = (const float*)d_in[12];
    const float* b2    = (const float*)d_in[13];
    float* out = (float*)d_out;

    float *X, *XN, *QKV, *QL, *KL, *S1, *S2, *S3, *Z, *Z2, *P, *T, *T2, *AV, *AVp, *ZAV, *OH, *WT;
    cudaGetSymbolAddress((void**)&X,   g_X);
    cudaGetSymbolAddress((void**)&XN,  g_XN);
    cudaGetSymbolAddress((void**)&QKV, g_QKV);
    cudaGetSymbolAddress((void**)&QL,  g_QL);
    cudaGetSymbolAddress((void**)&KL,  g_KL);
    cudaGetSymbolAddress((void**)&S1,  g_S1);
    cudaGetSymbolAddress((void**)&S2,  g_S2);
    cudaGetSymbolAddress((void**)&S3,  g_S3);
    cudaGetSymbolAddress((void**)&Z,   g_Zb);
    cudaGetSymbolAddress((void**)&Z2,  g_Z2b);
    cudaGetSymbolAddress((void**)&P,   g_Pb);
    cudaGetSymbolAddress((void**)&T,   g_Tb);
    cudaGetSymbolAddress((void**)&T2,  g_T2b);
    cudaGetSymbolAddress((void**)&AV,  g_AV);
    cudaGetSymbolAddress((void**)&AVp, g_AVp);
    cudaGetSymbolAddress((void**)&ZAV, g_ZAV);
    cudaGetSymbolAddress((void**)&OH,  g_OH);
    cudaGetSymbolAddress((void**)&WT,  g_WT);

    const long long SQb = (long long)NF * QD;
    const long long S2s = (long long)LM * LM;
    const long long S1s = (long long)NF * LM;
    const long long AVs = (long long)LM * DH;
    const long long OHs = (long long)NF * DH;

    // pre-transpose weights (5 launches; keeps big GEMM at ncu's -s 5 slot)
    transT(w1, WT + OW1, 1024, DIMM);
    for (int L = 0; L < 2; L++) {
        transT(wqkv + (long long)L * DIMM * QD, WT + OQKV(L), DIMM, QD);
        transT(wout + (long long)L * DIMM * DIMM, WT + OOUT(L), DIMM, DIMM);
    }

    // input projection: X[b, n+1, :] = relu(h @ w1 + b1)
    mgemm2(NB * 8191, DIMM, 1024, h_in, 1024, 0, 0, 0, WT + OW1, 1024, 0, 0,
           X, DIMM, 0, 0, 1, EP_RELU_REMAP, b1);
    cls_k<<<4, 256>>>(clst);

    for (int L = 0; L < 2; L++) {
        ln_k<<<TOT, 256>>>(X, XN, ln_g + L * DIMM, ln_b + L * DIMM);

        // qkv = ln(x) @ Wqkv (q cols scaled by 1/8)
        mgemm2(TOT, QD, DIMM, XN, DIMM, 0, 0, 0, WT + OQKV(L), DIMM, 0, 0,
               QKV, QD, 0, 0, 1, EP_SCALEQ, nullptr);

        landmark_k<<<NBH * LM, 64>>>();

        // sim2 = QL @ KL^T, softmax  (batched tf32)
        mgemm2(LM, LM, DH, QL, DH, 8 * AVs, AVs, 0, KL, DH, 8 * AVs, AVs,
               S2, LM, 8 * S2s, S2s, NBH, EP_NONE, nullptr);
        softmax256_k<<<NBH * LM / 8, 256>>>(S2);

        // Moore-Penrose pinv of S2 -> Z  (3xTF32 tensor GEMMs)
        reset_k<<<1, 1>>>();
        scalemax_k<<<NBH, 256>>>();
        zinit_k<<<4096, 256>>>();
        for (int it = 0; it < 6; it++) {
            float* Zin  = (it & 1) ? Z2 : Z;
            float* Zout = (it & 1) ? Z  : Z2;
            pgemm(S2, Zin, P, 1.f, 0, 0.f);      // P  = S2 @ Zin
            pgemm(P, P, T2, 1.f, 1, 7.f);        // T2 = P @ (7I - P)
            pgemm(P, T2, T, 1.f, 1, 15.f);       // T  = P @ (15I - T2)
            pgemm(Zin, T, Zout, 0.25f, 1, 13.f); // Zout = 0.25 Zin @ (13I - T)
        }

        // sim1 = Q @ KL^T, softmax  (batched tf32; KL is n-major BT)
        mgemm2(NF, LM, DH, QKV, QD, SQb, 64, 0, KL, DH, 8 * AVs, AVs,
               S1, LM, 8 * S1s, S1s, NBH, EP_NONE, nullptr);
        softmax256_k<<<NBH * NF / 8, 256>>>(S1);

        // sim3 = QL @ K^T, softmax over 8192  (K rows of QKV are n-major BT)
        mgemm2(LM, NF, DH, QL, DH, 8 * AVs, AVs, 0, QKV + 512, QD, SQb, 64,
               S3, NF, 8 * S1s, S1s, NBH, EP_NONE, nullptr);
        softmax_k<<<NBH * LM, 256, NF * 4>>>(S3, NF);

        // AV = attn3 @ V  (split-K by 8, then reduce)
        gemm64(0, LM, DH, NF / KSPL,
               S3, NF, 8 * S1s, S1s, 1024,
               QKV + 1024, QD, SQb, 64, 1024LL * QD,
               AVp, DH, 64 * AVs, 8 * AVs, AVs,
               KSPL, NBH * KSPL, 1.f, EP_NONE, nullptr, 0, 0.f);
        avreduce_k<<<1024, 256>>>();

        // ZAV = Z @ AV
        gemm64(0, LM, DH, LM, Z, LM, 8 * S2s, S2s, 0, AV, DH, 8 * AVs, AVs, 0,
               ZAV, DH, 8 * AVs, AVs, 0, 1, NBH, 1.f, EP_NONE, nullptr, 0, 0.f);
        // OH = attn1 @ ZAV
        gemm64(0, NF, DH, LM, S1, LM, 8 * S1s, S1s, 0, ZAV, DH, 8 * AVs, AVs, 0,
               OH, DH, 8 * OHs, OHs, 0, 1, NBH, 1.f, EP_NONE, nullptr, 0, 0.f);

        // OH += depthwise conv residual of V
        { dim3 g(NF / 128, NBH); conv_k<<<g, 256>>>(cw + L * NH * KER); }

        // X += OH(head-layout) @ Wout + bout
        mgemm2(TOT, DIMM, DIMM, OH, 0, 0, 0, 1, WT + OOUT(L), DIMM, 0, 0,
               X, DIMM, 0, 0, 1, EP_ADDBIAS, bout + L * DIMM);
    }

    final_k<<<NB, 256>>>(fg, fb, w2, b2, out);
}

// round 8
// speedup vs baseline: 2.4621x; 1.3434x over previous
#include <cuda_runtime.h>

#define NB   2
#define NF   8192
#define DIMM 512
#define NH   8
#define DH   64
#define LM   256
#define QD   1536
#define TOT  (NB*NF)    // 16384
#define NBH  (NB*NH)    // 16
#define KER  33
#define KSPL 8

// ------------------------- scratch (device globals, no allocs) -------------
__device__ float g_X  [TOT*DIMM];
__device__ float g_XN [TOT*DIMM];
__device__ float g_QKV[TOT*QD];
__device__ float g_QL [NBH*LM*DH];
__device__ float g_KL [NBH*LM*DH];
__device__ float g_S1 [NBH*NF*LM];
__device__ float g_S3 [NBH*LM*NF];
__device__ float g_S2 [NBH*LM*LM];
__device__ float g_Zb [NBH*LM*LM];
__device__ float g_Z2b[NBH*LM*LM];
__device__ float g_Pb [NBH*LM*LM];
__device__ float g_Tb [NBH*LM*LM];
__device__ float g_T2b[NBH*LM*LM];
__device__ float g_AV [NBH*LM*DH];
__device__ float g_AVp[NBH*KSPL*LM*DH];
__device__ float g_ZAV[NBH*LM*DH];
__device__ float g_OH [NBH*NF*DH];
__device__ float g_WT [2621440];
__device__ float2 g_RS1[NBH*NF];
__device__ float2 g_RS3[NBH*LM];
__device__ unsigned int g_scale[2];

enum { EP_NONE = 0, EP_RELU_REMAP = 1, EP_SCALEQ = 2, EP_ADDBIAS = 3 };

#define OW1   0
#define OQKV(L) (524288 + (L) * 786432)
#define OOUT(L) (2097152 + (L) * 262144)

__device__ __forceinline__ unsigned f2tf32(float f) {
    unsigned r;
    asm("cvt.rna.tf32.f32 %0, %1;" : "=r"(r) : "f"(f));
    return r;
}
__device__ __forceinline__ float tf32f(float f) {
    return __uint_as_float(f2tf32(f));
}

#define MMA_TF32(d, a, b) \
    asm volatile("mma.sync.aligned.m16n8k8.row.col.f32.tf32.tf32.f32 " \
        "{%0,%1,%2,%3}, {%4,%5,%6,%7}, {%8,%9}, {%0,%1,%2,%3};" \
        : "+f"((d)[0]), "+f"((d)[1]), "+f"((d)[2]), "+f"((d)[3]) \
        : "r"((a)[0]), "r"((a)[1]), "r"((a)[2]), "r"((a)[3]), \
          "r"((b)[0]), "r"((b)[1]))

// ------------------- fused transposes + cls (ONE launch) --------------------
__device__ __forceinline__ void doTrans(const float* __restrict__ src,
                                        float* __restrict__ dst,
                                        int K, int N, int kt, int nt)
{
    __shared__ float t[32][33];
    int kb = kt << 5, nb = nt << 5;
    int x = threadIdx.x & 31, y = threadIdx.x >> 5;
    #pragma unroll
    for (int i = 0; i < 32; i += 8)
        t[y + i][x] = src[(long long)(kb + y + i) * N + nb + x];
    __syncthreads();
    #pragma unroll
    for (int i = 0; i < 32; i += 8)
        dst[(long long)(nb + y + i) * K + kb + x] = t[x][y + i];
}

__global__ void __launch_bounds__(256) transAll_k(
    const float* __restrict__ w1, const float* __restrict__ wqkv,
    const float* __restrict__ wout, const float* __restrict__ clst)
{
    int b = blockIdx.x;
    if (b < 512) {
        doTrans(w1, g_WT + OW1, 1024, DIMM, b & 31, b >> 5);
    } else if (b < 2048) {
        int L = (b - 512) / 768, bb = (b - 512) % 768;
        doTrans(wqkv + (long long)L * DIMM * QD, g_WT + OQKV(L), DIMM, QD, bb & 15, bb >> 4);
    } else if (b < 2560) {
        int L = (b - 2048) / 256, bb = (b - 2048) % 256;
        doTrans(wout + (long long)L * DIMM * DIMM, g_WT + OOUT(L), DIMM, DIMM, bb & 15, bb >> 4);
    } else {
        int idx = (b - 2560) * 256 + threadIdx.x;   // 1024 total
        int bb = idx >> 9, c = idx & 511;
        g_X[(long long)bb * NF * DIMM + c] = clst[c];
    }
}

// ===================== mgemm2: cp.async + ldmatrix tf32, batched ============
__device__ __forceinline__ void cp16(unsigned dst, const void* src, int nbytes) {
    asm volatile("cp.async.cg.shared.global [%0], [%1], 16, %2;"
                 :: "r"(dst), "l"(src), "r"(nbytes) : "memory");
}

__global__ void __launch_bounds__(256) mgemm2_k(
    int M, int K,
    const float* __restrict__ A, int lda, long long sA1, long long sA2, int amode,
    const float* __restrict__ BT, int ldbt, long long sBT1, long long sBT2,
    float* __restrict__ C, int ldc, long long sC1, long long sC2,
    int ep, const float* __restrict__ bias)
{
    extern __shared__ float smem[];
    int tid = threadIdx.x;
    int lane = tid & 31, wid = tid >> 5;
    int wm = wid & 1, wn = wid >> 1;
    int row0 = blockIdx.y << 7, col0 = blockIdx.x << 8;
    int z = blockIdx.z;
    A  += (long long)(z >> 3) * sA1 + (long long)(z & 7) * sA2;
    BT += (long long)(z >> 3) * sBT1 + (long long)(z & 7) * sBT2;
    C  += (long long)(z >> 3) * sC1 + (long long)(z & 7) * sC2;

    unsigned sbase;
    asm("{ .reg .u64 t; cvta.to.shared.u64 t, %1; cvt.u32.u64 %0, t; }"
        : "=r"(sbase) : "l"(smem));

    float acc[4][8][4];
    #pragma unroll
    for (int mi = 0; mi < 4; mi++)
        #pragma unroll
        for (int ni = 0; ni < 8; ni++)
            #pragma unroll
            for (int q = 0; q < 4; q++) acc[mi][ni][q] = 0.f;

    auto fill = [&](int s, int k0) {
        unsigned Ab = sbase + s * 49152u;
        unsigned Bb = Ab + 16384u;
        #pragma unroll
        for (int it = 0; it < 4; it++) {
            int idx = (it << 8) + tid;
            int q = idx & 7, r = idx >> 3;
            int gr = row0 + r;
            const float* src;
            int nb = 16;
            if (amode == 0) {
                int gra = gr < M ? gr : (M - 1);
                if (gr >= M) nb = 0;
                src = A + (long long)gra * lda + k0 + (q << 2);
            } else {
                int k = k0 + (q << 2);
                int h = k >> 6, d = k & 63;
                src = A + ((((long long)(gr >> 13) << 3) + h) * 8192 + (gr & 8191)) * 64 + d;
            }
            unsigned dst = Ab + (((r << 5) + ((q ^ (r & 7)) << 2)) << 2);
            cp16(dst, src, nb);
        }
        #pragma unroll
        for (int it = 0; it < 8; it++) {
            int idx = (it << 8) + tid;
            int q = idx & 7, n = idx >> 3;
            const float* src = BT + (long long)(col0 + n) * ldbt + k0 + (q << 2);
            unsigned dst = Bb + (((n << 5) + ((q ^ (n & 7)) << 2)) << 2);
            cp16(dst, src, 16);
        }
        asm volatile("cp.async.commit_group;" ::: "memory");
    };

    auto compute = [&](int s) {
        unsigned Ab = sbase + s * 49152u;
        unsigned Bb = Ab + 16384u;
        int j = lane >> 3, rho = lane & 7;
        #pragma unroll
        for (int kt = 0; kt < 4; kt++) {
            unsigned a[4][4];
            #pragma unroll
            for (int mi = 0; mi < 4; mi++) {
                int row = (wm << 6) + (mi << 4) + ((j & 1) << 3) + rho;
                int quad = (kt << 1) + (j >> 1);
                unsigned ad = Ab + (((row << 5) + ((quad ^ (row & 7)) << 2)) << 2);
                asm volatile("ldmatrix.sync.aligned.m8n8.x4.shared.b16 {%0,%1,%2,%3}, [%4];"
                    : "=r"(a[mi][0]), "=r"(a[mi][1]), "=r"(a[mi][2]), "=r"(a[mi][3])
                    : "r"(ad));
            }
            unsigned b[8][2];
            #pragma unroll
            for (int np = 0; np < 4; np++) {
                int row = (((wn << 3) + (np << 1) + (j >> 1)) << 3) + rho;
                int quad = (kt << 1) + (j & 1);
                unsigned bd = Bb + (((row << 5) + ((quad ^ (row & 7)) << 2)) << 2);
                asm volatile("ldmatrix.sync.aligned.m8n8.x4.shared.b16 {%0,%1,%2,%3}, [%4];"
                    : "=r"(b[np * 2][0]), "=r"(b[np * 2][1]),
                      "=r"(b[np * 2 + 1][0]), "=r"(b[np * 2 + 1][1])
                    : "r"(bd));
            }
            #pragma unroll
            for (int mi = 0; mi < 4; mi++)
                #pragma unroll
                for (int ni = 0; ni < 8; ni++)
                    MMA_TF32(acc[mi][ni], a[mi], b[ni]);
        }
    };

    fill(0, 0);
    int nch = K >> 5;
    for (int ch = 0; ch < nch; ch++) {
        if (ch + 1 < nch) {
            fill((ch + 1) & 1, (ch + 1) << 5);
            asm volatile("cp.async.wait_group 1;" ::: "memory");
        } else {
            asm volatile("cp.async.wait_group 0;" ::: "memory");
        }
        __syncthreads();
        compute(ch & 1);
        __syncthreads();
    }

    int rb = row0 + (wm << 6) + (lane >> 2);
    int cb = col0 + (wn << 6) + ((lane & 3) << 1);
    #pragma unroll
    for (int mi = 0; mi < 4; mi++) {
        #pragma unroll
        for (int half = 0; half < 2; half++) {
            int r = rb + (mi << 4) + (half << 3);
            if (r >= M) continue;
            #pragma unroll
            for (int ni = 0; ni < 8; ni++) {
                int c = cb + (ni << 3);
                float v0 = acc[mi][ni][half * 2];
                float v1 = acc[mi][ni][half * 2 + 1];
                if (ep == EP_RELU_REMAP) {
                    long long o = (long long)(r + r / 8191 + 1) * ldc + c;
                    v0 = fmaxf(v0 + bias[c], 0.f);
                    v1 = fmaxf(v1 + bias[c + 1], 0.f);
                    *(float2*)(C + o) = make_float2(v0, v1);
                } else if (ep == EP_SCALEQ) {
                    float sc = (c < 512) ? 0.125f : 1.0f;
                    *(float2*)(C + (long long)r * ldc + c) = make_float2(v0 * sc, v1 * sc);
                } else if (ep == EP_ADDBIAS) {
                    long long o = (long long)r * ldc + c;
                    float2 old = *(float2*)(C + o);
                    *(float2*)(C + o) = make_float2(old.x + v0 + bias[c],
                                                    old.y + v1 + bias[c + 1]);
                } else {
                    *(float2*)(C + (long long)r * ldc + c) = make_float2(v0, v1);
                }
            }
        }
    }
}

// ===================== pgemm: 3xTF32 batched (pinv), 64x128 CTA =============
// C = alpha * A @ Beff; smem rows stride 20 -> conflict-free float4 + frag LDS.
__global__ void __launch_bounds__(256) pgemm_k(
    const float* __restrict__ Ag, const float* __restrict__ Bg,
    float* __restrict__ Cg, float alpha, int bmode, float bd)
{
    extern __shared__ float ps[];   // 2 stages x 7680 floats = 60KB
    int tid = threadIdx.x;
    int lane = tid & 31, wid = tid >> 5;
    int wm = wid & 3, wn = wid >> 2;           // 4 m-groups(16 rows), 2 n-groups(64)
    int row0 = blockIdx.y << 6, col0 = blockIdx.x << 7;
    long long zo = (long long)blockIdx.z << 16;
    Ag += zo; Bg += zo; Cg += zo;

    float acc[8][4];
    #pragma unroll
    for (int ni = 0; ni < 8; ni++)
        #pragma unroll
        for (int q = 0; q < 4; q++) acc[ni][q] = 0.f;

    int ar = tid >> 2, aq = tid & 3;           // A: 64 rows x 4 quads
    int bn = tid & 127, bkh = tid >> 7;        // B: 128 cols x 2 k-halves

    float4 pa;
    float pbv[8];

    auto fetch = [&](int k0) {
        pa = *(const float4*)(Ag + ((long long)(row0 + ar) << 8) + k0 + (aq << 2));
        #pragma unroll
        for (int j = 0; j < 8; j++) {
            int gk = k0 + (bkh << 3) + j;
            int gn = col0 + bn;
            float v = Bg[((long long)gk << 8) + gn];
            if (bmode) v = (gk == gn ? bd : 0.f) - v;
            pbv[j] = v;
        }
    };

    auto stash = [&](int s) {
        float* Sb = ps + s * 7680;
        float4 h, l;
        h.x = tf32f(pa.x); h.y = tf32f(pa.y); h.z = tf32f(pa.z); h.w = tf32f(pa.w);
        l.x = tf32f(pa.x - h.x); l.y = tf32f(pa.y - h.y);
        l.z = tf32f(pa.z - h.z); l.w = tf32f(pa.w - h.w);
        *(float4*)&Sb[ar * 20 + (aq << 2)] = h;
        *(float4*)&Sb[1280 + ar * 20 + (aq << 2)] = l;
        float4 bh0, bh1, bl0, bl1;
        bh0.x = tf32f(pbv[0]); bh0.y = tf32f(pbv[1]); bh0.z = tf32f(pbv[2]); bh0.w = tf32f(pbv[3]);
        bh1.x = tf32f(pbv[4]); bh1.y = tf32f(pbv[5]); bh1.z = tf32f(pbv[6]); bh1.w = tf32f(pbv[7]);
        bl0.x = tf32f(pbv[0] - bh0.x); bl0.y = tf32f(pbv[1] - bh0.y);
        bl0.z = tf32f(pbv[2] - bh0.z); bl0.w = tf32f(pbv[3] - bh0.w);
        bl1.x = tf32f(pbv[4] - bh1.x); bl1.y = tf32f(pbv[5] - bh1.y);
        bl1.z = tf32f(pbv[6] - bh1.z); bl1.w = tf32f(pbv[7] - bh1.w);
        *(float4*)&Sb[2560 + bn * 20 + (bkh << 3)] = bh0;
        *(float4*)&Sb[2560 + bn * 20 + (bkh << 3) + 4] = bh1;
        *(float4*)&Sb[5120 + bn * 20 + (bkh << 3)] = bl0;
        *(float4*)&Sb[5120 + bn * 20 + (bkh << 3) + 4] = bl1;
    };

    auto compute = [&](int s) {
        const float* Sb = ps + s * 7680;
        int g = lane >> 2, t = lane & 3;
        #pragma unroll
        for (int kt = 0; kt < 2; kt++) {
            int kb = kt << 3;
            int m = (wm << 4) + g;
            unsigned ah[4], al[4];
            ah[0] = __float_as_uint(Sb[m * 20 + kb + t]);
            ah[1] = __float_as_uint(Sb[(m + 8) * 20 + kb + t]);
            ah[2] = __float_as_uint(Sb[m * 20 + kb + t + 4]);
            ah[3] = __float_as_uint(Sb[(m + 8) * 20 + kb + t + 4]);
            al[0] = __float_as_uint(Sb[1280 + m * 20 + kb + t]);
            al[1] = __float_as_uint(Sb[1280 + (m + 8) * 20 + kb + t]);
            al[2] = __float_as_uint(Sb[1280 + m * 20 + kb + t + 4]);
            al[3] = __float_as_uint(Sb[1280 + (m + 8) * 20 + kb + t + 4]);
            #pragma unroll
            for (int ni = 0; ni < 8; ni++) {
                int n = (wn << 6) + (ni << 3) + g;
                unsigned bh[2], bl[2];
                bh[0] = __float_as_uint(Sb[2560 + n * 20 + kb + t]);
                bh[1] = __float_as_uint(Sb[2560 + n * 20 + kb + t + 4]);
                bl[0] = __float_as_uint(Sb[5120 + n * 20 + kb + t]);
                bl[1] = __float_as_uint(Sb[5120 + n * 20 + kb + t + 4]);
                MMA_TF32(acc[ni], ah, bh);
                MMA_TF32(acc[ni], ah, bl);
                MMA_TF32(acc[ni], al, bh);
            }
        }
    };

    fetch(0);
    for (int ch = 0; ch < 16; ch++) {
        stash(ch & 1);
        __syncthreads();
        if (ch < 15) fetch((ch + 1) << 4);
        compute(ch & 1);
        __syncthreads();
    }

    int g = lane >> 2, t = lane & 3;
    #pragma unroll
    for (int half = 0; half < 2; half++) {
        int r = row0 + (wm << 4) + (half << 3) + g;
        #pragma unroll
        for (int ni = 0; ni < 8; ni++) {
            int c = col0 + (wn << 6) + (ni << 3) + (t << 1);
            *(float2*)(Cg + ((long long)r << 8) + c) =
                make_float2(acc[ni][half * 2] * alpha, acc[ni][half * 2 + 1] * alpha);
        }
    }
}

// ------------------------- reductions --------------------------------------
__device__ __forceinline__ float blockReduce(float v, bool domax) {
    __shared__ float sh[32];
    __syncthreads();
    #pragma unroll
    for (int o = 16; o > 0; o >>= 1) {
        float w = __shfl_down_sync(0xffffffffu, v, o);
        v = domax ? fmaxf(v, w) : v + w;
    }
    int lane = threadIdx.x & 31, wid = threadIdx.x >> 5;
    if (lane == 0) sh[wid] = v;
    __syncthreads();
    int nw = (blockDim.x + 31) >> 5;
    if (wid == 0) {
        v = (lane < nw) ? sh[lane] : (domax ? -1e30f : 0.f);
        #pragma unroll
        for (int o = 16; o > 0; o >>= 1) {
            float w = __shfl_down_sync(0xffffffffu, v, o);
            v = domax ? fmaxf(v, w) : v + w;
        }
        if (lane == 0) sh[0] = v;
    }
    __syncthreads();
    return sh[0];
}

// ===================== 64x64x16 SIMT GEMM (AV/ZAV/OH), exp-fused A ==========
template<int TRANSB>
__global__ void __launch_bounds__(256) gemm64_k(
    int M, int N, int K,
    const float* __restrict__ A, int lda, long long sA1, long long sA2, long long sA3,
    const float* __restrict__ Bp, int ldb, long long sB1, long long sB2, long long sB3,
    float* __restrict__ C, int ldc, long long sC1, long long sC2, long long sC3,
    int SPLIT, float alpha, int ep, const float* __restrict__ bias,
    int bmode, float bdiag,
    const float2* __restrict__ rsA, long long rs1, long long rs2, int aexp)
{
    __shared__ float As[2][16 * 68];
    __shared__ float Bs[2][16 * 68];
    int z = blockIdx.z;
    int s  = z % SPLIT;
    int bh = z / SPLIT;
    int hh = bh & 7, bb = bh >> 3;
    A  += (long long)bb * sA1 + (long long)hh * sA2 + (long long)s * sA3;
    Bp += (long long)bb * sB1 + (long long)hh * sB2 + (long long)s * sB3;
    C  += (long long)bb * sC1 + (long long)hh * sC2 + (long long)s * sC3;
    rsA += bb * rs1 + hh * rs2;
    int row0 = blockIdx.y << 6;
    int col0 = blockIdx.x << 6;
    int tid = threadIdx.x;
    int tx = tid & 15, ty = tid >> 4;

    int a_r  = tid >> 2;
    int a_kk = (tid & 3) << 2;
    int bn_kk = tid >> 4;
    int bn_n  = (tid & 15) << 2;
    int bt_n  = tid >> 2;
    int bt_kk = (tid & 3) << 2;

    float acc[4][4];
    #pragma unroll
    for (int i = 0; i < 4; i++)
        #pragma unroll
        for (int j = 0; j < 4; j++) acc[i][j] = 0.f;

    float4 pa, pb;

    auto fetch = [&](int k0) {
        int gr = row0 + a_r;
        pa = make_float4(0.f, 0.f, 0.f, 0.f);
        if (gr < M) {
            pa = *(const float4*)(A + (long long)gr * lda + k0 + a_kk);
            if (aexp) {
                float2 st = rsA[gr];
                pa.x = __expf(pa.x - st.x) * st.y;
                pa.y = __expf(pa.y - st.x) * st.y;
                pa.z = __expf(pa.z - st.x) * st.y;
                pa.w = __expf(pa.w - st.x) * st.y;
            }
        }
        if (!TRANSB) {
            pb = *(const float4*)(Bp + (long long)(k0 + bn_kk) * ldb + col0 + bn_n);
        } else {
            pb = *(const float4*)(Bp + (long long)(col0 + bt_n) * ldb + k0 + bt_kk);
        }
    };

    auto stash = [&](int b, int k0) {
        float* Ab = As[b];
        Ab[(a_kk + 0) * 68 + a_r] = pa.x;
        Ab[(a_kk + 1) * 68 + a_r] = pa.y;
        Ab[(a_kk + 2) * 68 + a_r] = pa.z;
        Ab[(a_kk + 3) * 68 + a_r] = pa.w;
        float* Bb = Bs[b];
        if (!TRANSB) {
            float4 v = pb;
            if (bmode) {
                int gk = k0 + bn_kk, gn = col0 + bn_n;
                v.x = (gk == gn + 0 ? bdiag : 0.f) - v.x;
                v.y = (gk == gn + 1 ? bdiag : 0.f) - v.y;
                v.z = (gk == gn + 2 ? bdiag : 0.f) - v.z;
                v.w = (gk == gn + 3 ? bdiag : 0.f) - v.w;
            }
            *(float4*)&Bb[bn_kk * 68 + bn_n] = v;
        } else {
            Bb[(bt_kk + 0) * 68 + bt_n] = pb.x;
            Bb[(bt_kk + 1) * 68 + bt_n] = pb.y;
            Bb[(bt_kk + 2) * 68 + bt_n] = pb.z;
            Bb[(bt_kk + 3) * 68 + bt_n] = pb.w;
        }
    };

    fetch(0);
    stash(0, 0);
    __syncthreads();

    int nt = K >> 4;
    for (int t = 0; t < nt; t++) {
        int buf = t & 1;
        if (t + 1 < nt) fetch((t + 1) << 4);
        const float* Ab = As[buf];
        const float* Bb = Bs[buf];
        #pragma unroll
        for (int kk = 0; kk < 16; kk++) {
            float4 a = *(const float4*)&Ab[kk * 68 + (ty << 2)];
            float4 b = *(const float4*)&Bb[kk * 68 + (tx << 2)];
            acc[0][0] += a.x * b.x; acc[0][1] += a.x * b.y; acc[0][2] += a.x * b.z; acc[0][3] += a.x * b.w;
            acc[1][0] += a.y * b.x; acc[1][1] += a.y * b.y; acc[1][2] += a.y * b.z; acc[1][3] += a.y * b.w;
            acc[2][0] += a.z * b.x; acc[2][1] += a.z * b.y; acc[2][2] += a.z * b.z; acc[2][3] += a.z * b.w;
            acc[3][0] += a.w * b.x; acc[3][1] += a.w * b.y; acc[3][2] += a.w * b.z; acc[3][3] += a.w * b.w;
        }
        if (t + 1 < nt) stash(buf ^ 1, (t + 1) << 4);
        __syncthreads();
    }

    #pragma unroll
    for (int i = 0; i < 4; i++) {
        int r = row0 + (ty << 2) + i;
        if (r >= M) continue;
        #pragma unroll
        for (int j = 0; j < 4; j++) {
            int c = col0 + (tx << 2) + j;
            C[(long long)r * ldc + c] = alpha * acc[i][j];
        }
    }
}

// ------------------------- layernorm (rows of 512) --------------------------
__global__ void __launch_bounds__(256) ln_k(const float* __restrict__ X, float* __restrict__ Y,
                                            const float* __restrict__ g, const float* __restrict__ b)
{
    long long row = blockIdx.x;
    const float* x = X + row * DIMM;
    float* y = Y + row * DIMM;
    int t = threadIdx.x;
    float v0 = x[t], v1 = x[t + 256];
    float mu  = blockReduce(v0 + v1, false) * (1.f / 512.f);
    float d0 = v0 - mu, d1 = v1 - mu;
    float var = blockReduce(d0 * d0 + d1 * d1, false) * (1.f / 512.f);
    float inv = rsqrtf(var + 1e-5f);
    y[t]       = d0 * inv * g[t]       + b[t];
    y[t + 256] = d1 * inv * g[t + 256] + b[t + 256];
}

// ------------------------- softmax (S2 only) --------------------------------
__global__ void __launch_bounds__(256) softmax256_k(float* __restrict__ S)
{
    long long row = ((long long)blockIdx.x << 3) + (threadIdx.x >> 5);
    int lane = threadIdx.x & 31;
    float* s = S + (row << 8);
    float4 va = *(float4*)(s + (lane << 3));
    float4 vb = *(float4*)(s + (lane << 3) + 4);
    float m = fmaxf(fmaxf(fmaxf(va.x, va.y), fmaxf(va.z, va.w)),
                    fmaxf(fmaxf(vb.x, vb.y), fmaxf(vb.z, vb.w)));
    #pragma unroll
    for (int o = 16; o > 0; o >>= 1) m = fmaxf(m, __shfl_xor_sync(0xffffffffu, m, o));
    va.x = __expf(va.x - m); va.y = __expf(va.y - m); va.z = __expf(va.z - m); va.w = __expf(va.w - m);
    vb.x = __expf(vb.x - m); vb.y = __expf(vb.y - m); vb.z = __expf(vb.z - m); vb.w = __expf(vb.w - m);
    float sum = va.x + va.y + va.z + va.w + vb.x + vb.y + vb.z + vb.w;
    #pragma unroll
    for (int o = 16; o > 0; o >>= 1) sum += __shfl_xor_sync(0xffffffffu, sum, o);
    float inv = 1.f / sum;
    va.x *= inv; va.y *= inv; va.z *= inv; va.w *= inv;
    vb.x *= inv; vb.y *= inv; vb.z *= inv; vb.w *= inv;
    *(float4*)(s + (lane << 3)) = va;
    *(float4*)(s + (lane << 3) + 4) = vb;
}

// ------------------------- row stats (softmax fused into consumers) ---------
__global__ void __launch_bounds__(256) rowstat256_k(const float* __restrict__ S,
                                                    float2* __restrict__ RS)
{
    long long row = ((long long)blockIdx.x << 3) + (threadIdx.x >> 5);
    int lane = threadIdx.x & 31;
    const float* s = S + (row << 8);
    float4 va = *(const float4*)(s + (lane << 3));
    float4 vb = *(const float4*)(s + (lane << 3) + 4);
    float m = fmaxf(fmaxf(fmaxf(va.x, va.y), fmaxf(va.z, va.w)),
                    fmaxf(fmaxf(vb.x, vb.y), fmaxf(vb.z, vb.w)));
    #pragma unroll
    for (int o = 16; o > 0; o >>= 1) m = fmaxf(m, __shfl_xor_sync(0xffffffffu, m, o));
    float sum = __expf(va.x - m) + __expf(va.y - m) + __expf(va.z - m) + __expf(va.w - m)
              + __expf(vb.x - m) + __expf(vb.y - m) + __expf(vb.z - m) + __expf(vb.w - m);
    #pragma unroll
    for (int o = 16; o > 0; o >>= 1) sum += __shfl_xor_sync(0xffffffffu, sum, o);
    if (lane == 0) RS[row] = make_float2(m, 1.f / sum);
}

__global__ void __launch_bounds__(256) rowstatbig_k(const float* __restrict__ S,
                                                    float2* __restrict__ RS, int cols)
{
    extern __shared__ float buf[];
    long long row = blockIdx.x;
    const float* s = S + row * cols;
    int t = threadIdx.x;
    float mx = -1e30f;
    for (int i = t; i < cols; i += 256) { float v = s[i]; buf[i] = v; mx = fmaxf(mx, v); }
    float bmax = blockReduce(mx, true);
    float sum = 0.f;
    for (int i = t; i < cols; i += 256) sum += __expf(buf[i] - bmax);
    float bsum = blockReduce(sum, false);
    if (t == 0) RS[row] = make_float2(bmax, 1.f / bsum);
}

// ------------------------- landmarks ----------------------------------------
__global__ void __launch_bounds__(64) landmark_k()
{
    int zz = blockIdx.x;
    int mi = zz & 255, bh = zz >> 8;
    int b = bh >> 3, h = bh & 7;
    int d = threadIdx.x;
    const float* base = g_QKV + (long long)(b * NF + mi * 32) * QD + h * 64 + d;
    float sq = 0.f, sk = 0.f;
    #pragma unroll 8
    for (int il = 0; il < 32; il++) {
        sq += base[(long long)il * QD];
        sk += base[(long long)il * QD + 512];
    }
    long long o = ((long long)bh * LM + mi) * DH + d;
    g_QL[o] = sq * (1.f / 32.f);
    g_KL[o] = sk * (1.f / 32.f);
}

// ------------------------- pinv helpers -------------------------------------
__global__ void reset_k() { g_scale[0] = 0u; g_scale[1] = 0u; }

__global__ void __launch_bounds__(256) scalemax_k()
{
    int z = blockIdx.x;
    int i = threadIdx.x;
    const float* S = g_S2 + ((long long)z << 16);
    float rs = 0.f, cs = 0.f;
    for (int j = 0; j < 256; j++) { rs += S[(i << 8) + j]; cs += S[(j << 8) + i]; }
    float rm = blockReduce(rs, true);
    float cm = blockReduce(cs, true);
    if (i == 0) {
        atomicMax(&g_scale[0], __float_as_uint(rm));
        atomicMax(&g_scale[1], __float_as_uint(cm));
    }
}

__global__ void __launch_bounds__(256) zinit_k()
{
    int idx = blockIdx.x * 256 + threadIdx.x;
    float inv = 1.0f / (__uint_as_float(g_scale[0]) * __uint_as_float(g_scale[1]));
    int z = idx >> 16, r = idx & 65535;
    int i = r >> 8, j = r & 255;
    g_Zb[((long long)z << 16) + (i << 8) + j] = g_S2[((long long)z << 16) + (j << 8) + i] * inv;
}

// ------------------------- split-K reduce for AV ----------------------------
__global__ void __launch_bounds__(256) avreduce_k()
{
    int idx = blockIdx.x * 256 + threadIdx.x;
    int bh = idx >> 14;
    int r  = idx & 16383;
    const float* p = g_AVp + ((long long)bh << 17);
    float s = 0.f;
    #pragma unroll
    for (int k = 0; k < KSPL; k++) s += p[(k << 14) + r];
    g_AV[idx] = s;
}

// ------------------------- depthwise conv residual --------------------------
__global__ void __launch_bounds__(256) conv_k(const float* __restrict__ cw)
{
    __shared__ float sv[160 * 64];
    __shared__ float sw[KER];
    int tile = blockIdx.x;
    int bh = blockIdx.y;
    int b = bh >> 3, h = bh & 7;
    int n0 = tile * 128;
    int t = threadIdx.x;
    if (t < KER) sw[t] = cw[h * KER + t];
    for (int idx = t; idx < 160 * 64; idx += 256) {
        int r = idx >> 6, d = idx & 63;
        int nn = n0 - 16 + r;
        float v = 0.f;
        if (nn >= 0 && nn < NF) v = g_QKV[(long long)(b * NF + nn) * QD + 1024 + h * 64 + d];
        sv[idx] = v;
    }
    __syncthreads();
    int d = t & 63, r0 = t >> 6;
    for (int rr = r0; rr < 128; rr += 4) {
        float a = 0.f;
        #pragma unroll
        for (int k = 0; k < KER; k++) a += sv[(rr + k) * 64 + d] * sw[k];
        long long o = ((long long)bh * NF + n0 + rr) * DH + d;
        g_OH[o] += a;
    }
}

// ------------------------- final LN + head ----------------------------------
__global__ void __launch_bounds__(256) final_k(const float* __restrict__ fg, const float* __restrict__ fb,
                                               const float* __restrict__ w2, const float* __restrict__ b2,
                                               float* __restrict__ out)
{
    int b = blockIdx.x;
    const float* x = g_X + (long long)b * NF * DIMM;
    int t = threadIdx.x;
    float v0 = x[t], v1 = x[t + 256];
    float mu  = blockReduce(v0 + v1, false) * (1.f / 512.f);
    float d0 = v0 - mu, d1 = v1 - mu;
    float var = blockReduce(d0 * d0 + d1 * d1, false) * (1.f / 512.f);
    float inv = rsqrtf(var + 1e-5f);
    float n0 = d0 * inv * fg[t]       + fb[t];
    float n1 = d1 * inv * fg[t + 256] + fb[t + 256];
    float p0 = n0 * w2[2 * t]     + n1 * w2[2 * (t + 256)];
    float p1 = n0 * w2[2 * t + 1] + n1 * w2[2 * (t + 256) + 1];
    p0 = blockReduce(p0, false);
    p1 = blockReduce(p1, false);
    if (t == 0) {
        out[b * 2 + 0] = p0 + b2[0];
        out[b * 2 + 1] = p1 + b2[1];
    }
}

// ------------------------- host orchestration -------------------------------
static inline void gemm64(int transB, int M, int N, int K,
                          const float* A, int lda, long long sA1, long long sA2, long long sA3,
                          const float* Bp, int ldb, long long sB1, long long sB2, long long sB3,
                          float* C, int ldc, long long sC1, long long sC2, long long sC3,
                          int SPLIT, int batchZ, float alpha, int ep, const float* bias,
                          int bmode, float bdiag,
                          const float2* rsA, long long rs1, long long rs2, int aexp)
{
    dim3 g(N >> 6, (M + 63) >> 6, batchZ);
    if (transB)
        gemm64_k<1><<<g, 256>>>(M, N, K, A, lda, sA1, sA2, sA3, Bp, ldb, sB1, sB2, sB3,
                                C, ldc, sC1, sC2, sC3, SPLIT, alpha, ep, bias, bmode, bdiag,
                                rsA, rs1, rs2, aexp);
    else
        gemm64_k<0><<<g, 256>>>(M, N, K, A, lda, sA1, sA2, sA3, Bp, ldb, sB1, sB2, sB3,
                                C, ldc, sC1, sC2, sC3, SPLIT, alpha, ep, bias, bmode, bdiag,
                                rsA, rs1, rs2, aexp);
}

static inline void mgemm2(int M, int N, int K,
                          const float* A, int lda, long long sA1, long long sA2, int amode,
                          const float* BT, int ldbt, long long sBT1, long long sBT2,
                          float* C, int ldc, long long sC1, long long sC2,
                          int batch, int ep, const float* bias)
{
    cudaFuncSetAttribute(mgemm2_k, cudaFuncAttributeMaxDynamicSharedMemorySize, 98304);
    dim3 g(N >> 8, (M + 127) >> 7, batch);
    mgemm2_k<<<g, 256, 98304>>>(M, K, A, lda, sA1, sA2, amode, BT, ldbt, sBT1, sBT2,
                                C, ldc, sC1, sC2, ep, bias);
}

static inline void pgemm(const float* A, const float* B, float* C,
                         float alpha, int bmode, float bd)
{
    cudaFuncSetAttribute(pgemm_k, cudaFuncAttributeMaxDynamicSharedMemorySize, 61440);
    dim3 g(2, 4, NBH);
    pgemm_k<<<g, 256, 61440>>>(A, B, C, alpha, bmode, bd);
}

extern "C" void kernel_launch(void* const* d_in, const int* in_sizes, int n_in,
                              void* d_out, int out_size)
{
    const float* h_in  = (const float*)d_in[0];
    const float* w1    = (const float*)d_in[1];
    const float* b1    = (const float*)d_in[2];
    const float* clst  = (const float*)d_in[3];
    const float* ln_g  = (const float*)d_in[4];
    const float* ln_b  = (const float*)d_in[5];
    const float* wqkv  = (const float*)d_in[6];
    const float* wout  = (const float*)d_in[7];
    const float* bout  = (const float*)d_in[8];
    const float* cw    = (const float*)d_in[9];
    const float* fg    = (const float*)d_in[10];
    const float* fb    = (const float*)d_in[11];
    const float* w2    = (const float*)d_in[12];
    const float* b2    = (const float*)d_in[13];
    float* out = (float*)d_out;

    float *X, *XN, *QKV, *QL, *KL, *S1, *S2, *S3, *Z, *Z2, *P, *T, *T2, *AV, *AVp, *ZAV, *OH, *WT;
    float2 *RS1, *RS3;
    cudaGetSymbolAddress((void**)&X,   g_X);
    cudaGetSymbolAddress((void**)&XN,  g_XN);
    cudaGetSymbolAddress((void**)&QKV, g_QKV);
    cudaGetSymbolAddress((void**)&QL,  g_QL);
    cudaGetSymbolAddress((void**)&KL,  g_KL);
    cudaGetSymbolAddress((void**)&S1,  g_S1);
    cudaGetSymbolAddress((void**)&S2,  g_S2);
    cudaGetSymbolAddress((void**)&S3,  g_S3);
    cudaGetSymbolAddress((void**)&Z,   g_Zb);
    cudaGetSymbolAddress((void**)&Z2,  g_Z2b);
    cudaGetSymbolAddress((void**)&P,   g_Pb);
    cudaGetSymbolAddress((void**)&T,   g_Tb);
    cudaGetSymbolAddress((void**)&T2,  g_T2b);
    cudaGetSymbolAddress((void**)&AV,  g_AV);
    cudaGetSymbolAddress((void**)&AVp, g_AVp);
    cudaGetSymbolAddress((void**)&ZAV, g_ZAV);
    cudaGetSymbolAddress((void**)&OH,  g_OH);
    cudaGetSymbolAddress((void**)&WT,  g_WT);
    cudaGetSymbolAddress((void**)&RS1, g_RS1);
    cudaGetSymbolAddress((void**)&RS3, g_RS3);

    const long long SQb = (long long)NF * QD;
    const long long S2s = (long long)LM * LM;
    const long long S1s = (long long)NF * LM;
    const long long AVs = (long long)LM * DH;
    const long long OHs = (long long)NF * DH;

    // #1: all weight transposes + cls fill (one launch)
    transAll_k<<<2564, 256>>>(w1, wqkv, wout, clst);

    // #2: input projection
    mgemm2(NB * 8191, DIMM, 1024, h_in, 1024, 0, 0, 0, WT + OW1, 1024, 0, 0,
           X, DIMM, 0, 0, 1, EP_RELU_REMAP, b1);

    for (int L = 0; L < 2; L++) {
        // #3 (L=0): layernorm
        ln_k<<<TOT, 256>>>(X, XN, ln_g + L * DIMM, ln_b + L * DIMM);

        // #4 (L=0): qkv GEMM  <-- ncu capture slot
        mgemm2(TOT, QD, DIMM, XN, DIMM, 0, 0, 0, WT + OQKV(L), DIMM, 0, 0,
               QKV, QD, 0, 0, 1, EP_SCALEQ, nullptr);

        landmark_k<<<NBH * LM, 64>>>();

        // sim2 = QL @ KL^T, softmax (materialized: pinv consumes the matrix)
        mgemm2(LM, LM, DH, QL, DH, 8 * AVs, AVs, 0, KL, DH, 8 * AVs, AVs,
               S2, LM, 8 * S2s, S2s, NBH, EP_NONE, nullptr);
        softmax256_k<<<NBH * LM / 8, 256>>>(S2);

        // Moore-Penrose pinv of S2 -> Z
        reset_k<<<1, 1>>>();
        scalemax_k<<<NBH, 256>>>();
        zinit_k<<<4096, 256>>>();
        for (int it = 0; it < 6; it++) {
            float* Zin  = (it & 1) ? Z2 : Z;
            float* Zout = (it & 1) ? Z  : Z2;
            pgemm(S2, Zin, P, 1.f, 0, 0.f);
            pgemm(P, P, T2, 1.f, 1, 7.f);
            pgemm(P, T2, T, 1.f, 1, 15.f);
            pgemm(Zin, T, Zout, 0.25f, 1, 13.f);
        }

        // sim1 = Q @ KL^T (raw) + row stats
        mgemm2(NF, LM, DH, QKV, QD, SQb, 64, 0, KL, DH, 8 * AVs, AVs,
               S1, LM, 8 * S1s, S1s, NBH, EP_NONE, nullptr);
        rowstat256_k<<<NBH * NF / 8, 256>>>(S1, RS1);

        // sim3 = QL @ K^T (raw) + row stats
        mgemm2(LM, NF, DH, QL, DH, 8 * AVs, AVs, 0, QKV + 512, QD, SQb, 64,
               S3, NF, 8 * S1s, S1s, NBH, EP_NONE, nullptr);
        rowstatbig_k<<<NBH * LM, 256, NF * 4>>>(S3, RS3, NF);

        // AV = softmax(sim3) @ V  (exp fused in A-load; split-K by 8)
        gemm64(0, LM, DH, NF / KSPL,
               S3, NF, 8 * S1s, S1s, 1024,
               QKV + 1024, QD, SQb, 64, 1024LL * QD,
               AVp, DH, 64 * AVs, 8 * AVs, AVs,
               KSPL, NBH * KSPL, 1.f, EP_NONE, nullptr, 0, 0.f,
               RS3, 8 * LM, LM, 1);
        avreduce_k<<<1024, 256>>>();

        // ZAV = Z @ AV
        gemm64(0, LM, DH, LM, Z, LM, 8 * S2s, S2s, 0, AV, DH, 8 * AVs, AVs, 0,
               ZAV, DH, 8 * AVs, AVs, 0, 1, NBH, 1.f, EP_NONE, nullptr, 0, 0.f,
               RS3, 0, 0, 0);
        // OH = softmax(sim1) @ ZAV  (exp fused in A-load)
        gemm64(0, NF, DH, LM, S1, LM, 8 * S1s, S1s, 0, ZAV, DH, 8 * AVs, AVs, 0,
               OH, DH, 8 * OHs, OHs, 0, 1, NBH, 1.f, EP_NONE, nullptr, 0, 0.f,
               RS1, 8LL * NF, NF, 1);

        // OH += depthwise conv residual of V
        { dim3 g(NF / 128, NBH); conv_k<<<g, 256>>>(cw + L * NH * KER); }

        // X += OH(head-layout) @ Wout + bout
        mgemm2(TOT, DIMM, DIMM, OH, 0, 0, 0, 1, WT + OOUT(L), DIMM, 0, 0,
               X, DIMM, 0, 0, 1, EP_ADDBIAS, bout + L * DIMM);
    }

    final_k<<<NB, 256>>>(fg, fb, w2, b2, out);
}

// round 9
// speedup vs baseline: 2.5008x; 1.0157x over previous
#include <cuda_runtime.h>

#define NB   2
#define NF   8192
#define DIMM 512
#define NH   8
#define DH   64
#define LM   256
#define QD   1536
#define TOT  (NB*NF)    // 16384
#define NBH  (NB*NH)    // 16
#define KER  33
#define KSPL 8

// ------------------------- scratch (device globals, no allocs) -------------
__device__ float g_X  [TOT*DIMM];
__device__ float g_XN [TOT*DIMM];
__device__ float g_QKV[TOT*QD];
__device__ float g_QL [NBH*LM*DH];
__device__ float g_KL [NBH*LM*DH];
__device__ float g_S1 [NBH*NF*LM];
__device__ float g_S3 [NBH*LM*NF];
__device__ float g_S2 [NBH*LM*LM];
__device__ float g_Zb [NBH*LM*LM];
__device__ float g_Z2b[NBH*LM*LM];
__device__ float g_Pb [NBH*LM*LM];
__device__ float g_Tb [NBH*LM*LM];
__device__ float g_T2b[NBH*LM*LM];
__device__ float g_AV [NBH*LM*DH];
__device__ float g_AVp[NBH*KSPL*LM*DH];
__device__ float g_ZAV[NBH*LM*DH];
__device__ float g_OH [NBH*NF*DH];
__device__ float g_WT [2621440];
__device__ float2 g_RS1[NBH*NF];
__device__ float2 g_RS3[NBH*LM];
__device__ unsigned int g_scale[2];

enum { EP_NONE = 0, EP_RELU_REMAP = 1, EP_SCALEQ = 2, EP_ADDBIAS = 3 };

#define OW1   0
#define OQKV(L) (524288 + (L) * 786432)
#define OOUT(L) (2097152 + (L) * 262144)

__device__ __forceinline__ unsigned f2tf32(float f) {
    unsigned r;
    asm("cvt.rna.tf32.f32 %0, %1;" : "=r"(r) : "f"(f));
    return r;
}
__device__ __forceinline__ float tf32f(float f) {
    return __uint_as_float(f2tf32(f));
}

#define MMA_TF32(d, a, b) \
    asm volatile("mma.sync.aligned.m16n8k8.row.col.f32.tf32.tf32.f32 " \
        "{%0,%1,%2,%3}, {%4,%5,%6,%7}, {%8,%9}, {%0,%1,%2,%3};" \
        : "+f"((d)[0]), "+f"((d)[1]), "+f"((d)[2]), "+f"((d)[3]) \
        : "r"((a)[0]), "r"((a)[1]), "r"((a)[2]), "r"((a)[3]), \
          "r"((b)[0]), "r"((b)[1]))

// ------------------- fused transposes + cls (ONE launch) --------------------
__device__ __forceinline__ void doTrans(const float* __restrict__ src,
                                        float* __restrict__ dst,
                                        int K, int N, int kt, int nt)
{
    __shared__ float t[32][33];
    int kb = kt << 5, nb = nt << 5;
    int x = threadIdx.x & 31, y = threadIdx.x >> 5;
    #pragma unroll
    for (int i = 0; i < 32; i += 8)
        t[y + i][x] = src[(long long)(kb + y + i) * N + nb + x];
    __syncthreads();
    #pragma unroll
    for (int i = 0; i < 32; i += 8)
        dst[(long long)(nb + y + i) * K + kb + x] = t[x][y + i];
}

__global__ void __launch_bounds__(256) transAll_k(
    const float* __restrict__ w1, const float* __restrict__ wqkv,
    const float* __restrict__ wout, const float* __restrict__ clst)
{
    int b = blockIdx.x;
    if (b < 512) {
        doTrans(w1, g_WT + OW1, 1024, DIMM, b & 31, b >> 5);
    } else if (b < 2048) {
        int L = (b - 512) / 768, bb = (b - 512) % 768;
        doTrans(wqkv + (long long)L * DIMM * QD, g_WT + OQKV(L), DIMM, QD, bb & 15, bb >> 4);
    } else if (b < 2560) {
        int L = (b - 2048) / 256, bb = (b - 2048) % 256;
        doTrans(wout + (long long)L * DIMM * DIMM, g_WT + OOUT(L), DIMM, DIMM, bb & 15, bb >> 4);
    } else {
        int idx = (b - 2560) * 256 + threadIdx.x;
        int bb = idx >> 9, c = idx & 511;
        g_X[(long long)bb * NF * DIMM + c] = clst[c];
    }
}

// ===================== mgemm2: cp.async + ldmatrix tf32, 128x128, 2 CTA/SM ==
__device__ __forceinline__ void cp16(unsigned dst, const void* src, int nbytes) {
    asm volatile("cp.async.cg.shared.global [%0], [%1], 16, %2;"
                 :: "r"(dst), "l"(src), "r"(nbytes) : "memory");
}

__global__ void __launch_bounds__(256, 2) mgemm2_k(
    int M, int K,
    const float* __restrict__ A, int lda, long long sA1, long long sA2, int amode,
    const float* __restrict__ BT, int ldbt, long long sBT1, long long sBT2,
    float* __restrict__ C, int ldc, long long sC1, long long sC2,
    int ep, const float* __restrict__ bias)
{
    extern __shared__ float smem[];   // 2 stages x (A 16KB + B 16KB) = 64KB
    int tid = threadIdx.x;
    int lane = tid & 31, wid = tid >> 5;
    int wm = wid & 3, wn = wid >> 2;            // 4 m-groups(32r), 2 n-groups(64c)
    int row0 = blockIdx.y << 7, col0 = blockIdx.x << 7;
    int z = blockIdx.z;
    A  += (long long)(z >> 3) * sA1 + (long long)(z & 7) * sA2;
    BT += (long long)(z >> 3) * sBT1 + (long long)(z & 7) * sBT2;
    C  += (long long)(z >> 3) * sC1 + (long long)(z & 7) * sC2;

    unsigned sbase;
    asm("{ .reg .u64 t; cvta.to.shared.u64 t, %1; cvt.u32.u64 %0, t; }"
        : "=r"(sbase) : "l"(smem));

    float acc[2][8][4];
    #pragma unroll
    for (int mi = 0; mi < 2; mi++)
        #pragma unroll
        for (int ni = 0; ni < 8; ni++)
            #pragma unroll
            for (int q = 0; q < 4; q++) acc[mi][ni][q] = 0.f;

    auto fill = [&](int s, int k0) {
        unsigned Ab = sbase + s * 32768u;
        unsigned Bb = Ab + 16384u;
        #pragma unroll
        for (int it = 0; it < 4; it++) {
            int idx = (it << 8) + tid;
            int q = idx & 7, r = idx >> 3;
            int gr = row0 + r;
            const float* src;
            int nb = 16;
            if (amode == 0) {
                int gra = gr < M ? gr : (M - 1);
                if (gr >= M) nb = 0;
                src = A + (long long)gra * lda + k0 + (q << 2);
            } else {
                int k = k0 + (q << 2);
                int h = k >> 6, d = k & 63;
                src = A + ((((long long)(gr >> 13) << 3) + h) * 8192 + (gr & 8191)) * 64 + d;
            }
            unsigned dst = Ab + (((r << 5) + ((q ^ (r & 7)) << 2)) << 2);
            cp16(dst, src, nb);
        }
        #pragma unroll
        for (int it = 0; it < 4; it++) {
            int idx = (it << 8) + tid;
            int q = idx & 7, n = idx >> 3;
            const float* src = BT + (long long)(col0 + n) * ldbt + k0 + (q << 2);
            unsigned dst = Bb + (((n << 5) + ((q ^ (n & 7)) << 2)) << 2);
            cp16(dst, src, 16);
        }
        asm volatile("cp.async.commit_group;" ::: "memory");
    };

    auto compute = [&](int s) {
        unsigned Ab = sbase + s * 32768u;
        unsigned Bb = Ab + 16384u;
        int j = lane >> 3, rho = lane & 7;
        #pragma unroll
        for (int kt = 0; kt < 4; kt++) {
            unsigned a[2][4];
            #pragma unroll
            for (int mi = 0; mi < 2; mi++) {
                int row = (wm << 5) + (mi << 4) + ((j & 1) << 3) + rho;
                int quad = (kt << 1) + (j >> 1);
                unsigned ad = Ab + (((row << 5) + ((quad ^ (row & 7)) << 2)) << 2);
                asm volatile("ldmatrix.sync.aligned.m8n8.x4.shared.b16 {%0,%1,%2,%3}, [%4];"
                    : "=r"(a[mi][0]), "=r"(a[mi][1]), "=r"(a[mi][2]), "=r"(a[mi][3])
                    : "r"(ad));
            }
            unsigned b[8][2];
            #pragma unroll
            for (int np = 0; np < 4; np++) {
                int row = (((wn << 3) + (np << 1) + (j >> 1)) << 3) + rho;
                int quad = (kt << 1) + (j & 1);
                unsigned bd = Bb + (((row << 5) + ((quad ^ (row & 7)) << 2)) << 2);
                asm volatile("ldmatrix.sync.aligned.m8n8.x4.shared.b16 {%0,%1,%2,%3}, [%4];"
                    : "=r"(b[np * 2][0]), "=r"(b[np * 2][1]),
                      "=r"(b[np * 2 + 1][0]), "=r"(b[np * 2 + 1][1])
                    : "r"(bd));
            }
            #pragma unroll
            for (int mi = 0; mi < 2; mi++)
                #pragma unroll
                for (int ni = 0; ni < 8; ni++)
                    MMA_TF32(acc[mi][ni], a[mi], b[ni]);
        }
    };

    fill(0, 0);
    int nch = K >> 5;
    for (int ch = 0; ch < nch; ch++) {
        if (ch + 1 < nch) {
            fill((ch + 1) & 1, (ch + 1) << 5);
            asm volatile("cp.async.wait_group 1;" ::: "memory");
        } else {
            asm volatile("cp.async.wait_group 0;" ::: "memory");
        }
        __syncthreads();
        compute(ch & 1);
        __syncthreads();
    }

    int rb = row0 + (wm << 5) + (lane >> 2);
    int cb = col0 + (wn << 6) + ((lane & 3) << 1);
    #pragma unroll
    for (int mi = 0; mi < 2; mi++) {
        #pragma unroll
        for (int half = 0; half < 2; half++) {
            int r = rb + (mi << 4) + (half << 3);
            if (r >= M) continue;
            #pragma unroll
            for (int ni = 0; ni < 8; ni++) {
                int c = cb + (ni << 3);
                float v0 = acc[mi][ni][half * 2];
                float v1 = acc[mi][ni][half * 2 + 1];
                if (ep == EP_RELU_REMAP) {
                    long long o = (long long)(r + r / 8191 + 1) * ldc + c;
                    v0 = fmaxf(v0 + bias[c], 0.f);
                    v1 = fmaxf(v1 + bias[c + 1], 0.f);
                    *(float2*)(C + o) = make_float2(v0, v1);
                } else if (ep == EP_SCALEQ) {
                    float sc = (c < 512) ? 0.125f : 1.0f;
                    *(float2*)(C + (long long)r * ldc + c) = make_float2(v0 * sc, v1 * sc);
                } else if (ep == EP_ADDBIAS) {
                    long long o = (long long)r * ldc + c;
                    float2 old = *(float2*)(C + o);
                    *(float2*)(C + o) = make_float2(old.x + v0 + bias[c],
                                                    old.y + v1 + bias[c + 1]);
                } else {
                    *(float2*)(C + (long long)r * ldc + c) = make_float2(v0, v1);
                }
            }
        }
    }
}

// ===================== pgemm: 3xTF32 batched (pinv), 64x128 CTA =============
__global__ void __launch_bounds__(256, 2) pgemm_k(
    const float* __restrict__ Ag, const float* __restrict__ Bg,
    float* __restrict__ Cg, float alpha, int bmode, float bd)
{
    extern __shared__ float ps[];   // 2 stages x 7680 floats = 60KB
    int tid = threadIdx.x;
    int lane = tid & 31, wid = tid >> 5;
    int wm = wid & 3, wn = wid >> 2;
    int row0 = blockIdx.y << 6, col0 = blockIdx.x << 7;
    long long zo = (long long)blockIdx.z << 16;
    Ag += zo; Bg += zo; Cg += zo;

    float acc[8][4];
    #pragma unroll
    for (int ni = 0; ni < 8; ni++)
        #pragma unroll
        for (int q = 0; q < 4; q++) acc[ni][q] = 0.f;

    int ar = tid >> 2, aq = tid & 3;
    int bn = tid & 127, bkh = tid >> 7;

    float4 pa;
    float pbv[8];

    auto fetch = [&](int k0) {
        pa = *(const float4*)(Ag + ((long long)(row0 + ar) << 8) + k0 + (aq << 2));
        #pragma unroll
        for (int j = 0; j < 8; j++) {
            int gk = k0 + (bkh << 3) + j;
            int gn = col0 + bn;
            float v = Bg[((long long)gk << 8) + gn];
            if (bmode) v = (gk == gn ? bd : 0.f) - v;
            pbv[j] = v;
        }
    };

    auto stash = [&](int s) {
        float* Sb = ps + s * 7680;
        float4 h, l;
        h.x = tf32f(pa.x); h.y = tf32f(pa.y); h.z = tf32f(pa.z); h.w = tf32f(pa.w);
        l.x = tf32f(pa.x - h.x); l.y = tf32f(pa.y - h.y);
        l.z = tf32f(pa.z - h.z); l.w = tf32f(pa.w - h.w);
        *(float4*)&Sb[ar * 20 + (aq << 2)] = h;
        *(float4*)&Sb[1280 + ar * 20 + (aq << 2)] = l;
        float4 bh0, bh1, bl0, bl1;
        bh0.x = tf32f(pbv[0]); bh0.y = tf32f(pbv[1]); bh0.z = tf32f(pbv[2]); bh0.w = tf32f(pbv[3]);
        bh1.x = tf32f(pbv[4]); bh1.y = tf32f(pbv[5]); bh1.z = tf32f(pbv[6]); bh1.w = tf32f(pbv[7]);
        bl0.x = tf32f(pbv[0] - bh0.x); bl0.y = tf32f(pbv[1] - bh0.y);
        bl0.z = tf32f(pbv[2] - bh0.z); bl0.w = tf32f(pbv[3] - bh0.w);
        bl1.x = tf32f(pbv[4] - bh1.x); bl1.y = tf32f(pbv[5] - bh1.y);
        bl1.z = tf32f(pbv[6] - bh1.z); bl1.w = tf32f(pbv[7] - bh1.w);
        *(float4*)&Sb[2560 + bn * 20 + (bkh << 3)] = bh0;
        *(float4*)&Sb[2560 + bn * 20 + (bkh << 3) + 4] = bh1;
        *(float4*)&Sb[5120 + bn * 20 + (bkh << 3)] = bl0;
        *(float4*)&Sb[5120 + bn * 20 + (bkh << 3) + 4] = bl1;
    };

    auto compute = [&](int s) {
        const float* Sb = ps + s * 7680;
        int g = lane >> 2, t = lane & 3;
        #pragma unroll
        for (int kt = 0; kt < 2; kt++) {
            int kb = kt << 3;
            int m = (wm << 4) + g;
            unsigned ah[4], al[4];
            ah[0] = __float_as_uint(Sb[m * 20 + kb + t]);
            ah[1] = __float_as_uint(Sb[(m + 8) * 20 + kb + t]);
            ah[2] = __float_as_uint(Sb[m * 20 + kb + t + 4]);
            ah[3] = __float_as_uint(Sb[(m + 8) * 20 + kb + t + 4]);
            al[0] = __float_as_uint(Sb[1280 + m * 20 + kb + t]);
            al[1] = __float_as_uint(Sb[1280 + (m + 8) * 20 + kb + t]);
            al[2] = __float_as_uint(Sb[1280 + m * 20 + kb + t + 4]);
            al[3] = __float_as_uint(Sb[1280 + (m + 8) * 20 + kb + t + 4]);
            #pragma unroll
            for (int ni = 0; ni < 8; ni++) {
                int n = (wn << 6) + (ni << 3) + g;
                unsigned bh[2], bl[2];
                bh[0] = __float_as_uint(Sb[2560 + n * 20 + kb + t]);
                bh[1] = __float_as_uint(Sb[2560 + n * 20 + kb + t + 4]);
                bl[0] = __float_as_uint(Sb[5120 + n * 20 + kb + t]);
                bl[1] = __float_as_uint(Sb[5120 + n * 20 + kb + t + 4]);
                MMA_TF32(acc[ni], ah, bh);
                MMA_TF32(acc[ni], ah, bl);
                MMA_TF32(acc[ni], al, bh);
            }
        }
    };

    fetch(0);
    for (int ch = 0; ch < 16; ch++) {
        stash(ch & 1);
        __syncthreads();
        if (ch < 15) fetch((ch + 1) << 4);
        compute(ch & 1);
        __syncthreads();
    }

    int g = lane >> 2, t = lane & 3;
    #pragma unroll
    for (int half = 0; half < 2; half++) {
        int r = row0 + (wm << 4) + (half << 3) + g;
        #pragma unroll
        for (int ni = 0; ni < 8; ni++) {
            int c = col0 + (wn << 6) + (ni << 3) + (t << 1);
            *(float2*)(Cg + ((long long)r << 8) + c) =
                make_float2(acc[ni][half * 2] * alpha, acc[ni][half * 2 + 1] * alpha);
        }
    }
}

// ------------------------- reductions --------------------------------------
__device__ __forceinline__ float blockReduce(float v, bool domax) {
    __shared__ float sh[32];
    __syncthreads();
    #pragma unroll
    for (int o = 16; o > 0; o >>= 1) {
        float w = __shfl_down_sync(0xffffffffu, v, o);
        v = domax ? fmaxf(v, w) : v + w;
    }
    int lane = threadIdx.x & 31, wid = threadIdx.x >> 5;
    if (lane == 0) sh[wid] = v;
    __syncthreads();
    int nw = (blockDim.x + 31) >> 5;
    if (wid == 0) {
        v = (lane < nw) ? sh[lane] : (domax ? -1e30f : 0.f);
        #pragma unroll
        for (int o = 16; o > 0; o >>= 1) {
            float w = __shfl_down_sync(0xffffffffu, v, o);
            v = domax ? fmaxf(v, w) : v + w;
        }
        if (lane == 0) sh[0] = v;
    }
    __syncthreads();
    return sh[0];
}

// ===================== 64x64x16 SIMT GEMM (AV/ZAV/OH), exp-fused A ==========
template<int TRANSB>
__global__ void __launch_bounds__(256) gemm64_k(
    int M, int N, int K,
    const float* __restrict__ A, int lda, long long sA1, long long sA2, long long sA3,
    const float* __restrict__ Bp, int ldb, long long sB1, long long sB2, long long sB3,
    float* __restrict__ C, int ldc, long long sC1, long long sC2, long long sC3,
    int SPLIT, float alpha, int ep, const float* __restrict__ bias,
    int bmode, float bdiag,
    const float2* __restrict__ rsA, long long rs1, long long rs2, int aexp)
{
    __shared__ float As[2][16 * 68];
    __shared__ float Bs[2][16 * 68];
    int z = blockIdx.z;
    int s  = z % SPLIT;
    int bh = z / SPLIT;
    int hh = bh & 7, bb = bh >> 3;
    A  += (long long)bb * sA1 + (long long)hh * sA2 + (long long)s * sA3;
    Bp += (long long)bb * sB1 + (long long)hh * sB2 + (long long)s * sB3;
    C  += (long long)bb * sC1 + (long long)hh * sC2 + (long long)s * sC3;
    rsA += bb * rs1 + hh * rs2;
    int row0 = blockIdx.y << 6;
    int col0 = blockIdx.x << 6;
    int tid = threadIdx.x;
    int tx = tid & 15, ty = tid >> 4;

    int a_r  = tid >> 2;
    int a_kk = (tid & 3) << 2;
    int bn_kk = tid >> 4;
    int bn_n  = (tid & 15) << 2;
    int bt_n  = tid >> 2;
    int bt_kk = (tid & 3) << 2;

    float acc[4][4];
    #pragma unroll
    for (int i = 0; i < 4; i++)
        #pragma unroll
        for (int j = 0; j < 4; j++) acc[i][j] = 0.f;

    float4 pa, pb;

    auto fetch = [&](int k0) {
        int gr = row0 + a_r;
        pa = make_float4(0.f, 0.f, 0.f, 0.f);
        if (gr < M) {
            pa = *(const float4*)(A + (long long)gr * lda + k0 + a_kk);
            if (aexp) {
                float2 st = rsA[gr];
                pa.x = __expf(pa.x - st.x) * st.y;
                pa.y = __expf(pa.y - st.x) * st.y;
                pa.z = __expf(pa.z - st.x) * st.y;
                pa.w = __expf(pa.w - st.x) * st.y;
            }
        }
        if (!TRANSB) {
            pb = *(const float4*)(Bp + (long long)(k0 + bn_kk) * ldb + col0 + bn_n);
        } else {
            pb = *(const float4*)(Bp + (long long)(col0 + bt_n) * ldb + k0 + bt_kk);
        }
    };

    auto stash = [&](int b, int k0) {
        float* Ab = As[b];
        Ab[(a_kk + 0) * 68 + a_r] = pa.x;
        Ab[(a_kk + 1) * 68 + a_r] = pa.y;
        Ab[(a_kk + 2) * 68 + a_r] = pa.z;
        Ab[(a_kk + 3) * 68 + a_r] = pa.w;
        float* Bb = Bs[b];
        if (!TRANSB) {
            float4 v = pb;
            if (bmode) {
                int gk = k0 + bn_kk, gn = col0 + bn_n;
                v.x = (gk == gn + 0 ? bdiag : 0.f) - v.x;
                v.y = (gk == gn + 1 ? bdiag : 0.f) - v.y;
                v.z = (gk == gn + 2 ? bdiag : 0.f) - v.z;
                v.w = (gk == gn + 3 ? bdiag : 0.f) - v.w;
            }
            *(float4*)&Bb[bn_kk * 68 + bn_n] = v;
        } else {
            Bb[(bt_kk + 0) * 68 + bt_n] = pb.x;
            Bb[(bt_kk + 1) * 68 + bt_n] = pb.y;
            Bb[(bt_kk + 2) * 68 + bt_n] = pb.z;
            Bb[(bt_kk + 3) * 68 + bt_n] = pb.w;
        }
    };

    fetch(0);
    stash(0, 0);
    __syncthreads();

    int nt = K >> 4;
    for (int t = 0; t < nt; t++) {
        int buf = t & 1;
        if (t + 1 < nt) fetch((t + 1) << 4);
        const float* Ab = As[buf];
        const float* Bb = Bs[buf];
        #pragma unroll
        for (int kk = 0; kk < 16; kk++) {
            float4 a = *(const float4*)&Ab[kk * 68 + (ty << 2)];
            float4 b = *(const float4*)&Bb[kk * 68 + (tx << 2)];
            acc[0][0] += a.x * b.x; acc[0][1] += a.x * b.y; acc[0][2] += a.x * b.z; acc[0][3] += a.x * b.w;
            acc[1][0] += a.y * b.x; acc[1][1] += a.y * b.y; acc[1][2] += a.y * b.z; acc[1][3] += a.y * b.w;
            acc[2][0] += a.z * b.x; acc[2][1] += a.z * b.y; acc[2][2] += a.z * b.z; acc[2][3] += a.z * b.w;
            acc[3][0] += a.w * b.x; acc[3][1] += a.w * b.y; acc[3][2] += a.w * b.z; acc[3][3] += a.w * b.w;
        }
        if (t + 1 < nt) stash(buf ^ 1, (t + 1) << 4);
        __syncthreads();
    }

    #pragma unroll
    for (int i = 0; i < 4; i++) {
        int r = row0 + (ty << 2) + i;
        if (r >= M) continue;
        #pragma unroll
        for (int j = 0; j < 4; j++) {
            int c = col0 + (tx << 2) + j;
            C[(long long)r * ldc + c] = alpha * acc[i][j];
        }
    }
}

// ------------------------- layernorm (rows of 512) --------------------------
__global__ void __launch_bounds__(256) ln_k(const float* __restrict__ X, float* __restrict__ Y,
                                            const float* __restrict__ g, const float* __restrict__ b)
{
    long long row = blockIdx.x;
    const float* x = X + row * DIMM;
    float* y = Y + row * DIMM;
    int t = threadIdx.x;
    float v0 = x[t], v1 = x[t + 256];
    float mu  = blockReduce(v0 + v1, false) * (1.f / 512.f);
    float d0 = v0 - mu, d1 = v1 - mu;
    float var = blockReduce(d0 * d0 + d1 * d1, false) * (1.f / 512.f);
    float inv = rsqrtf(var + 1e-5f);
    y[t]       = d0 * inv * g[t]       + b[t];
    y[t + 256] = d1 * inv * g[t + 256] + b[t + 256];
}

// ------------------------- softmax (S2 only) --------------------------------
__global__ void __launch_bounds__(256) softmax256_k(float* __restrict__ S)
{
    long long row = ((long long)blockIdx.x << 3) + (threadIdx.x >> 5);
    int lane = threadIdx.x & 31;
    float* s = S + (row << 8);
    float4 va = *(float4*)(s + (lane << 3));
    float4 vb = *(float4*)(s + (lane << 3) + 4);
    float m = fmaxf(fmaxf(fmaxf(va.x, va.y), fmaxf(va.z, va.w)),
                    fmaxf(fmaxf(vb.x, vb.y), fmaxf(vb.z, vb.w)));
    #pragma unroll
    for (int o = 16; o > 0; o >>= 1) m = fmaxf(m, __shfl_xor_sync(0xffffffffu, m, o));
    va.x = __expf(va.x - m); va.y = __expf(va.y - m); va.z = __expf(va.z - m); va.w = __expf(va.w - m);
    vb.x = __expf(vb.x - m); vb.y = __expf(vb.y - m); vb.z = __expf(vb.z - m); vb.w = __expf(vb.w - m);
    float sum = va.x + va.y + va.z + va.w + vb.x + vb.y + vb.z + vb.w;
    #pragma unroll
    for (int o = 16; o > 0; o >>= 1) sum += __shfl_xor_sync(0xffffffffu, sum, o);
    float inv = 1.f / sum;
    va.x *= inv; va.y *= inv; va.z *= inv; va.w *= inv;
    vb.x *= inv; vb.y *= inv; vb.z *= inv; vb.w *= inv;
    *(float4*)(s + (lane << 3)) = va;
    *(float4*)(s + (lane << 3) + 4) = vb;
}

// ------------------------- row stats ----------------------------------------
__global__ void __launch_bounds__(256) rowstat256_k(const float* __restrict__ S,
                                                    float2* __restrict__ RS)
{
    long long row = ((long long)blockIdx.x << 3) + (threadIdx.x >> 5);
    int lane = threadIdx.x & 31;
    const float* s = S + (row << 8);
    float4 va = *(const float4*)(s + (lane << 3));
    float4 vb = *(const float4*)(s + (lane << 3) + 4);
    float m = fmaxf(fmaxf(fmaxf(va.x, va.y), fmaxf(va.z, va.w)),
                    fmaxf(fmaxf(vb.x, vb.y), fmaxf(vb.z, vb.w)));
    #pragma unroll
    for (int o = 16; o > 0; o >>= 1) m = fmaxf(m, __shfl_xor_sync(0xffffffffu, m, o));
    float sum = __expf(va.x - m) + __expf(va.y - m) + __expf(va.z - m) + __expf(va.w - m)
              + __expf(vb.x - m) + __expf(vb.y - m) + __expf(vb.z - m) + __expf(vb.w - m);
    #pragma unroll
    for (int o = 16; o > 0; o >>= 1) sum += __shfl_xor_sync(0xffffffffu, sum, o);
    if (lane == 0) RS[row] = make_float2(m, 1.f / sum);
}

__global__ void __launch_bounds__(256) rowstatbig_k(const float* __restrict__ S,
                                                    float2* __restrict__ RS, int cols)
{
    extern __shared__ float buf[];
    long long row = blockIdx.x;
    const float* s = S + row * cols;
    int t = threadIdx.x;
    float mx = -1e30f;
    for (int i = t; i < cols; i += 256) { float v = s[i]; buf[i] = v; mx = fmaxf(mx, v); }
    float bmax = blockReduce(mx, true);
    float sum = 0.f;
    for (int i = t; i < cols; i += 256) sum += __expf(buf[i] - bmax);
    float bsum = blockReduce(sum, false);
    if (t == 0) RS[row] = make_float2(bmax, 1.f / bsum);
}

// ------------------------- landmarks ----------------------------------------
__global__ void __launch_bounds__(64) landmark_k()
{
    int zz = blockIdx.x;
    int mi = zz & 255, bh = zz >> 8;
    int b = bh >> 3, h = bh & 7;
    int d = threadIdx.x;
    const float* base = g_QKV + (long long)(b * NF + mi * 32) * QD + h * 64 + d;
    float sq = 0.f, sk = 0.f;
    #pragma unroll 8
    for (int il = 0; il < 32; il++) {
        sq += base[(long long)il * QD];
        sk += base[(long long)il * QD + 512];
    }
    long long o = ((long long)bh * LM + mi) * DH + d;
    g_QL[o] = sq * (1.f / 32.f);
    g_KL[o] = sk * (1.f / 32.f);
}

// ------------------------- pinv helpers -------------------------------------
__global__ void reset_k() { g_scale[0] = 0u; g_scale[1] = 0u; }

__global__ void __launch_bounds__(256) scalemax_k()
{
    int z = blockIdx.x;
    int i = threadIdx.x;
    const float* S = g_S2 + ((long long)z << 16);
    float rs = 0.f, cs = 0.f;
    for (int j = 0; j < 256; j++) { rs += S[(i << 8) + j]; cs += S[(j << 8) + i]; }
    float rm = blockReduce(rs, true);
    float cm = blockReduce(cs, true);
    if (i == 0) {
        atomicMax(&g_scale[0], __float_as_uint(rm));
        atomicMax(&g_scale[1], __float_as_uint(cm));
    }
}

__global__ void __launch_bounds__(256) zinit_k()
{
    int idx = blockIdx.x * 256 + threadIdx.x;
    float inv = 1.0f / (__uint_as_float(g_scale[0]) * __uint_as_float(g_scale[1]));
    int z = idx >> 16, r = idx & 65535;
    int i = r >> 8, j = r & 255;
    g_Zb[((long long)z << 16) + (i << 8) + j] = g_S2[((long long)z << 16) + (j << 8) + i] * inv;
}

// ------------------------- split-K reduce for AV ----------------------------
__global__ void __launch_bounds__(256) avreduce_k()
{
    int idx = blockIdx.x * 256 + threadIdx.x;
    int bh = idx >> 14;
    int r  = idx & 16383;
    const float* p = g_AVp + ((long long)bh << 17);
    float s = 0.f;
    #pragma unroll
    for (int k = 0; k < KSPL; k++) s += p[(k << 14) + r];
    g_AV[idx] = s;
}

// ------------------------- depthwise conv residual --------------------------
__global__ void __launch_bounds__(256) conv_k(const float* __restrict__ cw)
{
    __shared__ float sv[160 * 64];
    __shared__ float sw[KER];
    int tile = blockIdx.x;
    int bh = blockIdx.y;
    int b = bh >> 3, h = bh & 7;
    int n0 = tile * 128;
    int t = threadIdx.x;
    if (t < KER) sw[t] = cw[h * KER + t];
    for (int idx = t; idx < 160 * 64; idx += 256) {
        int r = idx >> 6, d = idx & 63;
        int nn = n0 - 16 + r;
        float v = 0.f;
        if (nn >= 0 && nn < NF) v = g_QKV[(long long)(b * NF + nn) * QD + 1024 + h * 64 + d];
        sv[idx] = v;
    }
    __syncthreads();
    int d = t & 63, r0 = t >> 6;
    for (int rr = r0; rr < 128; rr += 4) {
        float a = 0.f;
        #pragma unroll
        for (int k = 0; k < KER; k++) a += sv[(rr + k) * 64 + d] * sw[k];
        long long o = ((long long)bh * NF + n0 + rr) * DH + d;
        g_OH[o] += a;
    }
}

// ------------------------- final LN + head ----------------------------------
__global__ void __launch_bounds__(256) final_k(const float* __restrict__ fg, const float* __restrict__ fb,
                                               const float* __restrict__ w2, const float* __restrict__ b2,
                                               float* __restrict__ out)
{
    int b = blockIdx.x;
    const float* x = g_X + (long long)b * NF * DIMM;
    int t = threadIdx.x;
    float v0 = x[t], v1 = x[t + 256];
    float mu  = blockReduce(v0 + v1, false) * (1.f / 512.f);
    float d0 = v0 - mu, d1 = v1 - mu;
    float var = blockReduce(d0 * d0 + d1 * d1, false) * (1.f / 512.f);
    float inv = rsqrtf(var + 1e-5f);
    float n0 = d0 * inv * fg[t]       + fb[t];
    float n1 = d1 * inv * fg[t + 256] + fb[t + 256];
    float p0 = n0 * w2[2 * t]     + n1 * w2[2 * (t + 256)];
    float p1 = n0 * w2[2 * t + 1] + n1 * w2[2 * (t + 256) + 1];
    p0 = blockReduce(p0, false);
    p1 = blockReduce(p1, false);
    if (t == 0) {
        out[b * 2 + 0] = p0 + b2[0];
        out[b * 2 + 1] = p1 + b2[1];
    }
}

// ------------------------- host orchestration -------------------------------
static inline void gemm64(int transB, int M, int N, int K,
                          const float* A, int lda, long long sA1, long long sA2, long long sA3,
                          const float* Bp, int ldb, long long sB1, long long sB2, long long sB3,
                          float* C, int ldc, long long sC1, long long sC2, long long sC3,
                          int SPLIT, int batchZ, float alpha, int ep, const float* bias,
                          int bmode, float bdiag,
                          const float2* rsA, long long rs1, long long rs2, int aexp)
{
    dim3 g(N >> 6, (M + 63) >> 6, batchZ);
    if (transB)
        gemm64_k<1><<<g, 256>>>(M, N, K, A, lda, sA1, sA2, sA3, Bp, ldb, sB1, sB2, sB3,
                                C, ldc, sC1, sC2, sC3, SPLIT, alpha, ep, bias, bmode, bdiag,
                                rsA, rs1, rs2, aexp);
    else
        gemm64_k<0><<<g, 256>>>(M, N, K, A, lda, sA1, sA2, sA3, Bp, ldb, sB1, sB2, sB3,
                                C, ldc, sC1, sC2, sC3, SPLIT, alpha, ep, bias, bmode, bdiag,
                                rsA, rs1, rs2, aexp);
}

static inline void mgemm2(int M, int N, int K,
                          const float* A, int lda, long long sA1, long long sA2, int amode,
                          const float* BT, int ldbt, long long sBT1, long long sBT2,
                          float* C, int ldc, long long sC1, long long sC2,
                          int batch, int ep, const float* bias)
{
    cudaFuncSetAttribute(mgemm2_k, cudaFuncAttributeMaxDynamicSharedMemorySize, 65536);
    dim3 g(N >> 7, (M + 127) >> 7, batch);
    mgemm2_k<<<g, 256, 65536>>>(M, K, A, lda, sA1, sA2, amode, BT, ldbt, sBT1, sBT2,
                                C, ldc, sC1, sC2, ep, bias);
}

static inline void pgemm(const float* A, const float* B, float* C,
                         float alpha, int bmode, float bd)
{
    cudaFuncSetAttribute(pgemm_k, cudaFuncAttributeMaxDynamicSharedMemorySize, 61440);
    dim3 g(2, 4, NBH);
    pgemm_k<<<g, 256, 61440>>>(A, B, C, alpha, bmode, bd);
}

extern "C" void kernel_launch(void* const* d_in, const int* in_sizes, int n_in,
                              void* d_out, int out_size)
{
    const float* h_in  = (const float*)d_in[0];
    const float* w1    = (const float*)d_in[1];
    const float* b1    = (const float*)d_in[2];
    const float* clst  = (const float*)d_in[3];
    const float* ln_g  = (const float*)d_in[4];
    const float* ln_b  = (const float*)d_in[5];
    const float* wqkv  = (const float*)d_in[6];
    const float* wout  = (const float*)d_in[7];
    const float* bout  = (const float*)d_in[8];
    const float* cw    = (const float*)d_in[9];
    const float* fg    = (const float*)d_in[10];
    const float* fb    = (const float*)d_in[11];
    const float* w2    = (const float*)d_in[12];
    const float* b2    = (const float*)d_in[13];
    float* out = (float*)d_out;

    float *X, *XN, *QKV, *QL, *KL, *S1, *S2, *S3, *Z, *Z2, *P, *T, *T2, *AV, *AVp, *ZAV, *OH, *WT;
    float2 *RS1, *RS3;
    cudaGetSymbolAddress((void**)&X,   g_X);
    cudaGetSymbolAddress((void**)&XN,  g_XN);
    cudaGetSymbolAddress((void**)&QKV, g_QKV);
    cudaGetSymbolAddress((void**)&QL,  g_QL);
    cudaGetSymbolAddress((void**)&KL,  g_KL);
    cudaGetSymbolAddress((void**)&S1,  g_S1);
    cudaGetSymbolAddress((void**)&S2,  g_S2);
    cudaGetSymbolAddress((void**)&S3,  g_S3);
    cudaGetSymbolAddress((void**)&Z,   g_Zb);
    cudaGetSymbolAddress((void**)&Z2,  g_Z2b);
    cudaGetSymbolAddress((void**)&P,   g_Pb);
    cudaGetSymbolAddress((void**)&T,   g_Tb);
    cudaGetSymbolAddress((void**)&T2,  g_T2b);
    cudaGetSymbolAddress((void**)&AV,  g_AV);
    cudaGetSymbolAddress((void**)&AVp, g_AVp);
    cudaGetSymbolAddress((void**)&ZAV, g_ZAV);
    cudaGetSymbolAddress((void**)&OH,  g_OH);
    cudaGetSymbolAddress((void**)&WT,  g_WT);
    cudaGetSymbolAddress((void**)&RS1, g_RS1);
    cudaGetSymbolAddress((void**)&RS3, g_RS3);

    const long long SQb = (long long)NF * QD;
    const long long S2s = (long long)LM * LM;
    const long long S1s = (long long)NF * LM;
    const long long AVs = (long long)LM * DH;
    const long long OHs = (long long)NF * DH;

    // #1: all weight transposes + cls fill
    transAll_k<<<2564, 256>>>(w1, wqkv, wout, clst);

    // #2: input projection
    mgemm2(NB * 8191, DIMM, 1024, h_in, 1024, 0, 0, 0, WT + OW1, 1024, 0, 0,
           X, DIMM, 0, 0, 1, EP_RELU_REMAP, b1);

    for (int L = 0; L < 2; L++) {
        // #3 (L=0): layernorm
        ln_k<<<TOT, 256>>>(X, XN, ln_g + L * DIMM, ln_b + L * DIMM);

        // #4 (L=0): qkv GEMM  <-- ncu capture slot
        mgemm2(TOT, QD, DIMM, XN, DIMM, 0, 0, 0, WT + OQKV(L), DIMM, 0, 0,
               QKV, QD, 0, 0, 1, EP_SCALEQ, nullptr);

        landmark_k<<<NBH * LM, 64>>>();

        // sim2 = QL @ KL^T, softmax
        mgemm2(LM, LM, DH, QL, DH, 8 * AVs, AVs, 0, KL, DH, 8 * AVs, AVs,
               S2, LM, 8 * S2s, S2s, NBH, EP_NONE, nullptr);
        softmax256_k<<<NBH * LM / 8, 256>>>(S2);

        // Moore-Penrose pinv of S2 -> Z
        reset_k<<<1, 1>>>();
        scalemax_k<<<NBH, 256>>>();
        zinit_k<<<4096, 256>>>();
        for (int it = 0; it < 6; it++) {
            float* Zin  = (it & 1) ? Z2 : Z;
            float* Zout = (it & 1) ? Z  : Z2;
            pgemm(S2, Zin, P, 1.f, 0, 0.f);
            pgemm(P, P, T2, 1.f, 1, 7.f);
            pgemm(P, T2, T, 1.f, 1, 15.f);
            pgemm(Zin, T, Zout, 0.25f, 1, 13.f);
        }

        // sim1 = Q @ KL^T (raw) + row stats
        mgemm2(NF, LM, DH, QKV, QD, SQb, 64, 0, KL, DH, 8 * AVs, AVs,
               S1, LM, 8 * S1s, S1s, NBH, EP_NONE, nullptr);
        rowstat256_k<<<NBH * NF / 8, 256>>>(S1, RS1);

        // sim3 = QL @ K^T (raw) + row stats
        mgemm2(LM, NF, DH, QL, DH, 8 * AVs, AVs, 0, QKV + 512, QD, SQb, 64,
               S3, NF, 8 * S1s, S1s, NBH, EP_NONE, nullptr);
        rowstatbig_k<<<NBH * LM, 256, NF * 4>>>(S3, RS3, NF);

        // AV = softmax(sim3) @ V
        gemm64(0, LM, DH, NF / KSPL,
               S3, NF, 8 * S1s, S1s, 1024,
               QKV + 1024, QD, SQb, 64, 1024LL * QD,
               AVp, DH, 64 * AVs, 8 * AVs, AVs,
               KSPL, NBH * KSPL, 1.f, EP_NONE, nullptr, 0, 0.f,
               RS3, 8 * LM, LM, 1);
        avreduce_k<<<1024, 256>>>();

        // ZAV = Z @ AV
        gemm64(0, LM, DH, LM, Z, LM, 8 * S2s, S2s, 0, AV, DH, 8 * AVs, AVs, 0,
               ZAV, DH, 8 * AVs, AVs, 0, 1, NBH, 1.f, EP_NONE, nullptr, 0, 0.f,
               RS3, 0, 0, 0);
        // OH = softmax(sim1) @ ZAV
        gemm64(0, NF, DH, LM, S1, LM, 8 * S1s, S1s, 0, ZAV, DH, 8 * AVs, AVs, 0,
               OH, DH, 8 * OHs, OHs, 0, 1, NBH, 1.f, EP_NONE, nullptr, 0, 0.f,
               RS1, 8LL * NF, NF, 1);

        // OH += depthwise conv residual of V
        { dim3 g(NF / 128, NBH); conv_k<<<g, 256>>>(cw + L * NH * KER); }

        // X += OH(head-layout) @ Wout + bout
        mgemm2(TOT, DIMM, DIMM, OH, 0, 0, 0, 1, WT + OOUT(L), DIMM, 0, 0,
               X, DIMM, 0, 0, 1, EP_ADDBIAS, bout + L * DIMM);
    }

    final_k<<<NB, 256>>>(fg, fb, w2, b2, out);
}

// round 10
// speedup vs baseline: 2.5249x; 1.0096x over previous
#include <cuda_runtime.h>

#define NB   2
#define NF   8192
#define DIMM 512
#define NH   8
#define DH   64
#define LM   256
#define QD   1536
#define TOT  (NB*NF)    // 16384
#define NBH  (NB*NH)    // 16
#define KER  33
#define KSPL 8

// ------------------------- scratch (device globals, no allocs) -------------
__device__ float g_X  [TOT*DIMM];
__device__ float g_XN [TOT*DIMM];
__device__ float g_QKV[TOT*QD];
__device__ float g_QL [NBH*LM*DH];
__device__ float g_KL [NBH*LM*DH];
__device__ float g_S1 [NBH*NF*LM];
__device__ float g_S3 [NBH*LM*NF];
__device__ float g_S2 [NBH*LM*LM];
__device__ float g_Zb [NBH*LM*LM];
__device__ float g_Z2b[NBH*LM*LM];
__device__ float g_Pb [NBH*LM*LM];
__device__ float g_Tb [NBH*LM*LM];
__device__ float g_T2b[NBH*LM*LM];
__device__ float g_AV [NBH*LM*DH];
__device__ float g_AVp[NBH*KSPL*LM*DH];
__device__ float g_ZAV[NBH*LM*DH];
__device__ float g_OH [NBH*NF*DH];
__device__ float g_WT [2621440];
__device__ float2 g_RS1[NBH*NF];
__device__ float2 g_RS3[NBH*LM];
__device__ unsigned int g_scale[2];
__device__ unsigned int g_bar;

enum { EP_NONE = 0, EP_RELU_REMAP = 1, EP_SCALEQ = 2, EP_ADDBIAS = 3 };

#define OW1   0
#define OQKV(L) (524288 + (L) * 786432)
#define OOUT(L) (2097152 + (L) * 262144)

__device__ __forceinline__ unsigned f2tf32(float f) {
    unsigned r;
    asm("cvt.rna.tf32.f32 %0, %1;" : "=r"(r) : "f"(f));
    return r;
}
__device__ __forceinline__ float tf32f(float f) {
    return __uint_as_float(f2tf32(f));
}

#define MMA_TF32(d, a, b) \
    asm volatile("mma.sync.aligned.m16n8k8.row.col.f32.tf32.tf32.f32 " \
        "{%0,%1,%2,%3}, {%4,%5,%6,%7}, {%8,%9}, {%0,%1,%2,%3};" \
        : "+f"((d)[0]), "+f"((d)[1]), "+f"((d)[2]), "+f"((d)[3]) \
        : "r"((a)[0]), "r"((a)[1]), "r"((a)[2]), "r"((a)[3]), \
          "r"((b)[0]), "r"((b)[1]))

// ------------------------- reductions --------------------------------------
__device__ __forceinline__ float blockReduce(float v, bool domax) {
    __shared__ float sh[32];
    __syncthreads();
    #pragma unroll
    for (int o = 16; o > 0; o >>= 1) {
        float w = __shfl_down_sync(0xffffffffu, v, o);
        v = domax ? fmaxf(v, w) : v + w;
    }
    int lane = threadIdx.x & 31, wid = threadIdx.x >> 5;
    if (lane == 0) sh[wid] = v;
    __syncthreads();
    int nw = (blockDim.x + 31) >> 5;
    if (wid == 0) {
        v = (lane < nw) ? sh[lane] : (domax ? -1e30f : 0.f);
        #pragma unroll
        for (int o = 16; o > 0; o >>= 1) {
            float w = __shfl_down_sync(0xffffffffu, v, o);
            v = domax ? fmaxf(v, w) : v + w;
        }
        if (lane == 0) sh[0] = v;
    }
    __syncthreads();
    return sh[0];
}

// ------------------- fused transposes + cls (ONE launch) --------------------
__device__ __forceinline__ void doTrans(const float* __restrict__ src,
                                        float* __restrict__ dst,
                                        int K, int N, int kt, int nt)
{
    __shared__ float t[32][33];
    int kb = kt << 5, nb = nt << 5;
    int x = threadIdx.x & 31, y = threadIdx.x >> 5;
    #pragma unroll
    for (int i = 0; i < 32; i += 8)
        t[y + i][x] = src[(long long)(kb + y + i) * N + nb + x];
    __syncthreads();
    #pragma unroll
    for (int i = 0; i < 32; i += 8)
        dst[(long long)(nb + y + i) * K + kb + x] = t[x][y + i];
}

__global__ void __launch_bounds__(256) transAll_k(
    const float* __restrict__ w1, const float* __restrict__ wqkv,
    const float* __restrict__ wout, const float* __restrict__ clst)
{
    int b = blockIdx.x;
    if (b < 512) {
        doTrans(w1, g_WT + OW1, 1024, DIMM, b & 31, b >> 5);
    } else if (b < 2048) {
        int L = (b - 512) / 768, bb = (b - 512) % 768;
        doTrans(wqkv + (long long)L * DIMM * QD, g_WT + OQKV(L), DIMM, QD, bb & 15, bb >> 4);
    } else if (b < 2560) {
        int L = (b - 2048) / 256, bb = (b - 2048) % 256;
        doTrans(wout + (long long)L * DIMM * DIMM, g_WT + OOUT(L), DIMM, DIMM, bb & 15, bb >> 4);
    } else {
        int idx = (b - 2560) * 256 + threadIdx.x;
        int bb = idx >> 9, c = idx & 511;
        g_X[(long long)bb * NF * DIMM + c] = clst[c];
    }
}

// ===================== mgemm2: cp.async + ldmatrix tf32, 128x128, 2 CTA/SM ==
__device__ __forceinline__ void cp16(unsigned dst, const void* src, int nbytes) {
    asm volatile("cp.async.cg.shared.global [%0], [%1], 16, %2;"
                 :: "r"(dst), "l"(src), "r"(nbytes) : "memory");
}

__global__ void __launch_bounds__(256, 2) mgemm2_k(
    int M, int K,
    const float* __restrict__ A, int lda, long long sA1, long long sA2, int amode,
    const float* __restrict__ BT, int ldbt, long long sBT1, long long sBT2,
    float* __restrict__ C, int ldc, long long sC1, long long sC2,
    int ep, const float* __restrict__ bias)
{
    extern __shared__ float smem[];   // 2 stages x (A 16KB + B 16KB) = 64KB
    int tid = threadIdx.x;
    int lane = tid & 31, wid = tid >> 5;
    int wm = wid & 3, wn = wid >> 2;
    int row0 = blockIdx.y << 7, col0 = blockIdx.x << 7;
    int z = blockIdx.z;
    A  += (long long)(z >> 3) * sA1 + (long long)(z & 7) * sA2;
    BT += (long long)(z >> 3) * sBT1 + (long long)(z & 7) * sBT2;
    C  += (long long)(z >> 3) * sC1 + (long long)(z & 7) * sC2;

    unsigned sbase;
    asm("{ .reg .u64 t; cvta.to.shared.u64 t, %1; cvt.u32.u64 %0, t; }"
        : "=r"(sbase) : "l"(smem));

    float acc[2][8][4];
    #pragma unroll
    for (int mi = 0; mi < 2; mi++)
        #pragma unroll
        for (int ni = 0; ni < 8; ni++)
            #pragma unroll
            for (int q = 0; q < 4; q++) acc[mi][ni][q] = 0.f;

    auto fill = [&](int s, int k0) {
        unsigned Ab = sbase + s * 32768u;
        unsigned Bb = Ab + 16384u;
        #pragma unroll
        for (int it = 0; it < 4; it++) {
            int idx = (it << 8) + tid;
            int q = idx & 7, r = idx >> 3;
            int gr = row0 + r;
            const float* src;
            int nb = 16;
            if (amode == 0) {
                int gra = gr < M ? gr : (M - 1);
                if (gr >= M) nb = 0;
                src = A + (long long)gra * lda + k0 + (q << 2);
            } else {
                int k = k0 + (q << 2);
                int h = k >> 6, d = k & 63;
                src = A + ((((long long)(gr >> 13) << 3) + h) * 8192 + (gr & 8191)) * 64 + d;
            }
            unsigned dst = Ab + (((r << 5) + ((q ^ (r & 7)) << 2)) << 2);
            cp16(dst, src, nb);
        }
        #pragma unroll
        for (int it = 0; it < 4; it++) {
            int idx = (it << 8) + tid;
            int q = idx & 7, n = idx >> 3;
            const float* src = BT + (long long)(col0 + n) * ldbt + k0 + (q << 2);
            unsigned dst = Bb + (((n << 5) + ((q ^ (n & 7)) << 2)) << 2);
            cp16(dst, src, 16);
        }
        asm volatile("cp.async.commit_group;" ::: "memory");
    };

    auto compute = [&](int s) {
        unsigned Ab = sbase + s * 32768u;
        unsigned Bb = Ab + 16384u;
        int j = lane >> 3, rho = lane & 7;
        #pragma unroll
        for (int kt = 0; kt < 4; kt++) {
            unsigned a[2][4];
            #pragma unroll
            for (int mi = 0; mi < 2; mi++) {
                int row = (wm << 5) + (mi << 4) + ((j & 1) << 3) + rho;
                int quad = (kt << 1) + (j >> 1);
                unsigned ad = Ab + (((row << 5) + ((quad ^ (row & 7)) << 2)) << 2);
                asm volatile("ldmatrix.sync.aligned.m8n8.x4.shared.b16 {%0,%1,%2,%3}, [%4];"
                    : "=r"(a[mi][0]), "=r"(a[mi][1]), "=r"(a[mi][2]), "=r"(a[mi][3])
                    : "r"(ad));
            }
            unsigned b[8][2];
            #pragma unroll
            for (int np = 0; np < 4; np++) {
                int row = (((wn << 3) + (np << 1) + (j >> 1)) << 3) + rho;
                int quad = (kt << 1) + (j & 1);
                unsigned bd = Bb + (((row << 5) + ((quad ^ (row & 7)) << 2)) << 2);
                asm volatile("ldmatrix.sync.aligned.m8n8.x4.shared.b16 {%0,%1,%2,%3}, [%4];"
                    : "=r"(b[np * 2][0]), "=r"(b[np * 2][1]),
                      "=r"(b[np * 2 + 1][0]), "=r"(b[np * 2 + 1][1])
                    : "r"(bd));
            }
            #pragma unroll
            for (int mi = 0; mi < 2; mi++)
                #pragma unroll
                for (int ni = 0; ni < 8; ni++)
                    MMA_TF32(acc[mi][ni], a[mi], b[ni]);
        }
    };

    fill(0, 0);
    int nch = K >> 5;
    for (int ch = 0; ch < nch; ch++) {
        if (ch + 1 < nch) {
            fill((ch + 1) & 1, (ch + 1) << 5);
            asm volatile("cp.async.wait_group 1;" ::: "memory");
        } else {
            asm volatile("cp.async.wait_group 0;" ::: "memory");
        }
        __syncthreads();
        compute(ch & 1);
        __syncthreads();
    }

    int rb = row0 + (wm << 5) + (lane >> 2);
    int cb = col0 + (wn << 6) + ((lane & 3) << 1);
    #pragma unroll
    for (int mi = 0; mi < 2; mi++) {
        #pragma unroll
        for (int half = 0; half < 2; half++) {
            int r = rb + (mi << 4) + (half << 3);
            if (r >= M) continue;
            #pragma unroll
            for (int ni = 0; ni < 8; ni++) {
                int c = cb + (ni << 3);
                float v0 = acc[mi][ni][half * 2];
                float v1 = acc[mi][ni][half * 2 + 1];
                if (ep == EP_RELU_REMAP) {
                    long long o = (long long)(r + r / 8191 + 1) * ldc + c;
                    v0 = fmaxf(v0 + bias[c], 0.f);
                    v1 = fmaxf(v1 + bias[c + 1], 0.f);
                    *(float2*)(C + o) = make_float2(v0, v1);
                } else if (ep == EP_SCALEQ) {
                    float sc = (c < 512) ? 0.125f : 1.0f;
                    *(float2*)(C + (long long)r * ldc + c) = make_float2(v0 * sc, v1 * sc);
                } else if (ep == EP_ADDBIAS) {
                    long long o = (long long)r * ldc + c;
                    float2 old = *(float2*)(C + o);
                    *(float2*)(C + o) = make_float2(old.x + v0 + bias[c],
                                                    old.y + v1 + bias[c + 1]);
                } else {
                    *(float2*)(C + (long long)r * ldc + c) = make_float2(v0, v1);
                }
            }
        }
    }
}

// ===================== pinv: persistent chain kernel ========================
// Grid = 128 CTAs (all co-resident on 148 SMs) with software grid barrier.
// Phases: scalemax (16 CTAs) | zinit | 6 x 4 GEMM phases (64x128 tiles).
__device__ __forceinline__ void gbar(unsigned target) {
    __syncthreads();
    if (threadIdx.x == 0) {
        __threadfence();
        atomicAdd(&g_bar, 1u);
        while (*(volatile unsigned*)&g_bar < target) {}
        __threadfence();
    }
    __syncthreads();
}

// one 64x128 tile of C = alpha * A @ (bmode ? bd*I - B : B), 256x256 batch 16
__device__ void pg_tile(const float* __restrict__ Ag, const float* __restrict__ Bg,
                        float* __restrict__ Cg, float alpha, int bmode, float bd,
                        float* ps)
{
    int bid = blockIdx.x;
    int tid = threadIdx.x;
    int lane = tid & 31, wid = tid >> 5;
    int wm = wid & 3, wn = wid >> 2;
    int col0 = (bid & 1) << 7;
    int row0 = ((bid >> 1) & 3) << 6;
    long long zo = (long long)(bid >> 3) << 16;
    Ag += zo; Bg += zo; Cg += zo;

    float acc[8][4];
    #pragma unroll
    for (int ni = 0; ni < 8; ni++)
        #pragma unroll
        for (int q = 0; q < 4; q++) acc[ni][q] = 0.f;

    int ar = tid >> 2, aq = tid & 3;
    int bn = tid & 127, bkh = tid >> 7;

    float4 pa;
    float pbv[8];

    auto fetch = [&](int k0) {
        pa = *(const float4*)(Ag + ((long long)(row0 + ar) << 8) + k0 + (aq << 2));
        #pragma unroll
        for (int j = 0; j < 8; j++) {
            int gk = k0 + (bkh << 3) + j;
            int gn = col0 + bn;
            float v = Bg[((long long)gk << 8) + gn];
            if (bmode) v = (gk == gn ? bd : 0.f) - v;
            pbv[j] = v;
        }
    };

    auto stash = [&](int s) {
        float* Sb = ps + s * 7680;
        float4 h, l;
        h.x = tf32f(pa.x); h.y = tf32f(pa.y); h.z = tf32f(pa.z); h.w = tf32f(pa.w);
        l.x = tf32f(pa.x - h.x); l.y = tf32f(pa.y - h.y);
        l.z = tf32f(pa.z - h.z); l.w = tf32f(pa.w - h.w);
        *(float4*)&Sb[ar * 20 + (aq << 2)] = h;
        *(float4*)&Sb[1280 + ar * 20 + (aq << 2)] = l;
        float4 bh0, bh1, bl0, bl1;
        bh0.x = tf32f(pbv[0]); bh0.y = tf32f(pbv[1]); bh0.z = tf32f(pbv[2]); bh0.w = tf32f(pbv[3]);
        bh1.x = tf32f(pbv[4]); bh1.y = tf32f(pbv[5]); bh1.z = tf32f(pbv[6]); bh1.w = tf32f(pbv[7]);
        bl0.x = tf32f(pbv[0] - bh0.x); bl0.y = tf32f(pbv[1] - bh0.y);
        bl0.z = tf32f(pbv[2] - bh0.z); bl0.w = tf32f(pbv[3] - bh0.w);
        bl1.x = tf32f(pbv[4] - bh1.x); bl1.y = tf32f(pbv[5] - bh1.y);
        bl1.z = tf32f(pbv[6] - bh1.z); bl1.w = tf32f(pbv[7] - bh1.w);
        *(float4*)&Sb[2560 + bn * 20 + (bkh << 3)] = bh0;
        *(float4*)&Sb[2560 + bn * 20 + (bkh << 3) + 4] = bh1;
        *(float4*)&Sb[5120 + bn * 20 + (bkh << 3)] = bl0;
        *(float4*)&Sb[5120 + bn * 20 + (bkh << 3) + 4] = bl1;
    };

    auto compute = [&](int s) {
        const float* Sb = ps + s * 7680;
        int g = lane >> 2, t = lane & 3;
        #pragma unroll
        for (int kt = 0; kt < 2; kt++) {
            int kb = kt << 3;
            int m = (wm << 4) + g;
            unsigned ah[4], al[4];
            ah[0] = __float_as_uint(Sb[m * 20 + kb + t]);
            ah[1] = __float_as_uint(Sb[(m + 8) * 20 + kb + t]);
            ah[2] = __float_as_uint(Sb[m * 20 + kb + t + 4]);
            ah[3] = __float_as_uint(Sb[(m + 8) * 20 + kb + t + 4]);
            al[0] = __float_as_uint(Sb[1280 + m * 20 + kb + t]);
            al[1] = __float_as_uint(Sb[1280 + (m + 8) * 20 + kb + t]);
            al[2] = __float_as_uint(Sb[1280 + m * 20 + kb + t + 4]);
            al[3] = __float_as_uint(Sb[1280 + (m + 8) * 20 + kb + t + 4]);
            #pragma unroll
            for (int ni = 0; ni < 8; ni++) {
                int n = (wn << 6) + (ni << 3) + g;
                unsigned bh[2], bl[2];
                bh[0] = __float_as_uint(Sb[2560 + n * 20 + kb + t]);
                bh[1] = __float_as_uint(Sb[2560 + n * 20 + kb + t + 4]);
                bl[0] = __float_as_uint(Sb[5120 + n * 20 + kb + t]);
                bl[1] = __float_as_uint(Sb[5120 + n * 20 + kb + t + 4]);
                MMA_TF32(acc[ni], ah, bh);
                MMA_TF32(acc[ni], ah, bl);
                MMA_TF32(acc[ni], al, bh);
            }
        }
    };

    fetch(0);
    for (int ch = 0; ch < 16; ch++) {
        stash(ch & 1);
        __syncthreads();
        if (ch < 15) fetch((ch + 1) << 4);
        compute(ch & 1);
        __syncthreads();
    }

    int g = lane >> 2, t = lane & 3;
    #pragma unroll
    for (int half = 0; half < 2; half++) {
        int r = row0 + (wm << 4) + (half << 3) + g;
        #pragma unroll
        for (int ni = 0; ni < 8; ni++) {
            int c = col0 + (wn << 6) + (ni << 3) + (t << 1);
            *(float2*)(Cg + ((long long)r << 8) + c) =
                make_float2(acc[ni][half * 2] * alpha, acc[ni][half * 2 + 1] * alpha);
        }
    }
}

__global__ void __launch_bounds__(256) pinvchain_k()
{
    extern __shared__ float ps[];
    int bid = blockIdx.x;
    int tid = threadIdx.x;

    // phase 1: scalemax (CTAs 0..15, one per batch)
    if (bid < 16) {
        const float* S = g_S2 + ((long long)bid << 16);
        float rs = 0.f, cs = 0.f;
        for (int j = 0; j < 256; j++) {
            rs += S[(tid << 8) + j];
            cs += S[(j << 8) + tid];
        }
        float rm = blockReduce(rs, true);
        float cm = blockReduce(cs, true);
        if (tid == 0) {
            atomicMax(&g_scale[0], __float_as_uint(rm));
            atomicMax(&g_scale[1], __float_as_uint(cm));
        }
    }
    gbar(128);

    // phase 2: zinit (transpose-scale): 1048576 elems / 128 CTAs
    {
        float inv = 1.0f / (__uint_as_float(g_scale[0]) * __uint_as_float(g_scale[1]));
        #pragma unroll
        for (int e = 0; e < 32; e++) {
            int idx = (bid << 13) + (e << 8) + tid;
            int z = idx >> 16, r = idx & 65535;
            int i = r >> 8, j = r & 255;
            g_Zb[((long long)z << 16) + (i << 8) + j] =
                g_S2[((long long)z << 16) + (j << 8) + i] * inv;
        }
    }
    gbar(256);

    // phases 3..26: 6 Newton iterations x 4 GEMMs
    unsigned t = 256;
    for (int it = 0; it < 6; it++) {
        float* Zi = (it & 1) ? g_Z2b : g_Zb;
        float* Zo = (it & 1) ? g_Zb : g_Z2b;
        pg_tile(g_S2, Zi, g_Pb, 1.f, 0, 0.f, ps);  t += 128; gbar(t);
        pg_tile(g_Pb, g_Pb, g_T2b, 1.f, 1, 7.f, ps);  t += 128; gbar(t);
        pg_tile(g_Pb, g_T2b, g_Tb, 1.f, 1, 15.f, ps);  t += 128; gbar(t);
        pg_tile(Zi, g_Tb, Zo, 0.25f, 1, 13.f, ps);  t += 128; gbar(t);
    }
    // result in g_Zb after it=5 (Zo = g_Zb)
}

__global__ void reset_k() { g_scale[0] = 0u; g_scale[1] = 0u; g_bar = 0u; }

// ===================== 64x64x16 SIMT GEMM (AV/ZAV/OH), exp-fused A ==========
template<int TRANSB>
__global__ void __launch_bounds__(256) gemm64_k(
    int M, int N, int K,
    const float* __restrict__ A, int lda, long long sA1, long long sA2, long long sA3,
    const float* __restrict__ Bp, int ldb, long long sB1, long long sB2, long long sB3,
    float* __restrict__ C, int ldc, long long sC1, long long sC2, long long sC3,
    int SPLIT, float alpha, int ep, const float* __restrict__ bias,
    int bmode, float bdiag,
    const float2* __restrict__ rsA, long long rs1, long long rs2, int aexp)
{
    __shared__ float As[2][16 * 68];
    __shared__ float Bs[2][16 * 68];
    int z = blockIdx.z;
    int s  = z % SPLIT;
    int bh = z / SPLIT;
    int hh = bh & 7, bb = bh >> 3;
    A  += (long long)bb * sA1 + (long long)hh * sA2 + (long long)s * sA3;
    Bp += (long long)bb * sB1 + (long long)hh * sB2 + (long long)s * sB3;
    C  += (long long)bb * sC1 + (long long)hh * sC2 + (long long)s * sC3;
    rsA += bb * rs1 + hh * rs2;
    int row0 = blockIdx.y << 6;
    int col0 = blockIdx.x << 6;
    int tid = threadIdx.x;
    int tx = tid & 15, ty = tid >> 4;

    int a_r  = tid >> 2;
    int a_kk = (tid & 3) << 2;
    int bn_kk = tid >> 4;
    int bn_n  = (tid & 15) << 2;
    int bt_n  = tid >> 2;
    int bt_kk = (tid & 3) << 2;

    float acc[4][4];
    #pragma unroll
    for (int i = 0; i < 4; i++)
        #pragma unroll
        for (int j = 0; j < 4; j++) acc[i][j] = 0.f;

    float4 pa, pb;

    auto fetch = [&](int k0) {
        int gr = row0 + a_r;
        pa = make_float4(0.f, 0.f, 0.f, 0.f);
        if (gr < M) {
            pa = *(const float4*)(A + (long long)gr * lda + k0 + a_kk);
            if (aexp) {
                float2 st = rsA[gr];
                pa.x = __expf(pa.x - st.x) * st.y;
                pa.y = __expf(pa.y - st.x) * st.y;
                pa.z = __expf(pa.z - st.x) * st.y;
                pa.w = __expf(pa.w - st.x) * st.y;
            }
        }
        if (!TRANSB) {
            pb = *(const float4*)(Bp + (long long)(k0 + bn_kk) * ldb + col0 + bn_n);
        } else {
            pb = *(const float4*)(Bp + (long long)(col0 + bt_n) * ldb + k0 + bt_kk);
        }
    };

    auto stash = [&](int b, int k0) {
        float* Ab = As[b];
        Ab[(a_kk + 0) * 68 + a_r] = pa.x;
        Ab[(a_kk + 1) * 68 + a_r] = pa.y;
        Ab[(a_kk + 2) * 68 + a_r] = pa.z;
        Ab[(a_kk + 3) * 68 + a_r] = pa.w;
        float* Bb = Bs[b];
        if (!TRANSB) {
            float4 v = pb;
            if (bmode) {
                int gk = k0 + bn_kk, gn = col0 + bn_n;
                v.x = (gk == gn + 0 ? bdiag : 0.f) - v.x;
                v.y = (gk == gn + 1 ? bdiag : 0.f) - v.y;
                v.z = (gk == gn + 2 ? bdiag : 0.f) - v.z;
                v.w = (gk == gn + 3 ? bdiag : 0.f) - v.w;
            }
            *(float4*)&Bb[bn_kk * 68 + bn_n] = v;
        } else {
            Bb[(bt_kk + 0) * 68 + bt_n] = pb.x;
            Bb[(bt_kk + 1) * 68 + bt_n] = pb.y;
            Bb[(bt_kk + 2) * 68 + bt_n] = pb.z;
            Bb[(bt_kk + 3) * 68 + bt_n] = pb.w;
        }
    };

    fetch(0);
    stash(0, 0);
    __syncthreads();

    int nt = K >> 4;
    for (int t = 0; t < nt; t++) {
        int buf = t & 1;
        if (t + 1 < nt) fetch((t + 1) << 4);
        const float* Ab = As[buf];
        const float* Bb = Bs[buf];
        #pragma unroll
        for (int kk = 0; kk < 16; kk++) {
            float4 a = *(const float4*)&Ab[kk * 68 + (ty << 2)];
            float4 b = *(const float4*)&Bb[kk * 68 + (tx << 2)];
            acc[0][0] += a.x * b.x; acc[0][1] += a.x * b.y; acc[0][2] += a.x * b.z; acc[0][3] += a.x * b.w;
            acc[1][0] += a.y * b.x; acc[1][1] += a.y * b.y; acc[1][2] += a.y * b.z; acc[1][3] += a.y * b.w;
            acc[2][0] += a.z * b.x; acc[2][1] += a.z * b.y; acc[2][2] += a.z * b.z; acc[2][3] += a.z * b.w;
            acc[3][0] += a.w * b.x; acc[3][1] += a.w * b.y; acc[3][2] += a.w * b.z; acc[3][3] += a.w * b.w;
        }
        if (t + 1 < nt) stash(buf ^ 1, (t + 1) << 4);
        __syncthreads();
    }

    #pragma unroll
    for (int i = 0; i < 4; i++) {
        int r = row0 + (ty << 2) + i;
        if (r >= M) continue;
        #pragma unroll
        for (int j = 0; j < 4; j++) {
            int c = col0 + (tx << 2) + j;
            C[(long long)r * ldc + c] = alpha * acc[i][j];
        }
    }
}

// ------------------------- layernorm (rows of 512) --------------------------
__global__ void __launch_bounds__(256) ln_k(const float* __restrict__ X, float* __restrict__ Y,
                                            const float* __restrict__ g, const float* __restrict__ b)
{
    long long row = blockIdx.x;
    const float* x = X + row * DIMM;
    float* y = Y + row * DIMM;
    int t = threadIdx.x;
    float v0 = x[t], v1 = x[t + 256];
    float mu  = blockReduce(v0 + v1, false) * (1.f / 512.f);
    float d0 = v0 - mu, d1 = v1 - mu;
    float var = blockReduce(d0 * d0 + d1 * d1, false) * (1.f / 512.f);
    float inv = rsqrtf(var + 1e-5f);
    y[t]       = d0 * inv * g[t]       + b[t];
    y[t + 256] = d1 * inv * g[t + 256] + b[t + 256];
}

// ------------------------- softmax (S2 only) --------------------------------
__global__ void __launch_bounds__(256) softmax256_k(float* __restrict__ S)
{
    long long row = ((long long)blockIdx.x << 3) + (threadIdx.x >> 5);
    int lane = threadIdx.x & 31;
    float* s = S + (row << 8);
    float4 va = *(float4*)(s + (lane << 3));
    float4 vb = *(float4*)(s + (lane << 3) + 4);
    float m = fmaxf(fmaxf(fmaxf(va.x, va.y), fmaxf(va.z, va.w)),
                    fmaxf(fmaxf(vb.x, vb.y), fmaxf(vb.z, vb.w)));
    #pragma unroll
    for (int o = 16; o > 0; o >>= 1) m = fmaxf(m, __shfl_xor_sync(0xffffffffu, m, o));
    va.x = __expf(va.x - m); va.y = __expf(va.y - m); va.z = __expf(va.z - m); va.w = __expf(va.w - m);
    vb.x = __expf(vb.x - m); vb.y = __expf(vb.y - m); vb.z = __expf(vb.z - m); vb.w = __expf(vb.w - m);
    float sum = va.x + va.y + va.z + va.w + vb.x + vb.y + vb.z + vb.w;
    #pragma unroll
    for (int o = 16; o > 0; o >>= 1) sum += __shfl_xor_sync(0xffffffffu, sum, o);
    float inv = 1.f / sum;
    va.x *= inv; va.y *= inv; va.z *= inv; va.w *= inv;
    vb.x *= inv; vb.y *= inv; vb.z *= inv; vb.w *= inv;
    *(float4*)(s + (lane << 3)) = va;
    *(float4*)(s + (lane << 3) + 4) = vb;
}

// ------------------------- row stats ----------------------------------------
__global__ void __launch_bounds__(256) rowstat256_k(const float* __restrict__ S,
                                                    float2* __restrict__ RS)
{
    long long row = ((long long)blockIdx.x << 3) + (threadIdx.x >> 5);
    int lane = threadIdx.x & 31;
    const float* s = S + (row << 8);
    float4 va = *(const float4*)(s + (lane << 3));
    float4 vb = *(const float4*)(s + (lane << 3) + 4);
    float m = fmaxf(fmaxf(fmaxf(va.x, va.y), fmaxf(va.z, va.w)),
                    fmaxf(fmaxf(vb.x, vb.y), fmaxf(vb.z, vb.w)));
    #pragma unroll
    for (int o = 16; o > 0; o >>= 1) m = fmaxf(m, __shfl_xor_sync(0xffffffffu, m, o));
    float sum = __expf(va.x - m) + __expf(va.y - m) + __expf(va.z - m) + __expf(va.w - m)
              + __expf(vb.x - m) + __expf(vb.y - m) + __expf(vb.z - m) + __expf(vb.w - m);
    #pragma unroll
    for (int o = 16; o > 0; o >>= 1) sum += __shfl_xor_sync(0xffffffffu, sum, o);
    if (lane == 0) RS[row] = make_float2(m, 1.f / sum);
}

__global__ void __launch_bounds__(256) rowstatbig_k(const float* __restrict__ S,
                                                    float2* __restrict__ RS, int cols)
{
    extern __shared__ float buf[];
    long long row = blockIdx.x;
    const float* s = S + row * cols;
    int t = threadIdx.x;
    float mx = -1e30f;
    for (int i = t; i < cols; i += 256) { float v = s[i]; buf[i] = v; mx = fmaxf(mx, v); }
    float bmax = blockReduce(mx, true);
    float sum = 0.f;
    for (int i = t; i < cols; i += 256) sum += __expf(buf[i] - bmax);
    float bsum = blockReduce(sum, false);
    if (t == 0) RS[row] = make_float2(bmax, 1.f / bsum);
}

// ------------------------- landmarks ----------------------------------------
__global__ void __launch_bounds__(64) landmark_k()
{
    int zz = blockIdx.x;
    int mi = zz & 255, bh = zz >> 8;
    int b = bh >> 3, h = bh & 7;
    int d = threadIdx.x;
    const float* base = g_QKV + (long long)(b * NF + mi * 32) * QD + h * 64 + d;
    float sq = 0.f, sk = 0.f;
    #pragma unroll 8
    for (int il = 0; il < 32; il++) {
        sq += base[(long long)il * QD];
        sk += base[(long long)il * QD + 512];
    }
    long long o = ((long long)bh * LM + mi) * DH + d;
    g_QL[o] = sq * (1.f / 32.f);
    g_KL[o] = sk * (1.f / 32.f);
}

// ------------------------- split-K reduce for AV ----------------------------
__global__ void __launch_bounds__(256) avreduce_k()
{
    int idx = blockIdx.x * 256 + threadIdx.x;
    int bh = idx >> 14;
    int r  = idx & 16383;
    const float* p = g_AVp + ((long long)bh << 17);
    float s = 0.f;
    #pragma unroll
    for (int k = 0; k < KSPL; k++) s += p[(k << 14) + r];
    g_AV[idx] = s;
}

// ------------------------- depthwise conv residual --------------------------
__global__ void __launch_bounds__(256) conv_k(const float* __restrict__ cw)
{
    __shared__ float sv[160 * 64];
    __shared__ float sw[KER];
    int tile = blockIdx.x;
    int bh = blockIdx.y;
    int b = bh >> 3, h = bh & 7;
    int n0 = tile * 128;
    int t = threadIdx.x;
    if (t < KER) sw[t] = cw[h * KER + t];
    for (int idx = t; idx < 160 * 64; idx += 256) {
        int r = idx >> 6, d = idx & 63;
        int nn = n0 - 16 + r;
        float v = 0.f;
        if (nn >= 0 && nn < NF) v = g_QKV[(long long)(b * NF + nn) * QD + 1024 + h * 64 + d];
        sv[idx] = v;
    }
    __syncthreads();
    int d = t & 63, r0 = t >> 6;
    for (int rr = r0; rr < 128; rr += 4) {
        float a = 0.f;
        #pragma unroll
        for (int k = 0; k < KER; k++) a += sv[(rr + k) * 64 + d] * sw[k];
        long long o = ((long long)bh * NF + n0 + rr) * DH + d;
        g_OH[o] += a;
    }
}

// ------------------------- final LN + head ----------------------------------
__global__ void __launch_bounds__(256) final_k(const float* __restrict__ fg, const float* __restrict__ fb,
                                               const float* __restrict__ w2, const float* __restrict__ b2,
                                               float* __restrict__ out)
{
    int b = blockIdx.x;
    const float* x = g_X + (long long)b * NF * DIMM;
    int t = threadIdx.x;
    float v0 = x[t], v1 = x[t + 256];
    float mu  = blockReduce(v0 + v1, false) * (1.f / 512.f);
    float d0 = v0 - mu, d1 = v1 - mu;
    float var = blockReduce(d0 * d0 + d1 * d1, false) * (1.f / 512.f);
    float inv = rsqrtf(var + 1e-5f);
    float n0 = d0 * inv * fg[t]       + fb[t];
    float n1 = d1 * inv * fg[t + 256] + fb[t + 256];
    float p0 = n0 * w2[2 * t]     + n1 * w2[2 * (t + 256)];
    float p1 = n0 * w2[2 * t + 1] + n1 * w2[2 * (t + 256) + 1];
    p0 = blockReduce(p0, false);
    p1 = blockReduce(p1, false);
    if (t == 0) {
        out[b * 2 + 0] = p0 + b2[0];
        out[b * 2 + 1] = p1 + b2[1];
    }
}

// ------------------------- host orchestration -------------------------------
static inline void gemm64(int transB, int M, int N, int K,
                          const float* A, int lda, long long sA1, long long sA2, long long sA3,
                          const float* Bp, int ldb, long long sB1, long long sB2, long long sB3,
                          float* C, int ldc, long long sC1, long long sC2, long long sC3,
                          int SPLIT, int batchZ, float alpha, int ep, const float* bias,
                          int bmode, float bdiag,
                          const float2* rsA, long long rs1, long long rs2, int aexp)
{
    dim3 g(N >> 6, (M + 63) >> 6, batchZ);
    if (transB)
        gemm64_k<1><<<g, 256>>>(M, N, K, A, lda, sA1, sA2, sA3, Bp, ldb, sB1, sB2, sB3,
                                C, ldc, sC1, sC2, sC3, SPLIT, alpha, ep, bias, bmode, bdiag,
                                rsA, rs1, rs2, aexp);
    else
        gemm64_k<0><<<g, 256>>>(M, N, K, A, lda, sA1, sA2, sA3, Bp, ldb, sB1, sB2, sB3,
                                C, ldc, sC1, sC2, sC3, SPLIT, alpha, ep, bias, bmode, bdiag,
                                rsA, rs1, rs2, aexp);
}

static inline void mgemm2(int M, int N, int K,
                          const float* A, int lda, long long sA1, long long sA2, int amode,
                          const float* BT, int ldbt, long long sBT1, long long sBT2,
                          float* C, int ldc, long long sC1, long long sC2,
                          int batch, int ep, const float* bias)
{
    cudaFuncSetAttribute(mgemm2_k, cudaFuncAttributeMaxDynamicSharedMemorySize, 65536);
    dim3 g(N >> 7, (M + 127) >> 7, batch);
    mgemm2_k<<<g, 256, 65536>>>(M, K, A, lda, sA1, sA2, amode, BT, ldbt, sBT1, sBT2,
                                C, ldc, sC1, sC2, ep, bias);
}

extern "C" void kernel_launch(void* const* d_in, const int* in_sizes, int n_in,
                              void* d_out, int out_size)
{
    const float* h_in  = (const float*)d_in[0];
    const float* w1    = (const float*)d_in[1];
    const float* b1    = (const float*)d_in[2];
    const float* clst  = (const float*)d_in[3];
    const float* ln_g  = (const float*)d_in[4];
    const float* ln_b  = (const float*)d_in[5];
    const float* wqkv  = (const float*)d_in[6];
    const float* wout  = (const float*)d_in[7];
    const float* bout  = (const float*)d_in[8];
    const float* cw    = (const float*)d_in[9];
    const float* fg    = (const float*)d_in[10];
    const float* fb    = (const float*)d_in[11];
    const float* w2    = (const float*)d_in[12];
    const float* b2    = (const float*)d_in[13];
    float* out = (float*)d_out;

    float *X, *XN, *QKV, *QL, *KL, *S1, *S2, *S3, *Z, *AV, *AVp, *ZAV, *OH, *WT;
    float2 *RS1, *RS3;
    cudaGetSymbolAddress((void**)&X,   g_X);
    cudaGetSymbolAddress((void**)&XN,  g_XN);
    cudaGetSymbolAddress((void**)&QKV, g_QKV);
    cudaGetSymbolAddress((void**)&QL,  g_QL);
    cudaGetSymbolAddress((void**)&KL,  g_KL);
    cudaGetSymbolAddress((void**)&S1,  g_S1);
    cudaGetSymbolAddress((void**)&S2,  g_S2);
    cudaGetSymbolAddress((void**)&S3,  g_S3);
    cudaGetSymbolAddress((void**)&Z,   g_Zb);
    cudaGetSymbolAddress((void**)&AV,  g_AV);
    cudaGetSymbolAddress((void**)&AVp, g_AVp);
    cudaGetSymbolAddress((void**)&ZAV, g_ZAV);
    cudaGetSymbolAddress((void**)&OH,  g_OH);
    cudaGetSymbolAddress((void**)&WT,  g_WT);
    cudaGetSymbolAddress((void**)&RS1, g_RS1);
    cudaGetSymbolAddress((void**)&RS3, g_RS3);

    const long long SQb = (long long)NF * QD;
    const long long S2s = (long long)LM * LM;
    const long long S1s = (long long)NF * LM;
    const long long AVs = (long long)LM * DH;
    const long long OHs = (long long)NF * DH;

    cudaFuncSetAttribute(pinvchain_k, cudaFuncAttributeMaxDynamicSharedMemorySize, 61440);

    // #1: all weight transposes + cls fill
    transAll_k<<<2564, 256>>>(w1, wqkv, wout, clst);

    // #2: input projection
    mgemm2(NB * 8191, DIMM, 1024, h_in, 1024, 0, 0, 0, WT + OW1, 1024, 0, 0,
           X, DIMM, 0, 0, 1, EP_RELU_REMAP, b1);

    for (int L = 0; L < 2; L++) {
        // #3 (L=0): layernorm
        ln_k<<<TOT, 256>>>(X, XN, ln_g + L * DIMM, ln_b + L * DIMM);

        // #4 (L=0): qkv GEMM  <-- ncu capture slot
        mgemm2(TOT, QD, DIMM, XN, DIMM, 0, 0, 0, WT + OQKV(L), DIMM, 0, 0,
               QKV, QD, 0, 0, 1, EP_SCALEQ, nullptr);

        landmark_k<<<NBH * LM, 64>>>();

        // sim2 = QL @ KL^T, softmax
        mgemm2(LM, LM, DH, QL, DH, 8 * AVs, AVs, 0, KL, DH, 8 * AVs, AVs,
               S2, LM, 8 * S2s, S2s, NBH, EP_NONE, nullptr);
        softmax256_k<<<NBH * LM / 8, 256>>>(S2);

        // Moore-Penrose pinv of S2 -> Z : ONE persistent launch
        reset_k<<<1, 1>>>();
        pinvchain_k<<<128, 256, 61440>>>();

        // sim1 = Q @ KL^T (raw) + row stats
        mgemm2(NF, LM, DH, QKV, QD, SQb, 64, 0, KL, DH, 8 * AVs, AVs,
               S1, LM, 8 * S1s, S1s, NBH, EP_NONE, nullptr);
        rowstat256_k<<<NBH * NF / 8, 256>>>(S1, RS1);

        // sim3 = QL @ K^T (raw) + row stats
        mgemm2(LM, NF, DH, QL, DH, 8 * AVs, AVs, 0, QKV + 512, QD, SQb, 64,
               S3, NF, 8 * S1s, S1s, NBH, EP_NONE, nullptr);
        rowstatbig_k<<<NBH * LM, 256, NF * 4>>>(S3, RS3, NF);

        // AV = softmax(sim3) @ V
        gemm64(0, LM, DH, NF / KSPL,
               S3, NF, 8 * S1s, S1s, 1024,
               QKV + 1024, QD, SQb, 64, 1024LL * QD,
               AVp, DH, 64 * AVs, 8 * AVs, AVs,
               KSPL, NBH * KSPL, 1.f, EP_NONE, nullptr, 0, 0.f,
               RS3, 8 * LM, LM, 1);
        avreduce_k<<<1024, 256>>>();

        // ZAV = Z @ AV
        gemm64(0, LM, DH, LM, Z, LM, 8 * S2s, S2s, 0, AV, DH, 8 * AVs, AVs, 0,
               ZAV, DH, 8 * AVs, AVs, 0, 1, NBH, 1.f, EP_NONE, nullptr, 0, 0.f,
               RS3, 0, 0, 0);
        // OH = softmax(sim1) @ ZAV
        gemm64(0, NF, DH, LM, S1, LM, 8 * S1s, S1s, 0, ZAV, DH, 8 * AVs, AVs, 0,
               OH, DH, 8 * OHs, OHs, 0, 1, NBH, 1.f, EP_NONE, nullptr, 0, 0.f,
               RS1, 8LL * NF, NF, 1);

        // OH += depthwise conv residual of V
        { dim3 g(NF / 128, NBH); conv_k<<<g, 256>>>(cw + L * NH * KER); }

        // X += OH(head-layout) @ Wout + bout
        mgemm2(TOT, DIMM, DIMM, OH, 0, 0, 0, 1, WT + OOUT(L), DIMM, 0, 0,
               X, DIMM, 0, 0, 1, EP_ADDBIAS, bout + L * DIMM);
    }

    final_k<<<NB, 256>>>(fg, fb, w2, b2, out);
}

// round 11
// speedup vs baseline: 2.6077x; 1.0328x over previous
#include <cuda_runtime.h>

#define NB   2
#define NF   8192
#define DIMM 512
#define NH   8
#define DH   64
#define LM   256
#define QD   1536
#define TOT  (NB*NF)    // 16384
#define NBH  (NB*NH)    // 16
#define KER  33
#define KSPL 8

// ------------------------- scratch (device globals, no allocs) -------------
__device__ float g_X  [TOT*DIMM];
__device__ float g_XN [TOT*DIMM];
__device__ float g_QKV[TOT*QD];
__device__ float g_QL [NBH*LM*DH];
__device__ float g_KL [NBH*LM*DH];
__device__ float g_S1 [NBH*NF*LM];
__device__ float g_S3 [NBH*LM*NF];
__device__ float g_S2 [NBH*LM*LM];
__device__ float g_Zb [NBH*LM*LM];
__device__ float g_Z2b[NBH*LM*LM];
__device__ float g_Pb [NBH*LM*LM];
__device__ float g_Tb [NBH*LM*LM];
__device__ float g_T2b[NBH*LM*LM];
__device__ float g_AV [NBH*LM*DH];
__device__ float g_AVp[NBH*KSPL*LM*DH];
__device__ float g_ZAV[NBH*LM*DH];
__device__ float g_OH [NBH*NF*DH];
__device__ float g_WT [2621440];
__device__ float2 g_RS1[NBH*NF];
__device__ float2 g_RS3[NBH*LM];
__device__ unsigned int g_scale[2];
__device__ unsigned int g_bar;

enum { EP_NONE = 0, EP_RELU_REMAP = 1, EP_SCALEQ = 2, EP_ADDBIAS = 3 };

#define OW1   0
#define OQKV(L) (524288 + (L) * 786432)
#define OOUT(L) (2097152 + (L) * 262144)

__device__ __forceinline__ unsigned f2tf32(float f) {
    unsigned r;
    asm("cvt.rna.tf32.f32 %0, %1;" : "=r"(r) : "f"(f));
    return r;
}
__device__ __forceinline__ float tf32f(float f) {
    return __uint_as_float(f2tf32(f));
}

#define MMA_TF32(d, a, b) \
    asm volatile("mma.sync.aligned.m16n8k8.row.col.f32.tf32.tf32.f32 " \
        "{%0,%1,%2,%3}, {%4,%5,%6,%7}, {%8,%9}, {%0,%1,%2,%3};" \
        : "+f"((d)[0]), "+f"((d)[1]), "+f"((d)[2]), "+f"((d)[3]) \
        : "r"((a)[0]), "r"((a)[1]), "r"((a)[2]), "r"((a)[3]), \
          "r"((b)[0]), "r"((b)[1]))

// ------------------------- reductions --------------------------------------
__device__ __forceinline__ float blockReduce(float v, bool domax) {
    __shared__ float sh[32];
    __syncthreads();
    #pragma unroll
    for (int o = 16; o > 0; o >>= 1) {
        float w = __shfl_down_sync(0xffffffffu, v, o);
        v = domax ? fmaxf(v, w) : v + w;
    }
    int lane = threadIdx.x & 31, wid = threadIdx.x >> 5;
    if (lane == 0) sh[wid] = v;
    __syncthreads();
    int nw = (blockDim.x + 31) >> 5;
    if (wid == 0) {
        v = (lane < nw) ? sh[lane] : (domax ? -1e30f : 0.f);
        #pragma unroll
        for (int o = 16; o > 0; o >>= 1) {
            float w = __shfl_down_sync(0xffffffffu, v, o);
            v = domax ? fmaxf(v, w) : v + w;
        }
        if (lane == 0) sh[0] = v;
    }
    __syncthreads();
    return sh[0];
}

// ------------------- fused transposes + cls (ONE launch) --------------------
__device__ __forceinline__ void doTrans(const float* __restrict__ src,
                                        float* __restrict__ dst,
                                        int K, int N, int kt, int nt)
{
    __shared__ float t[32][33];
    int kb = kt << 5, nb = nt << 5;
    int x = threadIdx.x & 31, y = threadIdx.x >> 5;
    #pragma unroll
    for (int i = 0; i < 32; i += 8)
        t[y + i][x] = src[(long long)(kb + y + i) * N + nb + x];
    __syncthreads();
    #pragma unroll
    for (int i = 0; i < 32; i += 8)
        dst[(long long)(nb + y + i) * K + kb + x] = t[x][y + i];
}

__global__ void __launch_bounds__(256) transAll_k(
    const float* __restrict__ w1, const float* __restrict__ wqkv,
    const float* __restrict__ wout, const float* __restrict__ clst)
{
    int b = blockIdx.x;
    if (b < 512) {
        doTrans(w1, g_WT + OW1, 1024, DIMM, b & 31, b >> 5);
    } else if (b < 2048) {
        int L = (b - 512) / 768, bb = (b - 512) % 768;
        doTrans(wqkv + (long long)L * DIMM * QD, g_WT + OQKV(L), DIMM, QD, bb & 15, bb >> 4);
    } else if (b < 2560) {
        int L = (b - 2048) / 256, bb = (b - 2048) % 256;
        doTrans(wout + (long long)L * DIMM * DIMM, g_WT + OOUT(L), DIMM, DIMM, bb & 15, bb >> 4);
    } else {
        int idx = (b - 2560) * 256 + threadIdx.x;
        int bb = idx >> 9, c = idx & 511;
        g_X[(long long)bb * NF * DIMM + c] = clst[c];
    }
}

// ===================== mgemm2: cp.async + ldmatrix tf32, 128x128, 2 CTA/SM ==
__device__ __forceinline__ void cp16(unsigned dst, const void* src, int nbytes) {
    asm volatile("cp.async.cg.shared.global [%0], [%1], 16, %2;"
                 :: "r"(dst), "l"(src), "r"(nbytes) : "memory");
}

__global__ void __launch_bounds__(256, 2) mgemm2_k(
    int M, int K,
    const float* __restrict__ A, int lda, long long sA1, long long sA2, int amode,
    const float* __restrict__ BT, int ldbt, long long sBT1, long long sBT2,
    float* __restrict__ C, int ldc, long long sC1, long long sC2,
    int ep, const float* __restrict__ bias)
{
    extern __shared__ float smem[];   // 2 stages x (A 16KB + B 16KB) = 64KB
    int tid = threadIdx.x;
    int lane = tid & 31, wid = tid >> 5;
    int wm = wid & 3, wn = wid >> 2;
    int row0 = blockIdx.y << 7, col0 = blockIdx.x << 7;
    int z = blockIdx.z;
    A  += (long long)(z >> 3) * sA1 + (long long)(z & 7) * sA2;
    BT += (long long)(z >> 3) * sBT1 + (long long)(z & 7) * sBT2;
    C  += (long long)(z >> 3) * sC1 + (long long)(z & 7) * sC2;

    unsigned sbase;
    asm("{ .reg .u64 t; cvta.to.shared.u64 t, %1; cvt.u32.u64 %0, t; }"
        : "=r"(sbase) : "l"(smem));

    float acc[2][8][4];
    #pragma unroll
    for (int mi = 0; mi < 2; mi++)
        #pragma unroll
        for (int ni = 0; ni < 8; ni++)
            #pragma unroll
            for (int q = 0; q < 4; q++) acc[mi][ni][q] = 0.f;

    auto fill = [&](int s, int k0) {
        unsigned Ab = sbase + s * 32768u;
        unsigned Bb = Ab + 16384u;
        #pragma unroll
        for (int it = 0; it < 4; it++) {
            int idx = (it << 8) + tid;
            int q = idx & 7, r = idx >> 3;
            int gr = row0 + r;
            const float* src;
            int nb = 16;
            if (amode == 0) {
                int gra = gr < M ? gr : (M - 1);
                if (gr >= M) nb = 0;
                src = A + (long long)gra * lda + k0 + (q << 2);
            } else {
                int k = k0 + (q << 2);
                int h = k >> 6, d = k & 63;
                src = A + ((((long long)(gr >> 13) << 3) + h) * 8192 + (gr & 8191)) * 64 + d;
            }
            unsigned dst = Ab + (((r << 5) + ((q ^ (r & 7)) << 2)) << 2);
            cp16(dst, src, nb);
        }
        #pragma unroll
        for (int it = 0; it < 4; it++) {
            int idx = (it << 8) + tid;
            int q = idx & 7, n = idx >> 3;
            const float* src = BT + (long long)(col0 + n) * ldbt + k0 + (q << 2);
            unsigned dst = Bb + (((n << 5) + ((q ^ (n & 7)) << 2)) << 2);
            cp16(dst, src, 16);
        }
        asm volatile("cp.async.commit_group;" ::: "memory");
    };

    auto compute = [&](int s) {
        unsigned Ab = sbase + s * 32768u;
        unsigned Bb = Ab + 16384u;
        int j = lane >> 3, rho = lane & 7;
        #pragma unroll
        for (int kt = 0; kt < 4; kt++) {
            unsigned a[2][4];
            #pragma unroll
            for (int mi = 0; mi < 2; mi++) {
                int row = (wm << 5) + (mi << 4) + ((j & 1) << 3) + rho;
                int quad = (kt << 1) + (j >> 1);
                unsigned ad = Ab + (((row << 5) + ((quad ^ (row & 7)) << 2)) << 2);
                asm volatile("ldmatrix.sync.aligned.m8n8.x4.shared.b16 {%0,%1,%2,%3}, [%4];"
                    : "=r"(a[mi][0]), "=r"(a[mi][1]), "=r"(a[mi][2]), "=r"(a[mi][3])
                    : "r"(ad));
            }
            unsigned b[8][2];
            #pragma unroll
            for (int np = 0; np < 4; np++) {
                int row = (((wn << 3) + (np << 1) + (j >> 1)) << 3) + rho;
                int quad = (kt << 1) + (j & 1);
                unsigned bd = Bb + (((row << 5) + ((quad ^ (row & 7)) << 2)) << 2);
                asm volatile("ldmatrix.sync.aligned.m8n8.x4.shared.b16 {%0,%1,%2,%3}, [%4];"
                    : "=r"(b[np * 2][0]), "=r"(b[np * 2][1]),
                      "=r"(b[np * 2 + 1][0]), "=r"(b[np * 2 + 1][1])
                    : "r"(bd));
            }
            #pragma unroll
            for (int mi = 0; mi < 2; mi++)
                #pragma unroll
                for (int ni = 0; ni < 8; ni++)
                    MMA_TF32(acc[mi][ni], a[mi], b[ni]);
        }
    };

    fill(0, 0);
    int nch = K >> 5;
    for (int ch = 0; ch < nch; ch++) {
        if (ch + 1 < nch) {
            fill((ch + 1) & 1, (ch + 1) << 5);
            asm volatile("cp.async.wait_group 1;" ::: "memory");
        } else {
            asm volatile("cp.async.wait_group 0;" ::: "memory");
        }
        __syncthreads();
        compute(ch & 1);
        __syncthreads();
    }

    int rb = row0 + (wm << 5) + (lane >> 2);
    int cb = col0 + (wn << 6) + ((lane & 3) << 1);
    #pragma unroll
    for (int mi = 0; mi < 2; mi++) {
        #pragma unroll
        for (int half = 0; half < 2; half++) {
            int r = rb + (mi << 4) + (half << 3);
            if (r >= M) continue;
            #pragma unroll
            for (int ni = 0; ni < 8; ni++) {
                int c = cb + (ni << 3);
                float v0 = acc[mi][ni][half * 2];
                float v1 = acc[mi][ni][half * 2 + 1];
                if (ep == EP_RELU_REMAP) {
                    long long o = (long long)(r + r / 8191 + 1) * ldc + c;
                    v0 = fmaxf(v0 + bias[c], 0.f);
                    v1 = fmaxf(v1 + bias[c + 1], 0.f);
                    *(float2*)(C + o) = make_float2(v0, v1);
                } else if (ep == EP_SCALEQ) {
                    float sc = (c < 512) ? 0.125f : 1.0f;
                    *(float2*)(C + (long long)r * ldc + c) = make_float2(v0 * sc, v1 * sc);
                } else if (ep == EP_ADDBIAS) {
                    long long o = (long long)r * ldc + c;
                    float2 old = *(float2*)(C + o);
                    *(float2*)(C + o) = make_float2(old.x + v0 + bias[c],
                                                    old.y + v1 + bias[c + 1]);
                } else {
                    *(float2*)(C + (long long)r * ldc + c) = make_float2(v0, v1);
                }
            }
        }
    }
}

// ===================== agemm: tf32 GEMM, 128xN64 tile, exp-fused A ==========
// C[M,64] = alpha * softmaxA(A) @ B, A row-major [M,K], B row-major [K,64].
// batch z = bh*SPLIT + s.  aexp: A row r -> exp(v - rs.x) * rs.y.
__global__ void __launch_bounds__(256, 2) agemm_k(
    int M, int K,
    const float* __restrict__ A, int lda, long long sA1, long long sA2, long long sA3,
    const float* __restrict__ B, int ldb, long long sB1, long long sB2, long long sB3,
    float* __restrict__ C, long long sC1, long long sC2, long long sC3,
    int SPLIT, float alpha,
    const float2* __restrict__ rsA, long long rs1, long long rs2, int aexp)
{
    extern __shared__ unsigned dsm[];   // As: 2x4096 u32 | Bs: 2x2112 f32 = 49664B
    int z = blockIdx.z;
    int s = z % SPLIT;
    int bh = z / SPLIT;
    int hh = bh & 7, bb = bh >> 3;
    A   += (long long)bb * sA1 + (long long)hh * sA2 + (long long)s * sA3;
    B   += (long long)bb * sB1 + (long long)hh * sB2 + (long long)s * sB3;
    C   += (long long)bb * sC1 + (long long)hh * sC2 + (long long)s * sC3;
    rsA += bb * rs1 + hh * rs2;
    int row0 = blockIdx.y << 7;
    int tid = threadIdx.x, lane = tid & 31, wm = tid >> 5;

    unsigned sbase;
    asm("{ .reg .u64 t; cvta.to.shared.u64 t, %1; cvt.u32.u64 %0, t; }"
        : "=r"(sbase) : "l"(dsm));
    float* Bsm = (float*)(dsm + 8192);

    float acc[8][4];
    #pragma unroll
    for (int ni = 0; ni < 8; ni++)
        #pragma unroll
        for (int q = 0; q < 4; q++) acc[ni][q] = 0.f;

    int a_q = tid & 7, a_r0 = tid >> 3;       // A loader coords
    int b_n = tid & 63, b_kh = tid >> 6;      // B loader coords

    float4 pa[4];
    float pbv[8];

    auto fetch = [&](int k0) {
        #pragma unroll
        for (int it = 0; it < 4; it++) {
            int r = a_r0 + (it << 5);
            int gr = row0 + r;
            float4 v = *(const float4*)(A + (long long)gr * lda + k0 + (a_q << 2));
            if (aexp) {
                float2 st = rsA[gr];
                v.x = __expf(v.x - st.x) * st.y;
                v.y = __expf(v.y - st.x) * st.y;
                v.z = __expf(v.z - st.x) * st.y;
                v.w = __expf(v.w - st.x) * st.y;
            }
            pa[it] = v;
        }
        #pragma unroll
        for (int j = 0; j < 8; j++) {
            int k = (b_kh << 3) + j;
            pbv[j] = B[(long long)(k0 + k) * ldb + b_n];
        }
    };

    auto stash = [&](int st) {
        unsigned* Ab = dsm + st * 4096;
        #pragma unroll
        for (int it = 0; it < 4; it++) {
            int r = a_r0 + (it << 5);
            uint4 u;
            u.x = f2tf32(pa[it].x); u.y = f2tf32(pa[it].y);
            u.z = f2tf32(pa[it].z); u.w = f2tf32(pa[it].w);
            *(uint4*)&Ab[(r << 5) + ((a_q ^ (r & 7)) << 2)] = u;
        }
        float* Bb = Bsm + st * 2112;
        #pragma unroll
        for (int j = 0; j < 8; j++) {
            int k = (b_kh << 3) + j;
            Bb[b_n * 33 + k] = tf32f(pbv[j]);
        }
    };

    auto compute = [&](int st) {
        unsigned Ab = sbase + st * 16384u;
        const float* Bb = Bsm + st * 2112;
        int j = lane >> 3, rho = lane & 7;
        int g = lane >> 2, t = lane & 3;
        #pragma unroll
        for (int kt = 0; kt < 4; kt++) {
            unsigned a[4];
            {
                int row = (wm << 4) + ((j & 1) << 3) + rho;
                int quad = (kt << 1) + (j >> 1);
                unsigned ad = Ab + (((row << 5) + ((quad ^ (row & 7)) << 2)) << 2);
                asm volatile("ldmatrix.sync.aligned.m8n8.x4.shared.b16 {%0,%1,%2,%3}, [%4];"
                    : "=r"(a[0]), "=r"(a[1]), "=r"(a[2]), "=r"(a[3])
                    : "r"(ad));
            }
            #pragma unroll
            for (int ni = 0; ni < 8; ni++) {
                int n = (ni << 3) + g;
                unsigned b[2];
                b[0] = __float_as_uint(Bb[n * 33 + (kt << 3) + t]);
                b[1] = __float_as_uint(Bb[n * 33 + (kt << 3) + t + 4]);
                MMA_TF32(acc[ni], a, b);
            }
        }
    };

    fetch(0);
    int nch = K >> 5;
    for (int ch = 0; ch < nch; ch++) {
        stash(ch & 1);
        __syncthreads();
        if (ch + 1 < nch) fetch((ch + 1) << 5);
        compute(ch & 1);
        __syncthreads();
    }

    int g = lane >> 2, t = lane & 3;
    #pragma unroll
    for (int half = 0; half < 2; half++) {
        int r = row0 + (wm << 4) + (half << 3) + g;
        #pragma unroll
        for (int ni = 0; ni < 8; ni++) {
            int c = (ni << 3) + (t << 1);
            *(float2*)(C + (long long)r * 64 + c) =
                make_float2(acc[ni][half * 2] * alpha, acc[ni][half * 2 + 1] * alpha);
        }
    }
}

// ===================== pinv: persistent chain kernel ========================
__device__ __forceinline__ void gbar(unsigned target) {
    __syncthreads();
    if (threadIdx.x == 0) {
        __threadfence();
        atomicAdd(&g_bar, 1u);
        while (*(volatile unsigned*)&g_bar < target) {}
        __threadfence();
    }
    __syncthreads();
}

__device__ void pg_tile(const float* __restrict__ Ag, const float* __restrict__ Bg,
                        float* __restrict__ Cg, float alpha, int bmode, float bd,
                        float* ps)
{
    int bid = blockIdx.x;
    int tid = threadIdx.x;
    int lane = tid & 31, wid = tid >> 5;
    int wm = wid & 3, wn = wid >> 2;
    int col0 = (bid & 1) << 7;
    int row0 = ((bid >> 1) & 3) << 6;
    long long zo = (long long)(bid >> 3) << 16;
    Ag += zo; Bg += zo; Cg += zo;

    float acc[8][4];
    #pragma unroll
    for (int ni = 0; ni < 8; ni++)
        #pragma unroll
        for (int q = 0; q < 4; q++) acc[ni][q] = 0.f;

    int ar = tid >> 2, aq = tid & 3;
    int bn = tid & 127, bkh = tid >> 7;

    float4 pa;
    float pbv[8];

    auto fetch = [&](int k0) {
        pa = *(const float4*)(Ag + ((long long)(row0 + ar) << 8) + k0 + (aq << 2));
        #pragma unroll
        for (int j = 0; j < 8; j++) {
            int gk = k0 + (bkh << 3) + j;
            int gn = col0 + bn;
            float v = Bg[((long long)gk << 8) + gn];
            if (bmode) v = (gk == gn ? bd : 0.f) - v;
            pbv[j] = v;
        }
    };

    auto stash = [&](int s) {
        float* Sb = ps + s * 7680;
        float4 h, l;
        h.x = tf32f(pa.x); h.y = tf32f(pa.y); h.z = tf32f(pa.z); h.w = tf32f(pa.w);
        l.x = tf32f(pa.x - h.x); l.y = tf32f(pa.y - h.y);
        l.z = tf32f(pa.z - h.z); l.w = tf32f(pa.w - h.w);
        *(float4*)&Sb[ar * 20 + (aq << 2)] = h;
        *(float4*)&Sb[1280 + ar * 20 + (aq << 2)] = l;
        float4 bh0, bh1, bl0, bl1;
        bh0.x = tf32f(pbv[0]); bh0.y = tf32f(pbv[1]); bh0.z = tf32f(pbv[2]); bh0.w = tf32f(pbv[3]);
        bh1.x = tf32f(pbv[4]); bh1.y = tf32f(pbv[5]); bh1.z = tf32f(pbv[6]); bh1.w = tf32f(pbv[7]);
        bl0.x = tf32f(pbv[0] - bh0.x); bl0.y = tf32f(pbv[1] - bh0.y);
        bl0.z = tf32f(pbv[2] - bh0.z); bl0.w = tf32f(pbv[3] - bh0.w);
        bl1.x = tf32f(pbv[4] - bh1.x); bl1.y = tf32f(pbv[5] - bh1.y);
        bl1.z = tf32f(pbv[6] - bh1.z); bl1.w = tf32f(pbv[7] - bh1.w);
        *(float4*)&Sb[2560 + bn * 20 + (bkh << 3)] = bh0;
        *(float4*)&Sb[2560 + bn * 20 + (bkh << 3) + 4] = bh1;
        *(float4*)&Sb[5120 + bn * 20 + (bkh << 3)] = bl0;
        *(float4*)&Sb[5120 + bn * 20 + (bkh << 3) + 4] = bl1;
    };

    auto compute = [&](int s) {
        const float* Sb = ps + s * 7680;
        int g = lane >> 2, t = lane & 3;
        #pragma unroll
        for (int kt = 0; kt < 2; kt++) {
            int kb = kt << 3;
            int m = (wm << 4) + g;
            unsigned ah[4], al[4];
            ah[0] = __float_as_uint(Sb[m * 20 + kb + t]);
            ah[1] = __float_as_uint(Sb[(m + 8) * 20 + kb + t]);
            ah[2] = __float_as_uint(Sb[m * 20 + kb + t + 4]);
            ah[3] = __float_as_uint(Sb[(m + 8) * 20 + kb + t + 4]);
            al[0] = __float_as_uint(Sb[1280 + m * 20 + kb + t]);
            al[1] = __float_as_uint(Sb[1280 + (m + 8) * 20 + kb + t]);
            al[2] = __float_as_uint(Sb[1280 + m * 20 + kb + t + 4]);
            al[3] = __float_as_uint(Sb[1280 + (m + 8) * 20 + kb + t + 4]);
            #pragma unroll
            for (int ni = 0; ni < 8; ni++) {
                int n = (wn << 6) + (ni << 3) + g;
                unsigned bh[2], bl[2];
                bh[0] = __float_as_uint(Sb[2560 + n * 20 + kb + t]);
                bh[1] = __float_as_uint(Sb[2560 + n * 20 + kb + t + 4]);
                bl[0] = __float_as_uint(Sb[5120 + n * 20 + kb + t]);
                bl[1] = __float_as_uint(Sb[5120 + n * 20 + kb + t + 4]);
                MMA_TF32(acc[ni], ah, bh);
                MMA_TF32(acc[ni], ah, bl);
                MMA_TF32(acc[ni], al, bh);
            }
        }
    };

    fetch(0);
    for (int ch = 0; ch < 16; ch++) {
        stash(ch & 1);
        __syncthreads();
        if (ch < 15) fetch((ch + 1) << 4);
        compute(ch & 1);
        __syncthreads();
    }

    int g = lane >> 2, t = lane & 3;
    #pragma unroll
    for (int half = 0; half < 2; half++) {
        int r = row0 + (wm << 4) + (half << 3) + g;
        #pragma unroll
        for (int ni = 0; ni < 8; ni++) {
            int c = col0 + (wn << 6) + (ni << 3) + (t << 1);
            *(float2*)(Cg + ((long long)r << 8) + c) =
                make_float2(acc[ni][half * 2] * alpha, acc[ni][half * 2 + 1] * alpha);
        }
    }
}

__global__ void __launch_bounds__(256) pinvchain_k()
{
    extern __shared__ float ps[];
    int bid = blockIdx.x;
    int tid = threadIdx.x;

    if (bid < 16) {
        const float* S = g_S2 + ((long long)bid << 16);
        float rs = 0.f, cs = 0.f;
        for (int j = 0; j < 256; j++) {
            rs += S[(tid << 8) + j];
            cs += S[(j << 8) + tid];
        }
        float rm = blockReduce(rs, true);
        float cm = blockReduce(cs, true);
        if (tid == 0) {
            atomicMax(&g_scale[0], __float_as_uint(rm));
            atomicMax(&g_scale[1], __float_as_uint(cm));
        }
    }
    gbar(128);

    {
        float inv = 1.0f / (__uint_as_float(g_scale[0]) * __uint_as_float(g_scale[1]));
        #pragma unroll
        for (int e = 0; e < 32; e++) {
            int idx = (bid << 13) + (e << 8) + tid;
            int z = idx >> 16, r = idx & 65535;
            int i = r >> 8, j = r & 255;
            g_Zb[((long long)z << 16) + (i << 8) + j] =
                g_S2[((long long)z << 16) + (j << 8) + i] * inv;
        }
    }
    gbar(256);

    unsigned t = 256;
    for (int it = 0; it < 6; it++) {
        float* Zi = (it & 1) ? g_Z2b : g_Zb;
        float* Zo = (it & 1) ? g_Zb : g_Z2b;
        pg_tile(g_S2, Zi, g_Pb, 1.f, 0, 0.f, ps);  t += 128; gbar(t);
        pg_tile(g_Pb, g_Pb, g_T2b, 1.f, 1, 7.f, ps);  t += 128; gbar(t);
        pg_tile(g_Pb, g_T2b, g_Tb, 1.f, 1, 15.f, ps);  t += 128; gbar(t);
        pg_tile(Zi, g_Tb, Zo, 0.25f, 1, 13.f, ps);  t += 128; gbar(t);
    }
}

__global__ void reset_k() { g_scale[0] = 0u; g_scale[1] = 0u; g_bar = 0u; }

// ------------------------- layernorm (rows of 512) --------------------------
__global__ void __launch_bounds__(256) ln_k(const float* __restrict__ X, float* __restrict__ Y,
                                            const float* __restrict__ g, const float* __restrict__ b)
{
    long long row = blockIdx.x;
    const float* x = X + row * DIMM;
    float* y = Y + row * DIMM;
    int t = threadIdx.x;
    float v0 = x[t], v1 = x[t + 256];
    float mu  = blockReduce(v0 + v1, false) * (1.f / 512.f);
    float d0 = v0 - mu, d1 = v1 - mu;
    float var = blockReduce(d0 * d0 + d1 * d1, false) * (1.f / 512.f);
    float inv = rsqrtf(var + 1e-5f);
    y[t]       = d0 * inv * g[t]       + b[t];
    y[t + 256] = d1 * inv * g[t + 256] + b[t + 256];
}

// ------------------------- softmax (S2 only) --------------------------------
__global__ void __launch_bounds__(256) softmax256_k(float* __restrict__ S)
{
    long long row = ((long long)blockIdx.x << 3) + (threadIdx.x >> 5);
    int lane = threadIdx.x & 31;
    float* s = S + (row << 8);
    float4 va = *(float4*)(s + (lane << 3));
    float4 vb = *(float4*)(s + (lane << 3) + 4);
    float m = fmaxf(fmaxf(fmaxf(va.x, va.y), fmaxf(va.z, va.w)),
                    fmaxf(fmaxf(vb.x, vb.y), fmaxf(vb.z, vb.w)));
    #pragma unroll
    for (int o = 16; o > 0; o >>= 1) m = fmaxf(m, __shfl_xor_sync(0xffffffffu, m, o));
    va.x = __expf(va.x - m); va.y = __expf(va.y - m); va.z = __expf(va.z - m); va.w = __expf(va.w - m);
    vb.x = __expf(vb.x - m); vb.y = __expf(vb.y - m); vb.z = __expf(vb.z - m); vb.w = __expf(vb.w - m);
    float sum = va.x + va.y + va.z + va.w + vb.x + vb.y + vb.z + vb.w;
    #pragma unroll
    for (int o = 16; o > 0; o >>= 1) sum += __shfl_xor_sync(0xffffffffu, sum, o);
    float inv = 1.f / sum;
    va.x *= inv; va.y *= inv; va.z *= inv; va.w *= inv;
    vb.x *= inv; vb.y *= inv; vb.z *= inv; vb.w *= inv;
    *(float4*)(s + (lane << 3)) = va;
    *(float4*)(s + (lane << 3) + 4) = vb;
}

// ------------------------- row stats ----------------------------------------
__global__ void __launch_bounds__(256) rowstat256_k(const float* __restrict__ S,
                                                    float2* __restrict__ RS)
{
    long long row = ((long long)blockIdx.x << 3) + (threadIdx.x >> 5);
    int lane = threadIdx.x & 31;
    const float* s = S + (row << 8);
    float4 va = *(const float4*)(s + (lane << 3));
    float4 vb = *(const float4*)(s + (lane << 3) + 4);
    float m = fmaxf(fmaxf(fmaxf(va.x, va.y), fmaxf(va.z, va.w)),
                    fmaxf(fmaxf(vb.x, vb.y), fmaxf(vb.z, vb.w)));
    #pragma unroll
    for (int o = 16; o > 0; o >>= 1) m = fmaxf(m, __shfl_xor_sync(0xffffffffu, m, o));
    float sum = __expf(va.x - m) + __expf(va.y - m) + __expf(va.z - m) + __expf(va.w - m)
              + __expf(vb.x - m) + __expf(vb.y - m) + __expf(vb.z - m) + __expf(vb.w - m);
    #pragma unroll
    for (int o = 16; o > 0; o >>= 1) sum += __shfl_xor_sync(0xffffffffu, sum, o);
    if (lane == 0) RS[row] = make_float2(m, 1.f / sum);
}

__global__ void __launch_bounds__(256) rowstatbig_k(const float* __restrict__ S,
                                                    float2* __restrict__ RS, int cols)
{
    extern __shared__ float buf[];
    long long row = blockIdx.x;
    const float* s = S + row * cols;
    int t = threadIdx.x;
    float mx = -1e30f;
    for (int i = t; i < cols; i += 256) { float v = s[i]; buf[i] = v; mx = fmaxf(mx, v); }
    float bmax = blockReduce(mx, true);
    float sum = 0.f;
    for (int i = t; i < cols; i += 256) sum += __expf(buf[i] - bmax);
    float bsum = blockReduce(sum, false);
    if (t == 0) RS[row] = make_float2(bmax, 1.f / bsum);
}

// ------------------------- landmarks ----------------------------------------
__global__ void __launch_bounds__(64) landmark_k()
{
    int zz = blockIdx.x;
    int mi = zz & 255, bh = zz >> 8;
    int b = bh >> 3, h = bh & 7;
    int d = threadIdx.x;
    const float* base = g_QKV + (long long)(b * NF + mi * 32) * QD + h * 64 + d;
    float sq = 0.f, sk = 0.f;
    #pragma unroll 8
    for (int il = 0; il < 32; il++) {
        sq += base[(long long)il * QD];
        sk += base[(long long)il * QD + 512];
    }
    long long o = ((long long)bh * LM + mi) * DH + d;
    g_QL[o] = sq * (1.f / 32.f);
    g_KL[o] = sk * (1.f / 32.f);
}

// ------------------------- split-K reduce for AV ----------------------------
__global__ void __launch_bounds__(256) avreduce_k()
{
    int idx = blockIdx.x * 256 + threadIdx.x;
    int bh = idx >> 14;
    int r  = idx & 16383;
    const float* p = g_AVp + ((long long)bh << 17);
    float s = 0.f;
    #pragma unroll
    for (int k = 0; k < KSPL; k++) s += p[(k << 14) + r];
    g_AV[idx] = s;
}

// ------------------------- depthwise conv residual --------------------------
__global__ void __launch_bounds__(256) conv_k(const float* __restrict__ cw)
{
    __shared__ float sv[160 * 64];
    __shared__ float sw[KER];
    int tile = blockIdx.x;
    int bh = blockIdx.y;
    int b = bh >> 3, h = bh & 7;
    int n0 = tile * 128;
    int t = threadIdx.x;
    if (t < KER) sw[t] = cw[h * KER + t];
    for (int idx = t; idx < 160 * 64; idx += 256) {
        int r = idx >> 6, d = idx & 63;
        int nn = n0 - 16 + r;
        float v = 0.f;
        if (nn >= 0 && nn < NF) v = g_QKV[(long long)(b * NF + nn) * QD + 1024 + h * 64 + d];
        sv[idx] = v;
    }
    __syncthreads();
    int d = t & 63, r0 = t >> 6;
    for (int rr = r0; rr < 128; rr += 4) {
        float a = 0.f;
        #pragma unroll
        for (int k = 0; k < KER; k++) a += sv[(rr + k) * 64 + d] * sw[k];
        long long o = ((long long)bh * NF + n0 + rr) * DH + d;
        g_OH[o] += a;
    }
}

// ------------------------- final LN + head ----------------------------------
__global__ void __launch_bounds__(256) final_k(const float* __restrict__ fg, const float* __restrict__ fb,
                                               const float* __restrict__ w2, const float* __restrict__ b2,
                                               float* __restrict__ out)
{
    int b = blockIdx.x;
    const float* x = g_X + (long long)b * NF * DIMM;
    int t = threadIdx.x;
    float v0 = x[t], v1 = x[t + 256];
    float mu  = blockReduce(v0 + v1, false) * (1.f / 512.f);
    float d0 = v0 - mu, d1 = v1 - mu;
    float var = blockReduce(d0 * d0 + d1 * d1, false) * (1.f / 512.f);
    float inv = rsqrtf(var + 1e-5f);
    float n0 = d0 * inv * fg[t]       + fb[t];
    float n1 = d1 * inv * fg[t + 256] + fb[t + 256];
    float p0 = n0 * w2[2 * t]     + n1 * w2[2 * (t + 256)];
    float p1 = n0 * w2[2 * t + 1] + n1 * w2[2 * (t + 256) + 1];
    p0 = blockReduce(p0, false);
    p1 = blockReduce(p1, false);
    if (t == 0) {
        out[b * 2 + 0] = p0 + b2[0];
        out[b * 2 + 1] = p1 + b2[1];
    }
}

// ------------------------- host orchestration -------------------------------
static inline void mgemm2(int M, int N, int K,
                          const float* A, int lda, long long sA1, long long sA2, int amode,
                          const float* BT, int ldbt, long long sBT1, long long sBT2,
                          float* C, int ldc, long long sC1, long long sC2,
                          int batch, int ep, const float* bias)
{
    cudaFuncSetAttribute(mgemm2_k, cudaFuncAttributeMaxDynamicSharedMemorySize, 65536);
    dim3 g(N >> 7, (M + 127) >> 7, batch);
    mgemm2_k<<<g, 256, 65536>>>(M, K, A, lda, sA1, sA2, amode, BT, ldbt, sBT1, sBT2,
                                C, ldc, sC1, sC2, ep, bias);
}

static inline void agemm(int M, int K,
                         const float* A, int lda, long long sA1, long long sA2, long long sA3,
                         const float* B, int ldb, long long sB1, long long sB2, long long sB3,
                         float* C, long long sC1, long long sC2, long long sC3,
                         int SPLIT, int batchZ, float alpha,
                         const float2* rsA, long long rs1, long long rs2, int aexp)
{
    cudaFuncSetAttribute(agemm_k, cudaFuncAttributeMaxDynamicSharedMemorySize, 49664);
    dim3 g(1, M >> 7, batchZ);
    agemm_k<<<g, 256, 49664>>>(M, K, A, lda, sA1, sA2, sA3, B, ldb, sB1, sB2, sB3,
                               C, sC1, sC2, sC3, SPLIT, alpha, rsA, rs1, rs2, aexp);
}

extern "C" void kernel_launch(void* const* d_in, const int* in_sizes, int n_in,
                              void* d_out, int out_size)
{
    const float* h_in  = (const float*)d_in[0];
    const float* w1    = (const float*)d_in[1];
    const float* b1    = (const float*)d_in[2];
    const float* clst  = (const float*)d_in[3];
    const float* ln_g  = (const float*)d_in[4];
    const float* ln_b  = (const float*)d_in[5];
    const float* wqkv  = (const float*)d_in[6];
    const float* wout  = (const float*)d_in[7];
    const float* bout  = (const float*)d_in[8];
    const float* cw    = (const float*)d_in[9];
    const float* fg    = (const float*)d_in[10];
    const float* fb    = (const float*)d_in[11];
    const float* w2    = (const float*)d_in[12];
    const float* b2    = (const float*)d_in[13];
    float* out = (float*)d_out;

    float *X, *XN, *QKV, *QL, *KL, *S1, *S2, *S3, *Z, *AV, *AVp, *ZAV, *OH, *WT;
    float2 *RS1, *RS3;
    cudaGetSymbolAddress((void**)&X,   g_X);
    cudaGetSymbolAddress((void**)&XN,  g_XN);
    cudaGetSymbolAddress((void**)&QKV, g_QKV);
    cudaGetSymbolAddress((void**)&QL,  g_QL);
    cudaGetSymbolAddress((void**)&KL,  g_KL);
    cudaGetSymbolAddress((void**)&S1,  g_S1);
    cudaGetSymbolAddress((void**)&S2,  g_S2);
    cudaGetSymbolAddress((void**)&S3,  g_S3);
    cudaGetSymbolAddress((void**)&Z,   g_Zb);
    cudaGetSymbolAddress((void**)&AV,  g_AV);
    cudaGetSymbolAddress((void**)&AVp, g_AVp);
    cudaGetSymbolAddress((void**)&ZAV, g_ZAV);
    cudaGetSymbolAddress((void**)&OH,  g_OH);
    cudaGetSymbolAddress((void**)&WT,  g_WT);
    cudaGetSymbolAddress((void**)&RS1, g_RS1);
    cudaGetSymbolAddress((void**)&RS3, g_RS3);

    const long long SQb = (long long)NF * QD;
    const long long S2s = (long long)LM * LM;
    const long long S1s = (long long)NF * LM;
    const long long AVs = (long long)LM * DH;
    const long long OHs = (long long)NF * DH;

    cudaFuncSetAttribute(pinvchain_k, cudaFuncAttributeMaxDynamicSharedMemorySize, 61440);

    // #1: all weight transposes + cls fill
    transAll_k<<<2564, 256>>>(w1, wqkv, wout, clst);

    // #2: input projection
    mgemm2(NB * 8191, DIMM, 1024, h_in, 1024, 0, 0, 0, WT + OW1, 1024, 0, 0,
           X, DIMM, 0, 0, 1, EP_RELU_REMAP, b1);

    for (int L = 0; L < 2; L++) {
        // #3 (L=0): layernorm
        ln_k<<<TOT, 256>>>(X, XN, ln_g + L * DIMM, ln_b + L * DIMM);

        // #4 (L=0): qkv GEMM  <-- ncu capture slot
        mgemm2(TOT, QD, DIMM, XN, DIMM, 0, 0, 0, WT + OQKV(L), DIMM, 0, 0,
               QKV, QD, 0, 0, 1, EP_SCALEQ, nullptr);

        landmark_k<<<NBH * LM, 64>>>();

        // sim2 = QL @ KL^T, softmax
        mgemm2(LM, LM, DH, QL, DH, 8 * AVs, AVs, 0, KL, DH, 8 * AVs, AVs,
               S2, LM, 8 * S2s, S2s, NBH, EP_NONE, nullptr);
        softmax256_k<<<NBH * LM / 8, 256>>>(S2);

        // Moore-Penrose pinv of S2 -> Z : persistent chain
        reset_k<<<1, 1>>>();
        pinvchain_k<<<128, 256, 61440>>>();

        // sim1 = Q @ KL^T (raw) + row stats
        mgemm2(NF, LM, DH, QKV, QD, SQb, 64, 0, KL, DH, 8 * AVs, AVs,
               S1, LM, 8 * S1s, S1s, NBH, EP_NONE, nullptr);
        rowstat256_k<<<NBH * NF / 8, 256>>>(S1, RS1);

        // sim3 = QL @ K^T (raw) + row stats
        mgemm2(LM, NF, DH, QL, DH, 8 * AVs, AVs, 0, QKV + 512, QD, SQb, 64,
               S3, NF, 8 * S1s, S1s, NBH, EP_NONE, nullptr);
        rowstatbig_k<<<NBH * LM, 256, NF * 4>>>(S3, RS3, NF);

        // AV = softmax(sim3) @ V  (tensor, exp fused, split-K by 8)
        agemm(LM, NF / KSPL,
              S3, NF, 8 * S1s, S1s, 1024,
              QKV + 1024, QD, SQb, 64, 1024LL * QD,
              AVp, 64 * AVs, 8 * AVs, AVs,
              KSPL, NBH * KSPL, 1.f, RS3, 8 * LM, LM, 1);
        avreduce_k<<<1024, 256>>>();

        // ZAV = Z @ AV  (tensor)
        agemm(LM, LM,
              Z, LM, 8 * S2s, S2s, 0,
              AV, DH, 8 * AVs, AVs, 0,
              ZAV, 8 * AVs, AVs, 0,
              1, NBH, 1.f, RS3, 0, 0, 0);

        // OH = softmax(sim1) @ ZAV  (tensor, exp fused)
        agemm(NF, LM,
              S1, LM, 8 * S1s, S1s, 0,
              ZAV, DH, 8 * AVs, AVs, 0,
              OH, 8 * OHs, OHs, 0,
              1, NBH, 1.f, RS1, 8LL * NF, NF, 1);

        // OH += depthwise conv residual of V
        { dim3 g(NF / 128, NBH); conv_k<<<g, 256>>>(cw + L * NH * KER); }

        // X += OH(head-layout) @ Wout + bout
        mgemm2(TOT, DIMM, DIMM, OH, 0, 0, 0, 1, WT + OOUT(L), DIMM, 0, 0,
               X, DIMM, 0, 0, 1, EP_ADDBIAS, bout + L * DIMM);
    }

    final_k<<<NB, 256>>>(fg, fb, w2, b2, out);
}

// round 12
// speedup vs baseline: 2.6734x; 1.0252x over previous
#include <cuda_runtime.h>

#define NB   2
#define NF   8192
#define DIMM 512
#define NH   8
#define DH   64
#define LM   256
#define QD   1536
#define TOT  (NB*NF)    // 16384
#define NBH  (NB*NH)    // 16
#define KER  33
#define KSPL 8

// ------------------------- scratch (device globals, no allocs) -------------
__device__ float g_X  [TOT*DIMM];
__device__ float g_XN [TOT*DIMM];
__device__ float g_QKV[TOT*QD];
__device__ float g_QL [NBH*LM*DH];
__device__ float g_KL [NBH*LM*DH];
__device__ float g_S1 [NBH*NF*LM];
__device__ float g_S3 [NBH*LM*NF];
__device__ float g_S2 [NBH*LM*LM];
__device__ float g_Zb [NBH*LM*LM];
__device__ float g_Z2b[NBH*LM*LM];
__device__ float g_Pb [NBH*LM*LM];
__device__ float g_Tb [NBH*LM*LM];
__device__ float g_T2b[NBH*LM*LM];
__device__ float g_AV [NBH*LM*DH];
__device__ float g_AVp[NBH*KSPL*LM*DH];
__device__ float g_ZAV[NBH*LM*DH];
__device__ float g_OH [NBH*NF*DH];
__device__ float g_WT [2621440];
__device__ float2 g_RS1[NBH*NF];
__device__ float2 g_RS3[NBH*LM];
__device__ float2 g_RSp[NBH*NF*2];     // softmax partials (also fits sim3: 4096*64)
__device__ unsigned int g_scale[2];
__device__ unsigned int g_bar;

enum { EP_NONE = 0, EP_RELU_REMAP = 1, EP_SCALEQ = 2, EP_ADDBIAS = 3 };

#define OW1   0
#define OQKV(L) (524288 + (L) * 786432)
#define OOUT(L) (2097152 + (L) * 262144)

__device__ __forceinline__ unsigned f2tf32(float f) {
    unsigned r;
    asm("cvt.rna.tf32.f32 %0, %1;" : "=r"(r) : "f"(f));
    return r;
}
__device__ __forceinline__ float tf32f(float f) {
    return __uint_as_float(f2tf32(f));
}

#define MMA_TF32(d, a, b) \
    asm volatile("mma.sync.aligned.m16n8k8.row.col.f32.tf32.tf32.f32 " \
        "{%0,%1,%2,%3}, {%4,%5,%6,%7}, {%8,%9}, {%0,%1,%2,%3};" \
        : "+f"((d)[0]), "+f"((d)[1]), "+f"((d)[2]), "+f"((d)[3]) \
        : "r"((a)[0]), "r"((a)[1]), "r"((a)[2]), "r"((a)[3]), \
          "r"((b)[0]), "r"((b)[1]))

// ------------------------- reductions --------------------------------------
__device__ __forceinline__ float blockReduce(float v, bool domax) {
    __shared__ float sh[32];
    __syncthreads();
    #pragma unroll
    for (int o = 16; o > 0; o >>= 1) {
        float w = __shfl_down_sync(0xffffffffu, v, o);
        v = domax ? fmaxf(v, w) : v + w;
    }
    int lane = threadIdx.x & 31, wid = threadIdx.x >> 5;
    if (lane == 0) sh[wid] = v;
    __syncthreads();
    int nw = (blockDim.x + 31) >> 5;
    if (wid == 0) {
        v = (lane < nw) ? sh[lane] : (domax ? -1e30f : 0.f);
        #pragma unroll
        for (int o = 16; o > 0; o >>= 1) {
            float w = __shfl_down_sync(0xffffffffu, v, o);
            v = domax ? fmaxf(v, w) : v + w;
        }
        if (lane == 0) sh[0] = v;
    }
    __syncthreads();
    return sh[0];
}

// ------------------- fused transposes + cls (ONE launch) --------------------
__device__ __forceinline__ void doTrans(const float* __restrict__ src,
                                        float* __restrict__ dst,
                                        int K, int N, int kt, int nt)
{
    __shared__ float t[32][33];
    int kb = kt << 5, nb = nt << 5;
    int x = threadIdx.x & 31, y = threadIdx.x >> 5;
    #pragma unroll
    for (int i = 0; i < 32; i += 8)
        t[y + i][x] = src[(long long)(kb + y + i) * N + nb + x];
    __syncthreads();
    #pragma unroll
    for (int i = 0; i < 32; i += 8)
        dst[(long long)(nb + y + i) * K + kb + x] = t[x][y + i];
}

__global__ void __launch_bounds__(256) transAll_k(
    const float* __restrict__ w1, const float* __restrict__ wqkv,
    const float* __restrict__ wout, const float* __restrict__ clst)
{
    int b = blockIdx.x;
    if (b < 512) {
        doTrans(w1, g_WT + OW1, 1024, DIMM, b & 31, b >> 5);
    } else if (b < 2048) {
        int L = (b - 512) / 768, bb = (b - 512) % 768;
        doTrans(wqkv + (long long)L * DIMM * QD, g_WT + OQKV(L), DIMM, QD, bb & 15, bb >> 4);
    } else if (b < 2560) {
        int L = (b - 2048) / 256, bb = (b - 2048) % 256;
        doTrans(wout + (long long)L * DIMM * DIMM, g_WT + OOUT(L), DIMM, DIMM, bb & 15, bb >> 4);
    } else {
        int idx = (b - 2560) * 256 + threadIdx.x;
        int bb = idx >> 9, c = idx & 511;
        g_X[(long long)bb * NF * DIMM + c] = clst[c];
    }
}

// ===================== mgemm2: cp.async + ldmatrix tf32, 128x128, 2 CTA/SM ==
__device__ __forceinline__ void cp16(unsigned dst, const void* src, int nbytes) {
    asm volatile("cp.async.cg.shared.global [%0], [%1], 16, %2;"
                 :: "r"(dst), "l"(src), "r"(nbytes) : "memory");
}

template<int STAT>
__global__ void __launch_bounds__(256, 2) mgemm2_k(
    int M, int K,
    const float* __restrict__ A, int lda, long long sA1, long long sA2, int amode,
    const float* __restrict__ BT, int ldbt, long long sBT1, long long sBT2,
    float* __restrict__ C, int ldc, long long sC1, long long sC2,
    int ep, const float* __restrict__ bias,
    float2* __restrict__ RSp, long long rsp1, long long rsp2)
{
    extern __shared__ float smem[];   // 2 stages x (A 16KB + B 16KB) = 64KB
    int tid = threadIdx.x;
    int lane = tid & 31, wid = tid >> 5;
    int wm = wid & 3, wn = wid >> 2;
    int row0 = blockIdx.y << 7, col0 = blockIdx.x << 7;
    int z = blockIdx.z;
    A  += (long long)(z >> 3) * sA1 + (long long)(z & 7) * sA2;
    BT += (long long)(z >> 3) * sBT1 + (long long)(z & 7) * sBT2;
    C  += (long long)(z >> 3) * sC1 + (long long)(z & 7) * sC2;
    if (STAT) RSp += (long long)(z >> 3) * rsp1 + (long long)(z & 7) * rsp2;

    unsigned sbase;
    asm("{ .reg .u64 t; cvta.to.shared.u64 t, %1; cvt.u32.u64 %0, t; }"
        : "=r"(sbase) : "l"(smem));

    float acc[2][8][4];
    #pragma unroll
    for (int mi = 0; mi < 2; mi++)
        #pragma unroll
        for (int ni = 0; ni < 8; ni++)
            #pragma unroll
            for (int q = 0; q < 4; q++) acc[mi][ni][q] = 0.f;

    auto fill = [&](int s, int k0) {
        unsigned Ab = sbase + s * 32768u;
        unsigned Bb = Ab + 16384u;
        #pragma unroll
        for (int it = 0; it < 4; it++) {
            int idx = (it << 8) + tid;
            int q = idx & 7, r = idx >> 3;
            int gr = row0 + r;
            const float* src;
            int nb = 16;
            if (amode == 0) {
                int gra = gr < M ? gr : (M - 1);
                if (gr >= M) nb = 0;
                src = A + (long long)gra * lda + k0 + (q << 2);
            } else {
                int k = k0 + (q << 2);
                int h = k >> 6, d = k & 63;
                src = A + ((((long long)(gr >> 13) << 3) + h) * 8192 + (gr & 8191)) * 64 + d;
            }
            unsigned dst = Ab + (((r << 5) + ((q ^ (r & 7)) << 2)) << 2);
            cp16(dst, src, nb);
        }
        #pragma unroll
        for (int it = 0; it < 4; it++) {
            int idx = (it << 8) + tid;
            int q = idx & 7, n = idx >> 3;
            const float* src = BT + (long long)(col0 + n) * ldbt + k0 + (q << 2);
            unsigned dst = Bb + (((n << 5) + ((q ^ (n & 7)) << 2)) << 2);
            cp16(dst, src, 16);
        }
        asm volatile("cp.async.commit_group;" ::: "memory");
    };

    auto compute = [&](int s) {
        unsigned Ab = sbase + s * 32768u;
        unsigned Bb = Ab + 16384u;
        int j = lane >> 3, rho = lane & 7;
        #pragma unroll
        for (int kt = 0; kt < 4; kt++) {
            unsigned a[2][4];
            #pragma unroll
            for (int mi = 0; mi < 2; mi++) {
                int row = (wm << 5) + (mi << 4) + ((j & 1) << 3) + rho;
                int quad = (kt << 1) + (j >> 1);
                unsigned ad = Ab + (((row << 5) + ((quad ^ (row & 7)) << 2)) << 2);
                asm volatile("ldmatrix.sync.aligned.m8n8.x4.shared.b16 {%0,%1,%2,%3}, [%4];"
                    : "=r"(a[mi][0]), "=r"(a[mi][1]), "=r"(a[mi][2]), "=r"(a[mi][3])
                    : "r"(ad));
            }
            unsigned b[8][2];
            #pragma unroll
            for (int np = 0; np < 4; np++) {
                int row = (((wn << 3) + (np << 1) + (j >> 1)) << 3) + rho;
                int quad = (kt << 1) + (j & 1);
                unsigned bd = Bb + (((row << 5) + ((quad ^ (row & 7)) << 2)) << 2);
                asm volatile("ldmatrix.sync.aligned.m8n8.x4.shared.b16 {%0,%1,%2,%3}, [%4];"
                    : "=r"(b[np * 2][0]), "=r"(b[np * 2][1]),
                      "=r"(b[np * 2 + 1][0]), "=r"(b[np * 2 + 1][1])
                    : "r"(bd));
            }
            #pragma unroll
            for (int mi = 0; mi < 2; mi++)
                #pragma unroll
                for (int ni = 0; ni < 8; ni++)
                    MMA_TF32(acc[mi][ni], a[mi], b[ni]);
        }
    };

    fill(0, 0);
    int nch = K >> 5;
    for (int ch = 0; ch < nch; ch++) {
        if (ch + 1 < nch) {
            fill((ch + 1) & 1, (ch + 1) << 5);
            asm volatile("cp.async.wait_group 1;" ::: "memory");
        } else {
            asm volatile("cp.async.wait_group 0;" ::: "memory");
        }
        __syncthreads();
        compute(ch & 1);
        __syncthreads();
    }

    int rb = row0 + (wm << 5) + (lane >> 2);
    int cb = col0 + (wn << 6) + ((lane & 3) << 1);
    #pragma unroll
    for (int mi = 0; mi < 2; mi++) {
        #pragma unroll
        for (int half = 0; half < 2; half++) {
            int r = rb + (mi << 4) + (half << 3);
            if (r >= M) continue;
            #pragma unroll
            for (int ni = 0; ni < 8; ni++) {
                int c = cb + (ni << 3);
                float v0 = acc[mi][ni][half * 2];
                float v1 = acc[mi][ni][half * 2 + 1];
                if (ep == EP_RELU_REMAP) {
                    long long o = (long long)(r + r / 8191 + 1) * ldc + c;
                    v0 = fmaxf(v0 + bias[c], 0.f);
                    v1 = fmaxf(v1 + bias[c + 1], 0.f);
                    *(float2*)(C + o) = make_float2(v0, v1);
                } else if (ep == EP_SCALEQ) {
                    float sc = (c < 512) ? 0.125f : 1.0f;
                    *(float2*)(C + (long long)r * ldc + c) = make_float2(v0 * sc, v1 * sc);
                } else if (ep == EP_ADDBIAS) {
                    long long o = (long long)r * ldc + c;
                    float2 old = *(float2*)(C + o);
                    *(float2*)(C + o) = make_float2(old.x + v0 + bias[c],
                                                    old.y + v1 + bias[c + 1]);
                } else {
                    *(float2*)(C + (long long)r * ldc + c) = make_float2(v0, v1);
                }
            }
        }
    }

    // ---- streaming-softmax partial stats for this 128-col tile -------------
    if (STAT) {
        float* red = smem;            // [128 rows][2 wn] maxes, then sums at +256
        int g = lane >> 2;
        float rowm[2][2];
        __syncthreads();
        #pragma unroll
        for (int mi = 0; mi < 2; mi++) {
            #pragma unroll
            for (int half = 0; half < 2; half++) {
                float m = -1e30f;
                #pragma unroll
                for (int ni = 0; ni < 8; ni++)
                    m = fmaxf(m, fmaxf(acc[mi][ni][half * 2], acc[mi][ni][half * 2 + 1]));
                m = fmaxf(m, __shfl_xor_sync(0xffffffffu, m, 1));
                m = fmaxf(m, __shfl_xor_sync(0xffffffffu, m, 2));
                if ((lane & 3) == 0) {
                    int rl = (wm << 5) + (mi << 4) + (half << 3) + g;
                    red[rl * 2 + wn] = m;
                }
            }
        }
        __syncthreads();
        #pragma unroll
        for (int mi = 0; mi < 2; mi++) {
            #pragma unroll
            for (int half = 0; half < 2; half++) {
                int rl = (wm << 5) + (mi << 4) + (half << 3) + g;
                rowm[mi][half] = fmaxf(red[rl * 2], red[rl * 2 + 1]);
            }
        }
        __syncthreads();
        #pragma unroll
        for (int mi = 0; mi < 2; mi++) {
            #pragma unroll
            for (int half = 0; half < 2; half++) {
                float m = rowm[mi][half];
                float s = 0.f;
                #pragma unroll
                for (int ni = 0; ni < 8; ni++)
                    s += __expf(acc[mi][ni][half * 2] - m) + __expf(acc[mi][ni][half * 2 + 1] - m);
                s += __shfl_xor_sync(0xffffffffu, s, 1);
                s += __shfl_xor_sync(0xffffffffu, s, 2);
                if ((lane & 3) == 0) {
                    int rl = (wm << 5) + (mi << 4) + (half << 3) + g;
                    red[256 + rl * 2 + wn] = s;
                }
            }
        }
        __syncthreads();
        if (wn == 0 && (lane & 3) == 0) {
            #pragma unroll
            for (int mi = 0; mi < 2; mi++) {
                #pragma unroll
                for (int half = 0; half < 2; half++) {
                    int rl = (wm << 5) + (mi << 4) + (half << 3) + g;
                    int gr = row0 + rl;
                    if (gr < M)
                        RSp[(long long)gr * gridDim.x + blockIdx.x] =
                            make_float2(rowm[mi][half],
                                        red[256 + rl * 2] + red[256 + rl * 2 + 1]);
                }
            }
        }
    }
}

// ------------------------- combine softmax partials -------------------------
__global__ void __launch_bounds__(256) combine_k(const float2* __restrict__ RSp,
                                                 float2* __restrict__ RS, int nblk)
{
    int row = blockIdx.x * 8 + (threadIdx.x >> 5);
    int lane = threadIdx.x & 31;
    const float2* p = RSp + (long long)row * nblk;
    float m = -1e30f;
    for (int i = lane; i < nblk; i += 32) m = fmaxf(m, p[i].x);
    #pragma unroll
    for (int o = 16; o > 0; o >>= 1) m = fmaxf(m, __shfl_xor_sync(0xffffffffu, m, o));
    float s = 0.f;
    for (int i = lane; i < nblk; i += 32) {
        float2 v = p[i];
        s += v.y * __expf(v.x - m);
    }
    #pragma unroll
    for (int o = 16; o > 0; o >>= 1) s += __shfl_xor_sync(0xffffffffu, s, o);
    if (lane == 0) RS[row] = make_float2(m, 1.f / s);
}

// ===================== agemm: tf32 GEMM, 128xN64 tile, exp-fused A ==========
__global__ void __launch_bounds__(256, 2) agemm_k(
    int M, int K,
    const float* __restrict__ A, int lda, long long sA1, long long sA2, long long sA3,
    const float* __restrict__ B, int ldb, long long sB1, long long sB2, long long sB3,
    float* __restrict__ C, long long sC1, long long sC2, long long sC3,
    int SPLIT, float alpha,
    const float2* __restrict__ rsA, long long rs1, long long rs2, int aexp)
{
    extern __shared__ unsigned dsm[];   // As: 2x4096 u32 | Bs: 2x2112 f32 = 49664B
    int z = blockIdx.z;
    int s = z % SPLIT;
    int bh = z / SPLIT;
    int hh = bh & 7, bb = bh >> 3;
    A   += (long long)bb * sA1 + (long long)hh * sA2 + (long long)s * sA3;
    B   += (long long)bb * sB1 + (long long)hh * sB2 + (long long)s * sB3;
    C   += (long long)bb * sC1 + (long long)hh * sC2 + (long long)s * sC3;
    rsA += bb * rs1 + hh * rs2;
    int row0 = blockIdx.y << 7;
    int tid = threadIdx.x, lane = tid & 31, wm = tid >> 5;

    unsigned sbase;
    asm("{ .reg .u64 t; cvta.to.shared.u64 t, %1; cvt.u32.u64 %0, t; }"
        : "=r"(sbase) : "l"(dsm));
    float* Bsm = (float*)(dsm + 8192);

    float acc[8][4];
    #pragma unroll
    for (int ni = 0; ni < 8; ni++)
        #pragma unroll
        for (int q = 0; q < 4; q++) acc[ni][q] = 0.f;

    int a_q = tid & 7, a_r0 = tid >> 3;
    int b_n = tid & 63, b_kh = tid >> 6;

    float4 pa[4];
    float pbv[8];

    auto fetch = [&](int k0) {
        #pragma unroll
        for (int it = 0; it < 4; it++) {
            int r = a_r0 + (it << 5);
            int gr = row0 + r;
            float4 v = *(const float4*)(A + (long long)gr * lda + k0 + (a_q << 2));
            if (aexp) {
                float2 st = rsA[gr];
                v.x = __expf(v.x - st.x) * st.y;
                v.y = __expf(v.y - st.x) * st.y;
                v.z = __expf(v.z - st.x) * st.y;
                v.w = __expf(v.w - st.x) * st.y;
            }
            pa[it] = v;
        }
        #pragma unroll
        for (int j = 0; j < 8; j++) {
            int k = (b_kh << 3) + j;
            pbv[j] = B[(long long)(k0 + k) * ldb + b_n];
        }
    };

    auto stash = [&](int st) {
        unsigned* Ab = dsm + st * 4096;
        #pragma unroll
        for (int it = 0; it < 4; it++) {
            int r = a_r0 + (it << 5);
            uint4 u;
            u.x = f2tf32(pa[it].x); u.y = f2tf32(pa[it].y);
            u.z = f2tf32(pa[it].z); u.w = f2tf32(pa[it].w);
            *(uint4*)&Ab[(r << 5) + ((a_q ^ (r & 7)) << 2)] = u;
        }
        float* Bb = Bsm + st * 2112;
        #pragma unroll
        for (int j = 0; j < 8; j++) {
            int k = (b_kh << 3) + j;
            Bb[b_n * 33 + k] = tf32f(pbv[j]);
        }
    };

    auto compute = [&](int st) {
        unsigned Ab = sbase + st * 16384u;
        const float* Bb = Bsm + st * 2112;
        int j = lane >> 3, rho = lane & 7;
        int g = lane >> 2, t = lane & 3;
        #pragma unroll
        for (int kt = 0; kt < 4; kt++) {
            unsigned a[4];
            {
                int row = (wm << 4) + ((j & 1) << 3) + rho;
                int quad = (kt << 1) + (j >> 1);
                unsigned ad = Ab + (((row << 5) + ((quad ^ (row & 7)) << 2)) << 2);
                asm volatile("ldmatrix.sync.aligned.m8n8.x4.shared.b16 {%0,%1,%2,%3}, [%4];"
                    : "=r"(a[0]), "=r"(a[1]), "=r"(a[2]), "=r"(a[3])
                    : "r"(ad));
            }
            #pragma unroll
            for (int ni = 0; ni < 8; ni++) {
                int n = (ni << 3) + g;
                unsigned b[2];
                b[0] = __float_as_uint(Bb[n * 33 + (kt << 3) + t]);
                b[1] = __float_as_uint(Bb[n * 33 + (kt << 3) + t + 4]);
                MMA_TF32(acc[ni], a, b);
            }
        }
    };

    fetch(0);
    int nch = K >> 5;
    for (int ch = 0; ch < nch; ch++) {
        stash(ch & 1);
        __syncthreads();
        if (ch + 1 < nch) fetch((ch + 1) << 5);
        compute(ch & 1);
        __syncthreads();
    }

    int g = lane >> 2, t = lane & 3;
    #pragma unroll
    for (int half = 0; half < 2; half++) {
        int r = row0 + (wm << 4) + (half << 3) + g;
        #pragma unroll
        for (int ni = 0; ni < 8; ni++) {
            int c = (ni << 3) + (t << 1);
            *(float2*)(C + (long long)r * 64 + c) =
                make_float2(acc[ni][half * 2] * alpha, acc[ni][half * 2 + 1] * alpha);
        }
    }
}

// ===================== pinv: persistent chain kernel ========================
__device__ __forceinline__ void gbar(unsigned target) {
    __syncthreads();
    if (threadIdx.x == 0) {
        __threadfence();
        atomicAdd(&g_bar, 1u);
        while (*(volatile unsigned*)&g_bar < target) {}
        __threadfence();
    }
    __syncthreads();
}

__device__ void pg_tile(const float* __restrict__ Ag, const float* __restrict__ Bg,
                        float* __restrict__ Cg, float alpha, int bmode, float bd,
                        float* ps)
{
    int bid = blockIdx.x;
    int tid = threadIdx.x;
    int lane = tid & 31, wid = tid >> 5;
    int wm = wid & 3, wn = wid >> 2;
    int col0 = (bid & 1) << 7;
    int row0 = ((bid >> 1) & 3) << 6;
    long long zo = (long long)(bid >> 3) << 16;
    Ag += zo; Bg += zo; Cg += zo;

    float acc[8][4];
    #pragma unroll
    for (int ni = 0; ni < 8; ni++)
        #pragma unroll
        for (int q = 0; q < 4; q++) acc[ni][q] = 0.f;

    int ar = tid >> 2, aq = tid & 3;
    int bn = tid & 127, bkh = tid >> 7;

    float4 pa;
    float pbv[8];

    auto fetch = [&](int k0) {
        pa = *(const float4*)(Ag + ((long long)(row0 + ar) << 8) + k0 + (aq << 2));
        #pragma unroll
        for (int j = 0; j < 8; j++) {
            int gk = k0 + (bkh << 3) + j;
            int gn = col0 + bn;
            float v = Bg[((long long)gk << 8) + gn];
            if (bmode) v = (gk == gn ? bd : 0.f) - v;
            pbv[j] = v;
        }
    };

    auto stash = [&](int s) {
        float* Sb = ps + s * 7680;
        float4 h, l;
        h.x = tf32f(pa.x); h.y = tf32f(pa.y); h.z = tf32f(pa.z); h.w = tf32f(pa.w);
        l.x = tf32f(pa.x - h.x); l.y = tf32f(pa.y - h.y);
        l.z = tf32f(pa.z - h.z); l.w = tf32f(pa.w - h.w);
        *(float4*)&Sb[ar * 20 + (aq << 2)] = h;
        *(float4*)&Sb[1280 + ar * 20 + (aq << 2)] = l;
        float4 bh0, bh1, bl0, bl1;
        bh0.x = tf32f(pbv[0]); bh0.y = tf32f(pbv[1]); bh0.z = tf32f(pbv[2]); bh0.w = tf32f(pbv[3]);
        bh1.x = tf32f(pbv[4]); bh1.y = tf32f(pbv[5]); bh1.z = tf32f(pbv[6]); bh1.w = tf32f(pbv[7]);
        bl0.x = tf32f(pbv[0] - bh0.x); bl0.y = tf32f(pbv[1] - bh0.y);
        bl0.z = tf32f(pbv[2] - bh0.z); bl0.w = tf32f(pbv[3] - bh0.w);
        bl1.x = tf32f(pbv[4] - bh1.x); bl1.y = tf32f(pbv[5] - bh1.y);
        bl1.z = tf32f(pbv[6] - bh1.z); bl1.w = tf32f(pbv[7] - bh1.w);
        *(float4*)&Sb[2560 + bn * 20 + (bkh << 3)] = bh0;
        *(float4*)&Sb[2560 + bn * 20 + (bkh << 3) + 4] = bh1;
        *(float4*)&Sb[5120 + bn * 20 + (bkh << 3)] = bl0;
        *(float4*)&Sb[5120 + bn * 20 + (bkh << 3) + 4] = bl1;
    };

    auto compute = [&](int s) {
        const float* Sb = ps + s * 7680;
        int g = lane >> 2, t = lane & 3;
        #pragma unroll
        for (int kt = 0; kt < 2; kt++) {
            int kb = kt << 3;
            int m = (wm << 4) + g;
            unsigned ah[4], al[4];
            ah[0] = __float_as_uint(Sb[m * 20 + kb + t]);
            ah[1] = __float_as_uint(Sb[(m + 8) * 20 + kb + t]);
            ah[2] = __float_as_uint(Sb[m * 20 + kb + t + 4]);
            ah[3] = __float_as_uint(Sb[(m + 8) * 20 + kb + t + 4]);
            al[0] = __float_as_uint(Sb[1280 + m * 20 + kb + t]);
            al[1] = __float_as_uint(Sb[1280 + (m + 8) * 20 + kb + t]);
            al[2] = __float_as_uint(Sb[1280 + m * 20 + kb + t + 4]);
            al[3] = __float_as_uint(Sb[1280 + (m + 8) * 20 + kb + t + 4]);
            #pragma unroll
            for (int ni = 0; ni < 8; ni++) {
                int n = (wn << 6) + (ni << 3) + g;
                unsigned bh[2], bl[2];
                bh[0] = __float_as_uint(Sb[2560 + n * 20 + kb + t]);
                bh[1] = __float_as_uint(Sb[2560 + n * 20 + kb + t + 4]);
                bl[0] = __float_as_uint(Sb[5120 + n * 20 + kb + t]);
                bl[1] = __float_as_uint(Sb[5120 + n * 20 + kb + t + 4]);
                MMA_TF32(acc[ni], ah, bh);
                MMA_TF32(acc[ni], ah, bl);
                MMA_TF32(acc[ni], al, bh);
            }
        }
    };

    fetch(0);
    for (int ch = 0; ch < 16; ch++) {
        stash(ch & 1);
        __syncthreads();
        if (ch < 15) fetch((ch + 1) << 4);
        compute(ch & 1);
        __syncthreads();
    }

    int g = lane >> 2, t = lane & 3;
    #pragma unroll
    for (int half = 0; half < 2; half++) {
        int r = row0 + (wm << 4) + (half << 3) + g;
        #pragma unroll
        for (int ni = 0; ni < 8; ni++) {
            int c = col0 + (wn << 6) + (ni << 3) + (t << 1);
            *(float2*)(Cg + ((long long)r << 8) + c) =
                make_float2(acc[ni][half * 2] * alpha, acc[ni][half * 2 + 1] * alpha);
        }
    }
}

__global__ void __launch_bounds__(256) pinvchain_k()
{
    extern __shared__ float ps[];
    int bid = blockIdx.x;
    int tid = threadIdx.x;

    if (bid < 16) {
        const float* S = g_S2 + ((long long)bid << 16);
        float rs = 0.f, cs = 0.f;
        for (int j = 0; j < 256; j++) {
            rs += S[(tid << 8) + j];
            cs += S[(j << 8) + tid];
        }
        float rm = blockReduce(rs, true);
        float cm = blockReduce(cs, true);
        if (tid == 0) {
            atomicMax(&g_scale[0], __float_as_uint(rm));
            atomicMax(&g_scale[1], __float_as_uint(cm));
        }
    }
    gbar(128);

    {
        float inv = 1.0f / (__uint_as_float(g_scale[0]) * __uint_as_float(g_scale[1]));
        #pragma unroll
        for (int e = 0; e < 32; e++) {
            int idx = (bid << 13) + (e << 8) + tid;
            int z = idx >> 16, r = idx & 65535;
            int i = r >> 8, j = r & 255;
            g_Zb[((long long)z << 16) + (i << 8) + j] =
                g_S2[((long long)z << 16) + (j << 8) + i] * inv;
        }
    }
    gbar(256);

    unsigned t = 256;
    for (int it = 0; it < 6; it++) {
        float* Zi = (it & 1) ? g_Z2b : g_Zb;
        float* Zo = (it & 1) ? g_Zb : g_Z2b;
        pg_tile(g_S2, Zi, g_Pb, 1.f, 0, 0.f, ps);  t += 128; gbar(t);
        pg_tile(g_Pb, g_Pb, g_T2b, 1.f, 1, 7.f, ps);  t += 128; gbar(t);
        pg_tile(g_Pb, g_T2b, g_Tb, 1.f, 1, 15.f, ps);  t += 128; gbar(t);
        pg_tile(Zi, g_Tb, Zo, 0.25f, 1, 13.f, ps);  t += 128; gbar(t);
    }
}

__global__ void reset_k() { g_scale[0] = 0u; g_scale[1] = 0u; g_bar = 0u; }

// ------------------------- layernorm (rows of 512) --------------------------
__global__ void __launch_bounds__(256) ln_k(const float* __restrict__ X, float* __restrict__ Y,
                                            const float* __restrict__ g, const float* __restrict__ b)
{
    long long row = blockIdx.x;
    const float* x = X + row * DIMM;
    float* y = Y + row * DIMM;
    int t = threadIdx.x;
    float v0 = x[t], v1 = x[t + 256];
    float mu  = blockReduce(v0 + v1, false) * (1.f / 512.f);
    float d0 = v0 - mu, d1 = v1 - mu;
    float var = blockReduce(d0 * d0 + d1 * d1, false) * (1.f / 512.f);
    float inv = rsqrtf(var + 1e-5f);
    y[t]       = d0 * inv * g[t]       + b[t];
    y[t + 256] = d1 * inv * g[t + 256] + b[t + 256];
}

// ------------------------- softmax (S2 only) --------------------------------
__global__ void __launch_bounds__(256) softmax256_k(float* __restrict__ S)
{
    long long row = ((long long)blockIdx.x << 3) + (threadIdx.x >> 5);
    int lane = threadIdx.x & 31;
    float* s = S + (row << 8);
    float4 va = *(float4*)(s + (lane << 3));
    float4 vb = *(float4*)(s + (lane << 3) + 4);
    float m = fmaxf(fmaxf(fmaxf(va.x, va.y), fmaxf(va.z, va.w)),
                    fmaxf(fmaxf(vb.x, vb.y), fmaxf(vb.z, vb.w)));
    #pragma unroll
    for (int o = 16; o > 0; o >>= 1) m = fmaxf(m, __shfl_xor_sync(0xffffffffu, m, o));
    va.x = __expf(va.x - m); va.y = __expf(va.y - m); va.z = __expf(va.z - m); va.w = __expf(va.w - m);
    vb.x = __expf(vb.x - m); vb.y = __expf(vb.y - m); vb.z = __expf(vb.z - m); vb.w = __expf(vb.w - m);
    float sum = va.x + va.y + va.z + va.w + vb.x + vb.y + vb.z + vb.w;
    #pragma unroll
    for (int o = 16; o > 0; o >>= 1) sum += __shfl_xor_sync(0xffffffffu, sum, o);
    float inv = 1.f / sum;
    va.x *= inv; va.y *= inv; va.z *= inv; va.w *= inv;
    vb.x *= inv; vb.y *= inv; vb.z *= inv; vb.w *= inv;
    *(float4*)(s + (lane << 3)) = va;
    *(float4*)(s + (lane << 3) + 4) = vb;
}

// ------------------------- landmarks ----------------------------------------
__global__ void __launch_bounds__(64) landmark_k()
{
    int zz = blockIdx.x;
    int mi = zz & 255, bh = zz >> 8;
    int b = bh >> 3, h = bh & 7;
    int d = threadIdx.x;
    const float* base = g_QKV + (long long)(b * NF + mi * 32) * QD + h * 64 + d;
    float sq = 0.f, sk = 0.f;
    #pragma unroll 8
    for (int il = 0; il < 32; il++) {
        sq += base[(long long)il * QD];
        sk += base[(long long)il * QD + 512];
    }
    long long o = ((long long)bh * LM + mi) * DH + d;
    g_QL[o] = sq * (1.f / 32.f);
    g_KL[o] = sk * (1.f / 32.f);
}

// ------------------------- split-K reduce for AV ----------------------------
__global__ void __launch_bounds__(256) avreduce_k()
{
    int idx = blockIdx.x * 256 + threadIdx.x;
    int bh = idx >> 14;
    int r  = idx & 16383;
    const float* p = g_AVp + ((long long)bh << 17);
    float s = 0.f;
    #pragma unroll
    for (int k = 0; k < KSPL; k++) s += p[(k << 14) + r];
    g_AV[idx] = s;
}

// ------------------------- depthwise conv residual --------------------------
__global__ void __launch_bounds__(256) conv_k(const float* __restrict__ cw)
{
    __shared__ float sv[160 * 64];
    __shared__ float sw[KER];
    int tile = blockIdx.x;
    int bh = blockIdx.y;
    int b = bh >> 3, h = bh & 7;
    int n0 = tile * 128;
    int t = threadIdx.x;
    if (t < KER) sw[t] = cw[h * KER + t];
    for (int idx = t; idx < 160 * 64; idx += 256) {
        int r = idx >> 6, d = idx & 63;
        int nn = n0 - 16 + r;
        float v = 0.f;
        if (nn >= 0 && nn < NF) v = g_QKV[(long long)(b * NF + nn) * QD + 1024 + h * 64 + d];
        sv[idx] = v;
    }
    __syncthreads();
    int d = t & 63, r0 = t >> 6;
    for (int rr = r0; rr < 128; rr += 4) {
        float a = 0.f;
        #pragma unroll
        for (int k = 0; k < KER; k++) a += sv[(rr + k) * 64 + d] * sw[k];
        long long o = ((long long)bh * NF + n0 + rr) * DH + d;
        g_OH[o] += a;
    }
}

// ------------------------- final LN + head ----------------------------------
__global__ void __launch_bounds__(256) final_k(const float* __restrict__ fg, const float* __restrict__ fb,
                                               const float* __restrict__ w2, const float* __restrict__ b2,
                                               float* __restrict__ out)
{
    int b = blockIdx.x;
    const float* x = g_X + (long long)b * NF * DIMM;
    int t = threadIdx.x;
    float v0 = x[t], v1 = x[t + 256];
    float mu  = blockReduce(v0 + v1, false) * (1.f / 512.f);
    float d0 = v0 - mu, d1 = v1 - mu;
    float var = blockReduce(d0 * d0 + d1 * d1, false) * (1.f / 512.f);
    float inv = rsqrtf(var + 1e-5f);
    float n0 = d0 * inv * fg[t]       + fb[t];
    float n1 = d1 * inv * fg[t + 256] + fb[t + 256];
    float p0 = n0 * w2[2 * t]     + n1 * w2[2 * (t + 256)];
    float p1 = n0 * w2[2 * t + 1] + n1 * w2[2 * (t + 256) + 1];
    p0 = blockReduce(p0, false);
    p1 = blockReduce(p1, false);
    if (t == 0) {
        out[b * 2 + 0] = p0 + b2[0];
        out[b * 2 + 1] = p1 + b2[1];
    }
}

// ------------------------- host orchestration -------------------------------
static inline void mgemm2(int M, int N, int K,
                          const float* A, int lda, long long sA1, long long sA2, int amode,
                          const float* BT, int ldbt, long long sBT1, long long sBT2,
                          float* C, int ldc, long long sC1, long long sC2,
                          int batch, int ep, const float* bias,
                          float2* RSp = nullptr, long long rsp1 = 0, long long rsp2 = 0)
{
    dim3 g(N >> 7, (M + 127) >> 7, batch);
    if (RSp) {
        cudaFuncSetAttribute(mgemm2_k<1>, cudaFuncAttributeMaxDynamicSharedMemorySize, 65536);
        mgemm2_k<1><<<g, 256, 65536>>>(M, K, A, lda, sA1, sA2, amode, BT, ldbt, sBT1, sBT2,
                                       C, ldc, sC1, sC2, ep, bias, RSp, rsp1, rsp2);
    } else {
        cudaFuncSetAttribute(mgemm2_k<0>, cudaFuncAttributeMaxDynamicSharedMemorySize, 65536);
        mgemm2_k<0><<<g, 256, 65536>>>(M, K, A, lda, sA1, sA2, amode, BT, ldbt, sBT1, sBT2,
                                       C, ldc, sC1, sC2, ep, bias, nullptr, 0, 0);
    }
}

static inline void agemm(int M, int K,
                         const float* A, int lda, long long sA1, long long sA2, long long sA3,
                         const float* B, int ldb, long long sB1, long long sB2, long long sB3,
                         float* C, long long sC1, long long sC2, long long sC3,
                         int SPLIT, int batchZ, float alpha,
                         const float2* rsA, long long rs1, long long rs2, int aexp)
{
    cudaFuncSetAttribute(agemm_k, cudaFuncAttributeMaxDynamicSharedMemorySize, 49664);
    dim3 g(1, M >> 7, batchZ);
    agemm_k<<<g, 256, 49664>>>(M, K, A, lda, sA1, sA2, sA3, B, ldb, sB1, sB2, sB3,
                               C, sC1, sC2, sC3, SPLIT, alpha, rsA, rs1, rs2, aexp);
}

extern "C" void kernel_launch(void* const* d_in, const int* in_sizes, int n_in,
                              void* d_out, int out_size)
{
    const float* h_in  = (const float*)d_in[0];
    const float* w1    = (const float*)d_in[1];
    const float* b1    = (const float*)d_in[2];
    const float* clst  = (const float*)d_in[3];
    const float* ln_g  = (const float*)d_in[4];
    const float* ln_b  = (const float*)d_in[5];
    const float* wqkv  = (const float*)d_in[6];
    const float* wout  = (const float*)d_in[7];
    const float* bout  = (const float*)d_in[8];
    const float* cw    = (const float*)d_in[9];
    const float* fg    = (const float*)d_in[10];
    const float* fb    = (const float*)d_in[11];
    const float* w2    = (const float*)d_in[12];
    const float* b2    = (const float*)d_in[13];
    float* out = (float*)d_out;

    float *X, *XN, *QKV, *QL, *KL, *S1, *S2, *S3, *Z, *AV, *AVp, *ZAV, *OH, *WT;
    float2 *RS1, *RS3, *RSp;
    cudaGetSymbolAddress((void**)&X,   g_X);
    cudaGetSymbolAddress((void**)&XN,  g_XN);
    cudaGetSymbolAddress((void**)&QKV, g_QKV);
    cudaGetSymbolAddress((void**)&QL,  g_QL);
    cudaGetSymbolAddress((void**)&KL,  g_KL);
    cudaGetSymbolAddress((void**)&S1,  g_S1);
    cudaGetSymbolAddress((void**)&S2,  g_S2);
    cudaGetSymbolAddress((void**)&S3,  g_S3);
    cudaGetSymbolAddress((void**)&Z,   g_Zb);
    cudaGetSymbolAddress((void**)&AV,  g_AV);
    cudaGetSymbolAddress((void**)&AVp, g_AVp);
    cudaGetSymbolAddress((void**)&ZAV, g_ZAV);
    cudaGetSymbolAddress((void**)&OH,  g_OH);
    cudaGetSymbolAddress((void**)&WT,  g_WT);
    cudaGetSymbolAddress((void**)&RS1, g_RS1);
    cudaGetSymbolAddress((void**)&RS3, g_RS3);
    cudaGetSymbolAddress((void**)&RSp, g_RSp);

    const long long SQb = (long long)NF * QD;
    const long long S2s = (long long)LM * LM;
    const long long S1s = (long long)NF * LM;
    const long long AVs = (long long)LM * DH;
    const long long OHs = (long long)NF * DH;

    cudaFuncSetAttribute(pinvchain_k, cudaFuncAttributeMaxDynamicSharedMemorySize, 61440);

    // #1: all weight transposes + cls fill
    transAll_k<<<2564, 256>>>(w1, wqkv, wout, clst);

    // #2: input projection
    mgemm2(NB * 8191, DIMM, 1024, h_in, 1024, 0, 0, 0, WT + OW1, 1024, 0, 0,
           X, DIMM, 0, 0, 1, EP_RELU_REMAP, b1);

    for (int L = 0; L < 2; L++) {
        // #3 (L=0): layernorm
        ln_k<<<TOT, 256>>>(X, XN, ln_g + L * DIMM, ln_b + L * DIMM);

        // #4 (L=0): qkv GEMM  <-- ncu capture slot
        mgemm2(TOT, QD, DIMM, XN, DIMM, 0, 0, 0, WT + OQKV(L), DIMM, 0, 0,
               QKV, QD, 0, 0, 1, EP_SCALEQ, nullptr);

        landmark_k<<<NBH * LM, 64>>>();

        // sim2 = QL @ KL^T, softmax
        mgemm2(LM, LM, DH, QL, DH, 8 * AVs, AVs, 0, KL, DH, 8 * AVs, AVs,
               S2, LM, 8 * S2s, S2s, NBH, EP_NONE, nullptr);
        softmax256_k<<<NBH * LM / 8, 256>>>(S2);

        // Moore-Penrose pinv of S2 -> Z : persistent chain
        reset_k<<<1, 1>>>();
        pinvchain_k<<<128, 256, 61440>>>();

        // sim1 = Q @ KL^T (raw) with fused per-tile softmax stats (2/row)
        mgemm2(NF, LM, DH, QKV, QD, SQb, 64, 0, KL, DH, 8 * AVs, AVs,
               S1, LM, 8 * S1s, S1s, NBH, EP_NONE, nullptr,
               RSp, 8LL * NF * 2, (long long)NF * 2);
        combine_k<<<NBH * NF / 8, 256>>>(RSp, RS1, 2);

        // sim3 = QL @ K^T (raw) with fused per-tile softmax stats (64/row)
        mgemm2(LM, NF, DH, QL, DH, 8 * AVs, AVs, 0, QKV + 512, QD, SQb, 64,
               S3, NF, 8 * S1s, S1s, NBH, EP_NONE, nullptr,
               RSp, 8LL * LM * 64, (long long)LM * 64);
        combine_k<<<NBH * LM / 8, 256>>>(RSp, RS3, 64);

        // AV = softmax(sim3) @ V  (tensor, exp fused, split-K by 8)
        agemm(LM, NF / KSPL,
              S3, NF, 8 * S1s, S1s, 1024,
              QKV + 1024, QD, SQb, 64, 1024LL * QD,
              AVp, 64 * AVs, 8 * AVs, AVs,
              KSPL, NBH * KSPL, 1.f, RS3, 8 * LM, LM, 1);
        avreduce_k<<<1024, 256>>>();

        // ZAV = Z @ AV  (tensor)
        agemm(LM, LM,
              Z, LM, 8 * S2s, S2s, 0,
              AV, DH, 8 * AVs, AVs, 0,
              ZAV, 8 * AVs, AVs, 0,
              1, NBH, 1.f, RS3, 0, 0, 0);

        // OH = softmax(sim1) @ ZAV  (tensor, exp fused)
        agemm(NF, LM,
              S1, LM, 8 * S1s, S1s, 0,
              ZAV, DH, 8 * AVs, AVs, 0,
              OH, 8 * OHs, OHs, 0,
              1, NBH, 1.f, RS1, 8LL * NF, NF, 1);

        // OH += depthwise conv residual of V
        { dim3 g(NF / 128, NBH); conv_k<<<g, 256>>>(cw + L * NH * KER); }

        // X += OH(head-layout) @ Wout + bout
        mgemm2(TOT, DIMM, DIMM, OH, 0, 0, 0, 1, WT + OOUT(L), DIMM, 0, 0,
               X, DIMM, 0, 0, 1, EP_ADDBIAS, bout + L * DIMM);
    }

    final_k<<<NB, 256>>>(fg, fb, w2, b2, out);
}

// round 13
// speedup vs baseline: 2.7013x; 1.0104x over previous
#include <cuda_runtime.h>

#define NB   2
#define NF   8192
#define DIMM 512
#define NH   8
#define DH   64
#define LM   256
#define QD   1536
#define TOT  (NB*NF)    // 16384
#define NBH  (NB*NH)    // 16
#define KER  33
#define KSPL 8

// ------------------------- scratch (device globals, no allocs) -------------
__device__ float g_X  [TOT*DIMM];
__device__ float g_XN [TOT*DIMM];
__device__ float g_QKV[TOT*QD];
__device__ float g_QL [NBH*LM*DH];
__device__ float g_KL [NBH*LM*DH];
__device__ float g_S1 [NBH*NF*LM];
__device__ float g_S3 [NBH*LM*NF];
__device__ float g_S2 [NBH*LM*LM];
__device__ float g_Zb [NBH*LM*LM];
__device__ float g_Z2b[NBH*LM*LM];
__device__ float g_Pb [NBH*LM*LM];
__device__ float g_Tb [NBH*LM*LM];
__device__ float g_T2b[NBH*LM*LM];
__device__ float g_AV [NBH*LM*DH];
__device__ float g_AVp[NBH*KSPL*LM*DH];
__device__ float g_ZAV[NBH*LM*DH];
__device__ float g_OH [NBH*NF*DH];
__device__ float g_WT [2621440];
__device__ float2 g_RS1[NBH*NF];
__device__ float2 g_RS3[NBH*LM];
__device__ float2 g_RSp[NBH*NF*2];     // softmax partials (also fits sim3: 4096*64)
__device__ unsigned int g_scale[2];
__device__ unsigned int g_bar;

enum { EP_NONE = 0, EP_RELU_REMAP = 1, EP_SCALEQ = 2, EP_ADDBIAS = 3 };

#define OW1   0
#define OQKV(L) (524288 + (L) * 786432)
#define OOUT(L) (2097152 + (L) * 262144)

__device__ __forceinline__ unsigned f2tf32(float f) {
    unsigned r;
    asm("cvt.rna.tf32.f32 %0, %1;" : "=r"(r) : "f"(f));
    return r;
}
__device__ __forceinline__ float tf32f(float f) {
    return __uint_as_float(f2tf32(f));
}

#define MMA_TF32(d, a, b) \
    asm volatile("mma.sync.aligned.m16n8k8.row.col.f32.tf32.tf32.f32 " \
        "{%0,%1,%2,%3}, {%4,%5,%6,%7}, {%8,%9}, {%0,%1,%2,%3};" \
        : "+f"((d)[0]), "+f"((d)[1]), "+f"((d)[2]), "+f"((d)[3]) \
        : "r"((a)[0]), "r"((a)[1]), "r"((a)[2]), "r"((a)[3]), \
          "r"((b)[0]), "r"((b)[1]))

// ------------------------- reductions --------------------------------------
__device__ __forceinline__ float blockReduce(float v, bool domax) {
    __shared__ float sh[32];
    __syncthreads();
    #pragma unroll
    for (int o = 16; o > 0; o >>= 1) {
        float w = __shfl_down_sync(0xffffffffu, v, o);
        v = domax ? fmaxf(v, w) : v + w;
    }
    int lane = threadIdx.x & 31, wid = threadIdx.x >> 5;
    if (lane == 0) sh[wid] = v;
    __syncthreads();
    int nw = (blockDim.x + 31) >> 5;
    if (wid == 0) {
        v = (lane < nw) ? sh[lane] : (domax ? -1e30f : 0.f);
        #pragma unroll
        for (int o = 16; o > 0; o >>= 1) {
            float w = __shfl_down_sync(0xffffffffu, v, o);
            v = domax ? fmaxf(v, w) : v + w;
        }
        if (lane == 0) sh[0] = v;
    }
    __syncthreads();
    return sh[0];
}

// ------------------- fused transposes + cls (ONE launch) --------------------
__device__ __forceinline__ void doTrans(const float* __restrict__ src,
                                        float* __restrict__ dst,
                                        int K, int N, int kt, int nt)
{
    __shared__ float t[32][33];
    int kb = kt << 5, nb = nt << 5;
    int x = threadIdx.x & 31, y = threadIdx.x >> 5;
    #pragma unroll
    for (int i = 0; i < 32; i += 8)
        t[y + i][x] = src[(long long)(kb + y + i) * N + nb + x];
    __syncthreads();
    #pragma unroll
    for (int i = 0; i < 32; i += 8)
        dst[(long long)(nb + y + i) * K + kb + x] = t[x][y + i];
}

__global__ void __launch_bounds__(256) transAll_k(
    const float* __restrict__ w1, const float* __restrict__ wqkv,
    const float* __restrict__ wout, const float* __restrict__ clst)
{
    int b = blockIdx.x;
    if (b < 512) {
        doTrans(w1, g_WT + OW1, 1024, DIMM, b & 31, b >> 5);
    } else if (b < 2048) {
        int L = (b - 512) / 768, bb = (b - 512) % 768;
        doTrans(wqkv + (long long)L * DIMM * QD, g_WT + OQKV(L), DIMM, QD, bb & 15, bb >> 4);
    } else if (b < 2560) {
        int L = (b - 2048) / 256, bb = (b - 2048) % 256;
        doTrans(wout + (long long)L * DIMM * DIMM, g_WT + OOUT(L), DIMM, DIMM, bb & 15, bb >> 4);
    } else {
        int idx = (b - 2560) * 256 + threadIdx.x;
        int bb = idx >> 9, c = idx & 511;
        g_X[(long long)bb * NF * DIMM + c] = clst[c];
    }
}

// ======= mgemm2: cp.async + ldmatrix tf32, 128x128, 3-stage, 2 CTA/SM =======
__device__ __forceinline__ void cp16(unsigned dst, const void* src, int nbytes) {
    asm volatile("cp.async.cg.shared.global [%0], [%1], 16, %2;"
                 :: "r"(dst), "l"(src), "r"(nbytes) : "memory");
}

template<int STAT>
__global__ void __launch_bounds__(256, 2) mgemm2_k(
    int M, int K,
    const float* __restrict__ A, int lda, long long sA1, long long sA2, int amode,
    const float* __restrict__ BT, int ldbt, long long sBT1, long long sBT2,
    float* __restrict__ C, int ldc, long long sC1, long long sC2,
    int ep, const float* __restrict__ bias,
    float2* __restrict__ RSp, long long rsp1, long long rsp2)
{
    extern __shared__ float smem[];   // 3 stages x (A 16KB + B 16KB) = 96KB
    int tid = threadIdx.x;
    int lane = tid & 31, wid = tid >> 5;
    int wm = wid & 3, wn = wid >> 2;
    int row0 = blockIdx.y << 7, col0 = blockIdx.x << 7;
    int z = blockIdx.z;
    A  += (long long)(z >> 3) * sA1 + (long long)(z & 7) * sA2;
    BT += (long long)(z >> 3) * sBT1 + (long long)(z & 7) * sBT2;
    C  += (long long)(z >> 3) * sC1 + (long long)(z & 7) * sC2;
    if (STAT) RSp += (long long)(z >> 3) * rsp1 + (long long)(z & 7) * rsp2;

    unsigned sbase;
    asm("{ .reg .u64 t; cvta.to.shared.u64 t, %1; cvt.u32.u64 %0, t; }"
        : "=r"(sbase) : "l"(smem));

    float acc[2][8][4];
    #pragma unroll
    for (int mi = 0; mi < 2; mi++)
        #pragma unroll
        for (int ni = 0; ni < 8; ni++)
            #pragma unroll
            for (int q = 0; q < 4; q++) acc[mi][ni][q] = 0.f;

    auto fill = [&](int s, int k0) {
        unsigned Ab = sbase + s * 32768u;
        unsigned Bb = Ab + 16384u;
        #pragma unroll
        for (int it = 0; it < 4; it++) {
            int idx = (it << 8) + tid;
            int q = idx & 7, r = idx >> 3;
            int gr = row0 + r;
            const float* src;
            int nb = 16;
            if (amode == 0) {
                int gra = gr < M ? gr : (M - 1);
                if (gr >= M) nb = 0;
                src = A + (long long)gra * lda + k0 + (q << 2);
            } else {
                int k = k0 + (q << 2);
                int h = k >> 6, d = k & 63;
                src = A + ((((long long)(gr >> 13) << 3) + h) * 8192 + (gr & 8191)) * 64 + d;
            }
            unsigned dst = Ab + (((r << 5) + ((q ^ (r & 7)) << 2)) << 2);
            cp16(dst, src, nb);
        }
        #pragma unroll
        for (int it = 0; it < 4; it++) {
            int idx = (it << 8) + tid;
            int q = idx & 7, n = idx >> 3;
            const float* src = BT + (long long)(col0 + n) * ldbt + k0 + (q << 2);
            unsigned dst = Bb + (((n << 5) + ((q ^ (n & 7)) << 2)) << 2);
            cp16(dst, src, 16);
        }
        asm volatile("cp.async.commit_group;" ::: "memory");
    };

    auto compute = [&](int s) {
        unsigned Ab = sbase + s * 32768u;
        unsigned Bb = Ab + 16384u;
        int j = lane >> 3, rho = lane & 7;
        #pragma unroll
        for (int kt = 0; kt < 4; kt++) {
            unsigned a[2][4];
            #pragma unroll
            for (int mi = 0; mi < 2; mi++) {
                int row = (wm << 5) + (mi << 4) + ((j & 1) << 3) + rho;
                int quad = (kt << 1) + (j >> 1);
                unsigned ad = Ab + (((row << 5) + ((quad ^ (row & 7)) << 2)) << 2);
                asm volatile("ldmatrix.sync.aligned.m8n8.x4.shared.b16 {%0,%1,%2,%3}, [%4];"
                    : "=r"(a[mi][0]), "=r"(a[mi][1]), "=r"(a[mi][2]), "=r"(a[mi][3])
                    : "r"(ad));
            }
            unsigned b[8][2];
            #pragma unroll
            for (int np = 0; np < 4; np++) {
                int row = (((wn << 3) + (np << 1) + (j >> 1)) << 3) + rho;
                int quad = (kt << 1) + (j & 1);
                unsigned bd = Bb + (((row << 5) + ((quad ^ (row & 7)) << 2)) << 2);
                asm volatile("ldmatrix.sync.aligned.m8n8.x4.shared.b16 {%0,%1,%2,%3}, [%4];"
                    : "=r"(b[np * 2][0]), "=r"(b[np * 2][1]),
                      "=r"(b[np * 2 + 1][0]), "=r"(b[np * 2 + 1][1])
                    : "r"(bd));
            }
            #pragma unroll
            for (int mi = 0; mi < 2; mi++)
                #pragma unroll
                for (int ni = 0; ni < 8; ni++)
                    MMA_TF32(acc[mi][ni], a[mi], b[ni]);
        }
    };

    int nch = K >> 5;
    fill(0, 0);
    if (nch > 1) fill(1, 32);
    for (int ch = 0; ch < nch; ch++) {
        if (ch + 1 < nch)
            asm volatile("cp.async.wait_group 1;" ::: "memory");
        else
            asm volatile("cp.async.wait_group 0;" ::: "memory");
        __syncthreads();
        if (ch + 2 < nch) fill((ch + 2) % 3, (ch + 2) << 5);
        compute(ch % 3);
    }

    int rb = row0 + (wm << 5) + (lane >> 2);
    int cb = col0 + (wn << 6) + ((lane & 3) << 1);
    #pragma unroll
    for (int mi = 0; mi < 2; mi++) {
        #pragma unroll
        for (int half = 0; half < 2; half++) {
            int r = rb + (mi << 4) + (half << 3);
            if (r >= M) continue;
            #pragma unroll
            for (int ni = 0; ni < 8; ni++) {
                int c = cb + (ni << 3);
                float v0 = acc[mi][ni][half * 2];
                float v1 = acc[mi][ni][half * 2 + 1];
                if (ep == EP_RELU_REMAP) {
                    long long o = (long long)(r + r / 8191 + 1) * ldc + c;
                    v0 = fmaxf(v0 + bias[c], 0.f);
                    v1 = fmaxf(v1 + bias[c + 1], 0.f);
                    *(float2*)(C + o) = make_float2(v0, v1);
                } else if (ep == EP_SCALEQ) {
                    float sc = (c < 512) ? 0.125f : 1.0f;
                    *(float2*)(C + (long long)r * ldc + c) = make_float2(v0 * sc, v1 * sc);
                } else if (ep == EP_ADDBIAS) {
                    long long o = (long long)r * ldc + c;
                    float2 old = *(float2*)(C + o);
                    *(float2*)(C + o) = make_float2(old.x + v0 + bias[c],
                                                    old.y + v1 + bias[c + 1]);
                } else {
                    *(float2*)(C + (long long)r * ldc + c) = make_float2(v0, v1);
                }
            }
        }
    }

    // ---- streaming-softmax partial stats for this 128-col tile -------------
    if (STAT) {
        float* red = smem;
        int g = lane >> 2;
        float rowm[2][2];
        __syncthreads();
        #pragma unroll
        for (int mi = 0; mi < 2; mi++) {
            #pragma unroll
            for (int half = 0; half < 2; half++) {
                float m = -1e30f;
                #pragma unroll
                for (int ni = 0; ni < 8; ni++)
                    m = fmaxf(m, fmaxf(acc[mi][ni][half * 2], acc[mi][ni][half * 2 + 1]));
                m = fmaxf(m, __shfl_xor_sync(0xffffffffu, m, 1));
                m = fmaxf(m, __shfl_xor_sync(0xffffffffu, m, 2));
                if ((lane & 3) == 0) {
                    int rl = (wm << 5) + (mi << 4) + (half << 3) + g;
                    red[rl * 2 + wn] = m;
                }
            }
        }
        __syncthreads();
        #pragma unroll
        for (int mi = 0; mi < 2; mi++) {
            #pragma unroll
            for (int half = 0; half < 2; half++) {
                int rl = (wm << 5) + (mi << 4) + (half << 3) + g;
                rowm[mi][half] = fmaxf(red[rl * 2], red[rl * 2 + 1]);
            }
        }
        __syncthreads();
        #pragma unroll
        for (int mi = 0; mi < 2; mi++) {
            #pragma unroll
            for (int half = 0; half < 2; half++) {
                float m = rowm[mi][half];
                float s = 0.f;
                #pragma unroll
                for (int ni = 0; ni < 8; ni++)
                    s += __expf(acc[mi][ni][half * 2] - m) + __expf(acc[mi][ni][half * 2 + 1] - m);
                s += __shfl_xor_sync(0xffffffffu, s, 1);
                s += __shfl_xor_sync(0xffffffffu, s, 2);
                if ((lane & 3) == 0) {
                    int rl = (wm << 5) + (mi << 4) + (half << 3) + g;
                    red[256 + rl * 2 + wn] = s;
                }
            }
        }
        __syncthreads();
        if (wn == 0 && (lane & 3) == 0) {
            #pragma unroll
            for (int mi = 0; mi < 2; mi++) {
                #pragma unroll
                for (int half = 0; half < 2; half++) {
                    int rl = (wm << 5) + (mi << 4) + (half << 3) + g;
                    int gr = row0 + rl;
                    if (gr < M)
                        RSp[(long long)gr * gridDim.x + blockIdx.x] =
                            make_float2(rowm[mi][half],
                                        red[256 + rl * 2] + red[256 + rl * 2 + 1]);
                }
            }
        }
    }
}

// ------------------------- combine softmax partials -------------------------
__global__ void __launch_bounds__(256) combine_k(const float2* __restrict__ RSp,
                                                 float2* __restrict__ RS, int nblk)
{
    int row = blockIdx.x * 8 + (threadIdx.x >> 5);
    int lane = threadIdx.x & 31;
    const float2* p = RSp + (long long)row * nblk;
    float m = -1e30f;
    for (int i = lane; i < nblk; i += 32) m = fmaxf(m, p[i].x);
    #pragma unroll
    for (int o = 16; o > 0; o >>= 1) m = fmaxf(m, __shfl_xor_sync(0xffffffffu, m, o));
    float s = 0.f;
    for (int i = lane; i < nblk; i += 32) {
        float2 v = p[i];
        s += v.y * __expf(v.x - m);
    }
    #pragma unroll
    for (int o = 16; o > 0; o >>= 1) s += __shfl_xor_sync(0xffffffffu, s, o);
    if (lane == 0) RS[row] = make_float2(m, 1.f / s);
}

// ===================== agemm: tf32 GEMM, 128xN64 tile, exp-fused A ==========
__global__ void __launch_bounds__(256, 2) agemm_k(
    int M, int K,
    const float* __restrict__ A, int lda, long long sA1, long long sA2, long long sA3,
    const float* __restrict__ B, int ldb, long long sB1, long long sB2, long long sB3,
    float* __restrict__ C, long long sC1, long long sC2, long long sC3,
    int SPLIT, float alpha,
    const float2* __restrict__ rsA, long long rs1, long long rs2, int aexp)
{
    extern __shared__ unsigned dsm[];   // As: 2x4096 u32 | Bs: 2x2112 f32 = 49664B
    int z = blockIdx.z;
    int s = z % SPLIT;
    int bh = z / SPLIT;
    int hh = bh & 7, bb = bh >> 3;
    A   += (long long)bb * sA1 + (long long)hh * sA2 + (long long)s * sA3;
    B   += (long long)bb * sB1 + (long long)hh * sB2 + (long long)s * sB3;
    C   += (long long)bb * sC1 + (long long)hh * sC2 + (long long)s * sC3;
    rsA += bb * rs1 + hh * rs2;
    int row0 = blockIdx.y << 7;
    int tid = threadIdx.x, lane = tid & 31, wm = tid >> 5;

    unsigned sbase;
    asm("{ .reg .u64 t; cvta.to.shared.u64 t, %1; cvt.u32.u64 %0, t; }"
        : "=r"(sbase) : "l"(dsm));
    float* Bsm = (float*)(dsm + 8192);

    float acc[8][4];
    #pragma unroll
    for (int ni = 0; ni < 8; ni++)
        #pragma unroll
        for (int q = 0; q < 4; q++) acc[ni][q] = 0.f;

    int a_q = tid & 7, a_r0 = tid >> 3;
    int b_n = tid & 63, b_kh = tid >> 6;

    float4 pa[4];
    float pbv[8];

    auto fetch = [&](int k0) {
        #pragma unroll
        for (int it = 0; it < 4; it++) {
            int r = a_r0 + (it << 5);
            int gr = row0 + r;
            float4 v = *(const float4*)(A + (long long)gr * lda + k0 + (a_q << 2));
            if (aexp) {
                float2 st = rsA[gr];
                v.x = __expf(v.x - st.x) * st.y;
                v.y = __expf(v.y - st.x) * st.y;
                v.z = __expf(v.z - st.x) * st.y;
                v.w = __expf(v.w - st.x) * st.y;
            }
            pa[it] = v;
        }
        #pragma unroll
        for (int j = 0; j < 8; j++) {
            int k = (b_kh << 3) + j;
            pbv[j] = B[(long long)(k0 + k) * ldb + b_n];
        }
    };

    auto stash = [&](int st) {
        unsigned* Ab = dsm + st * 4096;
        #pragma unroll
        for (int it = 0; it < 4; it++) {
            int r = a_r0 + (it << 5);
            uint4 u;
            u.x = f2tf32(pa[it].x); u.y = f2tf32(pa[it].y);
            u.z = f2tf32(pa[it].z); u.w = f2tf32(pa[it].w);
            *(uint4*)&Ab[(r << 5) + ((a_q ^ (r & 7)) << 2)] = u;
        }
        float* Bb = Bsm + st * 2112;
        #pragma unroll
        for (int j = 0; j < 8; j++) {
            int k = (b_kh << 3) + j;
            Bb[b_n * 33 + k] = tf32f(pbv[j]);
        }
    };

    auto compute = [&](int st) {
        unsigned Ab = sbase + st * 16384u;
        const float* Bb = Bsm + st * 2112;
        int j = lane >> 3, rho = lane & 7;
        int g = lane >> 2, t = lane & 3;
        #pragma unroll
        for (int kt = 0; kt < 4; kt++) {
            unsigned a[4];
            {
                int row = (wm << 4) + ((j & 1) << 3) + rho;
                int quad = (kt << 1) + (j >> 1);
                unsigned ad = Ab + (((row << 5) + ((quad ^ (row & 7)) << 2)) << 2);
                asm volatile("ldmatrix.sync.aligned.m8n8.x4.shared.b16 {%0,%1,%2,%3}, [%4];"
                    : "=r"(a[0]), "=r"(a[1]), "=r"(a[2]), "=r"(a[3])
                    : "r"(ad));
            }
            #pragma unroll
            for (int ni = 0; ni < 8; ni++) {
                int n = (ni << 3) + g;
                unsigned b[2];
                b[0] = __float_as_uint(Bb[n * 33 + (kt << 3) + t]);
                b[1] = __float_as_uint(Bb[n * 33 + (kt << 3) + t + 4]);
                MMA_TF32(acc[ni], a, b);
            }
        }
    };

    fetch(0);
    int nch = K >> 5;
    for (int ch = 0; ch < nch; ch++) {
        stash(ch & 1);
        __syncthreads();
        if (ch + 1 < nch) fetch((ch + 1) << 5);
        compute(ch & 1);
        __syncthreads();
    }

    int g = lane >> 2, t = lane & 3;
    #pragma unroll
    for (int half = 0; half < 2; half++) {
        int r = row0 + (wm << 4) + (half << 3) + g;
        #pragma unroll
        for (int ni = 0; ni < 8; ni++) {
            int c = (ni << 3) + (t << 1);
            *(float2*)(C + (long long)r * 64 + c) =
                make_float2(acc[ni][half * 2] * alpha, acc[ni][half * 2 + 1] * alpha);
        }
    }
}

// ===================== pinv: persistent chain kernel ========================
__device__ __forceinline__ void gbar(unsigned target) {
    __syncthreads();
    if (threadIdx.x == 0) {
        __threadfence();
        atomicAdd(&g_bar, 1u);
        while (*(volatile unsigned*)&g_bar < target) {}
        __threadfence();
    }
    __syncthreads();
}

__device__ void pg_tile(const float* __restrict__ Ag, const float* __restrict__ Bg,
                        float* __restrict__ Cg, float alpha, int bmode, float bd,
                        float* ps)
{
    int bid = blockIdx.x;
    int tid = threadIdx.x;
    int lane = tid & 31, wid = tid >> 5;
    int wm = wid & 3, wn = wid >> 2;
    int col0 = (bid & 1) << 7;
    int row0 = ((bid >> 1) & 3) << 6;
    long long zo = (long long)(bid >> 3) << 16;
    Ag += zo; Bg += zo; Cg += zo;

    float acc[8][4];
    #pragma unroll
    for (int ni = 0; ni < 8; ni++)
        #pragma unroll
        for (int q = 0; q < 4; q++) acc[ni][q] = 0.f;

    int ar = tid >> 2, aq = tid & 3;
    int bn = tid & 127, bkh = tid >> 7;

    float4 pa;
    float pbv[8];

    auto fetch = [&](int k0) {
        pa = *(const float4*)(Ag + ((long long)(row0 + ar) << 8) + k0 + (aq << 2));
        #pragma unroll
        for (int j = 0; j < 8; j++) {
            int gk = k0 + (bkh << 3) + j;
            int gn = col0 + bn;
            float v = Bg[((long long)gk << 8) + gn];
            if (bmode) v = (gk == gn ? bd : 0.f) - v;
            pbv[j] = v;
        }
    };

    auto stash = [&](int s) {
        float* Sb = ps + s * 7680;
        float4 h, l;
        h.x = tf32f(pa.x); h.y = tf32f(pa.y); h.z = tf32f(pa.z); h.w = tf32f(pa.w);
        l.x = tf32f(pa.x - h.x); l.y = tf32f(pa.y - h.y);
        l.z = tf32f(pa.z - h.z); l.w = tf32f(pa.w - h.w);
        *(float4*)&Sb[ar * 20 + (aq << 2)] = h;
        *(float4*)&Sb[1280 + ar * 20 + (aq << 2)] = l;
        float4 bh0, bh1, bl0, bl1;
        bh0.x = tf32f(pbv[0]); bh0.y = tf32f(pbv[1]); bh0.z = tf32f(pbv[2]); bh0.w = tf32f(pbv[3]);
        bh1.x = tf32f(pbv[4]); bh1.y = tf32f(pbv[5]); bh1.z = tf32f(pbv[6]); bh1.w = tf32f(pbv[7]);
        bl0.x = tf32f(pbv[0] - bh0.x); bl0.y = tf32f(pbv[1] - bh0.y);
        bl0.z = tf32f(pbv[2] - bh0.z); bl0.w = tf32f(pbv[3] - bh0.w);
        bl1.x = tf32f(pbv[4] - bh1.x); bl1.y = tf32f(pbv[5] - bh1.y);
        bl1.z = tf32f(pbv[6] - bh1.z); bl1.w = tf32f(pbv[7] - bh1.w);
        *(float4*)&Sb[2560 + bn * 20 + (bkh << 3)] = bh0;
        *(float4*)&Sb[2560 + bn * 20 + (bkh << 3) + 4] = bh1;
        *(float4*)&Sb[5120 + bn * 20 + (bkh << 3)] = bl0;
        *(float4*)&Sb[5120 + bn * 20 + (bkh << 3) + 4] = bl1;
    };

    auto compute = [&](int s) {
        const float* Sb = ps + s * 7680;
        int g = lane >> 2, t = lane & 3;
        #pragma unroll
        for (int kt = 0; kt < 2; kt++) {
            int kb = kt << 3;
            int m = (wm << 4) + g;
            unsigned ah[4], al[4];
            ah[0] = __float_as_uint(Sb[m * 20 + kb + t]);
            ah[1] = __float_as_uint(Sb[(m + 8) * 20 + kb + t]);
            ah[2] = __float_as_uint(Sb[m * 20 + kb + t + 4]);
            ah[3] = __float_as_uint(Sb[(m + 8) * 20 + kb + t + 4]);
            al[0] = __float_as_uint(Sb[1280 + m * 20 + kb + t]);
            al[1] = __float_as_uint(Sb[1280 + (m + 8) * 20 + kb + t]);
            al[2] = __float_as_uint(Sb[1280 + m * 20 + kb + t + 4]);
            al[3] = __float_as_uint(Sb[1280 + (m + 8) * 20 + kb + t + 4]);
            #pragma unroll
            for (int ni = 0; ni < 8; ni++) {
                int n = (wn << 6) + (ni << 3) + g;
                unsigned bh[2], bl[2];
                bh[0] = __float_as_uint(Sb[2560 + n * 20 + kb + t]);
                bh[1] = __float_as_uint(Sb[2560 + n * 20 + kb + t + 4]);
                bl[0] = __float_as_uint(Sb[5120 + n * 20 + kb + t]);
                bl[1] = __float_as_uint(Sb[5120 + n * 20 + kb + t + 4]);
                MMA_TF32(acc[ni], ah, bh);
                MMA_TF32(acc[ni], ah, bl);
                MMA_TF32(acc[ni], al, bh);
            }
        }
    };

    fetch(0);
    for (int ch = 0; ch < 16; ch++) {
        stash(ch & 1);
        __syncthreads();
        if (ch < 15) fetch((ch + 1) << 4);
        compute(ch & 1);
        __syncthreads();
    }

    int g = lane >> 2, t = lane & 3;
    #pragma unroll
    for (int half = 0; half < 2; half++) {
        int r = row0 + (wm << 4) + (half << 3) + g;
        #pragma unroll
        for (int ni = 0; ni < 8; ni++) {
            int c = col0 + (wn << 6) + (ni << 3) + (t << 1);
            *(float2*)(Cg + ((long long)r << 8) + c) =
                make_float2(acc[ni][half * 2] * alpha, acc[ni][half * 2 + 1] * alpha);
        }
    }
}

__global__ void __launch_bounds__(256) pinvchain_k()
{
    extern __shared__ float ps[];
    int bid = blockIdx.x;
    int tid = threadIdx.x;

    if (bid < 16) {
        const float* S = g_S2 + ((long long)bid << 16);
        float rs = 0.f, cs = 0.f;
        for (int j = 0; j < 256; j++) {
            rs += S[(tid << 8) + j];
            cs += S[(j << 8) + tid];
        }
        float rm = blockReduce(rs, true);
        float cm = blockReduce(cs, true);
        if (tid == 0) {
            atomicMax(&g_scale[0], __float_as_uint(rm));
            atomicMax(&g_scale[1], __float_as_uint(cm));
        }
    }
    gbar(128);

    {
        float inv = 1.0f / (__uint_as_float(g_scale[0]) * __uint_as_float(g_scale[1]));
        #pragma unroll
        for (int e = 0; e < 32; e++) {
            int idx = (bid << 13) + (e << 8) + tid;
            int z = idx >> 16, r = idx & 65535;
            int i = r >> 8, j = r & 255;
            g_Zb[((long long)z << 16) + (i << 8) + j] =
                g_S2[((long long)z << 16) + (j << 8) + i] * inv;
        }
    }
    gbar(256);

    unsigned t = 256;
    for (int it = 0; it < 6; it++) {
        float* Zi = (it & 1) ? g_Z2b : g_Zb;
        float* Zo = (it & 1) ? g_Zb : g_Z2b;
        pg_tile(g_S2, Zi, g_Pb, 1.f, 0, 0.f, ps);  t += 128; gbar(t);
        pg_tile(g_Pb, g_Pb, g_T2b, 1.f, 1, 7.f, ps);  t += 128; gbar(t);
        pg_tile(g_Pb, g_T2b, g_Tb, 1.f, 1, 15.f, ps);  t += 128; gbar(t);
        pg_tile(Zi, g_Tb, Zo, 0.25f, 1, 13.f, ps);  t += 128; gbar(t);
    }
}

__global__ void reset_k() { g_scale[0] = 0u; g_scale[1] = 0u; g_bar = 0u; }

// ------------------------- layernorm (rows of 512) --------------------------
__global__ void __launch_bounds__(256) ln_k(const float* __restrict__ X, float* __restrict__ Y,
                                            const float* __restrict__ g, const float* __restrict__ b)
{
    long long row = blockIdx.x;
    const float* x = X + row * DIMM;
    float* y = Y + row * DIMM;
    int t = threadIdx.x;
    float v0 = x[t], v1 = x[t + 256];
    float mu  = blockReduce(v0 + v1, false) * (1.f / 512.f);
    float d0 = v0 - mu, d1 = v1 - mu;
    float var = blockReduce(d0 * d0 + d1 * d1, false) * (1.f / 512.f);
    float inv = rsqrtf(var + 1e-5f);
    y[t]       = d0 * inv * g[t]       + b[t];
    y[t + 256] = d1 * inv * g[t + 256] + b[t + 256];
}

// ------------------------- softmax (S2 only) --------------------------------
__global__ void __launch_bounds__(256) softmax256_k(float* __restrict__ S)
{
    long long row = ((long long)blockIdx.x << 3) + (threadIdx.x >> 5);
    int lane = threadIdx.x & 31;
    float* s = S + (row << 8);
    float4 va = *(float4*)(s + (lane << 3));
    float4 vb = *(float4*)(s + (lane << 3) + 4);
    float m = fmaxf(fmaxf(fmaxf(va.x, va.y), fmaxf(va.z, va.w)),
                    fmaxf(fmaxf(vb.x, vb.y), fmaxf(vb.z, vb.w)));
    #pragma unroll
    for (int o = 16; o > 0; o >>= 1) m = fmaxf(m, __shfl_xor_sync(0xffffffffu, m, o));
    va.x = __expf(va.x - m); va.y = __expf(va.y - m); va.z = __expf(va.z - m); va.w = __expf(va.w - m);
    vb.x = __expf(vb.x - m); vb.y = __expf(vb.y - m); vb.z = __expf(vb.z - m); vb.w = __expf(vb.w - m);
    float sum = va.x + va.y + va.z + va.w + vb.x + vb.y + vb.z + vb.w;
    #pragma unroll
    for (int o = 16; o > 0; o >>= 1) sum += __shfl_xor_sync(0xffffffffu, sum, o);
    float inv = 1.f / sum;
    va.x *= inv; va.y *= inv; va.z *= inv; va.w *= inv;
    vb.x *= inv; vb.y *= inv; vb.z *= inv; vb.w *= inv;
    *(float4*)(s + (lane << 3)) = va;
    *(float4*)(s + (lane << 3) + 4) = vb;
}

// ------------------------- landmarks ----------------------------------------
__global__ void __launch_bounds__(64) landmark_k()
{
    int zz = blockIdx.x;
    int mi = zz & 255, bh = zz >> 8;
    int b = bh >> 3, h = bh & 7;
    int d = threadIdx.x;
    const float* base = g_QKV + (long long)(b * NF + mi * 32) * QD + h * 64 + d;
    float sq = 0.f, sk = 0.f;
    #pragma unroll 8
    for (int il = 0; il < 32; il++) {
        sq += base[(long long)il * QD];
        sk += base[(long long)il * QD + 512];
    }
    long long o = ((long long)bh * LM + mi) * DH + d;
    g_QL[o] = sq * (1.f / 32.f);
    g_KL[o] = sk * (1.f / 32.f);
}

// ------------------------- split-K reduce for AV ----------------------------
__global__ void __launch_bounds__(256) avreduce_k()
{
    int idx = blockIdx.x * 256 + threadIdx.x;
    int bh = idx >> 14;
    int r  = idx & 16383;
    const float* p = g_AVp + ((long long)bh << 17);
    float s = 0.f;
    #pragma unroll
    for (int k = 0; k < KSPL; k++) s += p[(k << 14) + r];
    g_AV[idx] = s;
}

// ------------------------- depthwise conv residual --------------------------
__global__ void __launch_bounds__(256) conv_k(const float* __restrict__ cw)
{
    __shared__ float sv[160 * 64];
    __shared__ float sw[KER];
    int tile = blockIdx.x;
    int bh = blockIdx.y;
    int b = bh >> 3, h = bh & 7;
    int n0 = tile * 128;
    int t = threadIdx.x;
    if (t < KER) sw[t] = cw[h * KER + t];
    for (int idx = t; idx < 160 * 64; idx += 256) {
        int r = idx >> 6, d = idx & 63;
        int nn = n0 - 16 + r;
        float v = 0.f;
        if (nn >= 0 && nn < NF) v = g_QKV[(long long)(b * NF + nn) * QD + 1024 + h * 64 + d];
        sv[idx] = v;
    }
    __syncthreads();
    int d = t & 63, r0 = t >> 6;
    for (int rr = r0; rr < 128; rr += 4) {
        float a = 0.f;
        #pragma unroll
        for (int k = 0; k < KER; k++) a += sv[(rr + k) * 64 + d] * sw[k];
        long long o = ((long long)bh * NF + n0 + rr) * DH + d;
        g_OH[o] += a;
    }
}

// ------------------------- final LN + head ----------------------------------
__global__ void __launch_bounds__(256) final_k(const float* __restrict__ fg, const float* __restrict__ fb,
                                               const float* __restrict__ w2, const float* __restrict__ b2,
                                               float* __restrict__ out)
{
    int b = blockIdx.x;
    const float* x = g_X + (long long)b * NF * DIMM;
    int t = threadIdx.x;
    float v0 = x[t], v1 = x[t + 256];
    float mu  = blockReduce(v0 + v1, false) * (1.f / 512.f);
    float d0 = v0 - mu, d1 = v1 - mu;
    float var = blockReduce(d0 * d0 + d1 * d1, false) * (1.f / 512.f);
    float inv = rsqrtf(var + 1e-5f);
    float n0 = d0 * inv * fg[t]       + fb[t];
    float n1 = d1 * inv * fg[t + 256] + fb[t + 256];
    float p0 = n0 * w2[2 * t]     + n1 * w2[2 * (t + 256)];
    float p1 = n0 * w2[2 * t + 1] + n1 * w2[2 * (t + 256) + 1];
    p0 = blockReduce(p0, false);
    p1 = blockReduce(p1, false);
    if (t == 0) {
        out[b * 2 + 0] = p0 + b2[0];
        out[b * 2 + 1] = p1 + b2[1];
    }
}

// ------------------------- host orchestration -------------------------------
static inline void mgemm2(int M, int N, int K,
                          const float* A, int lda, long long sA1, long long sA2, int amode,
                          const float* BT, int ldbt, long long sBT1, long long sBT2,
                          float* C, int ldc, long long sC1, long long sC2,
                          int batch, int ep, const float* bias,
                          float2* RSp = nullptr, long long rsp1 = 0, long long rsp2 = 0)
{
    dim3 g(N >> 7, (M + 127) >> 7, batch);
    if (RSp) {
        cudaFuncSetAttribute(mgemm2_k<1>, cudaFuncAttributeMaxDynamicSharedMemorySize, 98304);
        mgemm2_k<1><<<g, 256, 98304>>>(M, K, A, lda, sA1, sA2, amode, BT, ldbt, sBT1, sBT2,
                                       C, ldc, sC1, sC2, ep, bias, RSp, rsp1, rsp2);
    } else {
        cudaFuncSetAttribute(mgemm2_k<0>, cudaFuncAttributeMaxDynamicSharedMemorySize, 98304);
        mgemm2_k<0><<<g, 256, 98304>>>(M, K, A, lda, sA1, sA2, amode, BT, ldbt, sBT1, sBT2,
                                       C, ldc, sC1, sC2, ep, bias, nullptr, 0, 0);
    }
}

static inline void agemm(int M, int K,
                         const float* A, int lda, long long sA1, long long sA2, long long sA3,
                         const float* B, int ldb, long long sB1, long long sB2, long long sB3,
                         float* C, long long sC1, long long sC2, long long sC3,
                         int SPLIT, int batchZ, float alpha,
                         const float2* rsA, long long rs1, long long rs2, int aexp)
{
    cudaFuncSetAttribute(agemm_k, cudaFuncAttributeMaxDynamicSharedMemorySize, 49664);
    dim3 g(1, M >> 7, batchZ);
    agemm_k<<<g, 256, 49664>>>(M, K, A, lda, sA1, sA2, sA3, B, ldb, sB1, sB2, sB3,
                               C, sC1, sC2, sC3, SPLIT, alpha, rsA, rs1, rs2, aexp);
}

extern "C" void kernel_launch(void* const* d_in, const int* in_sizes, int n_in,
                              void* d_out, int out_size)
{
    const float* h_in  = (const float*)d_in[0];
    const float* w1    = (const float*)d_in[1];
    const float* b1    = (const float*)d_in[2];
    const float* clst  = (const float*)d_in[3];
    const float* ln_g  = (const float*)d_in[4];
    const float* ln_b  = (const float*)d_in[5];
    const float* wqkv  = (const float*)d_in[6];
    const float* wout  = (const float*)d_in[7];
    const float* bout  = (const float*)d_in[8];
    const float* cw    = (const float*)d_in[9];
    const float* fg    = (const float*)d_in[10];
    const float* fb    = (const float*)d_in[11];
    const float* w2    = (const float*)d_in[12];
    const float* b2    = (const float*)d_in[13];
    float* out = (float*)d_out;

    float *X, *XN, *QKV, *QL, *KL, *S1, *S2, *S3, *Z, *AV, *AVp, *ZAV, *OH, *WT;
    float2 *RS1, *RS3, *RSp;
    cudaGetSymbolAddress((void**)&X,   g_X);
    cudaGetSymbolAddress((void**)&XN,  g_XN);
    cudaGetSymbolAddress((void**)&QKV, g_QKV);
    cudaGetSymbolAddress((void**)&QL,  g_QL);
    cudaGetSymbolAddress((void**)&KL,  g_KL);
    cudaGetSymbolAddress((void**)&S1,  g_S1);
    cudaGetSymbolAddress((void**)&S2,  g_S2);
    cudaGetSymbolAddress((void**)&S3,  g_S3);
    cudaGetSymbolAddress((void**)&Z,   g_Zb);
    cudaGetSymbolAddress((void**)&AV,  g_AV);
    cudaGetSymbolAddress((void**)&AVp, g_AVp);
    cudaGetSymbolAddress((void**)&ZAV, g_ZAV);
    cudaGetSymbolAddress((void**)&OH,  g_OH);
    cudaGetSymbolAddress((void**)&WT,  g_WT);
    cudaGetSymbolAddress((void**)&RS1, g_RS1);
    cudaGetSymbolAddress((void**)&RS3, g_RS3);
    cudaGetSymbolAddress((void**)&RSp, g_RSp);

    const long long SQb = (long long)NF * QD;
    const long long S2s = (long long)LM * LM;
    const long long S1s = (long long)NF * LM;
    const long long AVs = (long long)LM * DH;
    const long long OHs = (long long)NF * DH;

    cudaFuncSetAttribute(pinvchain_k, cudaFuncAttributeMaxDynamicSharedMemorySize, 61440);

    // #1: all weight transposes + cls fill
    transAll_k<<<2564, 256>>>(w1, wqkv, wout, clst);

    // #2: input projection
    mgemm2(NB * 8191, DIMM, 1024, h_in, 1024, 0, 0, 0, WT + OW1, 1024, 0, 0,
           X, DIMM, 0, 0, 1, EP_RELU_REMAP, b1);

    for (int L = 0; L < 2; L++) {
        // #3 (L=0): layernorm
        ln_k<<<TOT, 256>>>(X, XN, ln_g + L * DIMM, ln_b + L * DIMM);

        // #4 (L=0): qkv GEMM  <-- ncu capture slot
        mgemm2(TOT, QD, DIMM, XN, DIMM, 0, 0, 0, WT + OQKV(L), DIMM, 0, 0,
               QKV, QD, 0, 0, 1, EP_SCALEQ, nullptr);

        landmark_k<<<NBH * LM, 64>>>();

        // sim2 = QL @ KL^T, softmax
        mgemm2(LM, LM, DH, QL, DH, 8 * AVs, AVs, 0, KL, DH, 8 * AVs, AVs,
               S2, LM, 8 * S2s, S2s, NBH, EP_NONE, nullptr);
        softmax256_k<<<NBH * LM / 8, 256>>>(S2);

        // Moore-Penrose pinv of S2 -> Z : persistent chain
        reset_k<<<1, 1>>>();
        pinvchain_k<<<128, 256, 61440>>>();

        // sim1 = Q @ KL^T (raw) with fused per-tile softmax stats (2/row)
        mgemm2(NF, LM, DH, QKV, QD, SQb, 64, 0, KL, DH, 8 * AVs, AVs,
               S1, LM, 8 * S1s, S1s, NBH, EP_NONE, nullptr,
               RSp, 8LL * NF * 2, (long long)NF * 2);
        combine_k<<<NBH * NF / 8, 256>>>(RSp, RS1, 2);

        // sim3 = QL @ K^T (raw) with fused per-tile softmax stats (64/row)
        mgemm2(LM, NF, DH, QL, DH, 8 * AVs, AVs, 0, QKV + 512, QD, SQb, 64,
               S3, NF, 8 * S1s, S1s, NBH, EP_NONE, nullptr,
               RSp, 8LL * LM * 64, (long long)LM * 64);
        combine_k<<<NBH * LM / 8, 256>>>(RSp, RS3, 64);

        // AV = softmax(sim3) @ V  (tensor, exp fused, split-K by 8)
        agemm(LM, NF / KSPL,
              S3, NF, 8 * S1s, S1s, 1024,
              QKV + 1024, QD, SQb, 64, 1024LL * QD,
              AVp, 64 * AVs, 8 * AVs, AVs,
              KSPL, NBH * KSPL, 1.f, RS3, 8 * LM, LM, 1);
        avreduce_k<<<1024, 256>>>();

        // ZAV = Z @ AV  (tensor)
        agemm(LM, LM,
              Z, LM, 8 * S2s, S2s, 0,
              AV, DH, 8 * AVs, AVs, 0,
              ZAV, 8 * AVs, AVs, 0,
              1, NBH, 1.f, RS3, 0, 0, 0);

        // OH = softmax(sim1) @ ZAV  (tensor, exp fused)
        agemm(NF, LM,
              S1, LM, 8 * S1s, S1s, 0,
              ZAV, DH, 8 * AVs, AVs, 0,
              OH, 8 * OHs, OHs, 0,
              1, NBH, 1.f, RS1, 8LL * NF, NF, 1);

        // OH += depthwise conv residual of V
        { dim3 g(NF / 128, NBH); conv_k<<<g, 256>>>(cw + L * NH * KER); }

        // X += OH(head-layout) @ Wout + bout
        mgemm2(TOT, DIMM, DIMM, OH, 0, 0, 0, 1, WT + OOUT(L), DIMM, 0, 0,
               X, DIMM, 0, 0, 1, EP_ADDBIAS, bout + L * DIMM);
    }

    final_k<<<NB, 256>>>(fg, fb, w2, b2, out);
}